// round 1
// baseline (speedup 1.0000x reference)
#include <cuda_runtime.h>
#include <math.h>
#include <stdint.h>

// Problem constants (fixed by the dataset)
static constexpr int NMAXN = 8000;
static constexpr int EMAX  = 96000;

// Scratch layout (offsets in floats) inside one big __device__ buffer
static constexpr size_t NS_OFF    = 0;                                   // ns:   N x 128
static constexpr size_t NV_OFF    = NS_OFF    + (size_t)NMAXN * 128;     // nv:   N x 192
static constexpr size_t M0IN_OFF  = NV_OFF    + (size_t)NMAXN * 192;     // m0in: E x 576
static constexpr size_t VF12_OFF  = M0IN_OFF  + (size_t)EMAX  * 576;     // vf12: E x 384
static constexpr size_t R_OFF     = VF12_OFF  + (size_t)EMAX  * 384;     // R:    E x 9
static constexpr size_t M0OUT_OFF = R_OFF     + (size_t)EMAX  * 9;       // m0out:E x 256
static constexpr size_t VPM_OFF   = M0OUT_OFF + (size_t)EMAX  * 256;     // vpm:  E x 128
static constexpr size_t MSGS_OFF  = VPM_OFF   + (size_t)EMAX  * 128;     // msgs: E x 128
static constexpr size_t MSGV_OFF  = MSGS_OFF  + (size_t)EMAX  * 128;     // msgv: 3 x E x 64
static constexpr size_t LPS_OFF   = MSGV_OFF  + (size_t)3*EMAX* 64;      // lps:  E x 128
static constexpr size_t LPV_OFF   = LPS_OFF   + (size_t)EMAX  * 128;     // lpv:  3 x E x 64
static constexpr size_t WENV_OFF  = LPV_OFF   + (size_t)3*EMAX* 64;      // wenv: E x 192
static constexpr size_t AGG_OFF   = WENV_OFF  + (size_t)EMAX  * 192;     // agg:  N x 320
static constexpr size_t W1C_OFF   = AGG_OFF   + (size_t)NMAXN * 320;     // w1c:  384 x 128
static constexpr size_t TOTAL_F   = W1C_OFF   + (size_t)384 * 128;

__device__ __align__(256) float g_buf[TOTAL_F];

// ---------------------------------------------------------------------------
// zero kernel
__global__ void zero_kernel(float* __restrict__ p, size_t n) {
    size_t i = (size_t)blockIdx.x * blockDim.x + threadIdx.x;
    if (i < n) p[i] = 0.0f;
}

// ---------------------------------------------------------------------------
// Node separable layernorm: warp per node
__global__ void node_ln_kernel(const float* __restrict__ nf,
                               const float* __restrict__ ws, const float* __restrict__ bs,
                               const float* __restrict__ wv,
                               float* __restrict__ ns, float* __restrict__ nv, int N) {
    int node = (blockIdx.x * blockDim.x + threadIdx.x) >> 5;
    int lane = threadIdx.x & 31;
    if (node >= N) return;
    const float* row = nf + (size_t)node * 320;
    float s[4]; float sum = 0.f;
#pragma unroll
    for (int i = 0; i < 4; i++) { s[i] = row[lane + 32*i]; sum += s[i]; }
#pragma unroll
    for (int o = 16; o; o >>= 1) sum += __shfl_xor_sync(0xffffffffu, sum, o);
    float mu = sum * (1.f/128.f);
    float var = 0.f;
#pragma unroll
    for (int i = 0; i < 4; i++) { s[i] -= mu; var += s[i]*s[i]; }
#pragma unroll
    for (int o = 16; o; o >>= 1) var += __shfl_xor_sync(0xffffffffu, var, o);
    float rs = rsqrtf(var * (1.f/128.f) + 1e-8f);
#pragma unroll
    for (int i = 0; i < 4; i++) {
        int c = lane + 32*i;
        ns[(size_t)node*128 + c] = s[i]*rs*ws[c] + bs[c];
    }
    float v[6]; float vs = 0.f;
#pragma unroll
    for (int i = 0; i < 6; i++) { v[i] = row[128 + lane + 32*i]; vs += v[i]*v[i]; }
#pragma unroll
    for (int o = 16; o; o >>= 1) vs += __shfl_xor_sync(0xffffffffu, vs, o);
    float rv = rsqrtf(vs * (1.f/192.f) + 1e-8f);
#pragma unroll
    for (int i = 0; i < 6; i++) {
        int c = lane + 32*i;
        nv[(size_t)node*192 + c] = v[i]*rv*wv[c/3];
    }
}

// ---------------------------------------------------------------------------
// Edge prep: edge LN, gather neighbor features, edge frame, rotate vectors.
// Warp per edge, 8 warps/block.
__global__ void edge_prep_kernel(const float* __restrict__ ef, const int* __restrict__ ei,
                                 const int* __restrict__ act, const float* __restrict__ evec,
                                 const float* __restrict__ ws, const float* __restrict__ bs,
                                 const float* __restrict__ wv,
                                 const float* __restrict__ ns, const float* __restrict__ nv,
                                 float* __restrict__ m0in, float* __restrict__ vf12,
                                 float* __restrict__ Rout, int E, int Etot) {
    __shared__ float evs[8][192];
    int wi = threadIdx.x >> 5;
    int lane = threadIdx.x & 31;
    int e = blockIdx.x * 8 + wi;
    if (e >= E) return;
    int ae = act[e];
    int ctr = ei[ae], nbr = ei[Etot + ae];
    const float* row = ef + (size_t)e * 320;

    // scalar LN of edge features -> m0in cols [128,256)
    float s[4]; float sum = 0.f;
#pragma unroll
    for (int i = 0; i < 4; i++) { s[i] = row[lane + 32*i]; sum += s[i]; }
#pragma unroll
    for (int o = 16; o; o >>= 1) sum += __shfl_xor_sync(0xffffffffu, sum, o);
    float mu = sum * (1.f/128.f);
    float var = 0.f;
#pragma unroll
    for (int i = 0; i < 4; i++) { s[i] -= mu; var += s[i]*s[i]; }
#pragma unroll
    for (int o = 16; o; o >>= 1) var += __shfl_xor_sync(0xffffffffu, var, o);
    float rs = rsqrtf(var * (1.f/128.f) + 1e-8f);

    float* m0 = m0in + (size_t)e * 576;
#pragma unroll
    for (int i = 0; i < 4; i++) {
        int c = lane + 32*i;
        m0[c]       = ns[(size_t)ctr*128 + c];
        m0[128 + c] = s[i]*rs*ws[c] + bs[c];
        m0[256 + c] = ns[(size_t)nbr*128 + c];
    }

    // vector LN of edge features -> staged in smem
    float v[6]; float vs = 0.f;
#pragma unroll
    for (int i = 0; i < 6; i++) { v[i] = row[128 + lane + 32*i]; vs += v[i]*v[i]; }
#pragma unroll
    for (int o = 16; o; o >>= 1) vs += __shfl_xor_sync(0xffffffffu, vs, o);
    float rv = rsqrtf(vs * (1.f/192.f) + 1e-8f);
#pragma unroll
    for (int i = 0; i < 6; i++) {
        int c = lane + 32*i;
        evs[wi][c] = v[i]*rv*wv[c/3];
    }
    __syncwarp();

    // edge frame (all lanes redundantly)
    float e0 = evec[(size_t)ae*3], e1 = evec[(size_t)ae*3+1], e2 = evec[(size_t)ae*3+2];
    float rn = rsqrtf(e0*e0 + e1*e1 + e2*e2 + 1e-8f);
    float ax = e0*rn, ay = e1*rn, az = e2*rn;
    float refx = (fabsf(ax) < 0.9f) ? 1.f : 0.f;
    float refy = 1.f - refx;
    // b = cross(a, ref); ref_z = 0
    float bx = -az*refy;
    float by =  az*refx;
    float bz =  ax*refy - ay*refx;
    float rb = rsqrtf(bx*bx + by*by + bz*bz + 1e-8f);
    bx *= rb; by *= rb; bz *= rb;
    float cx = ay*bz - az*by, cy = az*bx - ax*bz, cz = ax*by - ay*bx;
    if (lane == 0) {
        float* Rp = Rout + (size_t)e * 9;
        Rp[0]=ax; Rp[1]=ay; Rp[2]=az;
        Rp[3]=bx; Rp[4]=by; Rp[5]=bz;
        Rp[6]=cx; Rp[7]=cy; Rp[8]=cz;
    }

    // rotate concatenated vectors: vf0 -> m0in[384+u], vf1/vf2 -> vf12
    float* vf = vf12 + (size_t)e * 384;
#pragma unroll
    for (int i = 0; i < 6; i++) {
        int u = lane + 32*i;
        float vx, vy, vz;
        if (u < 64) {
            const float* p = nv + (size_t)ctr*192 + u*3;
            vx = p[0]; vy = p[1]; vz = p[2];
        } else if (u < 128) {
            const float* p = &evs[wi][(u - 64)*3];
            vx = p[0]; vy = p[1]; vz = p[2];
        } else {
            const float* p = nv + (size_t)nbr*192 + (u - 128)*3;
            vx = p[0]; vy = p[1]; vz = p[2];
        }
        m0[384 + u] = ax*vx + ay*vy + az*vz;
        vf[u]       = bx*vx + by*vy + bz*vz;
        vf[192 + u] = cx*vx + cy*vy + cz*vz;
    }
}

// ---------------------------------------------------------------------------
// Build combined complex weight: [[w1r, w1i], [-w1i, w1r]]  (384 x 128)
__global__ void build_w1c_kernel(const float* __restrict__ w1r, const float* __restrict__ w1i,
                                 float* __restrict__ w1c) {
    int idx = blockIdx.x * blockDim.x + threadIdx.x;
    if (idx >= 384*128) return;
    int r = idx / 128, c = idx % 128;
    float val;
    if (r < 192) val = (c < 64) ? w1r[r*64 + c] : w1i[r*64 + (c - 64)];
    else {
        int r2 = r - 192;
        val = (c < 64) ? -w1i[r2*64 + c] : w1r[r2*64 + (c - 64)];
    }
    w1c[idx] = val;
}

// ---------------------------------------------------------------------------
// Generic SGEMM: C[M x Nc] = (A[M x K] @ B[K x Nc]) * scale (+ bias[col]).
// Optional row gather on A via rowidx. BM=BN=128, BK=16, 256 threads, 8x8 microtile.
template<bool GATHER>
__global__ __launch_bounds__(256)
void sgemm_kernel(const float* __restrict__ A, const float* __restrict__ B,
                  float* __restrict__ C, int M, int Nc, int K,
                  float scale, const float* __restrict__ bias,
                  const int* __restrict__ rowidx, int lda) {
    __shared__ float As[16][128];
    __shared__ float Bs[16][128];
    int bm = blockIdx.x * 128, bn = blockIdx.y * 128;
    int tid = threadIdx.x;
    int tr = tid / 16, tc = tid % 16;
    float acc[8][8];
#pragma unroll
    for (int i = 0; i < 8; i++)
#pragma unroll
        for (int j = 0; j < 8; j++) acc[i][j] = 0.f;

    for (int k0 = 0; k0 < K; k0 += 16) {
        // load A tile (128 rows x 16 k), store transposed
#pragma unroll
        for (int it = 0; it < 2; it++) {
            int id = tid + 256*it;
            int row = id & 127, kc = id >> 7;
            int grow = bm + row;
            float4 va = make_float4(0.f, 0.f, 0.f, 0.f);
            if (grow < M) {
                const float* ap = GATHER ? (A + (size_t)rowidx[grow]*lda)
                                         : (A + (size_t)grow*lda);
                va = *(const float4*)(ap + k0 + kc*4);
            }
            As[kc*4+0][row] = va.x; As[kc*4+1][row] = va.y;
            As[kc*4+2][row] = va.z; As[kc*4+3][row] = va.w;
        }
        // load B tile (16 k x 128 cols)
#pragma unroll
        for (int it = 0; it < 2; it++) {
            int id = tid + 256*it;
            int row = id >> 5, nc = id & 31;
            int gn = bn + nc*4;
            float4 vb = make_float4(0.f, 0.f, 0.f, 0.f);
            if (gn < Nc) vb = *(const float4*)(B + (size_t)(k0 + row)*Nc + gn);
            *(float4*)&Bs[row][nc*4] = vb;
        }
        __syncthreads();
#pragma unroll
        for (int k = 0; k < 16; k++) {
            float ra[8], rb[8];
            *(float4*)&ra[0] = *(const float4*)&As[k][tr*8];
            *(float4*)&ra[4] = *(const float4*)&As[k][tr*8+4];
            *(float4*)&rb[0] = *(const float4*)&Bs[k][tc*8];
            *(float4*)&rb[4] = *(const float4*)&Bs[k][tc*8+4];
#pragma unroll
            for (int i = 0; i < 8; i++)
#pragma unroll
                for (int j = 0; j < 8; j++)
                    acc[i][j] += ra[i]*rb[j];
        }
        __syncthreads();
    }
#pragma unroll
    for (int i = 0; i < 8; i++) {
        int gr = bm + tr*8 + i;
        if (gr >= M) continue;
#pragma unroll
        for (int j = 0; j < 8; j++) {
            int gc = bn + tc*8 + j;
            if (gc < Nc) {
                float v = acc[i][j] * scale;
                if (bias) v += bias[gc];
                C[(size_t)gr*Nc + gc] = v;
            }
        }
    }
}

// ---------------------------------------------------------------------------
// Edge mid: back-rotate (m0_out_v, vp, vm), gate. Warp per edge.
__global__ void edge_mid_kernel(const float* __restrict__ m0out, const float* __restrict__ vpm,
                                const float* __restrict__ Rin,
                                float* __restrict__ msgs, float* __restrict__ msgv, int E) {
    int e = (blockIdx.x * blockDim.x + threadIdx.x) >> 5;
    int lane = threadIdx.x & 31;
    if (e >= E) return;
    const float* mo = m0out + (size_t)e * 256;
    const float* vp = vpm + (size_t)e * 128;
    const float* Rp = Rin + (size_t)e * 9;
    float R0=Rp[0],R1=Rp[1],R2=Rp[2],R3=Rp[3],R4=Rp[4],R5=Rp[5],R6=Rp[6],R7=Rp[7],R8=Rp[8];
#pragma unroll
    for (int i = 0; i < 4; i++) {
        int c = lane + 32*i;
        float x = mo[c];
        msgs[(size_t)e*128 + c] = x / (1.f + expf(-x));   // silu
    }
#pragma unroll
    for (int i = 0; i < 2; i++) {
        int u = lane + 32*i;
        float i0 = mo[192 + u], i1 = vp[u], i2 = vp[64 + u];
        float sg = 1.f / (1.f + expf(-mo[128 + u]));
        // v_out[u][j] = sum_i R[i][j] * vin[i]  (R^T)
        float o0 = R0*i0 + R3*i1 + R6*i2;
        float o1 = R1*i0 + R4*i1 + R7*i2;
        float o2 = R2*i0 + R5*i1 + R8*i2;
        msgv[(size_t)0*E*64 + (size_t)e*64 + u] = sg*o0;
        msgv[(size_t)1*E*64 + (size_t)e*64 + u] = sg*o1;
        msgv[(size_t)2*E*64 + (size_t)e*64 + u] = sg*o2;
    }
}

// ---------------------------------------------------------------------------
// Final edge epilogue: env weighting + scatter-add to nodes.
__global__ void scatter_kernel(const int* __restrict__ ei, const int* __restrict__ act,
                               const float* __restrict__ lps, const float* __restrict__ lpv,
                               const float* __restrict__ wenv, float* __restrict__ agg,
                               int E, int Etot) {
    size_t i = (size_t)blockIdx.x * blockDim.x + threadIdx.x;
    if (i >= (size_t)E * 320) return;
    int e = (int)(i / 320), c = (int)(i % 320);
    int ctr = ei[act[e]];
    float val;
    if (c < 128) {
        val = lps[(size_t)e*128 + c] * wenv[(size_t)e*192 + c];
    } else {
        int cc = c - 128;
        int k = cc / 3, m = cc - 3*k;
        val = lpv[(size_t)m*E*64 + (size_t)e*64 + k] * wenv[(size_t)e*192 + 128 + k];
    }
    atomicAdd(&agg[(size_t)ctr*320 + c], val * 0.28867513459481287f); // 1/sqrt(12)
}

// ---------------------------------------------------------------------------
// Per-node output: atom-type-indexed matvecs, gate, final linear, residual.
// One block (128 threads) per node.
__global__ void node_out_kernel(const float* __restrict__ nf, const int* __restrict__ at,
                                const float* __restrict__ wss, const float* __restrict__ wsg,
                                const float* __restrict__ wvv,
                                const float* __restrict__ ohlw, const float* __restrict__ ohlb,
                                const float* __restrict__ ohlwv,
                                const float* __restrict__ res,
                                const float* __restrict__ agg,
                                float* __restrict__ out, int N) {
    int n = blockIdx.x;
    if (n >= N) return;
    int tid = threadIdx.x; // 128
    __shared__ float ags[128], agv[192], gs[128], gv[192], tg[64];
    ags[tid] = agg[(size_t)n*320 + tid];
    agv[tid] = agg[(size_t)n*320 + 128 + tid];
    if (tid < 64) agv[128 + tid] = agg[(size_t)n*320 + 256 + tid];
    __syncthreads();
    int t = at[n];
    const float n_ss = 0.011048543456039806f;  // 1/sqrt(128*64)
    const float n_vv = 0.015625f;              // 1/64
    const float isq128 = 0.08838834764831845f; // 1/sqrt(128)

    // t_s -> gs = silu(t_s)
    {
        float acc = 0.f;
        for (int u = 0; u < 128; u++)
            acc += ags[u] * wss[((size_t)u*64 + t)*128 + tid];
        float ts = acc * n_ss;
        gs[tid] = ts / (1.f + expf(-ts));
    }
    // t_g -> tg = sigmoid(t_g)
    if (tid < 64) {
        float acc = 0.f;
        for (int u = 0; u < 128; u++)
            acc += ags[u] * wsg[((size_t)u*64 + t)*64 + tid];
        tg[tid] = 1.f / (1.f + expf(-acc * n_ss));
    }
    __syncthreads();
    // t_v -> gv
    for (int idx = tid; idx < 192; idx += 128) {
        int k = idx / 3, m = idx - 3*k;
        float acc = 0.f;
        for (int u = 0; u < 64; u++)
            acc += agv[u*3 + m] * wvv[((size_t)u*64 + t)*64 + k];
        gv[idx] = tg[k] * acc * n_vv;
    }
    __syncthreads();

    float alpha = 1.f / (1.f + expf(-res[0]));
    float beta = 1.f - alpha;
    // os
    {
        float acc = 0.f;
        for (int u = 0; u < 128; u++)
            acc += gs[u] * ohlw[(size_t)u*128 + tid];
        float osv = acc * isq128 + ohlb[tid];
        out[(size_t)n*320 + tid] = alpha * nf[(size_t)n*320 + tid] + beta * osv;
    }
    // ov
    for (int idx = tid; idx < 192; idx += 128) {
        int k = idx / 3, m = idx - 3*k;
        float acc = 0.f;
        for (int u = 0; u < 64; u++)
            acc += gv[u*3 + m] * ohlwv[(size_t)u*64 + k];
        float ovv = acc * 0.125f;
        out[(size_t)n*320 + 128 + idx] = alpha * nf[(size_t)n*320 + 128 + idx] + beta * ovv;
    }
}

// ---------------------------------------------------------------------------
extern "C" void kernel_launch(void* const* d_in, const int* in_sizes, int n_in,
                              void* d_out, int out_size) {
    const float* latents = (const float*)d_in[0];
    const float* nf      = (const float*)d_in[1];
    const float* ef      = (const float*)d_in[2];
    const int*   at      = (const int*)  d_in[3];
    // d_in[4] = node_onehot (unused; atom_type is exact)
    const int*   ei      = (const int*)  d_in[5];
    const float* evec    = (const float*)d_in[6];
    const int*   act     = (const int*)  d_in[7];
    const float* snws    = (const float*)d_in[8];
    const float* snbs    = (const float*)d_in[9];
    const float* snwv    = (const float*)d_in[10];
    const float* sews    = (const float*)d_in[11];
    const float* sebs    = (const float*)d_in[12];
    const float* sewv    = (const float*)d_in[13];
    const float* so2w0   = (const float*)d_in[14];
    const float* so2w1r  = (const float*)d_in[15];
    const float* so2w1i  = (const float*)d_in[16];
    const float* envw    = (const float*)d_in[17];
    const float* lpws    = (const float*)d_in[18];
    const float* lpbs    = (const float*)d_in[19];
    const float* lpwv    = (const float*)d_in[20];
    const float* ohwss   = (const float*)d_in[21];
    const float* ohwsg   = (const float*)d_in[22];
    const float* ohwvv   = (const float*)d_in[23];
    const float* ohlws   = (const float*)d_in[24];
    const float* ohlbs   = (const float*)d_in[25];
    const float* ohlwv   = (const float*)d_in[26];
    const float* resp    = (const float*)d_in[27];

    int N    = in_sizes[1] / 320;
    int E    = in_sizes[7];
    int Etot = in_sizes[5] / 2;

    float* base = nullptr;
    cudaGetSymbolAddress((void**)&base, g_buf);
    float* ns    = base + NS_OFF;
    float* nv    = base + NV_OFF;
    float* m0in  = base + M0IN_OFF;
    float* vf12  = base + VF12_OFF;
    float* Rbuf  = base + R_OFF;
    float* m0out = base + M0OUT_OFF;
    float* vpm   = base + VPM_OFF;
    float* msgs  = base + MSGS_OFF;
    float* msgv  = base + MSGV_OFF;
    float* lps   = base + LPS_OFF;
    float* lpv   = base + LPV_OFF;
    float* wenv  = base + WENV_OFF;
    float* agg   = base + AGG_OFF;
    float* w1c   = base + W1C_OFF;

    const float isq576 = 0.041666666666666664f; // 1/24
    const float isq192 = 0.07216878364870323f;
    const float isq128 = 0.08838834764831845f;

    // 1. zero agg
    zero_kernel<<<(int)(((size_t)N*320 + 255)/256), 256>>>(agg, (size_t)N*320);
    // 2. node layernorm
    node_ln_kernel<<<(N + 7)/8, 256>>>(nf, snws, snbs, snwv, ns, nv, N);
    // 3. combined complex weight
    build_w1c_kernel<<<(384*128 + 255)/256, 256>>>(so2w1r, so2w1i, w1c);
    // 4. edge prep
    edge_prep_kernel<<<(E + 7)/8, 256>>>(ef, ei, act, evec, sews, sebs, sewv,
                                         ns, nv, m0in, vf12, Rbuf, E, Etot);
    // 5. big SO2 GEMM: m0out = m0in @ so2_w0 / sqrt(576)
    {
        dim3 g((E + 127)/128, (256 + 127)/128);
        sgemm_kernel<false><<<g, 256>>>(m0in, so2w0, m0out, E, 256, 576, isq576,
                                        nullptr, nullptr, 576);
    }
    // 6. complex pair GEMM: vpm = vf12 @ w1c / sqrt(192)
    {
        dim3 g((E + 127)/128, 1);
        sgemm_kernel<false><<<g, 256>>>(vf12, w1c, vpm, E, 128, 384, isq192,
                                        nullptr, nullptr, 384);
    }
    // 7. back-rotation + gating
    edge_mid_kernel<<<(E + 7)/8, 256>>>(m0out, vpm, Rbuf, msgs, msgv, E);
    // 8. lp scalar GEMM: lps = msgs @ lp_ws / sqrt(128) + lp_bs
    {
        dim3 g((E + 127)/128, 1);
        sgemm_kernel<false><<<g, 256>>>(msgs, lpws, lps, E, 128, 128, isq128,
                                        lpbs, nullptr, 128);
    }
    // 9. lp vector GEMMs (3 component planes): lpv[m] = msgv[m] @ lp_wv / 8
    for (int m = 0; m < 3; m++) {
        dim3 g((E + 127)/128, 1);
        sgemm_kernel<false><<<g, 256>>>(msgv + (size_t)m*E*64, lpwv,
                                        lpv + (size_t)m*E*64, E, 64, 64, 0.125f,
                                        nullptr, nullptr, 64);
    }
    // 10. env GEMM with row gather: wenv = latents[act] @ env_w / sqrt(128)
    {
        dim3 g((E + 127)/128, (192 + 127)/128);
        sgemm_kernel<true><<<g, 256>>>(latents, envw, wenv, E, 192, 128, isq128,
                                       nullptr, act, 128);
    }
    // 11. env-weight + scatter add
    scatter_kernel<<<(int)(((size_t)E*320 + 255)/256), 256>>>(ei, act, lps, lpv,
                                                              wenv, agg, E, Etot);
    // 12. per-node output
    node_out_kernel<<<N, 128>>>(nf, at, ohwss, ohwsg, ohwvv,
                                ohlws, ohlbs, ohlwv, resp, agg, (float*)d_out, N);
}

// round 2
// speedup vs baseline: 1.9185x; 1.9185x over previous
#include <cuda_runtime.h>
#include <math.h>
#include <stdint.h>

// Problem constants (fixed by the dataset)
static constexpr int NMAXN = 8000;
static constexpr int EMAX  = 96000;

// Scratch layout (offsets in floats) inside one big __device__ buffer
static constexpr size_t NS_OFF    = 0;                                   // ns:   N x 128
static constexpr size_t NV_OFF    = NS_OFF    + (size_t)NMAXN * 128;     // nv:   N x 192
static constexpr size_t M0IN_OFF  = NV_OFF    + (size_t)NMAXN * 192;     // m0in: E x 576
static constexpr size_t VF12_OFF  = M0IN_OFF  + (size_t)EMAX  * 576;     // vf12: E x 384
static constexpr size_t R_OFF     = VF12_OFF  + (size_t)EMAX  * 384;     // R:    E x 9
static constexpr size_t M0OUT_OFF = R_OFF     + (size_t)EMAX  * 9;       // m0out:E x 256
static constexpr size_t VPM_OFF   = M0OUT_OFF + (size_t)EMAX  * 256;     // vpm:  E x 128
static constexpr size_t MSGS_OFF  = VPM_OFF   + (size_t)EMAX  * 128;     // msgs: E x 128
static constexpr size_t MSGV_OFF  = MSGS_OFF  + (size_t)EMAX  * 128;     // msgv: 3 x E x 64
static constexpr size_t LPS_OFF   = MSGV_OFF  + (size_t)3*EMAX* 64;      // lps:  E x 128
static constexpr size_t LPV_OFF   = LPS_OFF   + (size_t)EMAX  * 128;     // lpv:  3 x E x 64
static constexpr size_t WENV_OFF  = LPV_OFF   + (size_t)3*EMAX* 64;      // wenv: E x 192
static constexpr size_t AGG_OFF   = WENV_OFF  + (size_t)EMAX  * 192;     // agg:  N x 320
static constexpr size_t W1C_OFF   = AGG_OFF   + (size_t)NMAXN * 320;     // w1c:  384 x 128
static constexpr size_t TOTAL_F   = W1C_OFF   + (size_t)384 * 128;

__device__ __align__(256) float g_buf[TOTAL_F];

// ---------------------------------------------------------------------------
__global__ void zero_kernel(float* __restrict__ p, size_t n) {
    size_t i = (size_t)blockIdx.x * blockDim.x + threadIdx.x;
    if (i < n) p[i] = 0.0f;
}

// ---------------------------------------------------------------------------
// Node separable layernorm: warp per node
__global__ void node_ln_kernel(const float* __restrict__ nf,
                               const float* __restrict__ ws, const float* __restrict__ bs,
                               const float* __restrict__ wv,
                               float* __restrict__ ns, float* __restrict__ nv, int N) {
    int node = (blockIdx.x * blockDim.x + threadIdx.x) >> 5;
    int lane = threadIdx.x & 31;
    if (node >= N) return;
    const float* row = nf + (size_t)node * 320;
    float s[4]; float sum = 0.f;
#pragma unroll
    for (int i = 0; i < 4; i++) { s[i] = row[lane + 32*i]; sum += s[i]; }
#pragma unroll
    for (int o = 16; o; o >>= 1) sum += __shfl_xor_sync(0xffffffffu, sum, o);
    float mu = sum * (1.f/128.f);
    float var = 0.f;
#pragma unroll
    for (int i = 0; i < 4; i++) { s[i] -= mu; var += s[i]*s[i]; }
#pragma unroll
    for (int o = 16; o; o >>= 1) var += __shfl_xor_sync(0xffffffffu, var, o);
    float rs = rsqrtf(var * (1.f/128.f) + 1e-8f);
#pragma unroll
    for (int i = 0; i < 4; i++) {
        int c = lane + 32*i;
        ns[(size_t)node*128 + c] = s[i]*rs*ws[c] + bs[c];
    }
    float v[6]; float vs = 0.f;
#pragma unroll
    for (int i = 0; i < 6; i++) { v[i] = row[128 + lane + 32*i]; vs += v[i]*v[i]; }
#pragma unroll
    for (int o = 16; o; o >>= 1) vs += __shfl_xor_sync(0xffffffffu, vs, o);
    float rv = rsqrtf(vs * (1.f/192.f) + 1e-8f);
#pragma unroll
    for (int i = 0; i < 6; i++) {
        int c = lane + 32*i;
        nv[(size_t)node*192 + c] = v[i]*rv*wv[c/3];
    }
}

// ---------------------------------------------------------------------------
// Edge prep: edge LN, gather neighbor features, edge frame, rotate vectors.
__global__ void edge_prep_kernel(const float* __restrict__ ef, const int* __restrict__ ei,
                                 const int* __restrict__ act, const float* __restrict__ evec,
                                 const float* __restrict__ ws, const float* __restrict__ bs,
                                 const float* __restrict__ wv,
                                 const float* __restrict__ ns, const float* __restrict__ nv,
                                 float* __restrict__ m0in, float* __restrict__ vf12,
                                 float* __restrict__ Rout, int E, int Etot) {
    __shared__ float evs[8][192];
    int wi = threadIdx.x >> 5;
    int lane = threadIdx.x & 31;
    int e = blockIdx.x * 8 + wi;
    if (e >= E) return;
    int ae = act[e];
    int ctr = ei[ae], nbr = ei[Etot + ae];
    const float* row = ef + (size_t)e * 320;

    float s[4]; float sum = 0.f;
#pragma unroll
    for (int i = 0; i < 4; i++) { s[i] = row[lane + 32*i]; sum += s[i]; }
#pragma unroll
    for (int o = 16; o; o >>= 1) sum += __shfl_xor_sync(0xffffffffu, sum, o);
    float mu = sum * (1.f/128.f);
    float var = 0.f;
#pragma unroll
    for (int i = 0; i < 4; i++) { s[i] -= mu; var += s[i]*s[i]; }
#pragma unroll
    for (int o = 16; o; o >>= 1) var += __shfl_xor_sync(0xffffffffu, var, o);
    float rs = rsqrtf(var * (1.f/128.f) + 1e-8f);

    float* m0 = m0in + (size_t)e * 576;
#pragma unroll
    for (int i = 0; i < 4; i++) {
        int c = lane + 32*i;
        m0[c]       = ns[(size_t)ctr*128 + c];
        m0[128 + c] = s[i]*rs*ws[c] + bs[c];
        m0[256 + c] = ns[(size_t)nbr*128 + c];
    }

    float v[6]; float vs = 0.f;
#pragma unroll
    for (int i = 0; i < 6; i++) { v[i] = row[128 + lane + 32*i]; vs += v[i]*v[i]; }
#pragma unroll
    for (int o = 16; o; o >>= 1) vs += __shfl_xor_sync(0xffffffffu, vs, o);
    float rv = rsqrtf(vs * (1.f/192.f) + 1e-8f);
#pragma unroll
    for (int i = 0; i < 6; i++) {
        int c = lane + 32*i;
        evs[wi][c] = v[i]*rv*wv[c/3];
    }
    __syncwarp();

    float e0 = evec[(size_t)ae*3], e1 = evec[(size_t)ae*3+1], e2 = evec[(size_t)ae*3+2];
    float rn = rsqrtf(e0*e0 + e1*e1 + e2*e2 + 1e-8f);
    float ax = e0*rn, ay = e1*rn, az = e2*rn;
    float refx = (fabsf(ax) < 0.9f) ? 1.f : 0.f;
    float refy = 1.f - refx;
    float bx = -az*refy;
    float by =  az*refx;
    float bz =  ax*refy - ay*refx;
    float rb = rsqrtf(bx*bx + by*by + bz*bz + 1e-8f);
    bx *= rb; by *= rb; bz *= rb;
    float cx = ay*bz - az*by, cy = az*bx - ax*bz, cz = ax*by - ay*bx;
    if (lane == 0) {
        float* Rp = Rout + (size_t)e * 9;
        Rp[0]=ax; Rp[1]=ay; Rp[2]=az;
        Rp[3]=bx; Rp[4]=by; Rp[5]=bz;
        Rp[6]=cx; Rp[7]=cy; Rp[8]=cz;
    }

    float* vf = vf12 + (size_t)e * 384;
#pragma unroll
    for (int i = 0; i < 6; i++) {
        int u = lane + 32*i;
        float vx, vy, vz;
        if (u < 64) {
            const float* p = nv + (size_t)ctr*192 + u*3;
            vx = p[0]; vy = p[1]; vz = p[2];
        } else if (u < 128) {
            const float* p = &evs[wi][(u - 64)*3];
            vx = p[0]; vy = p[1]; vz = p[2];
        } else {
            const float* p = nv + (size_t)nbr*192 + (u - 128)*3;
            vx = p[0]; vy = p[1]; vz = p[2];
        }
        m0[384 + u] = ax*vx + ay*vy + az*vz;
        vf[u]       = bx*vx + by*vy + bz*vz;
        vf[192 + u] = cx*vx + cy*vy + cz*vz;
    }
}

// ---------------------------------------------------------------------------
// Build combined complex weight: [[w1r, w1i], [-w1i, w1r]]  (384 x 128)
__global__ void build_w1c_kernel(const float* __restrict__ w1r, const float* __restrict__ w1i,
                                 float* __restrict__ w1c) {
    int idx = blockIdx.x * blockDim.x + threadIdx.x;
    if (idx >= 384*128) return;
    int r = idx / 128, c = idx % 128;
    float val;
    if (r < 192) val = (c < 64) ? w1r[r*64 + c] : w1i[r*64 + (c - 64)];
    else {
        int r2 = r - 192;
        val = (c < 64) ? -w1i[r2*64 + c] : w1r[r2*64 + (c - 64)];
    }
    w1c[idx] = val;
}

// ---------------------------------------------------------------------------
// TF32 tensor-core GEMM: C[M x Nc] = (A[M x K] @ B[K x Nc]) * scale (+bias).
// BM=128, BN=128, BK=16, 256 threads, 8 warps of 64x32 warp tiles,
// mma.sync.m16n8k8.tf32 with fp32 accumulate, double-buffered smem.
__device__ __forceinline__ uint32_t f2tf32(float x) {
    uint32_t r; asm("cvt.rna.tf32.f32 %0, %1;" : "=r"(r) : "f"(x)); return r;
}
__device__ __forceinline__ float f2tf32f(float x) {
    return __uint_as_float(f2tf32(x));
}

template<bool GATHER>
__global__ __launch_bounds__(256)
void mma_gemm_kernel(const float* __restrict__ A, const float* __restrict__ B,
                     float* __restrict__ C, int M, int Nc, int K,
                     float scale, const float* __restrict__ bias,
                     const int* __restrict__ rowidx, int lda) {
    __shared__ float As[2][16][136];   // [buf][k][m], pad -> conflict-free frag LDS
    __shared__ float Bs[2][16][136];   // [buf][k][n]

    const int tid  = threadIdx.x;
    const int lane = tid & 31;
    const int wid  = tid >> 5;
    const int g = lane >> 2, t = lane & 3;
    const int wm = (wid >> 2) * 64;    // 2 warp rows
    const int wn = (wid & 3) * 32;     // 4 warp cols
    const int bm = blockIdx.x * 128, bn = blockIdx.y * 128;

    // Precompute per-thread gmem addresses (loop-invariant)
    // A: id in [0,512): row = id&127, q = id>>7 ; loads float4 at [row][k0+4q]
    const float* aptr[2];
    int arow[2], aq[2];
#pragma unroll
    for (int it = 0; it < 2; it++) {
        int id = tid + 256*it;
        int row = id & 127, q = id >> 7;
        arow[it] = row; aq[it] = q;
        int grow = bm + row;
        if (grow >= M) grow = M - 1;   // clamp (stores are guarded)
        const float* ap = GATHER ? (A + (size_t)rowidx[grow]*lda)
                                 : (A + (size_t)grow*lda);
        aptr[it] = ap + q*4;
    }
    // B: id in [0,512): r = id>>5, c4 = id&31 ; loads float4 at [k0+r][4c4]
    const float* bptr[2];
    int br_[2], bc4[2]; bool bok[2];
#pragma unroll
    for (int it = 0; it < 2; it++) {
        int id = tid + 256*it;
        int r = id >> 5, c4 = id & 31;
        br_[it] = r; bc4[it] = c4;
        int gn = bn + 4*c4;
        bok[it] = (gn < Nc);
        bptr[it] = B + (size_t)r*Nc + gn;
    }

    float acc[4][4][4];
#pragma unroll
    for (int mi = 0; mi < 4; mi++)
#pragma unroll
        for (int ni = 0; ni < 4; ni++)
#pragma unroll
            for (int j = 0; j < 4; j++) acc[mi][ni][j] = 0.f;

    const int kTiles = K >> 4;
    float4 ar[2], brv[2];

    // prologue: load tile 0
#pragma unroll
    for (int it = 0; it < 2; it++) {
        ar[it]  = *(const float4*)(aptr[it]);
        brv[it] = bok[it] ? *(const float4*)(bptr[it]) : make_float4(0.f,0.f,0.f,0.f);
    }
#pragma unroll
    for (int it = 0; it < 2; it++) {
        int kq = aq[it]*4, row = arow[it];
        As[0][kq+0][row] = f2tf32f(ar[it].x);
        As[0][kq+1][row] = f2tf32f(ar[it].y);
        As[0][kq+2][row] = f2tf32f(ar[it].z);
        As[0][kq+3][row] = f2tf32f(ar[it].w);
        float4 tb = make_float4(f2tf32f(brv[it].x), f2tf32f(brv[it].y),
                                f2tf32f(brv[it].z), f2tf32f(brv[it].w));
        *(float4*)&Bs[0][br_[it]][4*bc4[it]] = tb;
    }
    __syncthreads();

    for (int kt = 0; kt < kTiles; kt++) {
        int cur = kt & 1;
        // prefetch next tile into regs
        if (kt + 1 < kTiles) {
            int k0 = (kt + 1) << 4;
#pragma unroll
            for (int it = 0; it < 2; it++) {
                ar[it]  = *(const float4*)(aptr[it] + k0);
                brv[it] = bok[it] ? *(const float4*)(bptr[it] + (size_t)k0*Nc)
                                  : make_float4(0.f,0.f,0.f,0.f);
            }
        }
        // compute on current buffer
#pragma unroll
        for (int k8 = 0; k8 < 2; k8++) {
            const int kb = k8 * 8;
            uint32_t af[4][4], bf[4][2];
#pragma unroll
            for (int mi = 0; mi < 4; mi++) {
                int m = wm + mi*16 + g;
                af[mi][0] = __float_as_uint(As[cur][kb+t  ][m]);
                af[mi][1] = __float_as_uint(As[cur][kb+t  ][m+8]);
                af[mi][2] = __float_as_uint(As[cur][kb+t+4][m]);
                af[mi][3] = __float_as_uint(As[cur][kb+t+4][m+8]);
            }
#pragma unroll
            for (int ni = 0; ni < 4; ni++) {
                int n = wn + ni*8 + g;
                bf[ni][0] = __float_as_uint(Bs[cur][kb+t  ][n]);
                bf[ni][1] = __float_as_uint(Bs[cur][kb+t+4][n]);
            }
#pragma unroll
            for (int mi = 0; mi < 4; mi++)
#pragma unroll
                for (int ni = 0; ni < 4; ni++) {
                    asm volatile(
                        "mma.sync.aligned.m16n8k8.row.col.f32.tf32.tf32.f32 "
                        "{%0,%1,%2,%3}, {%4,%5,%6,%7}, {%8,%9}, {%0,%1,%2,%3};"
                        : "+f"(acc[mi][ni][0]), "+f"(acc[mi][ni][1]),
                          "+f"(acc[mi][ni][2]), "+f"(acc[mi][ni][3])
                        : "r"(af[mi][0]), "r"(af[mi][1]), "r"(af[mi][2]), "r"(af[mi][3]),
                          "r"(bf[ni][0]), "r"(bf[ni][1]));
                }
        }
        // store next tile to other buffer
        if (kt + 1 < kTiles) {
            int nxt = cur ^ 1;
#pragma unroll
            for (int it = 0; it < 2; it++) {
                int kq = aq[it]*4, row = arow[it];
                As[nxt][kq+0][row] = f2tf32f(ar[it].x);
                As[nxt][kq+1][row] = f2tf32f(ar[it].y);
                As[nxt][kq+2][row] = f2tf32f(ar[it].z);
                As[nxt][kq+3][row] = f2tf32f(ar[it].w);
                float4 tb = make_float4(f2tf32f(brv[it].x), f2tf32f(brv[it].y),
                                        f2tf32f(brv[it].z), f2tf32f(brv[it].w));
                *(float4*)&Bs[nxt][br_[it]][4*bc4[it]] = tb;
            }
        }
        __syncthreads();
    }

    // epilogue
#pragma unroll
    for (int mi = 0; mi < 4; mi++) {
        int r0 = bm + wm + mi*16 + g;
#pragma unroll
        for (int ni = 0; ni < 4; ni++) {
            int c = bn + wn + ni*8 + 2*t;
            if (c >= Nc) continue;
            float b0 = bias ? bias[c]   : 0.f;
            float b1 = bias ? bias[c+1] : 0.f;
            if (r0 < M) {
                float2 v = make_float2(acc[mi][ni][0]*scale + b0,
                                       acc[mi][ni][1]*scale + b1);
                *(float2*)&C[(size_t)r0*Nc + c] = v;
            }
            if (r0 + 8 < M) {
                float2 v = make_float2(acc[mi][ni][2]*scale + b0,
                                       acc[mi][ni][3]*scale + b1);
                *(float2*)&C[(size_t)(r0+8)*Nc + c] = v;
            }
        }
    }
}

// ---------------------------------------------------------------------------
// Edge mid: back-rotate (m0_out_v, vp, vm), gate. Warp per edge.
__global__ void edge_mid_kernel(const float* __restrict__ m0out, const float* __restrict__ vpm,
                                const float* __restrict__ Rin,
                                float* __restrict__ msgs, float* __restrict__ msgv, int E) {
    int e = (blockIdx.x * blockDim.x + threadIdx.x) >> 5;
    int lane = threadIdx.x & 31;
    if (e >= E) return;
    const float* mo = m0out + (size_t)e * 256;
    const float* vp = vpm + (size_t)e * 128;
    const float* Rp = Rin + (size_t)e * 9;
    float R0=Rp[0],R1=Rp[1],R2=Rp[2],R3=Rp[3],R4=Rp[4],R5=Rp[5],R6=Rp[6],R7=Rp[7],R8=Rp[8];
#pragma unroll
    for (int i = 0; i < 4; i++) {
        int c = lane + 32*i;
        float x = mo[c];
        msgs[(size_t)e*128 + c] = x / (1.f + expf(-x));   // silu
    }
#pragma unroll
    for (int i = 0; i < 2; i++) {
        int u = lane + 32*i;
        float i0 = mo[192 + u], i1 = vp[u], i2 = vp[64 + u];
        float sg = 1.f / (1.f + expf(-mo[128 + u]));
        float o0 = R0*i0 + R3*i1 + R6*i2;
        float o1 = R1*i0 + R4*i1 + R7*i2;
        float o2 = R2*i0 + R5*i1 + R8*i2;
        msgv[(size_t)0*E*64 + (size_t)e*64 + u] = sg*o0;
        msgv[(size_t)1*E*64 + (size_t)e*64 + u] = sg*o1;
        msgv[(size_t)2*E*64 + (size_t)e*64 + u] = sg*o2;
    }
}

// ---------------------------------------------------------------------------
// Final edge epilogue: env weighting + scatter-add to nodes.
__global__ void scatter_kernel(const int* __restrict__ ei, const int* __restrict__ act,
                               const float* __restrict__ lps, const float* __restrict__ lpv,
                               const float* __restrict__ wenv, float* __restrict__ agg,
                               int E, int Etot) {
    size_t i = (size_t)blockIdx.x * blockDim.x + threadIdx.x;
    if (i >= (size_t)E * 320) return;
    int e = (int)(i / 320), c = (int)(i % 320);
    int ctr = ei[act[e]];
    float val;
    if (c < 128) {
        val = lps[(size_t)e*128 + c] * wenv[(size_t)e*192 + c];
    } else {
        int cc = c - 128;
        int k = cc / 3, m = cc - 3*k;
        val = lpv[(size_t)m*E*64 + (size_t)e*64 + k] * wenv[(size_t)e*192 + 128 + k];
    }
    atomicAdd(&agg[(size_t)ctr*320 + c], val * 0.28867513459481287f); // 1/sqrt(12)
}

// ---------------------------------------------------------------------------
// Per-node output: atom-type-indexed matvecs, gate, final linear, residual.
__global__ void node_out_kernel(const float* __restrict__ nf, const int* __restrict__ at,
                                const float* __restrict__ wss, const float* __restrict__ wsg,
                                const float* __restrict__ wvv,
                                const float* __restrict__ ohlw, const float* __restrict__ ohlb,
                                const float* __restrict__ ohlwv,
                                const float* __restrict__ res,
                                const float* __restrict__ agg,
                                float* __restrict__ out, int N) {
    int n = blockIdx.x;
    if (n >= N) return;
    int tid = threadIdx.x; // 128
    __shared__ float ags[128], agv[192], gs[128], gv[192], tg[64];
    ags[tid] = agg[(size_t)n*320 + tid];
    agv[tid] = agg[(size_t)n*320 + 128 + tid];
    if (tid < 64) agv[128 + tid] = agg[(size_t)n*320 + 256 + tid];
    __syncthreads();
    int t = at[n];
    const float n_ss = 0.011048543456039806f;  // 1/sqrt(128*64)
    const float n_vv = 0.015625f;              // 1/64
    const float isq128 = 0.08838834764831845f; // 1/sqrt(128)

    {
        float acc = 0.f;
        for (int u = 0; u < 128; u++)
            acc += ags[u] * wss[((size_t)u*64 + t)*128 + tid];
        float ts = acc * n_ss;
        gs[tid] = ts / (1.f + expf(-ts));
    }
    if (tid < 64) {
        float acc = 0.f;
        for (int u = 0; u < 128; u++)
            acc += ags[u] * wsg[((size_t)u*64 + t)*64 + tid];
        tg[tid] = 1.f / (1.f + expf(-acc * n_ss));
    }
    __syncthreads();
    for (int idx = tid; idx < 192; idx += 128) {
        int k = idx / 3, m = idx - 3*k;
        float acc = 0.f;
        for (int u = 0; u < 64; u++)
            acc += agv[u*3 + m] * wvv[((size_t)u*64 + t)*64 + k];
        gv[idx] = tg[k] * acc * n_vv;
    }
    __syncthreads();

    float alpha = 1.f / (1.f + expf(-res[0]));
    float beta = 1.f - alpha;
    {
        float acc = 0.f;
        for (int u = 0; u < 128; u++)
            acc += gs[u] * ohlw[(size_t)u*128 + tid];
        float osv = acc * isq128 + ohlb[tid];
        out[(size_t)n*320 + tid] = alpha * nf[(size_t)n*320 + tid] + beta * osv;
    }
    for (int idx = tid; idx < 192; idx += 128) {
        int k = idx / 3, m = idx - 3*k;
        float acc = 0.f;
        for (int u = 0; u < 64; u++)
            acc += gv[u*3 + m] * ohlwv[(size_t)u*64 + k];
        float ovv = acc * 0.125f;
        out[(size_t)n*320 + 128 + idx] = alpha * nf[(size_t)n*320 + 128 + idx] + beta * ovv;
    }
}

// ---------------------------------------------------------------------------
extern "C" void kernel_launch(void* const* d_in, const int* in_sizes, int n_in,
                              void* d_out, int out_size) {
    const float* latents = (const float*)d_in[0];
    const float* nf      = (const float*)d_in[1];
    const float* ef      = (const float*)d_in[2];
    const int*   at      = (const int*)  d_in[3];
    const int*   ei      = (const int*)  d_in[5];
    const float* evec    = (const float*)d_in[6];
    const int*   act     = (const int*)  d_in[7];
    const float* snws    = (const float*)d_in[8];
    const float* snbs    = (const float*)d_in[9];
    const float* snwv    = (const float*)d_in[10];
    const float* sews    = (const float*)d_in[11];
    const float* sebs    = (const float*)d_in[12];
    const float* sewv    = (const float*)d_in[13];
    const float* so2w0   = (const float*)d_in[14];
    const float* so2w1r  = (const float*)d_in[15];
    const float* so2w1i  = (const float*)d_in[16];
    const float* envw    = (const float*)d_in[17];
    const float* lpws    = (const float*)d_in[18];
    const float* lpbs    = (const float*)d_in[19];
    const float* lpwv    = (const float*)d_in[20];
    const float* ohwss   = (const float*)d_in[21];
    const float* ohwsg   = (const float*)d_in[22];
    const float* ohwvv   = (const float*)d_in[23];
    const float* ohlws   = (const float*)d_in[24];
    const float* ohlbs   = (const float*)d_in[25];
    const float* ohlwv   = (const float*)d_in[26];
    const float* resp    = (const float*)d_in[27];

    int N    = in_sizes[1] / 320;
    int E    = in_sizes[7];
    int Etot = in_sizes[5] / 2;

    float* base = nullptr;
    cudaGetSymbolAddress((void**)&base, g_buf);
    float* ns    = base + NS_OFF;
    float* nv    = base + NV_OFF;
    float* m0in  = base + M0IN_OFF;
    float* vf12  = base + VF12_OFF;
    float* Rbuf  = base + R_OFF;
    float* m0out = base + M0OUT_OFF;
    float* vpm   = base + VPM_OFF;
    float* msgs  = base + MSGS_OFF;
    float* msgv  = base + MSGV_OFF;
    float* lps   = base + LPS_OFF;
    float* lpv   = base + LPV_OFF;
    float* wenv  = base + WENV_OFF;
    float* agg   = base + AGG_OFF;
    float* w1c   = base + W1C_OFF;

    const float isq576 = 0.041666666666666664f; // 1/24
    const float isq192 = 0.07216878364870323f;
    const float isq128 = 0.08838834764831845f;

    zero_kernel<<<(int)(((size_t)N*320 + 255)/256), 256>>>(agg, (size_t)N*320);
    node_ln_kernel<<<(N + 7)/8, 256>>>(nf, snws, snbs, snwv, ns, nv, N);
    build_w1c_kernel<<<(384*128 + 255)/256, 256>>>(so2w1r, so2w1i, w1c);
    edge_prep_kernel<<<(E + 7)/8, 256>>>(ef, ei, act, evec, sews, sebs, sewv,
                                         ns, nv, m0in, vf12, Rbuf, E, Etot);
    // big SO2 GEMM: m0out = m0in @ so2_w0 / sqrt(576)
    {
        dim3 g((E + 127)/128, 2);
        mma_gemm_kernel<false><<<g, 256>>>(m0in, so2w0, m0out, E, 256, 576, isq576,
                                           nullptr, nullptr, 576);
    }
    // complex pair GEMM: vpm = vf12 @ w1c / sqrt(192)
    {
        dim3 g((E + 127)/128, 1);
        mma_gemm_kernel<false><<<g, 256>>>(vf12, w1c, vpm, E, 128, 384, isq192,
                                           nullptr, nullptr, 384);
    }
    edge_mid_kernel<<<(E + 7)/8, 256>>>(m0out, vpm, Rbuf, msgs, msgv, E);
    // lp scalar GEMM: lps = msgs @ lp_ws / sqrt(128) + lp_bs
    {
        dim3 g((E + 127)/128, 1);
        mma_gemm_kernel<false><<<g, 256>>>(msgs, lpws, lps, E, 128, 128, isq128,
                                           lpbs, nullptr, 128);
    }
    // lp vector GEMMs merged: (3E x 64) @ (64 x 64) / 8
    {
        dim3 g((3*E + 127)/128, 1);
        mma_gemm_kernel<false><<<g, 256>>>(msgv, lpwv, lpv, 3*E, 64, 64, 0.125f,
                                           nullptr, nullptr, 64);
    }
    // env GEMM with row gather: wenv = latents[act] @ env_w / sqrt(128)
    {
        dim3 g((E + 127)/128, 2);
        mma_gemm_kernel<true><<<g, 256>>>(latents, envw, wenv, E, 192, 128, isq128,
                                          nullptr, act, 128);
    }
    scatter_kernel<<<(int)(((size_t)E*320 + 255)/256), 256>>>(ei, act, lps, lpv,
                                                              wenv, agg, E, Etot);
    node_out_kernel<<<N, 128>>>(nf, at, ohwss, ohwsg, ohwvv,
                                ohlws, ohlbs, ohlwv, resp, agg, (float*)d_out, N);
}

// round 3
// speedup vs baseline: 2.1656x; 1.1288x over previous
#include <cuda_runtime.h>
#include <math.h>
#include <stdint.h>

// Problem constants (fixed by the dataset)
static constexpr int NMAXN = 8000;
static constexpr int EMAX  = 96000;

// Scratch layout (offsets in floats) inside one big __device__ buffer
static constexpr size_t NS_OFF    = 0;                                   // ns:    N x 128
static constexpr size_t NV_OFF    = NS_OFF    + (size_t)NMAXN * 128;     // nv:    N x 192
static constexpr size_t ESV_OFF   = NV_OFF    + (size_t)NMAXN * 192;     // esvf0: E x 320
static constexpr size_t VF12_OFF  = ESV_OFF   + (size_t)EMAX  * 320;     // vf12:  E x 384
static constexpr size_t R_OFF     = VF12_OFF  + (size_t)EMAX  * 384;     // R:     E x 9
static constexpr size_t PROJ_OFF  = R_OFF     + (size_t)EMAX  * 9;       // proj:  N x 512
static constexpr size_t M0OUT_OFF = PROJ_OFF  + (size_t)NMAXN * 512;     // m0out: E x 256
static constexpr size_t VPM_OFF   = M0OUT_OFF + (size_t)EMAX  * 256;     // vpm:   E x 128
static constexpr size_t MSGS_OFF  = VPM_OFF   + (size_t)EMAX  * 128;     // msgs:  E x 128
static constexpr size_t MSGV_OFF  = MSGS_OFF  + (size_t)EMAX  * 128;     // msgv:  3 x E x 64
static constexpr size_t WENV_OFF  = MSGV_OFF  + (size_t)3*EMAX* 64;      // wenv:  E x 192
static constexpr size_t AGG_OFF   = WENV_OFF  + (size_t)EMAX  * 192;     // agg:   N x 320
static constexpr size_t W1C_OFF   = AGG_OFF   + (size_t)NMAXN * 320;     // w1c:   384 x 128
static constexpr size_t WCP_OFF   = W1C_OFF   + (size_t)384 * 128;       // wcp:   128 x 512
static constexpr size_t TOTAL_F   = WCP_OFF   + (size_t)128 * 512;

__device__ __align__(256) float g_buf[TOTAL_F];
__device__ int g_idx[2 * EMAX];   // [0:E) = ctr, [E:2E) = nbr

// ---------------------------------------------------------------------------
__global__ void zero_kernel(float* __restrict__ p, size_t n) {
    size_t i = (size_t)blockIdx.x * blockDim.x + threadIdx.x;
    if (i < n) p[i] = 0.0f;
}

// ---------------------------------------------------------------------------
// Node separable layernorm: warp per node
__global__ void node_ln_kernel(const float* __restrict__ nf,
                               const float* __restrict__ ws, const float* __restrict__ bs,
                               const float* __restrict__ wv,
                               float* __restrict__ ns, float* __restrict__ nv, int N) {
    int node = (blockIdx.x * blockDim.x + threadIdx.x) >> 5;
    int lane = threadIdx.x & 31;
    if (node >= N) return;
    const float* row = nf + (size_t)node * 320;
    float s[4]; float sum = 0.f;
#pragma unroll
    for (int i = 0; i < 4; i++) { s[i] = row[lane + 32*i]; sum += s[i]; }
#pragma unroll
    for (int o = 16; o; o >>= 1) sum += __shfl_xor_sync(0xffffffffu, sum, o);
    float mu = sum * (1.f/128.f);
    float var = 0.f;
#pragma unroll
    for (int i = 0; i < 4; i++) { s[i] -= mu; var += s[i]*s[i]; }
#pragma unroll
    for (int o = 16; o; o >>= 1) var += __shfl_xor_sync(0xffffffffu, var, o);
    float rs = rsqrtf(var * (1.f/128.f) + 1e-8f);
#pragma unroll
    for (int i = 0; i < 4; i++) {
        int c = lane + 32*i;
        ns[(size_t)node*128 + c] = s[i]*rs*ws[c] + bs[c];
    }
    float v[6]; float vs = 0.f;
#pragma unroll
    for (int i = 0; i < 6; i++) { v[i] = row[128 + lane + 32*i]; vs += v[i]*v[i]; }
#pragma unroll
    for (int o = 16; o; o >>= 1) vs += __shfl_xor_sync(0xffffffffu, vs, o);
    float rv = rsqrtf(vs * (1.f/192.f) + 1e-8f);
#pragma unroll
    for (int i = 0; i < 6; i++) {
        int c = lane + 32*i;
        nv[(size_t)node*192 + c] = v[i]*rv*wv[c/3];
    }
}

// ---------------------------------------------------------------------------
// Edge prep: edge LN, edge frame, rotate vectors; writes esvf0=[es|vf0], vf12,
// R, and ctr/nbr index arrays.
__global__ void edge_prep_kernel(const float* __restrict__ ef, const int* __restrict__ ei,
                                 const int* __restrict__ act, const float* __restrict__ evec,
                                 const float* __restrict__ ws, const float* __restrict__ bs,
                                 const float* __restrict__ wv,
                                 const float* __restrict__ nv,
                                 float* __restrict__ esvf0, float* __restrict__ vf12,
                                 float* __restrict__ Rout, int* __restrict__ idx,
                                 int E, int Etot) {
    __shared__ float evs[8][192];
    int wi = threadIdx.x >> 5;
    int lane = threadIdx.x & 31;
    int e = blockIdx.x * 8 + wi;
    if (e >= E) return;
    int ae = act[e];
    int ctr = ei[ae], nbr = ei[Etot + ae];
    if (lane == 0) { idx[e] = ctr; idx[E + e] = nbr; }
    const float* row = ef + (size_t)e * 320;

    float s[4]; float sum = 0.f;
#pragma unroll
    for (int i = 0; i < 4; i++) { s[i] = row[lane + 32*i]; sum += s[i]; }
#pragma unroll
    for (int o = 16; o; o >>= 1) sum += __shfl_xor_sync(0xffffffffu, sum, o);
    float mu = sum * (1.f/128.f);
    float var = 0.f;
#pragma unroll
    for (int i = 0; i < 4; i++) { s[i] -= mu; var += s[i]*s[i]; }
#pragma unroll
    for (int o = 16; o; o >>= 1) var += __shfl_xor_sync(0xffffffffu, var, o);
    float rs = rsqrtf(var * (1.f/128.f) + 1e-8f);

    float* esv = esvf0 + (size_t)e * 320;
#pragma unroll
    for (int i = 0; i < 4; i++) {
        int c = lane + 32*i;
        esv[c] = s[i]*rs*ws[c] + bs[c];
    }

    float v[6]; float vs = 0.f;
#pragma unroll
    for (int i = 0; i < 6; i++) { v[i] = row[128 + lane + 32*i]; vs += v[i]*v[i]; }
#pragma unroll
    for (int o = 16; o; o >>= 1) vs += __shfl_xor_sync(0xffffffffu, vs, o);
    float rv = rsqrtf(vs * (1.f/192.f) + 1e-8f);
#pragma unroll
    for (int i = 0; i < 6; i++) {
        int c = lane + 32*i;
        evs[wi][c] = v[i]*rv*wv[c/3];
    }
    __syncwarp();

    float e0 = evec[(size_t)ae*3], e1 = evec[(size_t)ae*3+1], e2 = evec[(size_t)ae*3+2];
    float rn = rsqrtf(e0*e0 + e1*e1 + e2*e2 + 1e-8f);
    float ax = e0*rn, ay = e1*rn, az = e2*rn;
    float refx = (fabsf(ax) < 0.9f) ? 1.f : 0.f;
    float refy = 1.f - refx;
    float bx = -az*refy;
    float by =  az*refx;
    float bz =  ax*refy - ay*refx;
    float rb = rsqrtf(bx*bx + by*by + bz*bz + 1e-8f);
    bx *= rb; by *= rb; bz *= rb;
    float cx = ay*bz - az*by, cy = az*bx - ax*bz, cz = ax*by - ay*bx;
    if (lane == 0) {
        float* Rp = Rout + (size_t)e * 9;
        Rp[0]=ax; Rp[1]=ay; Rp[2]=az;
        Rp[3]=bx; Rp[4]=by; Rp[5]=bz;
        Rp[6]=cx; Rp[7]=cy; Rp[8]=cz;
    }

    float* vf = vf12 + (size_t)e * 384;
#pragma unroll
    for (int i = 0; i < 6; i++) {
        int u = lane + 32*i;
        float vx, vy, vz;
        if (u < 64) {
            const float* p = nv + (size_t)ctr*192 + u*3;
            vx = p[0]; vy = p[1]; vz = p[2];
        } else if (u < 128) {
            const float* p = &evs[wi][(u - 64)*3];
            vx = p[0]; vy = p[1]; vz = p[2];
        } else {
            const float* p = nv + (size_t)nbr*192 + (u - 128)*3;
            vx = p[0]; vy = p[1]; vz = p[2];
        }
        esv[128 + u] = ax*vx + ay*vy + az*vz;
        vf[u]        = bx*vx + by*vy + bz*vz;
        vf[192 + u]  = cx*vx + cy*vy + cz*vz;
    }
}

// ---------------------------------------------------------------------------
// Build combined complex weight: [[w1r, w1i], [-w1i, w1r]]  (384 x 128)
__global__ void build_w1c_kernel(const float* __restrict__ w1r, const float* __restrict__ w1i,
                                 float* __restrict__ w1c) {
    int idx = blockIdx.x * blockDim.x + threadIdx.x;
    if (idx >= 384*128) return;
    int r = idx / 128, c = idx % 128;
    float val;
    if (r < 192) val = (c < 64) ? w1r[r*64 + c] : w1i[r*64 + (c - 64)];
    else {
        int r2 = r - 192;
        val = (c < 64) ? -w1i[r2*64 + c] : w1r[r2*64 + (c - 64)];
    }
    w1c[idx] = val;
}

// Build combined projection weight (128 x 512):
// wcp[k][c] = c<256 ? so2_w0[k][c] : so2_w0[256+k][c-256]
__global__ void build_wcp_kernel(const float* __restrict__ w0, float* __restrict__ wcp) {
    int idx = blockIdx.x * blockDim.x + threadIdx.x;
    if (idx >= 128*512) return;
    int k = idx / 512, c = idx % 512;
    wcp[idx] = (c < 256) ? w0[(size_t)k*256 + c] : w0[(size_t)(256 + k)*256 + (c - 256)];
}

// ---------------------------------------------------------------------------
// TF32 tensor-core GEMM with fused epilogues.
// MODE 0: C = A@B*scale (+bias)
// MODE 1: main SO2 GEMM: weight-row remap k->(k<128? k+128 : k+256),
//         C = (A@B + proj[ctr[e]][c] + proj[nbr[e]][256+c]) * scale
// MODE 2: scalar scatter: atomicAdd(agg[ctr[e]*320+c], (acc*scale+bias[c])*wenv[e,c]*INV)
// MODE 3: vector scatter: row=m*E+e, atomicAdd(agg[ctr[e]*320+128+3k+m], acc*scale*wenv[e,128+k]*INV)
__device__ __forceinline__ float f2tf32f(float x) {
    uint32_t r; asm("cvt.rna.tf32.f32 %0, %1;" : "=r"(r) : "f"(x));
    return __uint_as_float(r);
}

template<int MODE, bool GATHER>
__global__ __launch_bounds__(256)
void mma_gemm_kernel(const float* __restrict__ A, const float* __restrict__ B,
                     float* __restrict__ C, int M, int Nc, int K,
                     float scale, const float* __restrict__ bias,
                     const int* __restrict__ rowidx, int lda,
                     const int* __restrict__ ctr, const int* __restrict__ nbr,
                     const float* __restrict__ proj, const float* __restrict__ wenv,
                     float* __restrict__ agg, int E) {
    __shared__ float As[2][16][136];
    __shared__ float Bs[2][16][136];

    const int tid  = threadIdx.x;
    const int lane = tid & 31;
    const int wid  = tid >> 5;
    const int g = lane >> 2, t = lane & 3;
    const int wm = (wid >> 2) * 64;
    const int wn = (wid & 3) * 32;
    const int bm = blockIdx.x * 128, bn = blockIdx.y * 128;

    const float* aptr[2];
    int arow[2], aq[2];
#pragma unroll
    for (int it = 0; it < 2; it++) {
        int id = tid + 256*it;
        int row = id & 127, q = id >> 7;
        arow[it] = row; aq[it] = q;
        int grow = bm + row;
        if (grow >= M) grow = M - 1;
        const float* ap = GATHER ? (A + (size_t)rowidx[grow]*lda)
                                 : (A + (size_t)grow*lda);
        aptr[it] = ap + q*4;
    }
    const float* bbase[2];
    int br_[2], bc4[2]; bool bok[2];
#pragma unroll
    for (int it = 0; it < 2; it++) {
        int id = tid + 256*it;
        int r = id >> 5, c4 = id & 31;
        br_[it] = r; bc4[it] = c4;
        int gn = bn + 4*c4;
        bok[it] = (gn < Nc);
        bbase[it] = B + gn;
    }
    auto bload = [&](int it, int k0) -> float4 {
        if (!bok[it]) return make_float4(0.f, 0.f, 0.f, 0.f);
        int k = k0 + br_[it];
        if (MODE == 1) k = (k < 128) ? (k + 128) : (k + 256);
        return *(const float4*)(bbase[it] + (size_t)k * Nc);
    };

    float acc[4][4][4];
#pragma unroll
    for (int mi = 0; mi < 4; mi++)
#pragma unroll
        for (int ni = 0; ni < 4; ni++)
#pragma unroll
            for (int j = 0; j < 4; j++) acc[mi][ni][j] = 0.f;

    const int kTiles = K >> 4;
    float4 ar[2], brv[2];

#pragma unroll
    for (int it = 0; it < 2; it++) {
        ar[it]  = *(const float4*)(aptr[it]);
        brv[it] = bload(it, 0);
    }
#pragma unroll
    for (int it = 0; it < 2; it++) {
        int kq = aq[it]*4, row = arow[it];
        As[0][kq+0][row] = f2tf32f(ar[it].x);
        As[0][kq+1][row] = f2tf32f(ar[it].y);
        As[0][kq+2][row] = f2tf32f(ar[it].z);
        As[0][kq+3][row] = f2tf32f(ar[it].w);
        float4 tb = make_float4(f2tf32f(brv[it].x), f2tf32f(brv[it].y),
                                f2tf32f(brv[it].z), f2tf32f(brv[it].w));
        *(float4*)&Bs[0][br_[it]][4*bc4[it]] = tb;
    }
    __syncthreads();

    for (int kt = 0; kt < kTiles; kt++) {
        int cur = kt & 1;
        if (kt + 1 < kTiles) {
            int k0 = (kt + 1) << 4;
#pragma unroll
            for (int it = 0; it < 2; it++) {
                ar[it]  = *(const float4*)(aptr[it] + k0);
                brv[it] = bload(it, k0);
            }
        }
#pragma unroll
        for (int k8 = 0; k8 < 2; k8++) {
            const int kb = k8 * 8;
            uint32_t af[4][4], bf[4][2];
#pragma unroll
            for (int mi = 0; mi < 4; mi++) {
                int m = wm + mi*16 + g;
                af[mi][0] = __float_as_uint(As[cur][kb+t  ][m]);
                af[mi][1] = __float_as_uint(As[cur][kb+t  ][m+8]);
                af[mi][2] = __float_as_uint(As[cur][kb+t+4][m]);
                af[mi][3] = __float_as_uint(As[cur][kb+t+4][m+8]);
            }
#pragma unroll
            for (int ni = 0; ni < 4; ni++) {
                int n = wn + ni*8 + g;
                bf[ni][0] = __float_as_uint(Bs[cur][kb+t  ][n]);
                bf[ni][1] = __float_as_uint(Bs[cur][kb+t+4][n]);
            }
#pragma unroll
            for (int mi = 0; mi < 4; mi++)
#pragma unroll
                for (int ni = 0; ni < 4; ni++) {
                    asm volatile(
                        "mma.sync.aligned.m16n8k8.row.col.f32.tf32.tf32.f32 "
                        "{%0,%1,%2,%3}, {%4,%5,%6,%7}, {%8,%9}, {%0,%1,%2,%3};"
                        : "+f"(acc[mi][ni][0]), "+f"(acc[mi][ni][1]),
                          "+f"(acc[mi][ni][2]), "+f"(acc[mi][ni][3])
                        : "r"(af[mi][0]), "r"(af[mi][1]), "r"(af[mi][2]), "r"(af[mi][3]),
                          "r"(bf[ni][0]), "r"(bf[ni][1]));
                }
        }
        if (kt + 1 < kTiles) {
            int nxt = cur ^ 1;
#pragma unroll
            for (int it = 0; it < 2; it++) {
                int kq = aq[it]*4, row = arow[it];
                As[nxt][kq+0][row] = f2tf32f(ar[it].x);
                As[nxt][kq+1][row] = f2tf32f(ar[it].y);
                As[nxt][kq+2][row] = f2tf32f(ar[it].z);
                As[nxt][kq+3][row] = f2tf32f(ar[it].w);
                float4 tb = make_float4(f2tf32f(brv[it].x), f2tf32f(brv[it].y),
                                        f2tf32f(brv[it].z), f2tf32f(brv[it].w));
                *(float4*)&Bs[nxt][br_[it]][4*bc4[it]] = tb;
            }
        }
        __syncthreads();
    }

    // ---------------- epilogue ----------------
    const float INV = 0.28867513459481287f;  // 1/sqrt(12)
#pragma unroll
    for (int mi = 0; mi < 4; mi++) {
        int r0 = bm + wm + mi*16 + g;
#pragma unroll
        for (int h = 0; h < 2; h++) {
            int row = r0 + 8*h;
            if (row >= M) continue;
            if (MODE == 0 || MODE == 1) {
                const float *pc = nullptr, *pn = nullptr;
                if (MODE == 1) {
                    pc = proj + (size_t)ctr[row]*512;
                    pn = proj + (size_t)nbr[row]*512 + 256;
                }
#pragma unroll
                for (int ni = 0; ni < 4; ni++) {
                    int c = bn + wn + ni*8 + 2*t;
                    if (c >= Nc) continue;
                    float a0 = acc[mi][ni][2*h], a1 = acc[mi][ni][2*h+1];
                    if (MODE == 1) {
                        a0 = (a0 + pc[c]   + pn[c]  ) * scale;
                        a1 = (a1 + pc[c+1] + pn[c+1]) * scale;
                    } else {
                        a0 = a0*scale + (bias ? bias[c]   : 0.f);
                        a1 = a1*scale + (bias ? bias[c+1] : 0.f);
                    }
                    *(float2*)&C[(size_t)row*Nc + c] = make_float2(a0, a1);
                }
            } else if (MODE == 2) {
                int e = row;
                int base = ctr[e]*320;
                const float* we = wenv + (size_t)e*192;
#pragma unroll
                for (int ni = 0; ni < 4; ni++) {
                    int c = bn + wn + ni*8 + 2*t;
                    if (c >= Nc) continue;
                    float a0 = (acc[mi][ni][2*h]  *scale + bias[c])   * we[c]  *INV;
                    float a1 = (acc[mi][ni][2*h+1]*scale + bias[c+1]) * we[c+1]*INV;
                    atomicAdd(&agg[(size_t)base + c],     a0);
                    atomicAdd(&agg[(size_t)base + c + 1], a1);
                }
            } else { // MODE 3
                int m = row / E;
                int e = row - m*E;
                int base = ctr[e]*320 + 128 + m;
                const float* we = wenv + (size_t)e*192 + 128;
#pragma unroll
                for (int ni = 0; ni < 4; ni++) {
                    int c = bn + wn + ni*8 + 2*t;
                    if (c >= Nc) continue;
                    float a0 = acc[mi][ni][2*h]  *scale * we[c]  *INV;
                    float a1 = acc[mi][ni][2*h+1]*scale * we[c+1]*INV;
                    atomicAdd(&agg[(size_t)base + 3*c],     a0);
                    atomicAdd(&agg[(size_t)base + 3*(c+1)], a1);
                }
            }
        }
    }
}

// ---------------------------------------------------------------------------
// Edge mid: back-rotate (m0_out_v, vp, vm), gate. Warp per edge.
__global__ void edge_mid_kernel(const float* __restrict__ m0out, const float* __restrict__ vpm,
                                const float* __restrict__ Rin,
                                float* __restrict__ msgs, float* __restrict__ msgv, int E) {
    int e = (blockIdx.x * blockDim.x + threadIdx.x) >> 5;
    int lane = threadIdx.x & 31;
    if (e >= E) return;
    const float* mo = m0out + (size_t)e * 256;
    const float* vp = vpm + (size_t)e * 128;
    const float* Rp = Rin + (size_t)e * 9;
    float R0=Rp[0],R1=Rp[1],R2=Rp[2],R3=Rp[3],R4=Rp[4],R5=Rp[5],R6=Rp[6],R7=Rp[7],R8=Rp[8];
#pragma unroll
    for (int i = 0; i < 4; i++) {
        int c = lane + 32*i;
        float x = mo[c];
        msgs[(size_t)e*128 + c] = x / (1.f + expf(-x));   // silu
    }
#pragma unroll
    for (int i = 0; i < 2; i++) {
        int u = lane + 32*i;
        float i0 = mo[192 + u], i1 = vp[u], i2 = vp[64 + u];
        float sg = 1.f / (1.f + expf(-mo[128 + u]));
        float o0 = R0*i0 + R3*i1 + R6*i2;
        float o1 = R1*i0 + R4*i1 + R7*i2;
        float o2 = R2*i0 + R5*i1 + R8*i2;
        msgv[(size_t)0*E*64 + (size_t)e*64 + u] = sg*o0;
        msgv[(size_t)1*E*64 + (size_t)e*64 + u] = sg*o1;
        msgv[(size_t)2*E*64 + (size_t)e*64 + u] = sg*o2;
    }
}

// ---------------------------------------------------------------------------
// Per-node output: atom-type-indexed matvecs, gate, final linear, residual.
__global__ void node_out_kernel(const float* __restrict__ nf, const int* __restrict__ at,
                                const float* __restrict__ wss, const float* __restrict__ wsg,
                                const float* __restrict__ wvv,
                                const float* __restrict__ ohlw, const float* __restrict__ ohlb,
                                const float* __restrict__ ohlwv,
                                const float* __restrict__ res,
                                const float* __restrict__ agg,
                                float* __restrict__ out, int N) {
    int n = blockIdx.x;
    if (n >= N) return;
    int tid = threadIdx.x; // 128
    __shared__ float ags[128], agv[192], gs[128], gv[192], tg[64];
    ags[tid] = agg[(size_t)n*320 + tid];
    agv[tid] = agg[(size_t)n*320 + 128 + tid];
    if (tid < 64) agv[128 + tid] = agg[(size_t)n*320 + 256 + tid];
    __syncthreads();
    int t = at[n];
    const float n_ss = 0.011048543456039806f;  // 1/sqrt(128*64)
    const float n_vv = 0.015625f;              // 1/64
    const float isq128 = 0.08838834764831845f; // 1/sqrt(128)

    {
        float acc = 0.f;
        for (int u = 0; u < 128; u++)
            acc += ags[u] * wss[((size_t)u*64 + t)*128 + tid];
        float ts = acc * n_ss;
        gs[tid] = ts / (1.f + expf(-ts));
    }
    if (tid < 64) {
        float acc = 0.f;
        for (int u = 0; u < 128; u++)
            acc += ags[u] * wsg[((size_t)u*64 + t)*64 + tid];
        tg[tid] = 1.f / (1.f + expf(-acc * n_ss));
    }
    __syncthreads();
    for (int idx = tid; idx < 192; idx += 128) {
        int k = idx / 3, m = idx - 3*k;
        float acc = 0.f;
        for (int u = 0; u < 64; u++)
            acc += agv[u*3 + m] * wvv[((size_t)u*64 + t)*64 + k];
        gv[idx] = tg[k] * acc * n_vv;
    }
    __syncthreads();

    float alpha = 1.f / (1.f + expf(-res[0]));
    float beta = 1.f - alpha;
    {
        float acc = 0.f;
        for (int u = 0; u < 128; u++)
            acc += gs[u] * ohlw[(size_t)u*128 + tid];
        float osv = acc * isq128 + ohlb[tid];
        out[(size_t)n*320 + tid] = alpha * nf[(size_t)n*320 + tid] + beta * osv;
    }
    for (int idx = tid; idx < 192; idx += 128) {
        int k = idx / 3, m = idx - 3*k;
        float acc = 0.f;
        for (int u = 0; u < 64; u++)
            acc += gv[u*3 + m] * ohlwv[(size_t)u*64 + k];
        float ovv = acc * 0.125f;
        out[(size_t)n*320 + 128 + idx] = alpha * nf[(size_t)n*320 + 128 + idx] + beta * ovv;
    }
}

// ---------------------------------------------------------------------------
extern "C" void kernel_launch(void* const* d_in, const int* in_sizes, int n_in,
                              void* d_out, int out_size) {
    const float* latents = (const float*)d_in[0];
    const float* nf      = (const float*)d_in[1];
    const float* ef      = (const float*)d_in[2];
    const int*   at      = (const int*)  d_in[3];
    const int*   ei      = (const int*)  d_in[5];
    const float* evec    = (const float*)d_in[6];
    const int*   act     = (const int*)  d_in[7];
    const float* snws    = (const float*)d_in[8];
    const float* snbs    = (const float*)d_in[9];
    const float* snwv    = (const float*)d_in[10];
    const float* sews    = (const float*)d_in[11];
    const float* sebs    = (const float*)d_in[12];
    const float* sewv    = (const float*)d_in[13];
    const float* so2w0   = (const float*)d_in[14];
    const float* so2w1r  = (const float*)d_in[15];
    const float* so2w1i  = (const float*)d_in[16];
    const float* envw    = (const float*)d_in[17];
    const float* lpws    = (const float*)d_in[18];
    const float* lpbs    = (const float*)d_in[19];
    const float* lpwv    = (const float*)d_in[20];
    const float* ohwss   = (const float*)d_in[21];
    const float* ohwsg   = (const float*)d_in[22];
    const float* ohwvv   = (const float*)d_in[23];
    const float* ohlws   = (const float*)d_in[24];
    const float* ohlbs   = (const float*)d_in[25];
    const float* ohlwv   = (const float*)d_in[26];
    const float* resp    = (const float*)d_in[27];

    int N    = in_sizes[1] / 320;
    int E    = in_sizes[7];
    int Etot = in_sizes[5] / 2;

    float* base = nullptr;
    cudaGetSymbolAddress((void**)&base, g_buf);
    int* idx = nullptr;
    cudaGetSymbolAddress((void**)&idx, g_idx);
    float* ns    = base + NS_OFF;
    float* nv    = base + NV_OFF;
    float* esvf0 = base + ESV_OFF;
    float* vf12  = base + VF12_OFF;
    float* Rbuf  = base + R_OFF;
    float* proj  = base + PROJ_OFF;
    float* m0out = base + M0OUT_OFF;
    float* vpm   = base + VPM_OFF;
    float* msgs  = base + MSGS_OFF;
    float* msgv  = base + MSGV_OFF;
    float* wenv  = base + WENV_OFF;
    float* agg   = base + AGG_OFF;
    float* w1c   = base + W1C_OFF;
    float* wcp   = base + WCP_OFF;
    int* ctr = idx;
    int* nbr = idx + E;

    const float isq576 = 0.041666666666666664f; // 1/24
    const float isq192 = 0.07216878364870323f;
    const float isq128 = 0.08838834764831845f;

    zero_kernel<<<(int)(((size_t)N*320 + 255)/256), 256>>>(agg, (size_t)N*320);
    node_ln_kernel<<<(N + 7)/8, 256>>>(nf, snws, snbs, snwv, ns, nv, N);
    build_w1c_kernel<<<(384*128 + 255)/256, 256>>>(so2w1r, so2w1i, w1c);
    build_wcp_kernel<<<(128*512 + 255)/256, 256>>>(so2w0, wcp);
    edge_prep_kernel<<<(E + 7)/8, 256>>>(ef, ei, act, evec, sews, sebs, sewv,
                                         nv, esvf0, vf12, Rbuf, idx, E, Etot);
    // node projection GEMM: proj = ns @ wcp (unscaled), N x 512
    {
        dim3 g((N + 127)/128, 4);
        mma_gemm_kernel<0,false><<<g, 256>>>(ns, wcp, proj, N, 512, 128, 1.0f,
                                             nullptr, nullptr, 128,
                                             nullptr, nullptr, nullptr, nullptr, nullptr, E);
    }
    // env GEMM (row gather): wenv = latents[act] @ env_w / sqrt(128)
    {
        dim3 g((E + 127)/128, 2);
        mma_gemm_kernel<0,true><<<g, 256>>>(latents, envw, wenv, E, 192, 128, isq128,
                                            nullptr, act, 128,
                                            nullptr, nullptr, nullptr, nullptr, nullptr, E);
    }
    // main SO2 GEMM: m0out = ([es|vf0] @ W0[{128:256,384:576}] + proj[ctr] + proj[nbr]) / 24
    {
        dim3 g((E + 127)/128, 2);
        mma_gemm_kernel<1,false><<<g, 256>>>(esvf0, so2w0, m0out, E, 256, 320, isq576,
                                             nullptr, nullptr, 320,
                                             ctr, nbr, proj, nullptr, nullptr, E);
    }
    // complex pair GEMM: vpm = vf12 @ w1c / sqrt(192)
    {
        dim3 g((E + 127)/128, 1);
        mma_gemm_kernel<0,false><<<g, 256>>>(vf12, w1c, vpm, E, 128, 384, isq192,
                                             nullptr, nullptr, 384,
                                             nullptr, nullptr, nullptr, nullptr, nullptr, E);
    }
    edge_mid_kernel<<<(E + 7)/8, 256>>>(m0out, vpm, Rbuf, msgs, msgv, E);
    // lp scalar GEMM fused with env-weight + scatter
    {
        dim3 g((E + 127)/128, 1);
        mma_gemm_kernel<2,false><<<g, 256>>>(msgs, lpws, nullptr, E, 128, 128, isq128,
                                             lpbs, nullptr, 128,
                                             ctr, nullptr, nullptr, wenv, agg, E);
    }
    // lp vector GEMM (3E x 64 x 64) fused with env-weight + scatter
    {
        dim3 g((3*E + 127)/128, 1);
        mma_gemm_kernel<3,false><<<g, 256>>>(msgv, lpwv, nullptr, 3*E, 64, 64, 0.125f,
                                             nullptr, nullptr, 64,
                                             ctr, nullptr, nullptr, wenv, agg, E);
    }
    node_out_kernel<<<N, 128>>>(nf, at, ohwss, ohwsg, ohwvv,
                                ohlws, ohlbs, ohlwv, resp, agg, (float*)d_out, N);
}

// round 4
// speedup vs baseline: 2.5755x; 1.1892x over previous
#include <cuda_runtime.h>
#include <math.h>
#include <stdint.h>

static constexpr int NMAXN = 8000;
static constexpr int EMAX  = 96000;

// Scratch layout (offsets in floats)
static constexpr size_t NS_OFF    = 0;                                   // ns:    N x 128 (tf32-rounded)
static constexpr size_t NV_OFF    = NS_OFF    + (size_t)NMAXN * 128;     // nv:    N x 192
static constexpr size_t ESV_OFF   = NV_OFF    + (size_t)NMAXN * 192;     // esvf0: E x 320 (r)
static constexpr size_t VF12_OFF  = ESV_OFF   + (size_t)EMAX  * 320;     // vf12:  E x 384 (r)
static constexpr size_t R_OFF     = VF12_OFF  + (size_t)EMAX  * 384;     // R:     E x 9
static constexpr size_t PROJ_OFF  = R_OFF     + (size_t)EMAX  * 9;       // proj:  N x 512
static constexpr size_t GV_OFF    = PROJ_OFF  + (size_t)NMAXN * 512;     // gv:    E x 128 (sig|vraw)
static constexpr size_t VPM_OFF   = GV_OFF    + (size_t)EMAX  * 128;     // vpm:   E x 128
static constexpr size_t MSGS_OFF  = VPM_OFF   + (size_t)EMAX  * 128;     // msgs:  E x 128 (r)
static constexpr size_t MSGV_OFF  = MSGS_OFF  + (size_t)EMAX  * 128;     // msgv:  3 x E x 64 (r)
static constexpr size_t WENV_OFF  = MSGV_OFF  + (size_t)3*EMAX* 64;      // wenv:  E x 192
static constexpr size_t AGG_OFF   = WENV_OFF  + (size_t)EMAX  * 192;     // agg:   N x 320
static constexpr size_t LATR_OFF  = AGG_OFF   + (size_t)NMAXN * 320;     // latR:  E x 128 (r)
static constexpr size_t W1C_OFF   = LATR_OFF  + (size_t)EMAX  * 128;     // w1c:   384 x 128 (r)
static constexpr size_t WCP_OFF   = W1C_OFF   + (size_t)384 * 128;       // wcp:   128 x 512 (r)
static constexpr size_t W0M_OFF   = WCP_OFF   + (size_t)128 * 512;       // w0m:   320 x 256 (r)
static constexpr size_t ENVR_OFF  = W0M_OFF   + (size_t)320 * 256;       // envr:  128 x 192 (r)
static constexpr size_t LPWSR_OFF = ENVR_OFF  + (size_t)128 * 192;       // lpwsr: 128 x 128 (r)
static constexpr size_t LPWVR_OFF = LPWSR_OFF + (size_t)128 * 128;       // lpwvr: 64 x 64 (r)
static constexpr size_t TOTAL_F   = LPWVR_OFF + (size_t)64 * 64;

__device__ __align__(256) float g_buf[TOTAL_F];
__device__ int g_idx[2 * EMAX];   // [0:E) = ctr, [E:2E) = nbr

__device__ __forceinline__ float f2tf32f(float x) {
    uint32_t r; asm("cvt.rna.tf32.f32 %0, %1;" : "=r"(r) : "f"(x));
    return __uint_as_float(r);
}

// ---------------------------------------------------------------------------
__global__ void zero_kernel(float* __restrict__ p, size_t n) {
    size_t i = (size_t)blockIdx.x * blockDim.x + threadIdx.x;
    if (i < n) p[i] = 0.0f;
}

__global__ void round_copy_kernel(const float* __restrict__ in, float* __restrict__ out, size_t n) {
    size_t i = (size_t)blockIdx.x * blockDim.x + threadIdx.x;
    if (i < n) out[i] = f2tf32f(in[i]);
}

// ---------------------------------------------------------------------------
// Node separable layernorm: warp per node. ns written tf32-rounded.
__global__ void node_ln_kernel(const float* __restrict__ nf,
                               const float* __restrict__ ws, const float* __restrict__ bs,
                               const float* __restrict__ wv,
                               float* __restrict__ ns, float* __restrict__ nv, int N) {
    int node = (blockIdx.x * blockDim.x + threadIdx.x) >> 5;
    int lane = threadIdx.x & 31;
    if (node >= N) return;
    const float* row = nf + (size_t)node * 320;
    float s[4]; float sum = 0.f;
#pragma unroll
    for (int i = 0; i < 4; i++) { s[i] = row[lane + 32*i]; sum += s[i]; }
#pragma unroll
    for (int o = 16; o; o >>= 1) sum += __shfl_xor_sync(0xffffffffu, sum, o);
    float mu = sum * (1.f/128.f);
    float var = 0.f;
#pragma unroll
    for (int i = 0; i < 4; i++) { s[i] -= mu; var += s[i]*s[i]; }
#pragma unroll
    for (int o = 16; o; o >>= 1) var += __shfl_xor_sync(0xffffffffu, var, o);
    float rs = rsqrtf(var * (1.f/128.f) + 1e-8f);
#pragma unroll
    for (int i = 0; i < 4; i++) {
        int c = lane + 32*i;
        ns[(size_t)node*128 + c] = f2tf32f(s[i]*rs*ws[c] + bs[c]);
    }
    float v[6]; float vs = 0.f;
#pragma unroll
    for (int i = 0; i < 6; i++) { v[i] = row[128 + lane + 32*i]; vs += v[i]*v[i]; }
#pragma unroll
    for (int o = 16; o; o >>= 1) vs += __shfl_xor_sync(0xffffffffu, vs, o);
    float rv = rsqrtf(vs * (1.f/192.f) + 1e-8f);
#pragma unroll
    for (int i = 0; i < 6; i++) {
        int c = lane + 32*i;
        nv[(size_t)node*192 + c] = v[i]*rv*wv[c/3];
    }
}

// ---------------------------------------------------------------------------
// Edge prep: edge LN, edge frame, rotate vectors; esvf0/vf12 written rounded.
__global__ void edge_prep_kernel(const float* __restrict__ ef, const int* __restrict__ ei,
                                 const int* __restrict__ act, const float* __restrict__ evec,
                                 const float* __restrict__ ws, const float* __restrict__ bs,
                                 const float* __restrict__ wv,
                                 const float* __restrict__ nv,
                                 float* __restrict__ esvf0, float* __restrict__ vf12,
                                 float* __restrict__ Rout, int* __restrict__ idx,
                                 int E, int Etot) {
    __shared__ float evs[8][192];
    int wi = threadIdx.x >> 5;
    int lane = threadIdx.x & 31;
    int e = blockIdx.x * 8 + wi;
    if (e >= E) return;
    int ae = act[e];
    int ctr = ei[ae], nbr = ei[Etot + ae];
    if (lane == 0) { idx[e] = ctr; idx[E + e] = nbr; }
    const float* row = ef + (size_t)e * 320;

    float s[4]; float sum = 0.f;
#pragma unroll
    for (int i = 0; i < 4; i++) { s[i] = row[lane + 32*i]; sum += s[i]; }
#pragma unroll
    for (int o = 16; o; o >>= 1) sum += __shfl_xor_sync(0xffffffffu, sum, o);
    float mu = sum * (1.f/128.f);
    float var = 0.f;
#pragma unroll
    for (int i = 0; i < 4; i++) { s[i] -= mu; var += s[i]*s[i]; }
#pragma unroll
    for (int o = 16; o; o >>= 1) var += __shfl_xor_sync(0xffffffffu, var, o);
    float rs = rsqrtf(var * (1.f/128.f) + 1e-8f);

    float* esv = esvf0 + (size_t)e * 320;
#pragma unroll
    for (int i = 0; i < 4; i++) {
        int c = lane + 32*i;
        esv[c] = f2tf32f(s[i]*rs*ws[c] + bs[c]);
    }

    float v[6]; float vs = 0.f;
#pragma unroll
    for (int i = 0; i < 6; i++) { v[i] = row[128 + lane + 32*i]; vs += v[i]*v[i]; }
#pragma unroll
    for (int o = 16; o; o >>= 1) vs += __shfl_xor_sync(0xffffffffu, vs, o);
    float rv = rsqrtf(vs * (1.f/192.f) + 1e-8f);
#pragma unroll
    for (int i = 0; i < 6; i++) {
        int c = lane + 32*i;
        evs[wi][c] = v[i]*rv*wv[c/3];
    }
    __syncwarp();

    float e0 = evec[(size_t)ae*3], e1 = evec[(size_t)ae*3+1], e2 = evec[(size_t)ae*3+2];
    float rn = rsqrtf(e0*e0 + e1*e1 + e2*e2 + 1e-8f);
    float ax = e0*rn, ay = e1*rn, az = e2*rn;
    float refx = (fabsf(ax) < 0.9f) ? 1.f : 0.f;
    float refy = 1.f - refx;
    float bx = -az*refy;
    float by =  az*refx;
    float bz =  ax*refy - ay*refx;
    float rb = rsqrtf(bx*bx + by*by + bz*bz + 1e-8f);
    bx *= rb; by *= rb; bz *= rb;
    float cx = ay*bz - az*by, cy = az*bx - ax*bz, cz = ax*by - ay*bx;
    if (lane == 0) {
        float* Rp = Rout + (size_t)e * 9;
        Rp[0]=ax; Rp[1]=ay; Rp[2]=az;
        Rp[3]=bx; Rp[4]=by; Rp[5]=bz;
        Rp[6]=cx; Rp[7]=cy; Rp[8]=cz;
    }

    float* vf = vf12 + (size_t)e * 384;
#pragma unroll
    for (int i = 0; i < 6; i++) {
        int u = lane + 32*i;
        float vx, vy, vz;
        if (u < 64) {
            const float* p = nv + (size_t)ctr*192 + u*3;
            vx = p[0]; vy = p[1]; vz = p[2];
        } else if (u < 128) {
            const float* p = &evs[wi][(u - 64)*3];
            vx = p[0]; vy = p[1]; vz = p[2];
        } else {
            const float* p = nv + (size_t)nbr*192 + (u - 128)*3;
            vx = p[0]; vy = p[1]; vz = p[2];
        }
        esv[128 + u] = f2tf32f(ax*vx + ay*vy + az*vz);
        vf[u]        = f2tf32f(bx*vx + by*vy + bz*vz);
        vf[192 + u]  = f2tf32f(cx*vx + cy*vy + cz*vz);
    }
}

// ---------------------------------------------------------------------------
// Weight prep (all tf32-rounded)
__global__ void build_w1c_kernel(const float* __restrict__ w1r, const float* __restrict__ w1i,
                                 float* __restrict__ w1c) {
    int idx = blockIdx.x * blockDim.x + threadIdx.x;
    if (idx >= 384*128) return;
    int r = idx / 128, c = idx % 128;
    float val;
    if (r < 192) val = (c < 64) ? w1r[r*64 + c] : w1i[r*64 + (c - 64)];
    else {
        int r2 = r - 192;
        val = (c < 64) ? -w1i[r2*64 + c] : w1r[r2*64 + (c - 64)];
    }
    w1c[idx] = f2tf32f(val);
}

__global__ void build_wcp_kernel(const float* __restrict__ w0, float* __restrict__ wcp) {
    int idx = blockIdx.x * blockDim.x + threadIdx.x;
    if (idx >= 128*512) return;
    int k = idx / 512, c = idx % 512;
    float v = (c < 256) ? w0[(size_t)k*256 + c] : w0[(size_t)(256 + k)*256 + (c - 256)];
    wcp[idx] = f2tf32f(v);
}

// w0m[k][c] = rnd(so2_w0[k<128? k+128 : k+256][c]),  320 x 256
__global__ void build_w0m_kernel(const float* __restrict__ w0, float* __restrict__ w0m) {
    int idx = blockIdx.x * blockDim.x + threadIdx.x;
    if (idx >= 320*256) return;
    int k = idx / 256, c = idx % 256;
    int src = (k < 128) ? (k + 128) : (k + 256);
    w0m[idx] = f2tf32f(w0[(size_t)src*256 + c]);
}

// ---------------------------------------------------------------------------
// cp.async helpers
__device__ __forceinline__ void cp16(uint32_t dst, const void* src, int bytes) {
    asm volatile("cp.async.cg.shared.global [%0], [%1], 16, %2;"
                 :: "r"(dst), "l"(src), "r"(bytes));
}
__device__ __forceinline__ void cp_commit() { asm volatile("cp.async.commit_group;"); }

// ---------------------------------------------------------------------------
// TF32 tensor-core GEMM, cp.async 3-stage pipeline, inputs pre-rounded to tf32.
// MODE 0: C = A@B*scale (+bias)
// MODE 1: C(msgs) = rnd(silu(v)) for c<128; aux(gv) = sigmoid(v) [c<192] / v [else],
//         v = (acc + proj[ctr][c] + proj[nbr][256+c]) * scale
// MODE 2: atomicAdd(agg[ctr[e]*320+c], (acc*scale+bias[c])*wenv[e,c]*INV)
// MODE 3: row=m*E+e; atomicAdd(agg[ctr[e]*320+128+3c+m], acc*scale*wenv[e,128+c]*INV)
static constexpr int GSTAGES = 3;
static constexpr int ASTRIDE = 20;                 // As row stride (floats)
static constexpr int BSTRIDE = 136;                // Bs row stride (floats)
static constexpr int ASZ = 128 * ASTRIDE;          // 2560 floats / stage
static constexpr int BSZ = 16 * BSTRIDE;           // 2176 floats / stage
static constexpr int GEMM_SMEM_BYTES = GSTAGES * (ASZ + BSZ) * 4;  // 56832

template<int MODE, bool GATHER>
__global__ __launch_bounds__(256, 2)
void mma_gemm_kernel(const float* __restrict__ A, const float* __restrict__ B,
                     float* __restrict__ C, int M, int Nc, int K,
                     float scale, const float* __restrict__ bias,
                     const int* __restrict__ rowidx, int lda,
                     const int* __restrict__ ctr, const int* __restrict__ nbr,
                     const float* __restrict__ proj, const float* __restrict__ wenv,
                     float* __restrict__ agg, float* __restrict__ aux, int E) {
    extern __shared__ float smem[];
    float* AsBase = smem;
    float* BsBase = smem + GSTAGES * ASZ;

    const int tid  = threadIdx.x;
    const int lane = tid & 31;
    const int wid  = tid >> 5;
    const int g = lane >> 2, t = lane & 3;
    const int wm = (wid >> 2) * 64;
    const int wn = (wid & 3) * 32;
    const int bm = blockIdx.y * 128, bn = blockIdx.x * 128;

    // A: 512 chunks of 16B per tile; thread handles ids {tid, tid+256}
    const float* aptr[2]; uint32_t adst[2];
#pragma unroll
    for (int it = 0; it < 2; it++) {
        int id = tid + 256*it;
        int row = id >> 2, q = id & 3;
        int grow = bm + row;
        if (grow >= M) grow = M - 1;
        const float* ap = GATHER ? (A + (size_t)rowidx[grow]*lda)
                                 : (A + (size_t)grow*lda);
        aptr[it] = ap + q*4;
        adst[it] = (uint32_t)__cvta_generic_to_shared(AsBase + row*ASTRIDE + q*4);
    }
    // B: 512 chunks per tile
    const float* bptr[2]; uint32_t bdst[2]; int bbytes[2];
#pragma unroll
    for (int it = 0; it < 2; it++) {
        int id = tid + 256*it;
        int r = id >> 5, c4 = id & 31;
        int gn = bn + 4*c4;
        bbytes[it] = (gn < Nc) ? 16 : 0;
        bptr[it] = B + (size_t)r*Nc + gn;
        bdst[it] = (uint32_t)__cvta_generic_to_shared(BsBase + r*BSTRIDE + c4*4);
    }

    const int kTiles = K >> 4;
    auto loadStage = [&](int stage, int k0) {
        uint32_t ao = stage * (ASZ*4), bo = stage * (BSZ*4);
#pragma unroll
        for (int it = 0; it < 2; it++)
            cp16(adst[it] + ao, aptr[it] + k0, 16);
#pragma unroll
        for (int it = 0; it < 2; it++)
            cp16(bdst[it] + bo, bptr[it] + (size_t)k0*Nc, bbytes[it]);
        cp_commit();
    };

    float acc[4][4][4];
#pragma unroll
    for (int mi = 0; mi < 4; mi++)
#pragma unroll
        for (int ni = 0; ni < 4; ni++)
#pragma unroll
            for (int j = 0; j < 4; j++) acc[mi][ni][j] = 0.f;

    // prologue: stages 0..GSTAGES-2
#pragma unroll
    for (int s = 0; s < GSTAGES-1; s++) loadStage(s, s*16);

    for (int kt = 0; kt < kTiles; kt++) {
        asm volatile("cp.async.wait_group %0;" :: "n"(GSTAGES-2));
        __syncthreads();
        int pf = kt + GSTAGES - 1;
        if (pf < kTiles) loadStage(pf % GSTAGES, pf*16);
        else cp_commit();

        const float* As = AsBase + (kt % GSTAGES) * ASZ;
        const float* Bs = BsBase + (kt % GSTAGES) * BSZ;
#pragma unroll
        for (int k8 = 0; k8 < 2; k8++) {
            const int kb = k8 * 8;
            uint32_t af[4][4], bf[4][2];
#pragma unroll
            for (int mi = 0; mi < 4; mi++) {
                int m = wm + mi*16 + g;
                af[mi][0] = __float_as_uint(As[m*ASTRIDE + kb + t]);
                af[mi][1] = __float_as_uint(As[(m+8)*ASTRIDE + kb + t]);
                af[mi][2] = __float_as_uint(As[m*ASTRIDE + kb + t + 4]);
                af[mi][3] = __float_as_uint(As[(m+8)*ASTRIDE + kb + t + 4]);
            }
#pragma unroll
            for (int ni = 0; ni < 4; ni++) {
                int n = wn + ni*8 + g;
                bf[ni][0] = __float_as_uint(Bs[(kb+t)*BSTRIDE + n]);
                bf[ni][1] = __float_as_uint(Bs[(kb+t+4)*BSTRIDE + n]);
            }
#pragma unroll
            for (int mi = 0; mi < 4; mi++)
#pragma unroll
                for (int ni = 0; ni < 4; ni++) {
                    asm volatile(
                        "mma.sync.aligned.m16n8k8.row.col.f32.tf32.tf32.f32 "
                        "{%0,%1,%2,%3}, {%4,%5,%6,%7}, {%8,%9}, {%0,%1,%2,%3};"
                        : "+f"(acc[mi][ni][0]), "+f"(acc[mi][ni][1]),
                          "+f"(acc[mi][ni][2]), "+f"(acc[mi][ni][3])
                        : "r"(af[mi][0]), "r"(af[mi][1]), "r"(af[mi][2]), "r"(af[mi][3]),
                          "r"(bf[ni][0]), "r"(bf[ni][1]));
                }
        }
        __syncthreads();
    }

    // ---------------- epilogue ----------------
    const float INV = 0.28867513459481287f;  // 1/sqrt(12)
#pragma unroll
    for (int mi = 0; mi < 4; mi++) {
        int r0 = bm + wm + mi*16 + g;
#pragma unroll
        for (int h = 0; h < 2; h++) {
            int row = r0 + 8*h;
            if (row >= M) continue;
            if (MODE == 0) {
#pragma unroll
                for (int ni = 0; ni < 4; ni++) {
                    int c = bn + wn + ni*8 + 2*t;
                    if (c >= Nc) continue;
                    float a0 = acc[mi][ni][2*h]  *scale + (bias ? bias[c]   : 0.f);
                    float a1 = acc[mi][ni][2*h+1]*scale + (bias ? bias[c+1] : 0.f);
                    *(float2*)&C[(size_t)row*Nc + c] = make_float2(a0, a1);
                }
            } else if (MODE == 1) {
                const float* pc = proj + (size_t)ctr[row]*512;
                const float* pn = proj + (size_t)nbr[row]*512 + 256;
#pragma unroll
                for (int ni = 0; ni < 4; ni++) {
                    int c = bn + wn + ni*8 + 2*t;
                    float v0 = (acc[mi][ni][2*h]   + pc[c]   + pn[c]  ) * scale;
                    float v1 = (acc[mi][ni][2*h+1] + pc[c+1] + pn[c+1]) * scale;
                    if (c < 128) {
                        float m0 = f2tf32f(v0 / (1.f + expf(-v0)));
                        float m1 = f2tf32f(v1 / (1.f + expf(-v1)));
                        *(float2*)&C[(size_t)row*128 + c] = make_float2(m0, m1);
                    } else if (c < 192) {
                        float s0 = 1.f / (1.f + expf(-v0));
                        float s1 = 1.f / (1.f + expf(-v1));
                        *(float2*)&aux[(size_t)row*128 + (c-128)] = make_float2(s0, s1);
                    } else {
                        *(float2*)&aux[(size_t)row*128 + (c-128)] = make_float2(v0, v1);
                    }
                }
            } else if (MODE == 2) {
                int e = row;
                int base = ctr[e]*320;
                const float* we = wenv + (size_t)e*192;
#pragma unroll
                for (int ni = 0; ni < 4; ni++) {
                    int c = bn + wn + ni*8 + 2*t;
                    if (c >= Nc) continue;
                    float a0 = (acc[mi][ni][2*h]  *scale + bias[c])   * we[c]  *INV;
                    float a1 = (acc[mi][ni][2*h+1]*scale + bias[c+1]) * we[c+1]*INV;
                    atomicAdd(&agg[(size_t)base + c],     a0);
                    atomicAdd(&agg[(size_t)base + c + 1], a1);
                }
            } else { // MODE 3
                int m = row / E;
                int e = row - m*E;
                int base = ctr[e]*320 + 128 + m;
                const float* we = wenv + (size_t)e*192 + 128;
#pragma unroll
                for (int ni = 0; ni < 4; ni++) {
                    int c = bn + wn + ni*8 + 2*t;
                    if (c >= Nc) continue;
                    float a0 = acc[mi][ni][2*h]  *scale * we[c]  *INV;
                    float a1 = acc[mi][ni][2*h+1]*scale * we[c+1]*INV;
                    atomicAdd(&agg[(size_t)base + 3*c],     a0);
                    atomicAdd(&agg[(size_t)base + 3*(c+1)], a1);
                }
            }
        }
    }
}

// ---------------------------------------------------------------------------
// Edge mid: back-rotate (vraw, vp, vm) with gate, write msgv rounded.
__global__ void edge_mid_kernel(const float* __restrict__ gv, const float* __restrict__ vpm,
                                const float* __restrict__ Rin,
                                float* __restrict__ msgv, int E) {
    int e = (blockIdx.x * blockDim.x + threadIdx.x) >> 5;
    int lane = threadIdx.x & 31;
    if (e >= E) return;
    const float* gvp = gv + (size_t)e * 128;
    const float* vp = vpm + (size_t)e * 128;
    const float* Rp = Rin + (size_t)e * 9;
    float R0=Rp[0],R1=Rp[1],R2=Rp[2],R3=Rp[3],R4=Rp[4],R5=Rp[5],R6=Rp[6],R7=Rp[7],R8=Rp[8];
#pragma unroll
    for (int i = 0; i < 2; i++) {
        int u = lane + 32*i;
        float sg = gvp[u];
        float i0 = gvp[64 + u], i1 = vp[u], i2 = vp[64 + u];
        float o0 = R0*i0 + R3*i1 + R6*i2;
        float o1 = R1*i0 + R4*i1 + R7*i2;
        float o2 = R2*i0 + R5*i1 + R8*i2;
        msgv[(size_t)0*E*64 + (size_t)e*64 + u] = f2tf32f(sg*o0);
        msgv[(size_t)1*E*64 + (size_t)e*64 + u] = f2tf32f(sg*o1);
        msgv[(size_t)2*E*64 + (size_t)e*64 + u] = f2tf32f(sg*o2);
    }
}

// ---------------------------------------------------------------------------
// Per-node output: atom-type-indexed matvecs, gate, final linear, residual.
__global__ void node_out_kernel(const float* __restrict__ nf, const int* __restrict__ at,
                                const float* __restrict__ wss, const float* __restrict__ wsg,
                                const float* __restrict__ wvv,
                                const float* __restrict__ ohlw, const float* __restrict__ ohlb,
                                const float* __restrict__ ohlwv,
                                const float* __restrict__ res,
                                const float* __restrict__ agg,
                                float* __restrict__ out, int N) {
    int n = blockIdx.x;
    if (n >= N) return;
    int tid = threadIdx.x; // 128
    __shared__ float ags[128], agv[192], gs[128], gv[192], tg[64];
    ags[tid] = agg[(size_t)n*320 + tid];
    agv[tid] = agg[(size_t)n*320 + 128 + tid];
    if (tid < 64) agv[128 + tid] = agg[(size_t)n*320 + 256 + tid];
    __syncthreads();
    int t = at[n];
    const float n_ss = 0.011048543456039806f;  // 1/sqrt(128*64)
    const float n_vv = 0.015625f;              // 1/64
    const float isq128 = 0.08838834764831845f; // 1/sqrt(128)

    {
        float acc = 0.f;
        for (int u = 0; u < 128; u++)
            acc += ags[u] * wss[((size_t)u*64 + t)*128 + tid];
        float ts = acc * n_ss;
        gs[tid] = ts / (1.f + expf(-ts));
    }
    if (tid < 64) {
        float acc = 0.f;
        for (int u = 0; u < 128; u++)
            acc += ags[u] * wsg[((size_t)u*64 + t)*64 + tid];
        tg[tid] = 1.f / (1.f + expf(-acc * n_ss));
    }
    __syncthreads();
    for (int idx = tid; idx < 192; idx += 128) {
        int k = idx / 3, m = idx - 3*k;
        float acc = 0.f;
        for (int u = 0; u < 64; u++)
            acc += agv[u*3 + m] * wvv[((size_t)u*64 + t)*64 + k];
        gv[idx] = tg[k] * acc * n_vv;
    }
    __syncthreads();

    float alpha = 1.f / (1.f + expf(-res[0]));
    float beta = 1.f - alpha;
    {
        float acc = 0.f;
        for (int u = 0; u < 128; u++)
            acc += gs[u] * ohlw[(size_t)u*128 + tid];
        float osv = acc * isq128 + ohlb[tid];
        out[(size_t)n*320 + tid] = alpha * nf[(size_t)n*320 + tid] + beta * osv;
    }
    for (int idx = tid; idx < 192; idx += 128) {
        int k = idx / 3, m = idx - 3*k;
        float acc = 0.f;
        for (int u = 0; u < 64; u++)
            acc += gv[u*3 + m] * ohlwv[(size_t)u*64 + k];
        float ovv = acc * 0.125f;
        out[(size_t)n*320 + 128 + idx] = alpha * nf[(size_t)n*320 + 128 + idx] + beta * ovv;
    }
}

// ---------------------------------------------------------------------------
extern "C" void kernel_launch(void* const* d_in, const int* in_sizes, int n_in,
                              void* d_out, int out_size) {
    const float* latents = (const float*)d_in[0];
    const float* nf      = (const float*)d_in[1];
    const float* ef      = (const float*)d_in[2];
    const int*   at      = (const int*)  d_in[3];
    const int*   ei      = (const int*)  d_in[5];
    const float* evec    = (const float*)d_in[6];
    const int*   act     = (const int*)  d_in[7];
    const float* snws    = (const float*)d_in[8];
    const float* snbs    = (const float*)d_in[9];
    const float* snwv    = (const float*)d_in[10];
    const float* sews    = (const float*)d_in[11];
    const float* sebs    = (const float*)d_in[12];
    const float* sewv    = (const float*)d_in[13];
    const float* so2w0   = (const float*)d_in[14];
    const float* so2w1r  = (const float*)d_in[15];
    const float* so2w1i  = (const float*)d_in[16];
    const float* envw    = (const float*)d_in[17];
    const float* lpws    = (const float*)d_in[18];
    const float* lpbs    = (const float*)d_in[19];
    const float* lpwv    = (const float*)d_in[20];
    const float* ohwss   = (const float*)d_in[21];
    const float* ohwsg   = (const float*)d_in[22];
    const float* ohwvv   = (const float*)d_in[23];
    const float* ohlws   = (const float*)d_in[24];
    const float* ohlbs   = (const float*)d_in[25];
    const float* ohlwv   = (const float*)d_in[26];
    const float* resp    = (const float*)d_in[27];

    int N    = in_sizes[1] / 320;
    int E    = in_sizes[7];
    int Etot = in_sizes[5] / 2;
    size_t latN = (size_t)in_sizes[0];

    float* base = nullptr;
    cudaGetSymbolAddress((void**)&base, g_buf);
    int* idx = nullptr;
    cudaGetSymbolAddress((void**)&idx, g_idx);
    float* ns    = base + NS_OFF;
    float* nv    = base + NV_OFF;
    float* esvf0 = base + ESV_OFF;
    float* vf12  = base + VF12_OFF;
    float* Rbuf  = base + R_OFF;
    float* proj  = base + PROJ_OFF;
    float* gvb   = base + GV_OFF;
    float* vpm   = base + VPM_OFF;
    float* msgs  = base + MSGS_OFF;
    float* msgv  = base + MSGV_OFF;
    float* wenv  = base + WENV_OFF;
    float* agg   = base + AGG_OFF;
    float* latR  = base + LATR_OFF;
    float* w1c   = base + W1C_OFF;
    float* wcp   = base + WCP_OFF;
    float* w0m   = base + W0M_OFF;
    float* envr  = base + ENVR_OFF;
    float* lpwsr = base + LPWSR_OFF;
    float* lpwvr = base + LPWVR_OFF;
    int* ctr = idx;
    int* nbr = idx + E;

    const float isq576 = 0.041666666666666664f; // 1/24
    const float isq192 = 0.07216878364870323f;
    const float isq128 = 0.08838834764831845f;

    cudaFuncSetAttribute(mma_gemm_kernel<0,false>, cudaFuncAttributeMaxDynamicSharedMemorySize, GEMM_SMEM_BYTES);
    cudaFuncSetAttribute(mma_gemm_kernel<0,true>,  cudaFuncAttributeMaxDynamicSharedMemorySize, GEMM_SMEM_BYTES);
    cudaFuncSetAttribute(mma_gemm_kernel<1,false>, cudaFuncAttributeMaxDynamicSharedMemorySize, GEMM_SMEM_BYTES);
    cudaFuncSetAttribute(mma_gemm_kernel<2,false>, cudaFuncAttributeMaxDynamicSharedMemorySize, GEMM_SMEM_BYTES);
    cudaFuncSetAttribute(mma_gemm_kernel<3,false>, cudaFuncAttributeMaxDynamicSharedMemorySize, GEMM_SMEM_BYTES);

    zero_kernel<<<(int)(((size_t)N*320 + 255)/256), 256>>>(agg, (size_t)N*320);
    node_ln_kernel<<<(N + 7)/8, 256>>>(nf, snws, snbs, snwv, ns, nv, N);
    build_w1c_kernel<<<(384*128 + 255)/256, 256>>>(so2w1r, so2w1i, w1c);
    build_wcp_kernel<<<(128*512 + 255)/256, 256>>>(so2w0, wcp);
    build_w0m_kernel<<<(320*256 + 255)/256, 256>>>(so2w0, w0m);
    round_copy_kernel<<<(int)((latN + 255)/256), 256>>>(latents, latR, latN);
    round_copy_kernel<<<(128*192 + 255)/256, 256>>>(envw, envr, 128*192);
    round_copy_kernel<<<(128*128 + 255)/256, 256>>>(lpws, lpwsr, 128*128);
    round_copy_kernel<<<(64*64 + 255)/256, 256>>>(lpwv, lpwvr, 64*64);
    edge_prep_kernel<<<(E + 7)/8, 256>>>(ef, ei, act, evec, sews, sebs, sewv,
                                         nv, esvf0, vf12, Rbuf, idx, E, Etot);
    // proj = ns @ wcp  (N x 512)
    {
        dim3 g(4, (N + 127)/128);
        mma_gemm_kernel<0,false><<<g, 256, GEMM_SMEM_BYTES>>>(ns, wcp, proj, N, 512, 128, 1.0f,
            nullptr, nullptr, 128, nullptr, nullptr, nullptr, nullptr, nullptr, nullptr, E);
    }
    // wenv = latR[act] @ envr / sqrt(128)  (E x 192)
    {
        dim3 g(2, (E + 127)/128);
        mma_gemm_kernel<0,true><<<g, 256, GEMM_SMEM_BYTES>>>(latR, envr, wenv, E, 192, 128, isq128,
            nullptr, act, 128, nullptr, nullptr, nullptr, nullptr, nullptr, nullptr, E);
    }
    // main SO2 GEMM -> msgs (silu) + gv (sigmoid|vraw)
    {
        dim3 g(2, (E + 127)/128);
        mma_gemm_kernel<1,false><<<g, 256, GEMM_SMEM_BYTES>>>(esvf0, w0m, msgs, E, 256, 320, isq576,
            nullptr, nullptr, 320, ctr, nbr, proj, nullptr, nullptr, gvb, E);
    }
    // vpm = vf12 @ w1c / sqrt(192)  (E x 128)
    {
        dim3 g(1, (E + 127)/128);
        mma_gemm_kernel<0,false><<<g, 256, GEMM_SMEM_BYTES>>>(vf12, w1c, vpm, E, 128, 384, isq192,
            nullptr, nullptr, 384, nullptr, nullptr, nullptr, nullptr, nullptr, nullptr, E);
    }
    edge_mid_kernel<<<(E + 7)/8, 256>>>(gvb, vpm, Rbuf, msgv, E);
    // lps GEMM fused with env-weight + scatter
    {
        dim3 g(1, (E + 127)/128);
        mma_gemm_kernel<2,false><<<g, 256, GEMM_SMEM_BYTES>>>(msgs, lpwsr, nullptr, E, 128, 128, isq128,
            lpbs, nullptr, 128, ctr, nullptr, nullptr, wenv, agg, nullptr, E);
    }
    // lpv GEMM (3E x 64 x 64) fused with env-weight + scatter
    {
        dim3 g(1, (3*E + 127)/128);
        mma_gemm_kernel<3,false><<<g, 256, GEMM_SMEM_BYTES>>>(msgv, lpwvr, nullptr, 3*E, 64, 64, 0.125f,
            nullptr, nullptr, 64, ctr, nullptr, nullptr, wenv, agg, nullptr, E);
    }
    node_out_kernel<<<N, 128>>>(nf, at, ohwss, ohwsg, ohwvv,
                                ohlws, ohlbs, ohlwv, resp, agg, (float*)d_out, N);
}

// round 5
// speedup vs baseline: 2.6693x; 1.0364x over previous
#include <cuda_runtime.h>
#include <math.h>
#include <stdint.h>

static constexpr int NMAXN = 8000;
static constexpr int EMAX  = 96000;

// Scratch layout (offsets in floats)
static constexpr size_t NS_OFF    = 0;                                   // ns:    N x 128 (r)
static constexpr size_t NV_OFF    = NS_OFF    + (size_t)NMAXN * 128;     // nv:    N x 192
static constexpr size_t ESV_OFF   = NV_OFF    + (size_t)NMAXN * 192;     // esvf0: E x 320 (r)
static constexpr size_t VF12_OFF  = ESV_OFF   + (size_t)EMAX  * 320;     // vf12:  E x 384 (r)
static constexpr size_t R_OFF     = VF12_OFF  + (size_t)EMAX  * 384;     // R:     E x 9
static constexpr size_t PROJ_OFF  = R_OFF     + (size_t)EMAX  * 9;       // proj:  N x 512
static constexpr size_t GV_OFF    = PROJ_OFF  + (size_t)NMAXN * 512;     // gv:    E x 128 (sig|vraw)
static constexpr size_t MSGS_OFF  = GV_OFF    + (size_t)EMAX  * 128;     // msgs:  E x 128 (r)
static constexpr size_t MSGV_OFF  = MSGS_OFF  + (size_t)EMAX  * 128;     // msgv:  3 x E x 64 (r)
static constexpr size_t WENV_OFF  = MSGV_OFF  + (size_t)3*EMAX* 64;      // wenv:  E x 192
static constexpr size_t AGGS_OFF  = WENV_OFF  + (size_t)EMAX  * 192;     // aggs:  N x 128
static constexpr size_t AGGV_OFF  = AGGS_OFF  + (size_t)NMAXN * 128;     // aggv:  3 x N x 64
static constexpr size_t GS_OFF    = AGGV_OFF  + (size_t)3*NMAXN*64;      // gs:    N x 128 (r)
static constexpr size_t TG_OFF    = GS_OFF    + (size_t)NMAXN * 128;     // tg:    N x 64
static constexpr size_t GVM_OFF   = TG_OFF    + (size_t)NMAXN * 64;      // gvm:   3 x N x 64 (r)
static constexpr size_t LATR_OFF  = GVM_OFF   + (size_t)3*NMAXN*64;      // latR:  E x 128 (r)
static constexpr size_t W1C_OFF   = LATR_OFF  + (size_t)EMAX  * 128;     // w1c:   384 x 128 (r)
static constexpr size_t WCP_OFF   = W1C_OFF   + (size_t)384 * 128;       // wcp:   128 x 512 (r)
static constexpr size_t W0M_OFF   = WCP_OFF   + (size_t)128 * 512;       // w0m:   320 x 256 (r)
static constexpr size_t ENVR_OFF  = W0M_OFF   + (size_t)320 * 256;       // envr:  128 x 192 (r)
static constexpr size_t LPWSR_OFF = ENVR_OFF  + (size_t)128 * 192;       // lpwsr: 128 x 128 (r)
static constexpr size_t LPWVR_OFF = LPWSR_OFF + (size_t)128 * 128;       // lpwvr: 64 x 64 (r)
static constexpr size_t WSSR_OFF  = LPWVR_OFF + (size_t)64 * 64;         // wssR:  128*64*128 (r)
static constexpr size_t WSGR_OFF  = WSSR_OFF  + (size_t)128*64*128;      // wsgR:  128*64*64 (r)
static constexpr size_t WVVR_OFF  = WSGR_OFF  + (size_t)128*64*64;       // wvvR:  64*64*64 (r)
static constexpr size_t OHLWR_OFF = WVVR_OFF  + (size_t)64*64*64;        // ohlwR: 128*128 (r)
static constexpr size_t OHLVR_OFF = OHLWR_OFF + (size_t)128*128;         // ohlvR: 64*64 (r)
static constexpr size_t TOTAL_F   = OHLVR_OFF + (size_t)64*64;

__device__ __align__(256) float g_buf[TOTAL_F];
__device__ int g_idx[2 * EMAX];   // ctr | nbr
__device__ int g_cnt[128];        // [0:64) counts, [64:128) cursors
__device__ int g_offs[65];
__device__ int g_order[NMAXN];

__device__ __forceinline__ float f2tf32f(float x) {
    uint32_t r; asm("cvt.rna.tf32.f32 %0, %1;" : "=r"(r) : "f"(x));
    return __uint_as_float(r);
}

// ---------------------------------------------------------------------------
__global__ void zero_kernel(float* __restrict__ p, size_t n) {
    size_t i = (size_t)blockIdx.x * blockDim.x + threadIdx.x;
    if (i < n) p[i] = 0.0f;
}
__global__ void round_copy_kernel(const float* __restrict__ in, float* __restrict__ out, size_t n) {
    size_t i = (size_t)blockIdx.x * blockDim.x + threadIdx.x;
    if (i < n) out[i] = f2tf32f(in[i]);
}

// Bucket nodes by atom type
__global__ void count_kernel(const int* __restrict__ at, int* __restrict__ cnt, int N) {
    int n = blockIdx.x * blockDim.x + threadIdx.x;
    if (n < N) atomicAdd(&cnt[at[n]], 1);
}
__global__ void prefix_kernel(const int* __restrict__ cnt, int* __restrict__ offs) {
    if (threadIdx.x == 0) {
        int s = 0;
        for (int i = 0; i < 64; i++) { offs[i] = s; s += cnt[i]; }
        offs[64] = s;
    }
}
__global__ void scatter_order_kernel(const int* __restrict__ at, const int* __restrict__ offs,
                                     int* __restrict__ cur, int* __restrict__ order, int N) {
    int n = blockIdx.x * blockDim.x + threadIdx.x;
    if (n < N) {
        int t = at[n];
        int p = atomicAdd(&cur[t], 1);
        order[offs[t] + p] = n;
    }
}

// ---------------------------------------------------------------------------
// Node separable layernorm: warp per node. ns written tf32-rounded.
__global__ void node_ln_kernel(const float* __restrict__ nf,
                               const float* __restrict__ ws, const float* __restrict__ bs,
                               const float* __restrict__ wv,
                               float* __restrict__ ns, float* __restrict__ nv, int N) {
    int node = (blockIdx.x * blockDim.x + threadIdx.x) >> 5;
    int lane = threadIdx.x & 31;
    if (node >= N) return;
    const float* row = nf + (size_t)node * 320;
    float s[4]; float sum = 0.f;
#pragma unroll
    for (int i = 0; i < 4; i++) { s[i] = row[lane + 32*i]; sum += s[i]; }
#pragma unroll
    for (int o = 16; o; o >>= 1) sum += __shfl_xor_sync(0xffffffffu, sum, o);
    float mu = sum * (1.f/128.f);
    float var = 0.f;
#pragma unroll
    for (int i = 0; i < 4; i++) { s[i] -= mu; var += s[i]*s[i]; }
#pragma unroll
    for (int o = 16; o; o >>= 1) var += __shfl_xor_sync(0xffffffffu, var, o);
    float rs = rsqrtf(var * (1.f/128.f) + 1e-8f);
#pragma unroll
    for (int i = 0; i < 4; i++) {
        int c = lane + 32*i;
        ns[(size_t)node*128 + c] = f2tf32f(s[i]*rs*ws[c] + bs[c]);
    }
    float v[6]; float vs = 0.f;
#pragma unroll
    for (int i = 0; i < 6; i++) { v[i] = row[128 + lane + 32*i]; vs += v[i]*v[i]; }
#pragma unroll
    for (int o = 16; o; o >>= 1) vs += __shfl_xor_sync(0xffffffffu, vs, o);
    float rv = rsqrtf(vs * (1.f/192.f) + 1e-8f);
#pragma unroll
    for (int i = 0; i < 6; i++) {
        int c = lane + 32*i;
        nv[(size_t)node*192 + c] = v[i]*rv*wv[c/3];
    }
}

// ---------------------------------------------------------------------------
// Edge prep
__global__ void edge_prep_kernel(const float* __restrict__ ef, const int* __restrict__ ei,
                                 const int* __restrict__ act, const float* __restrict__ evec,
                                 const float* __restrict__ ws, const float* __restrict__ bs,
                                 const float* __restrict__ wv,
                                 const float* __restrict__ nv,
                                 float* __restrict__ esvf0, float* __restrict__ vf12,
                                 float* __restrict__ Rout, int* __restrict__ idx,
                                 int E, int Etot) {
    __shared__ float evs[8][192];
    int wi = threadIdx.x >> 5;
    int lane = threadIdx.x & 31;
    int e = blockIdx.x * 8 + wi;
    if (e >= E) return;
    int ae = act[e];
    int ctr = ei[ae], nbr = ei[Etot + ae];
    if (lane == 0) { idx[e] = ctr; idx[E + e] = nbr; }
    const float* row = ef + (size_t)e * 320;

    float s[4]; float sum = 0.f;
#pragma unroll
    for (int i = 0; i < 4; i++) { s[i] = row[lane + 32*i]; sum += s[i]; }
#pragma unroll
    for (int o = 16; o; o >>= 1) sum += __shfl_xor_sync(0xffffffffu, sum, o);
    float mu = sum * (1.f/128.f);
    float var = 0.f;
#pragma unroll
    for (int i = 0; i < 4; i++) { s[i] -= mu; var += s[i]*s[i]; }
#pragma unroll
    for (int o = 16; o; o >>= 1) var += __shfl_xor_sync(0xffffffffu, var, o);
    float rs = rsqrtf(var * (1.f/128.f) + 1e-8f);

    float* esv = esvf0 + (size_t)e * 320;
#pragma unroll
    for (int i = 0; i < 4; i++) {
        int c = lane + 32*i;
        esv[c] = f2tf32f(s[i]*rs*ws[c] + bs[c]);
    }

    float v[6]; float vs = 0.f;
#pragma unroll
    for (int i = 0; i < 6; i++) { v[i] = row[128 + lane + 32*i]; vs += v[i]*v[i]; }
#pragma unroll
    for (int o = 16; o; o >>= 1) vs += __shfl_xor_sync(0xffffffffu, vs, o);
    float rv = rsqrtf(vs * (1.f/192.f) + 1e-8f);
#pragma unroll
    for (int i = 0; i < 6; i++) {
        int c = lane + 32*i;
        evs[wi][c] = v[i]*rv*wv[c/3];
    }
    __syncwarp();

    float e0 = evec[(size_t)ae*3], e1 = evec[(size_t)ae*3+1], e2 = evec[(size_t)ae*3+2];
    float rn = rsqrtf(e0*e0 + e1*e1 + e2*e2 + 1e-8f);
    float ax = e0*rn, ay = e1*rn, az = e2*rn;
    float refx = (fabsf(ax) < 0.9f) ? 1.f : 0.f;
    float refy = 1.f - refx;
    float bx = -az*refy;
    float by =  az*refx;
    float bz =  ax*refy - ay*refx;
    float rb = rsqrtf(bx*bx + by*by + bz*bz + 1e-8f);
    bx *= rb; by *= rb; bz *= rb;
    float cx = ay*bz - az*by, cy = az*bx - ax*bz, cz = ax*by - ay*bx;
    if (lane == 0) {
        float* Rp = Rout + (size_t)e * 9;
        Rp[0]=ax; Rp[1]=ay; Rp[2]=az;
        Rp[3]=bx; Rp[4]=by; Rp[5]=bz;
        Rp[6]=cx; Rp[7]=cy; Rp[8]=cz;
    }

    float* vf = vf12 + (size_t)e * 384;
#pragma unroll
    for (int i = 0; i < 6; i++) {
        int u = lane + 32*i;
        float vx, vy, vz;
        if (u < 64) {
            const float* p = nv + (size_t)ctr*192 + u*3;
            vx = p[0]; vy = p[1]; vz = p[2];
        } else if (u < 128) {
            const float* p = &evs[wi][(u - 64)*3];
            vx = p[0]; vy = p[1]; vz = p[2];
        } else {
            const float* p = nv + (size_t)nbr*192 + (u - 128)*3;
            vx = p[0]; vy = p[1]; vz = p[2];
        }
        esv[128 + u] = f2tf32f(ax*vx + ay*vy + az*vz);
        vf[u]        = f2tf32f(bx*vx + by*vy + bz*vz);
        vf[192 + u]  = f2tf32f(cx*vx + cy*vy + cz*vz);
    }
}

// ---------------------------------------------------------------------------
// Weight prep
__global__ void build_w1c_kernel(const float* __restrict__ w1r, const float* __restrict__ w1i,
                                 float* __restrict__ w1c) {
    int idx = blockIdx.x * blockDim.x + threadIdx.x;
    if (idx >= 384*128) return;
    int r = idx / 128, c = idx % 128;
    float val;
    if (r < 192) val = (c < 64) ? w1r[r*64 + c] : w1i[r*64 + (c - 64)];
    else {
        int r2 = r - 192;
        val = (c < 64) ? -w1i[r2*64 + c] : w1r[r2*64 + (c - 64)];
    }
    w1c[idx] = f2tf32f(val);
}
__global__ void build_wcp_kernel(const float* __restrict__ w0, float* __restrict__ wcp) {
    int idx = blockIdx.x * blockDim.x + threadIdx.x;
    if (idx >= 128*512) return;
    int k = idx / 512, c = idx % 512;
    float v = (c < 256) ? w0[(size_t)k*256 + c] : w0[(size_t)(256 + k)*256 + (c - 256)];
    wcp[idx] = f2tf32f(v);
}
__global__ void build_w0m_kernel(const float* __restrict__ w0, float* __restrict__ w0m) {
    int idx = blockIdx.x * blockDim.x + threadIdx.x;
    if (idx >= 320*256) return;
    int k = idx / 256, c = idx % 256;
    int src = (k < 128) ? (k + 128) : (k + 256);
    w0m[idx] = f2tf32f(w0[(size_t)src*256 + c]);
}

// ---------------------------------------------------------------------------
__device__ __forceinline__ void cp16(uint32_t dst, const void* src, int bytes) {
    asm volatile("cp.async.cg.shared.global [%0], [%1], 16, %2;"
                 :: "r"(dst), "l"(src), "r"(bytes));
}
__device__ __forceinline__ void cp_commit() { asm volatile("cp.async.commit_group;"); }

// ---------------------------------------------------------------------------
// TF32 GEMM, cp.async 3-stage pipeline.
// MODE 0: C = A@B*scale (+bias), optional GATHER on A rows
// MODE 1: main SO2: C(msgs)=rnd(silu(v)) c<128; aux(gv)=sigmoid(v)[c<192] / v[else]
// MODE 2: lps scatter: atomicAdd(aggs[ctr[e]*128+c], (acc*scale+bias[c])*wenv[e,c]*INV)
// MODE 3: lpv scatter: row=m*E+e -> atomicAdd(aggv[m][ctr[e]][c], acc*scale*wenv[e,128+c]*INV)
// MODE 4: complex GEMM + fused back-rotation/gating -> msgv planes (C)
// MODE 5: typed: gs[node] = rnd(silu(acc*scale))          (B=wssR per type)
// MODE 6: typed: tg[node] = sigmoid(acc*scale)            (B=wsgR per type)
// MODE 7: typed, m=blockIdx.x: gvm[m][node] = rnd(acc*scale * tg[node][c])  (B=wvvR)
// MODE 8: out[row*320+c] = alpha*nf + beta*(acc*scale + bias[c])
// MODE 9: m=blockIdx.x: out[row*320+128+3c+m] = alpha*nf + beta*acc*scale
static constexpr int GSTAGES = 3;
static constexpr int ASTRIDE = 20;
static constexpr int BSTRIDE = 136;
static constexpr int ASZ = 128 * ASTRIDE;
static constexpr int BSZ = 16 * BSTRIDE;
static constexpr int GEMM_SMEM_BYTES = GSTAGES * (ASZ + BSZ) * 4;   // 56832
static constexpr int GEMM_SMEM_MODE4 = 128 * 132 * 4;               // 67584

template<int MODE, bool GATHER>
__global__ __launch_bounds__(256, 2)
void mma_gemm_kernel(const float* __restrict__ A, const float* __restrict__ B,
                     float* __restrict__ C, int M, int Nc, int K, int lda, int ldb,
                     float scale, const float* __restrict__ bias,
                     const int* __restrict__ rowidx,
                     const int* __restrict__ ctr, const int* __restrict__ nbr,
                     const float* __restrict__ proj,
                     const float* __restrict__ Rrot,
                     const float* __restrict__ gvbuf,
                     const float* __restrict__ wenv, float* __restrict__ agg,
                     float* __restrict__ aux,
                     const float* __restrict__ nf, const float* __restrict__ resp,
                     const int* __restrict__ offs, const int* __restrict__ order,
                     int tOffB, size_t aplane, int Nnodes, int E) {
    constexpr bool TYPED = (MODE == 5 || MODE == 6 || MODE == 7);
    extern __shared__ float smem[];
    float* AsBase = smem;
    float* BsBase = smem + GSTAGES * ASZ;

    const int tid  = threadIdx.x;
    const int lane = tid & 31;
    const int wid  = tid >> 5;
    const int g = lane >> 2, t = lane & 3;
    const int wm = (wid >> 2) * 64;
    const int wn = (wid & 3) * 32;

    int mplane = 0, bn;
    if (MODE == 7 || MODE == 9) { mplane = blockIdx.x; bn = 0; }
    else bn = blockIdx.x * 128;
    const int bm = blockIdx.y * 128;

    int Mloc = M, rowbase = 0, typ = 0;
    if (TYPED) {
        typ = blockIdx.z;
        int s0 = offs[typ];
        Mloc = offs[typ + 1] - s0;
        rowbase = s0;
        if (Mloc == 0 || bm >= Mloc) return;
    }
    const float* Ause = A + (size_t)mplane * aplane;
    const float* Buse = B + (TYPED ? (size_t)typ * tOffB : 0);

    // A load setup
    const float* aptr[2]; uint32_t adst[2];
#pragma unroll
    for (int it = 0; it < 2; it++) {
        int id = tid + 256*it;
        int row = id >> 2, q = id & 3;
        int r = bm + row;
        if (TYPED) {
            if (r >= Mloc) r = Mloc - 1;
            aptr[it] = Ause + (size_t)order[rowbase + r]*lda + q*4;
        } else {
            if (r >= M) r = M - 1;
            const float* ap = GATHER ? (Ause + (size_t)rowidx[r]*lda)
                                     : (Ause + (size_t)r*lda);
            aptr[it] = ap + q*4;
        }
        adst[it] = (uint32_t)__cvta_generic_to_shared(AsBase + row*ASTRIDE + q*4);
    }
    // B load setup
    const float* bptr[2]; uint32_t bdst[2]; int bbytes[2];
#pragma unroll
    for (int it = 0; it < 2; it++) {
        int id = tid + 256*it;
        int r = id >> 5, c4 = id & 31;
        int gn = bn + 4*c4;
        bbytes[it] = (gn < Nc) ? 16 : 0;
        bptr[it] = Buse + (size_t)r*ldb + gn;
        bdst[it] = (uint32_t)__cvta_generic_to_shared(BsBase + r*BSTRIDE + c4*4);
    }

    const int kTiles = K >> 4;
    auto loadStage = [&](int stage, int k0) {
        uint32_t ao = stage * (ASZ*4), bo = stage * (BSZ*4);
#pragma unroll
        for (int it = 0; it < 2; it++)
            cp16(adst[it] + ao, aptr[it] + k0, 16);
#pragma unroll
        for (int it = 0; it < 2; it++)
            cp16(bdst[it] + bo, bptr[it] + (size_t)k0*ldb, bbytes[it]);
        cp_commit();
    };

    float acc[4][4][4];
#pragma unroll
    for (int mi = 0; mi < 4; mi++)
#pragma unroll
        for (int ni = 0; ni < 4; ni++)
#pragma unroll
            for (int j = 0; j < 4; j++) acc[mi][ni][j] = 0.f;

#pragma unroll
    for (int s = 0; s < GSTAGES-1; s++) loadStage(s, s*16);

    for (int kt = 0; kt < kTiles; kt++) {
        asm volatile("cp.async.wait_group %0;" :: "n"(GSTAGES-2));
        __syncthreads();
        int pf = kt + GSTAGES - 1;
        if (pf < kTiles) loadStage(pf % GSTAGES, pf*16);
        else cp_commit();

        const float* As = AsBase + (kt % GSTAGES) * ASZ;
        const float* Bs = BsBase + (kt % GSTAGES) * BSZ;
#pragma unroll
        for (int k8 = 0; k8 < 2; k8++) {
            const int kb = k8 * 8;
            uint32_t af[4][4], bf[4][2];
#pragma unroll
            for (int mi = 0; mi < 4; mi++) {
                int m = wm + mi*16 + g;
                af[mi][0] = __float_as_uint(As[m*ASTRIDE + kb + t]);
                af[mi][1] = __float_as_uint(As[(m+8)*ASTRIDE + kb + t]);
                af[mi][2] = __float_as_uint(As[m*ASTRIDE + kb + t + 4]);
                af[mi][3] = __float_as_uint(As[(m+8)*ASTRIDE + kb + t + 4]);
            }
#pragma unroll
            for (int ni = 0; ni < 4; ni++) {
                int n = wn + ni*8 + g;
                bf[ni][0] = __float_as_uint(Bs[(kb+t)*BSTRIDE + n]);
                bf[ni][1] = __float_as_uint(Bs[(kb+t+4)*BSTRIDE + n]);
            }
#pragma unroll
            for (int mi = 0; mi < 4; mi++)
#pragma unroll
                for (int ni = 0; ni < 4; ni++) {
                    asm volatile(
                        "mma.sync.aligned.m16n8k8.row.col.f32.tf32.tf32.f32 "
                        "{%0,%1,%2,%3}, {%4,%5,%6,%7}, {%8,%9}, {%0,%1,%2,%3};"
                        : "+f"(acc[mi][ni][0]), "+f"(acc[mi][ni][1]),
                          "+f"(acc[mi][ni][2]), "+f"(acc[mi][ni][3])
                        : "r"(af[mi][0]), "r"(af[mi][1]), "r"(af[mi][2]), "r"(af[mi][3]),
                          "r"(bf[ni][0]), "r"(bf[ni][1]));
                }
        }
        __syncthreads();
    }

    // ---------------- epilogue ----------------
    const float INV = 0.28867513459481287f;  // 1/sqrt(12)

    if (MODE == 4) {
        // stage acc*scale into smem, then back-rotate + gate -> msgv planes
        float* Vs = smem;
#pragma unroll
        for (int mi = 0; mi < 4; mi++)
#pragma unroll
            for (int h = 0; h < 2; h++) {
                int r = wm + mi*16 + g + 8*h;
#pragma unroll
                for (int ni = 0; ni < 4; ni++) {
                    int c = wn + ni*8 + 2*t;
                    *(float2*)&Vs[r*132 + c] =
                        make_float2(acc[mi][ni][2*h]*scale, acc[mi][ni][2*h+1]*scale);
                }
            }
        __syncthreads();
        for (int r = wid; r < 128; r += 8) {
            int e = bm + r;
            const float* Rp = Rrot + (size_t)e * 9;
            float R0=Rp[0],R1=Rp[1],R2=Rp[2],R3=Rp[3],R4=Rp[4],R5=Rp[5],R6=Rp[6],R7=Rp[7],R8=Rp[8];
            const float* gvp = gvbuf + (size_t)e * 128;
#pragma unroll
            for (int i = 0; i < 2; i++) {
                int u = lane + 32*i;
                float sg = gvp[u];
                float i0 = gvp[64 + u];
                float i1 = Vs[r*132 + u], i2 = Vs[r*132 + 64 + u];
                float o0 = R0*i0 + R3*i1 + R6*i2;
                float o1 = R1*i0 + R4*i1 + R7*i2;
                float o2 = R2*i0 + R5*i1 + R8*i2;
                C[(size_t)0*E*64 + (size_t)e*64 + u] = f2tf32f(sg*o0);
                C[(size_t)1*E*64 + (size_t)e*64 + u] = f2tf32f(sg*o1);
                C[(size_t)2*E*64 + (size_t)e*64 + u] = f2tf32f(sg*o2);
            }
        }
        return;
    }

    float alpha = 0.f, beta = 0.f;
    if (MODE == 8 || MODE == 9) {
        alpha = 1.f / (1.f + expf(-resp[0]));
        beta = 1.f - alpha;
    }

#pragma unroll
    for (int mi = 0; mi < 4; mi++) {
        int r0 = bm + wm + mi*16 + g;
#pragma unroll
        for (int h = 0; h < 2; h++) {
            int row = r0 + 8*h;
            if (row >= (TYPED ? Mloc : M)) continue;
            if (MODE == 0) {
#pragma unroll
                for (int ni = 0; ni < 4; ni++) {
                    int c = bn + wn + ni*8 + 2*t;
                    if (c >= Nc) continue;
                    float a0 = acc[mi][ni][2*h]  *scale + (bias ? bias[c]   : 0.f);
                    float a1 = acc[mi][ni][2*h+1]*scale + (bias ? bias[c+1] : 0.f);
                    *(float2*)&C[(size_t)row*Nc + c] = make_float2(a0, a1);
                }
            } else if (MODE == 1) {
                const float* pc = proj + (size_t)ctr[row]*512;
                const float* pn = proj + (size_t)nbr[row]*512 + 256;
#pragma unroll
                for (int ni = 0; ni < 4; ni++) {
                    int c = bn + wn + ni*8 + 2*t;
                    float v0 = (acc[mi][ni][2*h]   + pc[c]   + pn[c]  ) * scale;
                    float v1 = (acc[mi][ni][2*h+1] + pc[c+1] + pn[c+1]) * scale;
                    if (c < 128) {
                        float m0 = f2tf32f(v0 / (1.f + expf(-v0)));
                        float m1 = f2tf32f(v1 / (1.f + expf(-v1)));
                        *(float2*)&C[(size_t)row*128 + c] = make_float2(m0, m1);
                    } else if (c < 192) {
                        float s0 = 1.f / (1.f + expf(-v0));
                        float s1 = 1.f / (1.f + expf(-v1));
                        *(float2*)&aux[(size_t)row*128 + (c-128)] = make_float2(s0, s1);
                    } else {
                        *(float2*)&aux[(size_t)row*128 + (c-128)] = make_float2(v0, v1);
                    }
                }
            } else if (MODE == 2) {
                int e = row;
                float* ap = agg + (size_t)ctr[e]*128;
                const float* we = wenv + (size_t)e*192;
#pragma unroll
                for (int ni = 0; ni < 4; ni++) {
                    int c = bn + wn + ni*8 + 2*t;
                    if (c >= Nc) continue;
                    float a0 = (acc[mi][ni][2*h]  *scale + bias[c])   * we[c]  *INV;
                    float a1 = (acc[mi][ni][2*h+1]*scale + bias[c+1]) * we[c+1]*INV;
                    atomicAdd(&ap[c],     a0);
                    atomicAdd(&ap[c + 1], a1);
                }
            } else if (MODE == 3) {
                int m = row / E;
                int e = row - m*E;
                float* ap = agg + (size_t)m*Nnodes*64 + (size_t)ctr[e]*64;
                const float* we = wenv + (size_t)e*192 + 128;
#pragma unroll
                for (int ni = 0; ni < 4; ni++) {
                    int c = bn + wn + ni*8 + 2*t;
                    if (c >= Nc) continue;
                    float a0 = acc[mi][ni][2*h]  *scale * we[c]  *INV;
                    float a1 = acc[mi][ni][2*h+1]*scale * we[c+1]*INV;
                    atomicAdd(&ap[c],     a0);
                    atomicAdd(&ap[c + 1], a1);
                }
            } else if (MODE == 5) {
                int node = order[rowbase + row];
#pragma unroll
                for (int ni = 0; ni < 4; ni++) {
                    int c = wn + ni*8 + 2*t;
                    float v0 = acc[mi][ni][2*h]  *scale;
                    float v1 = acc[mi][ni][2*h+1]*scale;
                    float g0 = f2tf32f(v0 / (1.f + expf(-v0)));
                    float g1 = f2tf32f(v1 / (1.f + expf(-v1)));
                    *(float2*)&C[(size_t)node*128 + c] = make_float2(g0, g1);
                }
            } else if (MODE == 6) {
                int node = order[rowbase + row];
#pragma unroll
                for (int ni = 0; ni < 4; ni++) {
                    int c = wn + ni*8 + 2*t;
                    if (c >= Nc) continue;
                    float s0 = 1.f / (1.f + expf(-acc[mi][ni][2*h]  *scale));
                    float s1 = 1.f / (1.f + expf(-acc[mi][ni][2*h+1]*scale));
                    *(float2*)&C[(size_t)node*64 + c] = make_float2(s0, s1);
                }
            } else if (MODE == 7) {
                int node = order[rowbase + row];
                const float* tgp = gvbuf + (size_t)node*64;
#pragma unroll
                for (int ni = 0; ni < 4; ni++) {
                    int c = wn + ni*8 + 2*t;
                    if (c >= Nc) continue;
                    float v0 = f2tf32f(acc[mi][ni][2*h]  *scale * tgp[c]);
                    float v1 = f2tf32f(acc[mi][ni][2*h+1]*scale * tgp[c+1]);
                    *(float2*)&C[(size_t)mplane*aplane + (size_t)node*64 + c] = make_float2(v0, v1);
                }
            } else if (MODE == 8) {
#pragma unroll
                for (int ni = 0; ni < 4; ni++) {
                    int c = wn + ni*8 + 2*t;
                    float a0 = acc[mi][ni][2*h]  *scale + bias[c];
                    float a1 = acc[mi][ni][2*h+1]*scale + bias[c+1];
                    float o0 = alpha*nf[(size_t)row*320 + c]     + beta*a0;
                    float o1 = alpha*nf[(size_t)row*320 + c + 1] + beta*a1;
                    *(float2*)&C[(size_t)row*320 + c] = make_float2(o0, o1);
                }
            } else { // MODE 9
#pragma unroll
                for (int ni = 0; ni < 4; ni++) {
                    int c = wn + ni*8 + 2*t;
                    if (c >= Nc) continue;
                    float a0 = acc[mi][ni][2*h]  *scale;
                    float a1 = acc[mi][ni][2*h+1]*scale;
                    size_t o0i = (size_t)row*320 + 128 + 3*c + mplane;
                    size_t o1i = (size_t)row*320 + 128 + 3*(c+1) + mplane;
                    C[o0i] = alpha*nf[o0i] + beta*a0;
                    C[o1i] = alpha*nf[o1i] + beta*a1;
                }
            }
        }
    }
}

// ---------------------------------------------------------------------------
extern "C" void kernel_launch(void* const* d_in, const int* in_sizes, int n_in,
                              void* d_out, int out_size) {
    const float* latents = (const float*)d_in[0];
    const float* nf      = (const float*)d_in[1];
    const float* ef      = (const float*)d_in[2];
    const int*   at      = (const int*)  d_in[3];
    const int*   ei      = (const int*)  d_in[5];
    const float* evec    = (const float*)d_in[6];
    const int*   act     = (const int*)  d_in[7];
    const float* snws    = (const float*)d_in[8];
    const float* snbs    = (const float*)d_in[9];
    const float* snwv    = (const float*)d_in[10];
    const float* sews    = (const float*)d_in[11];
    const float* sebs    = (const float*)d_in[12];
    const float* sewv    = (const float*)d_in[13];
    const float* so2w0   = (const float*)d_in[14];
    const float* so2w1r  = (const float*)d_in[15];
    const float* so2w1i  = (const float*)d_in[16];
    const float* envw    = (const float*)d_in[17];
    const float* lpws    = (const float*)d_in[18];
    const float* lpbs    = (const float*)d_in[19];
    const float* lpwv    = (const float*)d_in[20];
    const float* ohwss   = (const float*)d_in[21];
    const float* ohwsg   = (const float*)d_in[22];
    const float* ohwvv   = (const float*)d_in[23];
    const float* ohlws   = (const float*)d_in[24];
    const float* ohlbs   = (const float*)d_in[25];
    const float* ohlwv   = (const float*)d_in[26];
    const float* resp    = (const float*)d_in[27];

    int N    = in_sizes[1] / 320;
    int E    = in_sizes[7];
    int Etot = in_sizes[5] / 2;
    size_t latN = (size_t)in_sizes[0];

    float* base = nullptr;  cudaGetSymbolAddress((void**)&base, g_buf);
    int* idx = nullptr;     cudaGetSymbolAddress((void**)&idx, g_idx);
    int* cnt = nullptr;     cudaGetSymbolAddress((void**)&cnt, g_cnt);
    int* offs = nullptr;    cudaGetSymbolAddress((void**)&offs, g_offs);
    int* order = nullptr;   cudaGetSymbolAddress((void**)&order, g_order);

    float* ns    = base + NS_OFF;
    float* nv    = base + NV_OFF;
    float* esvf0 = base + ESV_OFF;
    float* vf12  = base + VF12_OFF;
    float* Rbuf  = base + R_OFF;
    float* proj  = base + PROJ_OFF;
    float* gvb   = base + GV_OFF;
    float* msgs  = base + MSGS_OFF;
    float* msgv  = base + MSGV_OFF;
    float* wenv  = base + WENV_OFF;
    float* aggs  = base + AGGS_OFF;
    float* aggv  = base + AGGV_OFF;
    float* gsb   = base + GS_OFF;
    float* tgb   = base + TG_OFF;
    float* gvm   = base + GVM_OFF;
    float* latR  = base + LATR_OFF;
    float* w1c   = base + W1C_OFF;
    float* wcp   = base + WCP_OFF;
    float* w0m   = base + W0M_OFF;
    float* envr  = base + ENVR_OFF;
    float* lpwsr = base + LPWSR_OFF;
    float* lpwvr = base + LPWVR_OFF;
    float* wssR  = base + WSSR_OFF;
    float* wsgR  = base + WSGR_OFF;
    float* wvvR  = base + WVVR_OFF;
    float* ohlwR = base + OHLWR_OFF;
    float* ohlvR = base + OHLVR_OFF;
    int* ctr = idx;
    int* nbr = idx + E;

    const float isq576 = 0.041666666666666664f; // 1/24
    const float isq192 = 0.07216878364870323f;
    const float isq128 = 0.08838834764831845f;
    const float n_ss   = 0.011048543456039806f; // 1/sqrt(128*64)
    const float n_vv   = 0.015625f;             // 1/64

    cudaFuncSetAttribute(mma_gemm_kernel<0,false>, cudaFuncAttributeMaxDynamicSharedMemorySize, GEMM_SMEM_BYTES);
    cudaFuncSetAttribute(mma_gemm_kernel<0,true>,  cudaFuncAttributeMaxDynamicSharedMemorySize, GEMM_SMEM_BYTES);
    cudaFuncSetAttribute(mma_gemm_kernel<1,false>, cudaFuncAttributeMaxDynamicSharedMemorySize, GEMM_SMEM_BYTES);
    cudaFuncSetAttribute(mma_gemm_kernel<2,false>, cudaFuncAttributeMaxDynamicSharedMemorySize, GEMM_SMEM_BYTES);
    cudaFuncSetAttribute(mma_gemm_kernel<3,false>, cudaFuncAttributeMaxDynamicSharedMemorySize, GEMM_SMEM_BYTES);
    cudaFuncSetAttribute(mma_gemm_kernel<4,false>, cudaFuncAttributeMaxDynamicSharedMemorySize, GEMM_SMEM_MODE4);
    cudaFuncSetAttribute(mma_gemm_kernel<5,false>, cudaFuncAttributeMaxDynamicSharedMemorySize, GEMM_SMEM_BYTES);
    cudaFuncSetAttribute(mma_gemm_kernel<6,false>, cudaFuncAttributeMaxDynamicSharedMemorySize, GEMM_SMEM_BYTES);
    cudaFuncSetAttribute(mma_gemm_kernel<7,false>, cudaFuncAttributeMaxDynamicSharedMemorySize, GEMM_SMEM_BYTES);
    cudaFuncSetAttribute(mma_gemm_kernel<8,false>, cudaFuncAttributeMaxDynamicSharedMemorySize, GEMM_SMEM_BYTES);
    cudaFuncSetAttribute(mma_gemm_kernel<9,false>, cudaFuncAttributeMaxDynamicSharedMemorySize, GEMM_SMEM_BYTES);

    int etile = (E + 127)/128;
    int ntile = (N + 127)/128;

    // zero accumulators + bucket counters
    zero_kernel<<<(int)(((size_t)N*320 + 255)/256), 256>>>(aggs, (size_t)N*320);
    zero_kernel<<<1, 128>>>((float*)cnt, 128);
    node_ln_kernel<<<(N + 7)/8, 256>>>(nf, snws, snbs, snwv, ns, nv, N);
    build_w1c_kernel<<<(384*128 + 255)/256, 256>>>(so2w1r, so2w1i, w1c);
    build_wcp_kernel<<<(128*512 + 255)/256, 256>>>(so2w0, wcp);
    build_w0m_kernel<<<(320*256 + 255)/256, 256>>>(so2w0, w0m);
    round_copy_kernel<<<(int)((latN + 255)/256), 256>>>(latents, latR, latN);
    round_copy_kernel<<<(128*192 + 255)/256, 256>>>(envw, envr, 128*192);
    round_copy_kernel<<<(128*128 + 255)/256, 256>>>(lpws, lpwsr, 128*128);
    round_copy_kernel<<<(64*64 + 255)/256, 256>>>(lpwv, lpwvr, 64*64);
    round_copy_kernel<<<(128*64*128 + 255)/256, 256>>>(ohwss, wssR, 128*64*128);
    round_copy_kernel<<<(128*64*64 + 255)/256, 256>>>(ohwsg, wsgR, 128*64*64);
    round_copy_kernel<<<(64*64*64 + 255)/256, 256>>>(ohwvv, wvvR, 64*64*64);
    round_copy_kernel<<<(128*128 + 255)/256, 256>>>(ohlws, ohlwR, 128*128);
    round_copy_kernel<<<(64*64 + 255)/256, 256>>>(ohlwv, ohlvR, 64*64);
    // bucket nodes by type
    count_kernel<<<(N + 255)/256, 256>>>(at, cnt, N);
    prefix_kernel<<<1, 32>>>(cnt, offs);
    scatter_order_kernel<<<(N + 255)/256, 256>>>(at, offs, cnt + 64, order, N);

    edge_prep_kernel<<<(E + 7)/8, 256>>>(ef, ei, act, evec, sews, sebs, sewv,
                                         nv, esvf0, vf12, Rbuf, idx, E, Etot);

    // proj = ns @ wcp  (N x 512)
    mma_gemm_kernel<0,false><<<dim3(4, ntile), 256, GEMM_SMEM_BYTES>>>(
        ns, wcp, proj, N, 512, 128, 128, 512, 1.0f, nullptr,
        nullptr, nullptr, nullptr, nullptr, nullptr, nullptr, nullptr, nullptr, nullptr,
        nullptr, nullptr, nullptr, nullptr, 0, 0, N, E);
    // wenv = latR[act] @ envr / sqrt(128)
    mma_gemm_kernel<0,true><<<dim3(2, etile), 256, GEMM_SMEM_BYTES>>>(
        latR, envr, wenv, E, 192, 128, 128, 192, isq128, nullptr,
        act, nullptr, nullptr, nullptr, nullptr, nullptr, nullptr, nullptr, nullptr,
        nullptr, nullptr, nullptr, nullptr, 0, 0, N, E);
    // main SO2 GEMM -> msgs + gv
    mma_gemm_kernel<1,false><<<dim3(2, etile), 256, GEMM_SMEM_BYTES>>>(
        esvf0, w0m, msgs, E, 256, 320, 320, 256, isq576, nullptr,
        nullptr, ctr, nbr, proj, nullptr, nullptr, nullptr, nullptr, gvb,
        nullptr, nullptr, nullptr, nullptr, 0, 0, N, E);
    // complex GEMM + fused rotation/gate -> msgv
    mma_gemm_kernel<4,false><<<dim3(1, etile), 256, GEMM_SMEM_MODE4>>>(
        vf12, w1c, msgv, E, 128, 384, 384, 128, isq192, nullptr,
        nullptr, nullptr, nullptr, nullptr, Rbuf, gvb, nullptr, nullptr, nullptr,
        nullptr, nullptr, nullptr, nullptr, 0, 0, N, E);
    // lps GEMM + env-weight + scatter -> aggs
    mma_gemm_kernel<2,false><<<dim3(1, etile), 256, GEMM_SMEM_BYTES>>>(
        msgs, lpwsr, nullptr, E, 128, 128, 128, 128, isq128, lpbs,
        nullptr, ctr, nullptr, nullptr, nullptr, nullptr, wenv, aggs, nullptr,
        nullptr, nullptr, nullptr, nullptr, 0, 0, N, E);
    // lpv GEMM + env-weight + scatter -> aggv
    mma_gemm_kernel<3,false><<<dim3(1, (3*E + 127)/128), 256, GEMM_SMEM_BYTES>>>(
        msgv, lpwvr, nullptr, 3*E, 64, 64, 64, 64, 0.125f, nullptr,
        nullptr, ctr, nullptr, nullptr, nullptr, nullptr, wenv, aggv, nullptr,
        nullptr, nullptr, nullptr, nullptr, 0, 0, N, E);
    // typed: gs = rnd(silu(aggs @ wss[:,t,:] * n_ss))
    mma_gemm_kernel<5,false><<<dim3(1, 2, 64), 256, GEMM_SMEM_BYTES>>>(
        aggs, wssR, gsb, N, 128, 128, 128, 64*128, n_ss, nullptr,
        nullptr, nullptr, nullptr, nullptr, nullptr, nullptr, nullptr, nullptr, nullptr,
        nullptr, nullptr, offs, order, 128, 0, N, E);
    // typed: tg = sigmoid(aggs @ wsg[:,t,:] * n_ss)
    mma_gemm_kernel<6,false><<<dim3(1, 2, 64), 256, GEMM_SMEM_BYTES>>>(
        aggs, wsgR, tgb, N, 64, 128, 128, 64*64, n_ss, nullptr,
        nullptr, nullptr, nullptr, nullptr, nullptr, nullptr, nullptr, nullptr, nullptr,
        nullptr, nullptr, offs, order, 64, 0, N, E);
    // typed, 3 planes: gvm = rnd(tg * (aggv @ wvv[:,t,:] * n_vv))
    mma_gemm_kernel<7,false><<<dim3(3, 2, 64), 256, GEMM_SMEM_BYTES>>>(
        aggv, wvvR, gvm, N, 64, 64, 64, 64*64, n_vv, nullptr,
        nullptr, nullptr, nullptr, nullptr, nullptr, tgb, nullptr, nullptr, nullptr,
        nullptr, nullptr, offs, order, 64, (size_t)N*64, N, E);
    // final scalar: out[:,0:128] = alpha*nf + beta*(gs @ ohlws /sqrt(128) + ohlbs)
    mma_gemm_kernel<8,false><<<dim3(1, ntile), 256, GEMM_SMEM_BYTES>>>(
        gsb, ohlwR, (float*)d_out, N, 128, 128, 128, 128, isq128, ohlbs,
        nullptr, nullptr, nullptr, nullptr, nullptr, nullptr, nullptr, nullptr, nullptr,
        nf, resp, nullptr, nullptr, 0, 0, N, E);
    // final vector: out[:,128+3k+m] = alpha*nf + beta*(gvm @ ohlwv / 8)
    mma_gemm_kernel<9,false><<<dim3(3, ntile), 256, GEMM_SMEM_BYTES>>>(
        gvm, ohlvR, (float*)d_out, N, 64, 64, 64, 64, 0.125f, nullptr,
        nullptr, nullptr, nullptr, nullptr, nullptr, nullptr, nullptr, nullptr, nullptr,
        nf, resp, nullptr, nullptr, 0, (size_t)N*64, N, E);
}

// round 6
// speedup vs baseline: 2.6742x; 1.0019x over previous
#include <cuda_runtime.h>
#include <math.h>
#include <stdint.h>

static constexpr int NMAXN = 8000;
static constexpr int EMAX  = 96000;

// Scratch layout (offsets in floats)
static constexpr size_t NS_OFF    = 0;                                   // ns:    N x 128 (r)
static constexpr size_t NV_OFF    = NS_OFF    + (size_t)NMAXN * 128;     // nv:    N x 192
static constexpr size_t ESV_OFF   = NV_OFF    + (size_t)NMAXN * 192;     // esvf0: E x 320 (r)
static constexpr size_t VF12_OFF  = ESV_OFF   + (size_t)EMAX  * 320;     // vf12:  E x 384 (r)
static constexpr size_t R_OFF     = VF12_OFF  + (size_t)EMAX  * 384;     // R:     E x 9
static constexpr size_t PROJ_OFF  = R_OFF     + (size_t)EMAX  * 9;       // proj:  N x 512
static constexpr size_t GV_OFF    = PROJ_OFF  + (size_t)NMAXN * 512;     // gv:    E x 128 (sig|vraw)
static constexpr size_t MSGS_OFF  = GV_OFF    + (size_t)EMAX  * 128;     // msgs:  E x 128 (r)
static constexpr size_t MSGV_OFF  = MSGS_OFF  + (size_t)EMAX  * 128;     // msgv:  3 x E x 64 (r)
static constexpr size_t WENV_OFF  = MSGV_OFF  + (size_t)3*EMAX* 64;      // wenv:  E x 192
static constexpr size_t AGGS_OFF  = WENV_OFF  + (size_t)EMAX  * 192;     // aggs:  N x 128
static constexpr size_t AGGV_OFF  = AGGS_OFF  + (size_t)NMAXN * 128;     // aggv:  3 x N x 64
static constexpr size_t GS_OFF    = AGGV_OFF  + (size_t)3*NMAXN*64;      // gs:    N x 128 (r)
static constexpr size_t TG_OFF    = GS_OFF    + (size_t)NMAXN * 128;     // tg:    N x 64
static constexpr size_t GVM_OFF   = TG_OFF    + (size_t)NMAXN * 64;      // gvm:   3 x N x 64 (r)
static constexpr size_t LATR_OFF  = GVM_OFF   + (size_t)3*NMAXN*64;      // latR:  E x 128 (r)
static constexpr size_t W1C_OFF   = LATR_OFF  + (size_t)EMAX  * 128;     // w1c:   384 x 128 (r)
static constexpr size_t WCP_OFF   = W1C_OFF   + (size_t)384 * 128;       // wcp:   128 x 512 (r)
static constexpr size_t W0M_OFF   = WCP_OFF   + (size_t)128 * 512;       // w0m:   320 x 256 (r)
static constexpr size_t ENVR_OFF  = W0M_OFF   + (size_t)320 * 256;       // envr:  128 x 192 (r)
static constexpr size_t LPWSR_OFF = ENVR_OFF  + (size_t)128 * 192;       // lpwsr: 128 x 128 (r)
static constexpr size_t LPWVR_OFF = LPWSR_OFF + (size_t)128 * 128;       // lpwvr: 64 x 64 (r)
static constexpr size_t WSSR_OFF  = LPWVR_OFF + (size_t)64 * 64;         // wssR:  128*64*128 (r)
static constexpr size_t WSGR_OFF  = WSSR_OFF  + (size_t)128*64*128;      // wsgR:  128*64*64 (r)
static constexpr size_t WVVR_OFF  = WSGR_OFF  + (size_t)128*64*64;       // wvvR:  64*64*64 (r)
static constexpr size_t OHLWR_OFF = WVVR_OFF  + (size_t)64*64*64;        // ohlwR: 128*128 (r)
static constexpr size_t OHLVR_OFF = OHLWR_OFF + (size_t)128*128;         // ohlvR: 64*64 (r)
static constexpr size_t TOTAL_F   = OHLVR_OFF + (size_t)64*64;

__device__ __align__(256) float g_buf[TOTAL_F];
__device__ int g_idx[2 * EMAX];   // ctr | nbr
__device__ int g_cnt[128];        // [0:64) counts, [64:128) cursors
__device__ int g_offs[65];
__device__ int g_order[NMAXN];

__device__ __forceinline__ float f2tf32f(float x) {
    uint32_t r; asm("cvt.rna.tf32.f32 %0, %1;" : "=r"(r) : "f"(x));
    return __uint_as_float(r);
}

// ---------------------------------------------------------------------------
__global__ void zero_kernel(float* __restrict__ p, size_t n) {
    size_t i = (size_t)blockIdx.x * blockDim.x + threadIdx.x;
    if (i < n) p[i] = 0.0f;
}
__global__ void round_copy_kernel(const float* __restrict__ in, float* __restrict__ out, size_t n) {
    size_t i = (size_t)blockIdx.x * blockDim.x + threadIdx.x;
    if (i < n) out[i] = f2tf32f(in[i]);
}

// Bucket nodes by atom type
__global__ void count_kernel(const int* __restrict__ at, int* __restrict__ cnt, int N) {
    int n = blockIdx.x * blockDim.x + threadIdx.x;
    if (n < N) atomicAdd(&cnt[at[n]], 1);
}
__global__ void prefix_kernel(const int* __restrict__ cnt, int* __restrict__ offs) {
    if (threadIdx.x == 0) {
        int s = 0;
        for (int i = 0; i < 64; i++) { offs[i] = s; s += cnt[i]; }
        offs[64] = s;
    }
}
__global__ void scatter_order_kernel(const int* __restrict__ at, const int* __restrict__ offs,
                                     int* __restrict__ cur, int* __restrict__ order, int N) {
    int n = blockIdx.x * blockDim.x + threadIdx.x;
    if (n < N) {
        int t = at[n];
        int p = atomicAdd(&cur[t], 1);
        order[offs[t] + p] = n;
    }
}

// ---------------------------------------------------------------------------
// Node separable layernorm: warp per node. ns written tf32-rounded.
__global__ void node_ln_kernel(const float* __restrict__ nf,
                               const float* __restrict__ ws, const float* __restrict__ bs,
                               const float* __restrict__ wv,
                               float* __restrict__ ns, float* __restrict__ nv, int N) {
    int node = (blockIdx.x * blockDim.x + threadIdx.x) >> 5;
    int lane = threadIdx.x & 31;
    if (node >= N) return;
    const float* row = nf + (size_t)node * 320;
    float s[4]; float sum = 0.f;
#pragma unroll
    for (int i = 0; i < 4; i++) { s[i] = row[lane + 32*i]; sum += s[i]; }
#pragma unroll
    for (int o = 16; o; o >>= 1) sum += __shfl_xor_sync(0xffffffffu, sum, o);
    float mu = sum * (1.f/128.f);
    float var = 0.f;
#pragma unroll
    for (int i = 0; i < 4; i++) { s[i] -= mu; var += s[i]*s[i]; }
#pragma unroll
    for (int o = 16; o; o >>= 1) var += __shfl_xor_sync(0xffffffffu, var, o);
    float rs = rsqrtf(var * (1.f/128.f) + 1e-8f);
#pragma unroll
    for (int i = 0; i < 4; i++) {
        int c = lane + 32*i;
        ns[(size_t)node*128 + c] = f2tf32f(s[i]*rs*ws[c] + bs[c]);
    }
    float v[6]; float vs = 0.f;
#pragma unroll
    for (int i = 0; i < 6; i++) { v[i] = row[128 + lane + 32*i]; vs += v[i]*v[i]; }
#pragma unroll
    for (int o = 16; o; o >>= 1) vs += __shfl_xor_sync(0xffffffffu, vs, o);
    float rv = rsqrtf(vs * (1.f/192.f) + 1e-8f);
#pragma unroll
    for (int i = 0; i < 6; i++) {
        int c = lane + 32*i;
        nv[(size_t)node*192 + c] = v[i]*rv*wv[c/3];
    }
}

// ---------------------------------------------------------------------------
// Edge prep
__global__ void edge_prep_kernel(const float* __restrict__ ef, const int* __restrict__ ei,
                                 const int* __restrict__ act, const float* __restrict__ evec,
                                 const float* __restrict__ ws, const float* __restrict__ bs,
                                 const float* __restrict__ wv,
                                 const float* __restrict__ nv,
                                 float* __restrict__ esvf0, float* __restrict__ vf12,
                                 float* __restrict__ Rout, int* __restrict__ idx,
                                 int E, int Etot) {
    __shared__ float evs[8][192];
    int wi = threadIdx.x >> 5;
    int lane = threadIdx.x & 31;
    int e = blockIdx.x * 8 + wi;
    if (e >= E) return;
    int ae = act[e];
    int ctr = ei[ae], nbr = ei[Etot + ae];
    if (lane == 0) { idx[e] = ctr; idx[E + e] = nbr; }
    const float* row = ef + (size_t)e * 320;

    float s[4]; float sum = 0.f;
#pragma unroll
    for (int i = 0; i < 4; i++) { s[i] = row[lane + 32*i]; sum += s[i]; }
#pragma unroll
    for (int o = 16; o; o >>= 1) sum += __shfl_xor_sync(0xffffffffu, sum, o);
    float mu = sum * (1.f/128.f);
    float var = 0.f;
#pragma unroll
    for (int i = 0; i < 4; i++) { s[i] -= mu; var += s[i]*s[i]; }
#pragma unroll
    for (int o = 16; o; o >>= 1) var += __shfl_xor_sync(0xffffffffu, var, o);
    float rs = rsqrtf(var * (1.f/128.f) + 1e-8f);

    float* esv = esvf0 + (size_t)e * 320;
#pragma unroll
    for (int i = 0; i < 4; i++) {
        int c = lane + 32*i;
        esv[c] = f2tf32f(s[i]*rs*ws[c] + bs[c]);
    }

    float v[6]; float vs = 0.f;
#pragma unroll
    for (int i = 0; i < 6; i++) { v[i] = row[128 + lane + 32*i]; vs += v[i]*v[i]; }
#pragma unroll
    for (int o = 16; o; o >>= 1) vs += __shfl_xor_sync(0xffffffffu, vs, o);
    float rv = rsqrtf(vs * (1.f/192.f) + 1e-8f);
#pragma unroll
    for (int i = 0; i < 6; i++) {
        int c = lane + 32*i;
        evs[wi][c] = v[i]*rv*wv[c/3];
    }
    __syncwarp();

    float e0 = evec[(size_t)ae*3], e1 = evec[(size_t)ae*3+1], e2 = evec[(size_t)ae*3+2];
    float rn = rsqrtf(e0*e0 + e1*e1 + e2*e2 + 1e-8f);
    float ax = e0*rn, ay = e1*rn, az = e2*rn;
    float refx = (fabsf(ax) < 0.9f) ? 1.f : 0.f;
    float refy = 1.f - refx;
    float bx = -az*refy;
    float by =  az*refx;
    float bz =  ax*refy - ay*refx;
    float rb = rsqrtf(bx*bx + by*by + bz*bz + 1e-8f);
    bx *= rb; by *= rb; bz *= rb;
    float cx = ay*bz - az*by, cy = az*bx - ax*bz, cz = ax*by - ay*bx;
    if (lane == 0) {
        float* Rp = Rout + (size_t)e * 9;
        Rp[0]=ax; Rp[1]=ay; Rp[2]=az;
        Rp[3]=bx; Rp[4]=by; Rp[5]=bz;
        Rp[6]=cx; Rp[7]=cy; Rp[8]=cz;
    }

    float* vf = vf12 + (size_t)e * 384;
#pragma unroll
    for (int i = 0; i < 6; i++) {
        int u = lane + 32*i;
        float vx, vy, vz;
        if (u < 64) {
            const float* p = nv + (size_t)ctr*192 + u*3;
            vx = p[0]; vy = p[1]; vz = p[2];
        } else if (u < 128) {
            const float* p = &evs[wi][(u - 64)*3];
            vx = p[0]; vy = p[1]; vz = p[2];
        } else {
            const float* p = nv + (size_t)nbr*192 + (u - 128)*3;
            vx = p[0]; vy = p[1]; vz = p[2];
        }
        esv[128 + u] = f2tf32f(ax*vx + ay*vy + az*vz);
        vf[u]        = f2tf32f(bx*vx + by*vy + bz*vz);
        vf[192 + u]  = f2tf32f(cx*vx + cy*vy + cz*vz);
    }
}

// ---------------------------------------------------------------------------
// Weight prep
__global__ void build_w1c_kernel(const float* __restrict__ w1r, const float* __restrict__ w1i,
                                 float* __restrict__ w1c) {
    int idx = blockIdx.x * blockDim.x + threadIdx.x;
    if (idx >= 384*128) return;
    int r = idx / 128, c = idx % 128;
    float val;
    if (r < 192) val = (c < 64) ? w1r[r*64 + c] : w1i[r*64 + (c - 64)];
    else {
        int r2 = r - 192;
        val = (c < 64) ? -w1i[r2*64 + c] : w1r[r2*64 + (c - 64)];
    }
    w1c[idx] = f2tf32f(val);
}
__global__ void build_wcp_kernel(const float* __restrict__ w0, float* __restrict__ wcp) {
    int idx = blockIdx.x * blockDim.x + threadIdx.x;
    if (idx >= 128*512) return;
    int k = idx / 512, c = idx % 512;
    float v = (c < 256) ? w0[(size_t)k*256 + c] : w0[(size_t)(256 + k)*256 + (c - 256)];
    wcp[idx] = f2tf32f(v);
}
__global__ void build_w0m_kernel(const float* __restrict__ w0, float* __restrict__ w0m) {
    int idx = blockIdx.x * blockDim.x + threadIdx.x;
    if (idx >= 320*256) return;
    int k = idx / 256, c = idx % 256;
    int src = (k < 128) ? (k + 128) : (k + 256);
    w0m[idx] = f2tf32f(w0[(size_t)src*256 + c]);
}

// ---------------------------------------------------------------------------
__device__ __forceinline__ void cp16(uint32_t dst, const void* src, int bytes) {
    asm volatile("cp.async.cg.shared.global [%0], [%1], 16, %2;"
                 :: "r"(dst), "l"(src), "r"(bytes));
}
__device__ __forceinline__ void cp_commit() { asm volatile("cp.async.commit_group;"); }

// ---------------------------------------------------------------------------
// TF32 GEMM, cp.async 3-stage pipeline.
// MODE 0: C = A@B*scale (+bias), optional GATHER on A rows
// MODE 1: main SO2: C(msgs)=rnd(silu(v)) c<128; aux(gv)=sigmoid(v)[c<192] / v[else]
// MODE 2: lps scatter: atomicAdd(aggs[ctr[e]*128+c], (acc*scale+bias[c])*wenv[e,c]*INV)
// MODE 3: lpv scatter: row=m*E+e -> atomicAdd(aggv[m][ctr[e]][c], acc*scale*wenv[e,128+c]*INV)
// MODE 4: complex GEMM + fused back-rotation/gating -> msgv planes (C)
// MODE 5: typed: gs[node] = rnd(silu(acc*scale))          (B=wssR per type)
// MODE 6: typed: tg[node] = sigmoid(acc*scale)            (B=wsgR per type)
// MODE 7: typed, m=blockIdx.x: gvm[m][node] = rnd(acc*scale * tg[node][c])  (B=wvvR)
// MODE 8: out[row*320+c] = alpha*nf + beta*(acc*scale + bias[c])
// MODE 9: m=blockIdx.x: out[row*320+128+3c+m] = alpha*nf + beta*acc*scale
static constexpr int GSTAGES = 3;
static constexpr int ASTRIDE = 20;
static constexpr int BSTRIDE = 136;
static constexpr int ASZ = 128 * ASTRIDE;
static constexpr int BSZ = 16 * BSTRIDE;
static constexpr int GEMM_SMEM_BYTES = GSTAGES * (ASZ + BSZ) * 4;   // 56832
static constexpr int GEMM_SMEM_MODE4 = 128 * 132 * 4;               // 67584

template<int MODE, bool GATHER>
__global__ __launch_bounds__(256, 2)
void mma_gemm_kernel(const float* __restrict__ A, const float* __restrict__ B,
                     float* __restrict__ C, int M, int Nc, int K, int lda, int ldb,
                     float scale, const float* __restrict__ bias,
                     const int* __restrict__ rowidx,
                     const int* __restrict__ ctr, const int* __restrict__ nbr,
                     const float* __restrict__ proj,
                     const float* __restrict__ Rrot,
                     const float* __restrict__ gvbuf,
                     const float* __restrict__ wenv, float* __restrict__ agg,
                     float* __restrict__ aux,
                     const float* __restrict__ nf, const float* __restrict__ resp,
                     const int* __restrict__ offs, const int* __restrict__ order,
                     int tOffB, size_t aplane, int Nnodes, int E) {
    constexpr bool TYPED = (MODE == 5 || MODE == 6 || MODE == 7);
    extern __shared__ float smem[];
    float* AsBase = smem;
    float* BsBase = smem + GSTAGES * ASZ;

    const int tid  = threadIdx.x;
    const int lane = tid & 31;
    const int wid  = tid >> 5;
    const int g = lane >> 2, t = lane & 3;
    const int wm = (wid >> 2) * 64;
    const int wn = (wid & 3) * 32;

    int mplane = 0, bn;
    if (MODE == 7 || MODE == 9) { mplane = blockIdx.x; bn = 0; }
    else bn = blockIdx.x * 128;
    const int bm = blockIdx.y * 128;

    int Mloc = M, rowbase = 0, typ = 0;
    if (TYPED) {
        typ = blockIdx.z;
        int s0 = offs[typ];
        Mloc = offs[typ + 1] - s0;
        rowbase = s0;
        if (Mloc == 0 || bm >= Mloc) return;
    }
    const float* Ause = A + (size_t)mplane * aplane;
    const float* Buse = B + (TYPED ? (size_t)typ * tOffB : 0);

    // A load setup
    const float* aptr[2]; uint32_t adst[2];
#pragma unroll
    for (int it = 0; it < 2; it++) {
        int id = tid + 256*it;
        int row = id >> 2, q = id & 3;
        int r = bm + row;
        if (TYPED) {
            if (r >= Mloc) r = Mloc - 1;
            aptr[it] = Ause + (size_t)order[rowbase + r]*lda + q*4;
        } else {
            if (r >= M) r = M - 1;
            const float* ap = GATHER ? (Ause + (size_t)rowidx[r]*lda)
                                     : (Ause + (size_t)r*lda);
            aptr[it] = ap + q*4;
        }
        adst[it] = (uint32_t)__cvta_generic_to_shared(AsBase + row*ASTRIDE + q*4);
    }
    // B load setup
    const float* bptr[2]; uint32_t bdst[2]; int bbytes[2];
#pragma unroll
    for (int it = 0; it < 2; it++) {
        int id = tid + 256*it;
        int r = id >> 5, c4 = id & 31;
        int gn = bn + 4*c4;
        bbytes[it] = (gn < Nc) ? 16 : 0;
        bptr[it] = Buse + (size_t)r*ldb + gn;
        bdst[it] = (uint32_t)__cvta_generic_to_shared(BsBase + r*BSTRIDE + c4*4);
    }

    const int kTiles = K >> 4;
    auto loadStage = [&](int stage, int k0) {
        uint32_t ao = stage * (ASZ*4), bo = stage * (BSZ*4);
#pragma unroll
        for (int it = 0; it < 2; it++)
            cp16(adst[it] + ao, aptr[it] + k0, 16);
#pragma unroll
        for (int it = 0; it < 2; it++)
            cp16(bdst[it] + bo, bptr[it] + (size_t)k0*ldb, bbytes[it]);
        cp_commit();
    };

    float acc[4][4][4];
#pragma unroll
    for (int mi = 0; mi < 4; mi++)
#pragma unroll
        for (int ni = 0; ni < 4; ni++)
#pragma unroll
            for (int j = 0; j < 4; j++) acc[mi][ni][j] = 0.f;

#pragma unroll
    for (int s = 0; s < GSTAGES-1; s++) loadStage(s, s*16);

    for (int kt = 0; kt < kTiles; kt++) {
        asm volatile("cp.async.wait_group %0;" :: "n"(GSTAGES-2));
        __syncthreads();
        int pf = kt + GSTAGES - 1;
        if (pf < kTiles) loadStage(pf % GSTAGES, pf*16);
        else cp_commit();

        const float* As = AsBase + (kt % GSTAGES) * ASZ;
        const float* Bs = BsBase + (kt % GSTAGES) * BSZ;
#pragma unroll
        for (int k8 = 0; k8 < 2; k8++) {
            const int kb = k8 * 8;
            uint32_t af[4][4], bf[4][2];
#pragma unroll
            for (int mi = 0; mi < 4; mi++) {
                int m = wm + mi*16 + g;
                af[mi][0] = __float_as_uint(As[m*ASTRIDE + kb + t]);
                af[mi][1] = __float_as_uint(As[(m+8)*ASTRIDE + kb + t]);
                af[mi][2] = __float_as_uint(As[m*ASTRIDE + kb + t + 4]);
                af[mi][3] = __float_as_uint(As[(m+8)*ASTRIDE + kb + t + 4]);
            }
#pragma unroll
            for (int ni = 0; ni < 4; ni++) {
                int n = wn + ni*8 + g;
                bf[ni][0] = __float_as_uint(Bs[(kb+t)*BSTRIDE + n]);
                bf[ni][1] = __float_as_uint(Bs[(kb+t+4)*BSTRIDE + n]);
            }
#pragma unroll
            for (int mi = 0; mi < 4; mi++)
#pragma unroll
                for (int ni = 0; ni < 4; ni++) {
                    asm volatile(
                        "mma.sync.aligned.m16n8k8.row.col.f32.tf32.tf32.f32 "
                        "{%0,%1,%2,%3}, {%4,%5,%6,%7}, {%8,%9}, {%0,%1,%2,%3};"
                        : "+f"(acc[mi][ni][0]), "+f"(acc[mi][ni][1]),
                          "+f"(acc[mi][ni][2]), "+f"(acc[mi][ni][3])
                        : "r"(af[mi][0]), "r"(af[mi][1]), "r"(af[mi][2]), "r"(af[mi][3]),
                          "r"(bf[ni][0]), "r"(bf[ni][1]));
                }
        }
        __syncthreads();
    }

    // ---------------- epilogue ----------------
    const float INV = 0.28867513459481287f;  // 1/sqrt(12)

    if (MODE == 4) {
        // stage acc*scale into smem, then back-rotate + gate -> msgv planes
        float* Vs = smem;
#pragma unroll
        for (int mi = 0; mi < 4; mi++)
#pragma unroll
            for (int h = 0; h < 2; h++) {
                int r = wm + mi*16 + g + 8*h;
#pragma unroll
                for (int ni = 0; ni < 4; ni++) {
                    int c = wn + ni*8 + 2*t;
                    *(float2*)&Vs[r*132 + c] =
                        make_float2(acc[mi][ni][2*h]*scale, acc[mi][ni][2*h+1]*scale);
                }
            }
        __syncthreads();
        for (int r = wid; r < 128; r += 8) {
            int e = bm + r;
            const float* Rp = Rrot + (size_t)e * 9;
            float R0=Rp[0],R1=Rp[1],R2=Rp[2],R3=Rp[3],R4=Rp[4],R5=Rp[5],R6=Rp[6],R7=Rp[7],R8=Rp[8];
            const float* gvp = gvbuf + (size_t)e * 128;
#pragma unroll
            for (int i = 0; i < 2; i++) {
                int u = lane + 32*i;
                float sg = gvp[u];
                float i0 = gvp[64 + u];
                float i1 = Vs[r*132 + u], i2 = Vs[r*132 + 64 + u];
                float o0 = R0*i0 + R3*i1 + R6*i2;
                float o1 = R1*i0 + R4*i1 + R7*i2;
                float o2 = R2*i0 + R5*i1 + R8*i2;
                C[(size_t)0*E*64 + (size_t)e*64 + u] = f2tf32f(sg*o0);
                C[(size_t)1*E*64 + (size_t)e*64 + u] = f2tf32f(sg*o1);
                C[(size_t)2*E*64 + (size_t)e*64 + u] = f2tf32f(sg*o2);
            }
        }
        return;
    }

    float alpha = 0.f, beta = 0.f;
    if (MODE == 8 || MODE == 9) {
        alpha = 1.f / (1.f + expf(-resp[0]));
        beta = 1.f - alpha;
    }

#pragma unroll
    for (int mi = 0; mi < 4; mi++) {
        int r0 = bm + wm + mi*16 + g;
#pragma unroll
        for (int h = 0; h < 2; h++) {
            int row = r0 + 8*h;
            if (row >= (TYPED ? Mloc : M)) continue;
            if (MODE == 0) {
#pragma unroll
                for (int ni = 0; ni < 4; ni++) {
                    int c = bn + wn + ni*8 + 2*t;
                    if (c >= Nc) continue;
                    float a0 = acc[mi][ni][2*h]  *scale + (bias ? bias[c]   : 0.f);
                    float a1 = acc[mi][ni][2*h+1]*scale + (bias ? bias[c+1] : 0.f);
                    *(float2*)&C[(size_t)row*Nc + c] = make_float2(a0, a1);
                }
            } else if (MODE == 1) {
                const float* pc = proj + (size_t)ctr[row]*512;
                const float* pn = proj + (size_t)nbr[row]*512 + 256;
#pragma unroll
                for (int ni = 0; ni < 4; ni++) {
                    int c = bn + wn + ni*8 + 2*t;
                    float v0 = (acc[mi][ni][2*h]   + pc[c]   + pn[c]  ) * scale;
                    float v1 = (acc[mi][ni][2*h+1] + pc[c+1] + pn[c+1]) * scale;
                    if (c < 128) {
                        float m0 = f2tf32f(v0 / (1.f + expf(-v0)));
                        float m1 = f2tf32f(v1 / (1.f + expf(-v1)));
                        *(float2*)&C[(size_t)row*128 + c] = make_float2(m0, m1);
                    } else if (c < 192) {
                        float s0 = 1.f / (1.f + expf(-v0));
                        float s1 = 1.f / (1.f + expf(-v1));
                        *(float2*)&aux[(size_t)row*128 + (c-128)] = make_float2(s0, s1);
                    } else {
                        *(float2*)&aux[(size_t)row*128 + (c-128)] = make_float2(v0, v1);
                    }
                }
            } else if (MODE == 2) {
                int e = row;
                float* ap = agg + (size_t)ctr[e]*128;
                const float* we = wenv + (size_t)e*192;
#pragma unroll
                for (int ni = 0; ni < 4; ni++) {
                    int c = bn + wn + ni*8 + 2*t;
                    if (c >= Nc) continue;
                    float a0 = (acc[mi][ni][2*h]  *scale + bias[c])   * we[c]  *INV;
                    float a1 = (acc[mi][ni][2*h+1]*scale + bias[c+1]) * we[c+1]*INV;
                    atomicAdd(&ap[c],     a0);
                    atomicAdd(&ap[c + 1], a1);
                }
            } else if (MODE == 3) {
                int m = row / E;
                int e = row - m*E;
                float* ap = agg + (size_t)m*Nnodes*64 + (size_t)ctr[e]*64;
                const float* we = wenv + (size_t)e*192 + 128;
#pragma unroll
                for (int ni = 0; ni < 4; ni++) {
                    int c = bn + wn + ni*8 + 2*t;
                    if (c >= Nc) continue;
                    float a0 = acc[mi][ni][2*h]  *scale * we[c]  *INV;
                    float a1 = acc[mi][ni][2*h+1]*scale * we[c+1]*INV;
                    atomicAdd(&ap[c],     a0);
                    atomicAdd(&ap[c + 1], a1);
                }
            } else if (MODE == 5) {
                int node = order[rowbase + row];
#pragma unroll
                for (int ni = 0; ni < 4; ni++) {
                    int c = wn + ni*8 + 2*t;
                    float v0 = acc[mi][ni][2*h]  *scale;
                    float v1 = acc[mi][ni][2*h+1]*scale;
                    float g0 = f2tf32f(v0 / (1.f + expf(-v0)));
                    float g1 = f2tf32f(v1 / (1.f + expf(-v1)));
                    *(float2*)&C[(size_t)node*128 + c] = make_float2(g0, g1);
                }
            } else if (MODE == 6) {
                int node = order[rowbase + row];
#pragma unroll
                for (int ni = 0; ni < 4; ni++) {
                    int c = wn + ni*8 + 2*t;
                    if (c >= Nc) continue;
                    float s0 = 1.f / (1.f + expf(-acc[mi][ni][2*h]  *scale));
                    float s1 = 1.f / (1.f + expf(-acc[mi][ni][2*h+1]*scale));
                    *(float2*)&C[(size_t)node*64 + c] = make_float2(s0, s1);
                }
            } else if (MODE == 7) {
                int node = order[rowbase + row];
                const float* tgp = gvbuf + (size_t)node*64;
#pragma unroll
                for (int ni = 0; ni < 4; ni++) {
                    int c = wn + ni*8 + 2*t;
                    if (c >= Nc) continue;
                    float v0 = f2tf32f(acc[mi][ni][2*h]  *scale * tgp[c]);
                    float v1 = f2tf32f(acc[mi][ni][2*h+1]*scale * tgp[c+1]);
                    *(float2*)&C[(size_t)mplane*aplane + (size_t)node*64 + c] = make_float2(v0, v1);
                }
            } else if (MODE == 8) {
#pragma unroll
                for (int ni = 0; ni < 4; ni++) {
                    int c = wn + ni*8 + 2*t;
                    float a0 = acc[mi][ni][2*h]  *scale + bias[c];
                    float a1 = acc[mi][ni][2*h+1]*scale + bias[c+1];
                    float o0 = alpha*nf[(size_t)row*320 + c]     + beta*a0;
                    float o1 = alpha*nf[(size_t)row*320 + c + 1] + beta*a1;
                    *(float2*)&C[(size_t)row*320 + c] = make_float2(o0, o1);
                }
            } else { // MODE 9
#pragma unroll
                for (int ni = 0; ni < 4; ni++) {
                    int c = wn + ni*8 + 2*t;
                    if (c >= Nc) continue;
                    float a0 = acc[mi][ni][2*h]  *scale;
                    float a1 = acc[mi][ni][2*h+1]*scale;
                    size_t o0i = (size_t)row*320 + 128 + 3*c + mplane;
                    size_t o1i = (size_t)row*320 + 128 + 3*(c+1) + mplane;
                    C[o0i] = alpha*nf[o0i] + beta*a0;
                    C[o1i] = alpha*nf[o1i] + beta*a1;
                }
            }
        }
    }
}

// ---------------------------------------------------------------------------
extern "C" void kernel_launch(void* const* d_in, const int* in_sizes, int n_in,
                              void* d_out, int out_size) {
    const float* latents = (const float*)d_in[0];
    const float* nf      = (const float*)d_in[1];
    const float* ef      = (const float*)d_in[2];
    const int*   at      = (const int*)  d_in[3];
    const int*   ei      = (const int*)  d_in[5];
    const float* evec    = (const float*)d_in[6];
    const int*   act     = (const int*)  d_in[7];
    const float* snws    = (const float*)d_in[8];
    const float* snbs    = (const float*)d_in[9];
    const float* snwv    = (const float*)d_in[10];
    const float* sews    = (const float*)d_in[11];
    const float* sebs    = (const float*)d_in[12];
    const float* sewv    = (const float*)d_in[13];
    const float* so2w0   = (const float*)d_in[14];
    const float* so2w1r  = (const float*)d_in[15];
    const float* so2w1i  = (const float*)d_in[16];
    const float* envw    = (const float*)d_in[17];
    const float* lpws    = (const float*)d_in[18];
    const float* lpbs    = (const float*)d_in[19];
    const float* lpwv    = (const float*)d_in[20];
    const float* ohwss   = (const float*)d_in[21];
    const float* ohwsg   = (const float*)d_in[22];
    const float* ohwvv   = (const float*)d_in[23];
    const float* ohlws   = (const float*)d_in[24];
    const float* ohlbs   = (const float*)d_in[25];
    const float* ohlwv   = (const float*)d_in[26];
    const float* resp    = (const float*)d_in[27];

    int N    = in_sizes[1] / 320;
    int E    = in_sizes[7];
    int Etot = in_sizes[5] / 2;
    size_t latN = (size_t)in_sizes[0];

    float* base = nullptr;  cudaGetSymbolAddress((void**)&base, g_buf);
    int* idx = nullptr;     cudaGetSymbolAddress((void**)&idx, g_idx);
    int* cnt = nullptr;     cudaGetSymbolAddress((void**)&cnt, g_cnt);
    int* offs = nullptr;    cudaGetSymbolAddress((void**)&offs, g_offs);
    int* order = nullptr;   cudaGetSymbolAddress((void**)&order, g_order);

    float* ns    = base + NS_OFF;
    float* nv    = base + NV_OFF;
    float* esvf0 = base + ESV_OFF;
    float* vf12  = base + VF12_OFF;
    float* Rbuf  = base + R_OFF;
    float* proj  = base + PROJ_OFF;
    float* gvb   = base + GV_OFF;
    float* msgs  = base + MSGS_OFF;
    float* msgv  = base + MSGV_OFF;
    float* wenv  = base + WENV_OFF;
    float* aggs  = base + AGGS_OFF;
    float* aggv  = base + AGGV_OFF;
    float* gsb   = base + GS_OFF;
    float* tgb   = base + TG_OFF;
    float* gvm   = base + GVM_OFF;
    float* latR  = base + LATR_OFF;
    float* w1c   = base + W1C_OFF;
    float* wcp   = base + WCP_OFF;
    float* w0m   = base + W0M_OFF;
    float* envr  = base + ENVR_OFF;
    float* lpwsr = base + LPWSR_OFF;
    float* lpwvr = base + LPWVR_OFF;
    float* wssR  = base + WSSR_OFF;
    float* wsgR  = base + WSGR_OFF;
    float* wvvR  = base + WVVR_OFF;
    float* ohlwR = base + OHLWR_OFF;
    float* ohlvR = base + OHLVR_OFF;
    int* ctr = idx;
    int* nbr = idx + E;

    const float isq576 = 0.041666666666666664f; // 1/24
    const float isq192 = 0.07216878364870323f;
    const float isq128 = 0.08838834764831845f;
    const float n_ss   = 0.011048543456039806f; // 1/sqrt(128*64)
    const float n_vv   = 0.015625f;             // 1/64

    cudaFuncSetAttribute(mma_gemm_kernel<0,false>, cudaFuncAttributeMaxDynamicSharedMemorySize, GEMM_SMEM_BYTES);
    cudaFuncSetAttribute(mma_gemm_kernel<0,true>,  cudaFuncAttributeMaxDynamicSharedMemorySize, GEMM_SMEM_BYTES);
    cudaFuncSetAttribute(mma_gemm_kernel<1,false>, cudaFuncAttributeMaxDynamicSharedMemorySize, GEMM_SMEM_BYTES);
    cudaFuncSetAttribute(mma_gemm_kernel<2,false>, cudaFuncAttributeMaxDynamicSharedMemorySize, GEMM_SMEM_BYTES);
    cudaFuncSetAttribute(mma_gemm_kernel<3,false>, cudaFuncAttributeMaxDynamicSharedMemorySize, GEMM_SMEM_BYTES);
    cudaFuncSetAttribute(mma_gemm_kernel<4,false>, cudaFuncAttributeMaxDynamicSharedMemorySize, GEMM_SMEM_MODE4);
    cudaFuncSetAttribute(mma_gemm_kernel<5,false>, cudaFuncAttributeMaxDynamicSharedMemorySize, GEMM_SMEM_BYTES);
    cudaFuncSetAttribute(mma_gemm_kernel<6,false>, cudaFuncAttributeMaxDynamicSharedMemorySize, GEMM_SMEM_BYTES);
    cudaFuncSetAttribute(mma_gemm_kernel<7,false>, cudaFuncAttributeMaxDynamicSharedMemorySize, GEMM_SMEM_BYTES);
    cudaFuncSetAttribute(mma_gemm_kernel<8,false>, cudaFuncAttributeMaxDynamicSharedMemorySize, GEMM_SMEM_BYTES);
    cudaFuncSetAttribute(mma_gemm_kernel<9,false>, cudaFuncAttributeMaxDynamicSharedMemorySize, GEMM_SMEM_BYTES);

    int etile = (E + 127)/128;
    int ntile = (N + 127)/128;

    // zero accumulators + bucket counters
    zero_kernel<<<(int)(((size_t)N*320 + 255)/256), 256>>>(aggs, (size_t)N*320);
    zero_kernel<<<1, 128>>>((float*)cnt, 128);
    node_ln_kernel<<<(N + 7)/8, 256>>>(nf, snws, snbs, snwv, ns, nv, N);
    build_w1c_kernel<<<(384*128 + 255)/256, 256>>>(so2w1r, so2w1i, w1c);
    build_wcp_kernel<<<(128*512 + 255)/256, 256>>>(so2w0, wcp);
    build_w0m_kernel<<<(320*256 + 255)/256, 256>>>(so2w0, w0m);
    round_copy_kernel<<<(int)((latN + 255)/256), 256>>>(latents, latR, latN);
    round_copy_kernel<<<(128*192 + 255)/256, 256>>>(envw, envr, 128*192);
    round_copy_kernel<<<(128*128 + 255)/256, 256>>>(lpws, lpwsr, 128*128);
    round_copy_kernel<<<(64*64 + 255)/256, 256>>>(lpwv, lpwvr, 64*64);
    round_copy_kernel<<<(128*64*128 + 255)/256, 256>>>(ohwss, wssR, 128*64*128);
    round_copy_kernel<<<(128*64*64 + 255)/256, 256>>>(ohwsg, wsgR, 128*64*64);
    round_copy_kernel<<<(64*64*64 + 255)/256, 256>>>(ohwvv, wvvR, 64*64*64);
    round_copy_kernel<<<(128*128 + 255)/256, 256>>>(ohlws, ohlwR, 128*128);
    round_copy_kernel<<<(64*64 + 255)/256, 256>>>(ohlwv, ohlvR, 64*64);
    // bucket nodes by type
    count_kernel<<<(N + 255)/256, 256>>>(at, cnt, N);
    prefix_kernel<<<1, 32>>>(cnt, offs);
    scatter_order_kernel<<<(N + 255)/256, 256>>>(at, offs, cnt + 64, order, N);

    edge_prep_kernel<<<(E + 7)/8, 256>>>(ef, ei, act, evec, sews, sebs, sewv,
                                         nv, esvf0, vf12, Rbuf, idx, E, Etot);

    // proj = ns @ wcp  (N x 512)
    mma_gemm_kernel<0,false><<<dim3(4, ntile), 256, GEMM_SMEM_BYTES>>>(
        ns, wcp, proj, N, 512, 128, 128, 512, 1.0f, nullptr,
        nullptr, nullptr, nullptr, nullptr, nullptr, nullptr, nullptr, nullptr, nullptr,
        nullptr, nullptr, nullptr, nullptr, 0, 0, N, E);
    // wenv = latR[act] @ envr / sqrt(128)
    mma_gemm_kernel<0,true><<<dim3(2, etile), 256, GEMM_SMEM_BYTES>>>(
        latR, envr, wenv, E, 192, 128, 128, 192, isq128, nullptr,
        act, nullptr, nullptr, nullptr, nullptr, nullptr, nullptr, nullptr, nullptr,
        nullptr, nullptr, nullptr, nullptr, 0, 0, N, E);
    // main SO2 GEMM -> msgs + gv
    mma_gemm_kernel<1,false><<<dim3(2, etile), 256, GEMM_SMEM_BYTES>>>(
        esvf0, w0m, msgs, E, 256, 320, 320, 256, isq576, nullptr,
        nullptr, ctr, nbr, proj, nullptr, nullptr, nullptr, nullptr, gvb,
        nullptr, nullptr, nullptr, nullptr, 0, 0, N, E);
    // complex GEMM + fused rotation/gate -> msgv
    mma_gemm_kernel<4,false><<<dim3(1, etile), 256, GEMM_SMEM_MODE4>>>(
        vf12, w1c, msgv, E, 128, 384, 384, 128, isq192, nullptr,
        nullptr, nullptr, nullptr, nullptr, Rbuf, gvb, nullptr, nullptr, nullptr,
        nullptr, nullptr, nullptr, nullptr, 0, 0, N, E);
    // lps GEMM + env-weight + scatter -> aggs
    mma_gemm_kernel<2,false><<<dim3(1, etile), 256, GEMM_SMEM_BYTES>>>(
        msgs, lpwsr, nullptr, E, 128, 128, 128, 128, isq128, lpbs,
        nullptr, ctr, nullptr, nullptr, nullptr, nullptr, wenv, aggs, nullptr,
        nullptr, nullptr, nullptr, nullptr, 0, 0, N, E);
    // lpv GEMM + env-weight + scatter -> aggv
    mma_gemm_kernel<3,false><<<dim3(1, (3*E + 127)/128), 256, GEMM_SMEM_BYTES>>>(
        msgv, lpwvr, nullptr, 3*E, 64, 64, 64, 64, 0.125f, nullptr,
        nullptr, ctr, nullptr, nullptr, nullptr, nullptr, wenv, aggv, nullptr,
        nullptr, nullptr, nullptr, nullptr, 0, 0, N, E);
    // typed: gs = rnd(silu(aggs @ wss[:,t,:] * n_ss))
    mma_gemm_kernel<5,false><<<dim3(1, 2, 64), 256, GEMM_SMEM_BYTES>>>(
        aggs, wssR, gsb, N, 128, 128, 128, 64*128, n_ss, nullptr,
        nullptr, nullptr, nullptr, nullptr, nullptr, nullptr, nullptr, nullptr, nullptr,
        nullptr, nullptr, offs, order, 128, 0, N, E);
    // typed: tg = sigmoid(aggs @ wsg[:,t,:] * n_ss)
    mma_gemm_kernel<6,false><<<dim3(1, 2, 64), 256, GEMM_SMEM_BYTES>>>(
        aggs, wsgR, tgb, N, 64, 128, 128, 64*64, n_ss, nullptr,
        nullptr, nullptr, nullptr, nullptr, nullptr, nullptr, nullptr, nullptr, nullptr,
        nullptr, nullptr, offs, order, 64, 0, N, E);
    // typed, 3 planes: gvm = rnd(tg * (aggv @ wvv[:,t,:] * n_vv))
    mma_gemm_kernel<7,false><<<dim3(3, 2, 64), 256, GEMM_SMEM_BYTES>>>(
        aggv, wvvR, gvm, N, 64, 64, 64, 64*64, n_vv, nullptr,
        nullptr, nullptr, nullptr, nullptr, nullptr, tgb, nullptr, nullptr, nullptr,
        nullptr, nullptr, offs, order, 64, (size_t)N*64, N, E);
    // final scalar: out[:,0:128] = alpha*nf + beta*(gs @ ohlws /sqrt(128) + ohlbs)
    mma_gemm_kernel<8,false><<<dim3(1, ntile), 256, GEMM_SMEM_BYTES>>>(
        gsb, ohlwR, (float*)d_out, N, 128, 128, 128, 128, isq128, ohlbs,
        nullptr, nullptr, nullptr, nullptr, nullptr, nullptr, nullptr, nullptr, nullptr,
        nf, resp, nullptr, nullptr, 0, 0, N, E);
    // final vector: out[:,128+3k+m] = alpha*nf + beta*(gvm @ ohlwv / 8)
    mma_gemm_kernel<9,false><<<dim3(3, ntile), 256, GEMM_SMEM_BYTES>>>(
        gvm, ohlvR, (float*)d_out, N, 64, 64, 64, 64, 0.125f, nullptr,
        nullptr, nullptr, nullptr, nullptr, nullptr, nullptr, nullptr, nullptr, nullptr,
        nf, resp, nullptr, nullptr, 0, (size_t)N*64, N, E);
}

// round 7
// speedup vs baseline: 3.0342x; 1.1346x over previous
#include <cuda_runtime.h>
#include <cuda_bf16.h>
#include <math.h>
#include <stdint.h>

static constexpr int NMAXN = 8000;
static constexpr int EMAX  = 96000;

// ---- fp32 scratch ----
static constexpr size_t NV_OFF   = 0;                                  // nv:   N x 192
static constexpr size_t R_OFF    = NV_OFF   + (size_t)NMAXN*192;       // R:    E x 9
static constexpr size_t PROJ_OFF = R_OFF    + (size_t)EMAX*9;          // proj: N x 512
static constexpr size_t GVF_OFF  = PROJ_OFF + (size_t)NMAXN*512;       // gv:   E x 128
static constexpr size_t WENV_OFF = GVF_OFF  + (size_t)EMAX*128;        // wenv: E x 192
static constexpr size_t AGGS_OFF = WENV_OFF + (size_t)EMAX*192;        // aggs: N x 128
static constexpr size_t AGGV_OFF = AGGS_OFF + (size_t)NMAXN*128;       // aggv: 3 x N x 64
static constexpr size_t TG_OFF   = AGGV_OFF + (size_t)3*NMAXN*64;      // tg:   N x 64
static constexpr size_t TOTAL_F  = TG_OFF   + (size_t)NMAXN*64;
__device__ __align__(256) float g_buf[TOTAL_F];

// ---- bf16 scratch ----
static constexpr size_t NSB   = 0;                                     // ns:    N x 128
static constexpr size_t ESVB  = NSB   + (size_t)NMAXN*128;             // esvf0: E x 320
static constexpr size_t VF12B = ESVB  + (size_t)EMAX*320;              // vf12:  E x 384
static constexpr size_t MSGSB = VF12B + (size_t)EMAX*384;              // msgs:  E x 128
static constexpr size_t MSGVB = MSGSB + (size_t)EMAX*128;              // msgv:  3 x E x 64
static constexpr size_t LATB  = MSGVB + (size_t)3*EMAX*64;             // latB:  E x 128
static constexpr size_t GSB   = LATB  + (size_t)EMAX*128;              // gs:    N x 128
static constexpr size_t GVMB  = GSB   + (size_t)NMAXN*128;             // gvm:   3 x N x 64
static constexpr size_t AGSB  = GVMB  + (size_t)3*NMAXN*64;            // aggsB: N x 128
static constexpr size_t AGVB  = AGSB  + (size_t)NMAXN*128;             // aggvB: 3 x N x 64 (contig after AGSB)
static constexpr size_t WCPT  = AGVB  + (size_t)3*NMAXN*64;            // 512 x 128
static constexpr size_t W0MT  = WCPT  + (size_t)512*128;               // 256 x 320
static constexpr size_t W1CT  = W0MT  + (size_t)256*320;               // 128 x 384
static constexpr size_t ENVT  = W1CT  + (size_t)128*384;               // 192 x 128
static constexpr size_t LPWST = ENVT  + (size_t)192*128;               // 128 x 128
static constexpr size_t LPWVT = LPWST + (size_t)128*128;               // 64 x 64
static constexpr size_t WSST  = LPWVT + (size_t)64*64;                 // 64 x 128 x 128
static constexpr size_t WSGT  = WSST  + (size_t)64*128*128;            // 64 x 64 x 128
static constexpr size_t WVVT  = WSGT  + (size_t)64*64*128;             // 64 x 64 x 64
static constexpr size_t OHLWT = WVVT  + (size_t)64*64*64;              // 128 x 128
static constexpr size_t OHLVT = OHLWT + (size_t)128*128;               // 64 x 64
static constexpr size_t TOTAL_B = OHLVT + (size_t)64*64;
__device__ __align__(256) __nv_bfloat16 g_bbuf[TOTAL_B];

__device__ int g_idx[2*EMAX];
__device__ int g_cnt[128];
__device__ int g_offs[65];
__device__ int g_order[NMAXN];

typedef __nv_bfloat16 bf16;
typedef __nv_bfloat162 bf162;
__device__ __forceinline__ bf162 f2b2(float a, float b) { return __floats2bfloat162_rn(a, b); }

// ---------------------------------------------------------------------------
__global__ void zero_kernel(float* __restrict__ p, size_t n) {
    size_t i = (size_t)blockIdx.x*blockDim.x + threadIdx.x;
    if (i < n) p[i] = 0.f;
}
__global__ void c2b_kernel(const float* __restrict__ in, bf16* __restrict__ out, size_t n) {
    size_t i = (size_t)blockIdx.x*blockDim.x + threadIdx.x;
    if (i < n) out[i] = __float2bfloat16(in[i]);
}
// out[c*R + r] = bf16(in[r*C + c])
__global__ void tr_kernel(const float* __restrict__ in, bf16* __restrict__ out, int R, int C) {
    int i = blockIdx.x*blockDim.x + threadIdx.x;
    if (i >= R*C) return;
    int r = i / C, c = i - r*C;
    out[(size_t)c*R + r] = __float2bfloat16(in[i]);
}
// in [U][64][Nc] -> out[t][n][u]
__global__ void trt_kernel(const float* __restrict__ in, bf16* __restrict__ out, int U, int Nc) {
    int i = blockIdx.x*blockDim.x + threadIdx.x;
    if (i >= U*64*Nc) return;
    int u = i / (64*Nc); int rem = i - u*64*Nc; int t = rem / Nc; int n = rem - t*Nc;
    out[((size_t)t*Nc + n)*U + u] = __float2bfloat16(in[i]);
}
__global__ void w1cT_kernel(const float* __restrict__ w1r, const float* __restrict__ w1i,
                            bf16* __restrict__ out) {
    int i = blockIdx.x*blockDim.x + threadIdx.x;
    if (i >= 128*384) return;
    int c = i / 384, r = i - c*384;
    float v;
    if (r < 192) v = (c < 64) ? w1r[r*64 + c] : w1i[r*64 + c - 64];
    else { int r2 = r - 192; v = (c < 64) ? -w1i[r2*64 + c] : w1r[r2*64 + c - 64]; }
    out[i] = __float2bfloat16(v);
}
__global__ void wcpT_kernel(const float* __restrict__ w0, bf16* __restrict__ out) {
    int i = blockIdx.x*blockDim.x + threadIdx.x;
    if (i >= 512*128) return;
    int c = i / 128, k = i - c*128;
    float v = (c < 256) ? w0[(size_t)k*256 + c] : w0[(size_t)(256 + k)*256 + c - 256];
    out[i] = __float2bfloat16(v);
}
__global__ void w0mT_kernel(const float* __restrict__ w0, bf16* __restrict__ out) {
    int i = blockIdx.x*blockDim.x + threadIdx.x;
    if (i >= 256*320) return;
    int c = i / 320, k = i - c*320;
    int src = (k < 128) ? k + 128 : k + 256;
    out[i] = __float2bfloat16(w0[(size_t)src*256 + c]);
}
__global__ void count_kernel(const int* __restrict__ at, int* __restrict__ cnt, int N) {
    int n = blockIdx.x*blockDim.x + threadIdx.x;
    if (n < N) atomicAdd(&cnt[at[n]], 1);
}
__global__ void prefix_kernel(const int* __restrict__ cnt, int* __restrict__ offs) {
    if (threadIdx.x == 0) { int s = 0; for (int i = 0; i < 64; i++) { offs[i] = s; s += cnt[i]; } offs[64] = s; }
}
__global__ void order_kernel(const int* __restrict__ at, const int* __restrict__ offs,
                             int* __restrict__ cur, int* __restrict__ order, int N) {
    int n = blockIdx.x*blockDim.x + threadIdx.x;
    if (n < N) { int t = at[n]; order[offs[t] + atomicAdd(&cur[t], 1)] = n; }
}

// ---------------------------------------------------------------------------
__global__ void node_ln_kernel(const float* __restrict__ nf, const float* __restrict__ ws,
                               const float* __restrict__ bs, const float* __restrict__ wv,
                               bf16* __restrict__ ns, float* __restrict__ nv, int N) {
    int node = (blockIdx.x*blockDim.x + threadIdx.x) >> 5;
    int lane = threadIdx.x & 31;
    if (node >= N) return;
    const float* row = nf + (size_t)node*320;
    float s[4]; float sum = 0.f;
#pragma unroll
    for (int i = 0; i < 4; i++) { s[i] = row[lane + 32*i]; sum += s[i]; }
#pragma unroll
    for (int o = 16; o; o >>= 1) sum += __shfl_xor_sync(~0u, sum, o);
    float mu = sum*(1.f/128.f), var = 0.f;
#pragma unroll
    for (int i = 0; i < 4; i++) { s[i] -= mu; var += s[i]*s[i]; }
#pragma unroll
    for (int o = 16; o; o >>= 1) var += __shfl_xor_sync(~0u, var, o);
    float rs = rsqrtf(var*(1.f/128.f) + 1e-8f);
#pragma unroll
    for (int i = 0; i < 4; i++) {
        int c = lane + 32*i;
        ns[(size_t)node*128 + c] = __float2bfloat16(s[i]*rs*ws[c] + bs[c]);
    }
    float v[6]; float vs = 0.f;
#pragma unroll
    for (int i = 0; i < 6; i++) { v[i] = row[128 + lane + 32*i]; vs += v[i]*v[i]; }
#pragma unroll
    for (int o = 16; o; o >>= 1) vs += __shfl_xor_sync(~0u, vs, o);
    float rv = rsqrtf(vs*(1.f/192.f) + 1e-8f);
#pragma unroll
    for (int i = 0; i < 6; i++) { int c = lane + 32*i; nv[(size_t)node*192 + c] = v[i]*rv*wv[c/3]; }
}

__global__ void edge_prep_kernel(const float* __restrict__ ef, const int* __restrict__ ei,
                                 const int* __restrict__ act, const float* __restrict__ evec,
                                 const float* __restrict__ ws, const float* __restrict__ bs,
                                 const float* __restrict__ wv, const float* __restrict__ nv,
                                 bf16* __restrict__ esv0, bf16* __restrict__ vf12,
                                 float* __restrict__ Rout, int* __restrict__ idx, int E, int Etot) {
    __shared__ float evs[8][192];
    int wi = threadIdx.x >> 5, lane = threadIdx.x & 31;
    int e = blockIdx.x*8 + wi;
    if (e >= E) return;
    int ae = act[e];
    int ctr = ei[ae], nbr = ei[Etot + ae];
    if (lane == 0) { idx[e] = ctr; idx[E + e] = nbr; }
    const float* row = ef + (size_t)e*320;

    float s[4]; float sum = 0.f;
#pragma unroll
    for (int i = 0; i < 4; i++) { s[i] = row[lane + 32*i]; sum += s[i]; }
#pragma unroll
    for (int o = 16; o; o >>= 1) sum += __shfl_xor_sync(~0u, sum, o);
    float mu = sum*(1.f/128.f), var = 0.f;
#pragma unroll
    for (int i = 0; i < 4; i++) { s[i] -= mu; var += s[i]*s[i]; }
#pragma unroll
    for (int o = 16; o; o >>= 1) var += __shfl_xor_sync(~0u, var, o);
    float rs = rsqrtf(var*(1.f/128.f) + 1e-8f);
    bf16* esv = esv0 + (size_t)e*320;
#pragma unroll
    for (int i = 0; i < 4; i++) { int c = lane + 32*i; esv[c] = __float2bfloat16(s[i]*rs*ws[c] + bs[c]); }

    float v[6]; float vs = 0.f;
#pragma unroll
    for (int i = 0; i < 6; i++) { v[i] = row[128 + lane + 32*i]; vs += v[i]*v[i]; }
#pragma unroll
    for (int o = 16; o; o >>= 1) vs += __shfl_xor_sync(~0u, vs, o);
    float rv = rsqrtf(vs*(1.f/192.f) + 1e-8f);
#pragma unroll
    for (int i = 0; i < 6; i++) { int c = lane + 32*i; evs[wi][c] = v[i]*rv*wv[c/3]; }
    __syncwarp();

    float e0 = evec[(size_t)ae*3], e1 = evec[(size_t)ae*3+1], e2 = evec[(size_t)ae*3+2];
    float rn = rsqrtf(e0*e0 + e1*e1 + e2*e2 + 1e-8f);
    float ax = e0*rn, ay = e1*rn, az = e2*rn;
    float refx = (fabsf(ax) < 0.9f) ? 1.f : 0.f, refy = 1.f - refx;
    float bx = -az*refy, by = az*refx, bz = ax*refy - ay*refx;
    float rb = rsqrtf(bx*bx + by*by + bz*bz + 1e-8f);
    bx *= rb; by *= rb; bz *= rb;
    float cx = ay*bz - az*by, cy = az*bx - ax*bz, cz = ax*by - ay*bx;
    if (lane == 0) {
        float* Rp = Rout + (size_t)e*9;
        Rp[0]=ax; Rp[1]=ay; Rp[2]=az; Rp[3]=bx; Rp[4]=by; Rp[5]=bz; Rp[6]=cx; Rp[7]=cy; Rp[8]=cz;
    }
    bf16* vf = vf12 + (size_t)e*384;
#pragma unroll
    for (int i = 0; i < 6; i++) {
        int u = lane + 32*i;
        float vx, vy, vz;
        if (u < 64)       { const float* p = nv + (size_t)ctr*192 + u*3;        vx=p[0]; vy=p[1]; vz=p[2]; }
        else if (u < 128) { const float* p = &evs[wi][(u-64)*3];                vx=p[0]; vy=p[1]; vz=p[2]; }
        else              { const float* p = nv + (size_t)nbr*192 + (u-128)*3;  vx=p[0]; vy=p[1]; vz=p[2]; }
        esv[128 + u] = __float2bfloat16(ax*vx + ay*vy + az*vz);
        vf[u]        = __float2bfloat16(bx*vx + by*vy + bz*vz);
        vf[192 + u]  = __float2bfloat16(cx*vx + cy*vy + cz*vz);
    }
}

// ---------------------------------------------------------------------------
// bf16 tensor-core GEMM (m16n8k16), cp.async 3-stage, B pre-transposed [Nc,K].
// Smem rows padded to 24 bf16 (48B) -> conflict-free 32-bit fragment loads.
// Modes as in previous rounds.
static constexpr int STG_B = 12288;                      // bytes per stage (A 6144 + B 6144)
static constexpr int GEMM_SMEM = 3*STG_B;                // 36864
static constexpr int GEMM_SMEM4 = 128*132*4;             // 67584 (MODE4 staging)

template<int MODE, bool GATHER>
__global__ __launch_bounds__(256, 2)
void mma_gemm_kernel(const bf16* __restrict__ A, const bf16* __restrict__ B,
                     float* __restrict__ C, int M, int Nc, int K, int lda, int ldb,
                     float scale, const float* __restrict__ bias, const int* __restrict__ rowidx,
                     const int* __restrict__ ctr, const int* __restrict__ nbr,
                     const float* __restrict__ proj, const float* __restrict__ Rrot,
                     const float* __restrict__ gvbuf, const float* __restrict__ wenv,
                     float* __restrict__ agg, float* __restrict__ aux,
                     const float* __restrict__ nf, const float* __restrict__ resp,
                     const int* __restrict__ offs, const int* __restrict__ order,
                     int tOffB, size_t aplane, int Nnodes, int E) {
    constexpr bool TYPED = (MODE == 5 || MODE == 6 || MODE == 7);
    extern __shared__ char smc[];
    const int tid = threadIdx.x, lane = tid & 31, wid = tid >> 5;
    const int g = lane >> 2, t = lane & 3;
    const int wm = (wid >> 2)*64, wn = (wid & 3)*32;

    int mplane = 0, bn;
    if (MODE == 7 || MODE == 9) { mplane = blockIdx.x; bn = 0; } else bn = blockIdx.x*128;
    const int bm = blockIdx.y*128;

    int Mloc = M, rowbase = 0, typ = 0;
    if (TYPED) {
        typ = blockIdx.z;
        rowbase = offs[typ];
        Mloc = offs[typ+1] - rowbase;
        if (Mloc == 0 || bm >= Mloc) return;
    }
    const bf16* Ause = A + (size_t)mplane*aplane;
    const bf16* Buse = B + (TYPED ? (size_t)typ*tOffB : 0);

    // per-thread: one 16B A chunk + one 16B B chunk per stage
    int arow = tid >> 1, ahalf = tid & 1;
    int r = bm + arow, gr;
    if (TYPED) { if (r >= Mloc) r = Mloc - 1; gr = order[rowbase + r]; }
    else       { if (r >= M) r = M - 1;       gr = GATHER ? rowidx[r] : r; }
    const bf16* asrc = Ause + (size_t)gr*lda + ahalf*8;
    int bn_row = bn + arow;
    int bby = (bn_row < Nc) ? 16 : 0;
    const bf16* bsrc = Buse + (size_t)min(bn_row, Nc-1)*ldb + ahalf*8;
    uint32_t sbase = (uint32_t)__cvta_generic_to_shared(smc);
    uint32_t adst = sbase + arow*48 + ahalf*16;
    uint32_t bdst = sbase + 6144 + arow*48 + ahalf*16;

    const int kT = K >> 4;
    auto loadStage = [&](int slot, int k0) {
        uint32_t so = slot*STG_B;
        asm volatile("cp.async.cg.shared.global [%0], [%1], 16;" :: "r"(adst + so), "l"(asrc + k0) : "memory");
        asm volatile("cp.async.cg.shared.global [%0], [%1], 16, %2;" :: "r"(bdst + so), "l"(bsrc + k0), "r"(bby) : "memory");
        asm volatile("cp.async.commit_group;");
    };

    float acc[4][4][4];
#pragma unroll
    for (int mi = 0; mi < 4; mi++)
#pragma unroll
        for (int ni = 0; ni < 4; ni++)
#pragma unroll
            for (int j = 0; j < 4; j++) acc[mi][ni][j] = 0.f;

    loadStage(0, 0); loadStage(1, 16);

    for (int kt = 0; kt < kT; kt++) {
        asm volatile("cp.async.wait_group 1;");
        __syncthreads();
        int pf = kt + 2;
        if (pf < kT) loadStage(pf % 3, pf*16);
        else asm volatile("cp.async.commit_group;");

        const char* Ss = smc + (kt % 3)*STG_B;
        const bf16* As = (const bf16*)Ss;
        const bf16* Bs = (const bf16*)(Ss + 6144);
        uint32_t af[4][4], bf[4][2];
#pragma unroll
        for (int mi = 0; mi < 4; mi++) {
            int m = wm + mi*16 + g;
            af[mi][0] = *(const uint32_t*)&As[m*24 + 2*t];
            af[mi][1] = *(const uint32_t*)&As[(m+8)*24 + 2*t];
            af[mi][2] = *(const uint32_t*)&As[m*24 + 2*t + 8];
            af[mi][3] = *(const uint32_t*)&As[(m+8)*24 + 2*t + 8];
        }
#pragma unroll
        for (int ni = 0; ni < 4; ni++) {
            int n = wn + ni*8 + g;
            bf[ni][0] = *(const uint32_t*)&Bs[n*24 + 2*t];
            bf[ni][1] = *(const uint32_t*)&Bs[n*24 + 2*t + 8];
        }
#pragma unroll
        for (int mi = 0; mi < 4; mi++)
#pragma unroll
            for (int ni = 0; ni < 4; ni++) {
                asm volatile(
                    "mma.sync.aligned.m16n8k16.row.col.f32.bf16.bf16.f32 "
                    "{%0,%1,%2,%3}, {%4,%5,%6,%7}, {%8,%9}, {%0,%1,%2,%3};"
                    : "+f"(acc[mi][ni][0]), "+f"(acc[mi][ni][1]),
                      "+f"(acc[mi][ni][2]), "+f"(acc[mi][ni][3])
                    : "r"(af[mi][0]), "r"(af[mi][1]), "r"(af[mi][2]), "r"(af[mi][3]),
                      "r"(bf[ni][0]), "r"(bf[ni][1]));
            }
    }

    // ---------------- epilogue ----------------
    const float INV = 0.28867513459481287f;
    if (MODE == 4) {
        __syncthreads();
        float* Vs = (float*)smc;
#pragma unroll
        for (int mi = 0; mi < 4; mi++)
#pragma unroll
            for (int h = 0; h < 2; h++) {
                int rr = wm + mi*16 + g + 8*h;
#pragma unroll
                for (int ni = 0; ni < 4; ni++) {
                    int c = wn + ni*8 + 2*t;
                    *(float2*)&Vs[rr*132 + c] = make_float2(acc[mi][ni][2*h]*scale, acc[mi][ni][2*h+1]*scale);
                }
            }
        __syncthreads();
        bf16* Cb = (bf16*)C;
        for (int rr = wid; rr < 128; rr += 8) {
            int e = bm + rr;
            const float* Rp = Rrot + (size_t)e*9;
            float R0=Rp[0],R1=Rp[1],R2=Rp[2],R3=Rp[3],R4=Rp[4],R5=Rp[5],R6=Rp[6],R7=Rp[7],R8=Rp[8];
            const float* gvp = gvbuf + (size_t)e*128;
#pragma unroll
            for (int i = 0; i < 2; i++) {
                int u = lane + 32*i;
                float sg = gvp[u], i0 = gvp[64 + u];
                float i1 = Vs[rr*132 + u], i2 = Vs[rr*132 + 64 + u];
                Cb[(size_t)0*E*64 + (size_t)e*64 + u] = __float2bfloat16(sg*(R0*i0 + R3*i1 + R6*i2));
                Cb[(size_t)1*E*64 + (size_t)e*64 + u] = __float2bfloat16(sg*(R1*i0 + R4*i1 + R7*i2));
                Cb[(size_t)2*E*64 + (size_t)e*64 + u] = __float2bfloat16(sg*(R2*i0 + R5*i1 + R8*i2));
            }
        }
        return;
    }

    float alpha = 0.f, beta = 0.f;
    if (MODE == 8 || MODE == 9) { alpha = 1.f/(1.f + expf(-resp[0])); beta = 1.f - alpha; }

#pragma unroll
    for (int mi = 0; mi < 4; mi++) {
        int r0 = bm + wm + mi*16 + g;
#pragma unroll
        for (int h = 0; h < 2; h++) {
            int row = r0 + 8*h;
            if (row >= (TYPED ? Mloc : M)) continue;
            if (MODE == 0) {
#pragma unroll
                for (int ni = 0; ni < 4; ni++) {
                    int c = bn + wn + ni*8 + 2*t;
                    if (c >= Nc) continue;
                    float a0 = acc[mi][ni][2*h]*scale + (bias ? bias[c] : 0.f);
                    float a1 = acc[mi][ni][2*h+1]*scale + (bias ? bias[c+1] : 0.f);
                    *(float2*)&C[(size_t)row*Nc + c] = make_float2(a0, a1);
                }
            } else if (MODE == 1) {
                const float* pc = proj + (size_t)ctr[row]*512;
                const float* pn = proj + (size_t)nbr[row]*512 + 256;
                bf16* Cb = (bf16*)C;
#pragma unroll
                for (int ni = 0; ni < 4; ni++) {
                    int c = bn + wn + ni*8 + 2*t;
                    float v0 = (acc[mi][ni][2*h]   + pc[c]   + pn[c]  )*scale;
                    float v1 = (acc[mi][ni][2*h+1] + pc[c+1] + pn[c+1])*scale;
                    if (c < 128) {
                        *(bf162*)&Cb[(size_t)row*128 + c] = f2b2(v0/(1.f+expf(-v0)), v1/(1.f+expf(-v1)));
                    } else if (c < 192) {
                        *(float2*)&aux[(size_t)row*128 + c-128] =
                            make_float2(1.f/(1.f+expf(-v0)), 1.f/(1.f+expf(-v1)));
                    } else {
                        *(float2*)&aux[(size_t)row*128 + c-128] = make_float2(v0, v1);
                    }
                }
            } else if (MODE == 2) {
                float* ap = agg + (size_t)ctr[row]*128;
                const float* we = wenv + (size_t)row*192;
#pragma unroll
                for (int ni = 0; ni < 4; ni++) {
                    int c = bn + wn + ni*8 + 2*t;
                    if (c >= Nc) continue;
                    atomicAdd(&ap[c],   (acc[mi][ni][2*h]  *scale + bias[c])  *we[c]  *INV);
                    atomicAdd(&ap[c+1], (acc[mi][ni][2*h+1]*scale + bias[c+1])*we[c+1]*INV);
                }
            } else if (MODE == 3) {
                int m = row / E, e = row - m*E;
                float* ap = agg + (size_t)m*Nnodes*64 + (size_t)ctr[e]*64;
                const float* we = wenv + (size_t)e*192 + 128;
#pragma unroll
                for (int ni = 0; ni < 4; ni++) {
                    int c = bn + wn + ni*8 + 2*t;
                    if (c >= Nc) continue;
                    atomicAdd(&ap[c],   acc[mi][ni][2*h]  *scale*we[c]  *INV);
                    atomicAdd(&ap[c+1], acc[mi][ni][2*h+1]*scale*we[c+1]*INV);
                }
            } else if (MODE == 5) {
                int node = order[rowbase + row];
                bf16* Cb = (bf16*)C;
#pragma unroll
                for (int ni = 0; ni < 4; ni++) {
                    int c = wn + ni*8 + 2*t;
                    float v0 = acc[mi][ni][2*h]*scale, v1 = acc[mi][ni][2*h+1]*scale;
                    *(bf162*)&Cb[(size_t)node*128 + c] = f2b2(v0/(1.f+expf(-v0)), v1/(1.f+expf(-v1)));
                }
            } else if (MODE == 6) {
                int node = order[rowbase + row];
#pragma unroll
                for (int ni = 0; ni < 4; ni++) {
                    int c = wn + ni*8 + 2*t;
                    if (c >= Nc) continue;
                    *(float2*)&C[(size_t)node*64 + c] =
                        make_float2(1.f/(1.f+expf(-acc[mi][ni][2*h]*scale)),
                                    1.f/(1.f+expf(-acc[mi][ni][2*h+1]*scale)));
                }
            } else if (MODE == 7) {
                int node = order[rowbase + row];
                const float* tgp = gvbuf + (size_t)node*64;
                bf16* Cb = (bf16*)C;
#pragma unroll
                for (int ni = 0; ni < 4; ni++) {
                    int c = wn + ni*8 + 2*t;
                    if (c >= Nc) continue;
                    *(bf162*)&Cb[(size_t)mplane*aplane + (size_t)node*64 + c] =
                        f2b2(acc[mi][ni][2*h]*scale*tgp[c], acc[mi][ni][2*h+1]*scale*tgp[c+1]);
                }
            } else if (MODE == 8) {
#pragma unroll
                for (int ni = 0; ni < 4; ni++) {
                    int c = wn + ni*8 + 2*t;
                    float a0 = acc[mi][ni][2*h]*scale + bias[c];
                    float a1 = acc[mi][ni][2*h+1]*scale + bias[c+1];
                    *(float2*)&C[(size_t)row*320 + c] =
                        make_float2(alpha*nf[(size_t)row*320 + c] + beta*a0,
                                    alpha*nf[(size_t)row*320 + c + 1] + beta*a1);
                }
            } else { // MODE 9
#pragma unroll
                for (int ni = 0; ni < 4; ni++) {
                    int c = wn + ni*8 + 2*t;
                    if (c >= Nc) continue;
                    size_t o0 = (size_t)row*320 + 128 + 3*c + mplane;
                    size_t o1 = (size_t)row*320 + 128 + 3*(c+1) + mplane;
                    C[o0] = alpha*nf[o0] + beta*acc[mi][ni][2*h]*scale;
                    C[o1] = alpha*nf[o1] + beta*acc[mi][ni][2*h+1]*scale;
                }
            }
        }
    }
}

// ---------------------------------------------------------------------------
extern "C" void kernel_launch(void* const* d_in, const int* in_sizes, int n_in,
                              void* d_out, int out_size) {
    const float* latents = (const float*)d_in[0];
    const float* nf    = (const float*)d_in[1];
    const float* ef    = (const float*)d_in[2];
    const int*   at    = (const int*)  d_in[3];
    const int*   ei    = (const int*)  d_in[5];
    const float* evec  = (const float*)d_in[6];
    const int*   act   = (const int*)  d_in[7];
    const float* snws  = (const float*)d_in[8];
    const float* snbs  = (const float*)d_in[9];
    const float* snwv  = (const float*)d_in[10];
    const float* sews  = (const float*)d_in[11];
    const float* sebs  = (const float*)d_in[12];
    const float* sewv  = (const float*)d_in[13];
    const float* so2w0 = (const float*)d_in[14];
    const float* w1r   = (const float*)d_in[15];
    const float* w1i   = (const float*)d_in[16];
    const float* envw  = (const float*)d_in[17];
    const float* lpws  = (const float*)d_in[18];
    const float* lpbs  = (const float*)d_in[19];
    const float* lpwv  = (const float*)d_in[20];
    const float* ohwss = (const float*)d_in[21];
    const float* ohwsg = (const float*)d_in[22];
    const float* ohwvv = (const float*)d_in[23];
    const float* ohlws = (const float*)d_in[24];
    const float* ohlbs = (const float*)d_in[25];
    const float* ohlwv = (const float*)d_in[26];
    const float* resp  = (const float*)d_in[27];

    int N = in_sizes[1]/320, E = in_sizes[7], Etot = in_sizes[5]/2;
    size_t latN = (size_t)in_sizes[0];

    float* fb = nullptr;  cudaGetSymbolAddress((void**)&fb, g_buf);
    bf16* bb = nullptr;   cudaGetSymbolAddress((void**)&bb, g_bbuf);
    int* idx = nullptr;   cudaGetSymbolAddress((void**)&idx, g_idx);
    int* cnt = nullptr;   cudaGetSymbolAddress((void**)&cnt, g_cnt);
    int* offs = nullptr;  cudaGetSymbolAddress((void**)&offs, g_offs);
    int* order = nullptr; cudaGetSymbolAddress((void**)&order, g_order);

    float *nv = fb+NV_OFF, *Rbuf = fb+R_OFF, *proj = fb+PROJ_OFF, *gvb = fb+GVF_OFF,
          *wenv = fb+WENV_OFF, *aggs = fb+AGGS_OFF, *aggv = fb+AGGV_OFF, *tgb = fb+TG_OFF;
    bf16 *nsB = bb+NSB, *esvB = bb+ESVB, *vfB = bb+VF12B, *msgsB = bb+MSGSB, *msgvB = bb+MSGVB,
         *latB = bb+LATB, *gsB = bb+GSB, *gvmB = bb+GVMB, *agsB = bb+AGSB, *agvB = bb+AGVB,
         *wcpT = bb+WCPT, *w0mT = bb+W0MT, *w1cT = bb+W1CT, *envT = bb+ENVT, *lpwsT = bb+LPWST,
         *lpwvT = bb+LPWVT, *wssT = bb+WSST, *wsgT = bb+WSGT, *wvvT = bb+WVVT,
         *ohlwT = bb+OHLWT, *ohlvT = bb+OHLVT;
    int *ctr = idx, *nbr = idx + E;

    const float isq576 = 0.041666666666666664f, isq192 = 0.07216878364870323f,
                isq128 = 0.08838834764831845f, n_ss = 0.011048543456039806f, n_vv = 0.015625f;

    cudaFuncSetAttribute(mma_gemm_kernel<0,false>, cudaFuncAttributeMaxDynamicSharedMemorySize, GEMM_SMEM);
    cudaFuncSetAttribute(mma_gemm_kernel<0,true>,  cudaFuncAttributeMaxDynamicSharedMemorySize, GEMM_SMEM);
    cudaFuncSetAttribute(mma_gemm_kernel<1,false>, cudaFuncAttributeMaxDynamicSharedMemorySize, GEMM_SMEM);
    cudaFuncSetAttribute(mma_gemm_kernel<2,false>, cudaFuncAttributeMaxDynamicSharedMemorySize, GEMM_SMEM);
    cudaFuncSetAttribute(mma_gemm_kernel<3,false>, cudaFuncAttributeMaxDynamicSharedMemorySize, GEMM_SMEM);
    cudaFuncSetAttribute(mma_gemm_kernel<4,false>, cudaFuncAttributeMaxDynamicSharedMemorySize, GEMM_SMEM4);
    cudaFuncSetAttribute(mma_gemm_kernel<5,false>, cudaFuncAttributeMaxDynamicSharedMemorySize, GEMM_SMEM);
    cudaFuncSetAttribute(mma_gemm_kernel<6,false>, cudaFuncAttributeMaxDynamicSharedMemorySize, GEMM_SMEM);
    cudaFuncSetAttribute(mma_gemm_kernel<7,false>, cudaFuncAttributeMaxDynamicSharedMemorySize, GEMM_SMEM);
    cudaFuncSetAttribute(mma_gemm_kernel<8,false>, cudaFuncAttributeMaxDynamicSharedMemorySize, GEMM_SMEM);
    cudaFuncSetAttribute(mma_gemm_kernel<9,false>, cudaFuncAttributeMaxDynamicSharedMemorySize, GEMM_SMEM);

    int etile = (E + 127)/128, ntile = (N + 127)/128;

    zero_kernel<<<(int)(((size_t)N*320 + 255)/256), 256>>>(aggs, (size_t)N*320);
    zero_kernel<<<1, 128>>>((float*)cnt, 128);
    node_ln_kernel<<<(N + 7)/8, 256>>>(nf, snws, snbs, snwv, nsB, nv, N);
    // weight prep (bf16, transposed to [N,K])
    wcpT_kernel<<<(512*128 + 255)/256, 256>>>(so2w0, wcpT);
    w0mT_kernel<<<(256*320 + 255)/256, 256>>>(so2w0, w0mT);
    w1cT_kernel<<<(128*384 + 255)/256, 256>>>(w1r, w1i, w1cT);
    tr_kernel<<<(128*192 + 255)/256, 256>>>(envw, envT, 128, 192);
    tr_kernel<<<(128*128 + 255)/256, 256>>>(lpws, lpwsT, 128, 128);
    tr_kernel<<<(64*64 + 255)/256, 256>>>(lpwv, lpwvT, 64, 64);
    trt_kernel<<<(128*64*128 + 255)/256, 256>>>(ohwss, wssT, 128, 128);
    trt_kernel<<<(128*64*64 + 255)/256, 256>>>(ohwsg, wsgT, 128, 64);
    trt_kernel<<<(64*64*64 + 255)/256, 256>>>(ohwvv, wvvT, 64, 64);
    tr_kernel<<<(128*128 + 255)/256, 256>>>(ohlws, ohlwT, 128, 128);
    tr_kernel<<<(64*64 + 255)/256, 256>>>(ohlwv, ohlvT, 64, 64);
    c2b_kernel<<<(int)((latN + 255)/256), 256>>>(latents, latB, latN);
    count_kernel<<<(N + 255)/256, 256>>>(at, cnt, N);
    prefix_kernel<<<1, 32>>>(cnt, offs);
    order_kernel<<<(N + 255)/256, 256>>>(at, offs, cnt + 64, order, N);
    edge_prep_kernel<<<(E + 7)/8, 256>>>(ef, ei, act, evec, sews, sebs, sewv,
                                         nv, esvB, vfB, Rbuf, idx, E, Etot);

    // proj = ns @ wcpT  (N x 512, fp32 out)
    mma_gemm_kernel<0,false><<<dim3(4, ntile), 256, GEMM_SMEM>>>(
        nsB, wcpT, proj, N, 512, 128, 128, 128, 1.0f, nullptr, nullptr,
        nullptr, nullptr, nullptr, nullptr, nullptr, nullptr, nullptr, nullptr,
        nullptr, nullptr, nullptr, nullptr, 0, 0, N, E);
    // wenv = latB[act] @ envT / sqrt(128)
    mma_gemm_kernel<0,true><<<dim3(2, etile), 256, GEMM_SMEM>>>(
        latB, envT, wenv, E, 192, 128, 128, 128, isq128, nullptr, act,
        nullptr, nullptr, nullptr, nullptr, nullptr, nullptr, nullptr, nullptr,
        nullptr, nullptr, nullptr, nullptr, 0, 0, N, E);
    // main SO2 -> msgs(bf16) + gv(fp32)
    mma_gemm_kernel<1,false><<<dim3(2, etile), 256, GEMM_SMEM>>>(
        esvB, w0mT, (float*)msgsB, E, 256, 320, 320, 320, isq576, nullptr, nullptr,
        ctr, nbr, proj, nullptr, nullptr, nullptr, nullptr, gvb,
        nullptr, nullptr, nullptr, nullptr, 0, 0, N, E);
    // complex GEMM + fused rotation/gate -> msgv(bf16)
    mma_gemm_kernel<4,false><<<dim3(1, etile), 256, GEMM_SMEM4>>>(
        vfB, w1cT, (float*)msgvB, E, 128, 384, 384, 384, isq192, nullptr, nullptr,
        nullptr, nullptr, nullptr, Rbuf, gvb, nullptr, nullptr, nullptr,
        nullptr, nullptr, nullptr, nullptr, 0, 0, N, E);
    // lps + env-weight + scatter -> aggs
    mma_gemm_kernel<2,false><<<dim3(1, etile), 256, GEMM_SMEM>>>(
        msgsB, lpwsT, nullptr, E, 128, 128, 128, 128, isq128, lpbs, nullptr,
        ctr, nullptr, nullptr, nullptr, nullptr, wenv, aggs, nullptr,
        nullptr, nullptr, nullptr, nullptr, 0, 0, N, E);
    // lpv + env-weight + scatter -> aggv
    mma_gemm_kernel<3,false><<<dim3(1, (3*E + 127)/128), 256, GEMM_SMEM>>>(
        msgvB, lpwvT, nullptr, 3*E, 64, 64, 64, 64, 0.125f, nullptr, nullptr,
        ctr, nullptr, nullptr, nullptr, nullptr, wenv, aggv, nullptr,
        nullptr, nullptr, nullptr, nullptr, 0, 0, N, E);
    // aggs|aggv -> bf16 (contiguous N*320)
    c2b_kernel<<<(int)(((size_t)N*320 + 255)/256), 256>>>(aggs, agsB, (size_t)N*320);
    // typed: gs = bf16(silu(aggsB @ wssT[t] * n_ss))
    mma_gemm_kernel<5,false><<<dim3(1, 2, 64), 256, GEMM_SMEM>>>(
        agsB, wssT, (float*)gsB, N, 128, 128, 128, 128, n_ss, nullptr, nullptr,
        nullptr, nullptr, nullptr, nullptr, nullptr, nullptr, nullptr, nullptr,
        nullptr, nullptr, offs, order, 128*128, 0, N, E);
    // typed: tg = sigmoid(aggsB @ wsgT[t] * n_ss)  (fp32)
    mma_gemm_kernel<6,false><<<dim3(1, 2, 64), 256, GEMM_SMEM>>>(
        agsB, wsgT, tgb, N, 64, 128, 128, 128, n_ss, nullptr, nullptr,
        nullptr, nullptr, nullptr, nullptr, nullptr, nullptr, nullptr, nullptr,
        nullptr, nullptr, offs, order, 64*128, 0, N, E);
    // typed, 3 planes: gvm = bf16(tg * (aggvB @ wvvT[t] * n_vv))
    mma_gemm_kernel<7,false><<<dim3(3, 2, 64), 256, GEMM_SMEM>>>(
        agvB, wvvT, (float*)gvmB, N, 64, 64, 64, 64, n_vv, nullptr, nullptr,
        nullptr, nullptr, nullptr, nullptr, tgb, nullptr, nullptr, nullptr,
        nullptr, nullptr, offs, order, 64*64, (size_t)N*64, N, E);
    // final scalar: out[:,0:128]
    mma_gemm_kernel<8,false><<<dim3(1, ntile), 256, GEMM_SMEM>>>(
        gsB, ohlwT, (float*)d_out, N, 128, 128, 128, 128, isq128, ohlbs, nullptr,
        nullptr, nullptr, nullptr, nullptr, nullptr, nullptr, nullptr, nullptr,
        nf, resp, nullptr, nullptr, 0, 0, N, E);
    // final vector: out[:,128+3k+m]
    mma_gemm_kernel<9,false><<<dim3(3, ntile), 256, GEMM_SMEM>>>(
        gvmB, ohlvT, (float*)d_out, N, 64, 64, 64, 64, 0.125f, nullptr, nullptr,
        nullptr, nullptr, nullptr, nullptr, nullptr, nullptr, nullptr, nullptr,
        nf, resp, nullptr, nullptr, 0, (size_t)N*64, N, E);
}

// round 8
// speedup vs baseline: 3.1992x; 1.0544x over previous
#include <cuda_runtime.h>
#include <cuda_bf16.h>
#include <math.h>
#include <stdint.h>

static constexpr int NMAXN = 8000;
static constexpr int EMAX  = 96000;

// ---- fp32 scratch ----
static constexpr size_t NV_OFF   = 0;                                  // nv:   N x 192
static constexpr size_t R_OFF    = NV_OFF   + (size_t)NMAXN*192;       // R:    E x 9
static constexpr size_t PROJ_OFF = R_OFF    + (size_t)EMAX*9;          // proj: N x 512
static constexpr size_t GVF_OFF  = PROJ_OFF + (size_t)NMAXN*512;       // gv:   E x 128
static constexpr size_t WENV_OFF = GVF_OFF  + (size_t)EMAX*128;        // wenv: E x 192
static constexpr size_t AGGS_OFF = WENV_OFF + (size_t)EMAX*192;        // aggs: N x 128
static constexpr size_t AGGV_OFF = AGGS_OFF + (size_t)NMAXN*128;       // aggv: 3 x N x 64
static constexpr size_t TG_OFF   = AGGV_OFF + (size_t)3*NMAXN*64;      // tg:   N x 64
static constexpr size_t TOTAL_F  = TG_OFF   + (size_t)NMAXN*64;
__device__ __align__(256) float g_buf[TOTAL_F];

// ---- bf16 scratch ----
static constexpr size_t NSB   = 0;                                     // ns:    N x 128
static constexpr size_t ESVB  = NSB   + (size_t)NMAXN*128;             // esvf0: E x 320
static constexpr size_t VF12B = ESVB  + (size_t)EMAX*320;              // vf12:  E x 384
static constexpr size_t MSGSB = VF12B + (size_t)EMAX*384;              // msgs:  E x 128
static constexpr size_t MSGVB = MSGSB + (size_t)EMAX*128;              // msgv:  3 x E x 64
static constexpr size_t LATB  = MSGVB + (size_t)3*EMAX*64;             // latB:  E x 128
static constexpr size_t GSB   = LATB  + (size_t)EMAX*128;              // gs:    N x 128
static constexpr size_t GVMB  = GSB   + (size_t)NMAXN*128;             // gvm:   3 x N x 64
static constexpr size_t AGSB  = GVMB  + (size_t)3*NMAXN*64;            // aggsB: N x 128
static constexpr size_t AGVB  = AGSB  + (size_t)NMAXN*128;             // aggvB: 3 x N x 64
static constexpr size_t WCPT  = AGVB  + (size_t)3*NMAXN*64;            // 512 x 128
static constexpr size_t W0MT  = WCPT  + (size_t)512*128;               // 256 x 320
static constexpr size_t W1CT  = W0MT  + (size_t)256*320;               // 128 x 384
static constexpr size_t ENVT  = W1CT  + (size_t)128*384;               // 192 x 128
static constexpr size_t LPWST = ENVT  + (size_t)192*128;               // 128 x 128
static constexpr size_t LPWVT = LPWST + (size_t)128*128;               // 64 x 64
static constexpr size_t WSST  = LPWVT + (size_t)64*64;                 // 64 x 128 x 128
static constexpr size_t WSGT  = WSST  + (size_t)64*128*128;            // 64 x 64 x 128
static constexpr size_t WVVT  = WSGT  + (size_t)64*64*128;             // 64 x 64 x 64
static constexpr size_t OHLWT = WVVT  + (size_t)64*64*64;              // 128 x 128
static constexpr size_t OHLVT = OHLWT + (size_t)128*128;               // 64 x 64
static constexpr size_t TOTAL_B = OHLVT + (size_t)64*64;
__device__ __align__(256) __nv_bfloat16 g_bbuf[TOTAL_B];

__device__ int g_idx[2*EMAX];
__device__ int g_cnt[128];
__device__ int g_offs[65];
__device__ int g_order[NMAXN];

typedef __nv_bfloat16 bf16;
typedef __nv_bfloat162 bf162;
__device__ __forceinline__ bf162 f2b2(float a, float b) { return __floats2bfloat162_rn(a, b); }

// ---------------------------------------------------------------------------
__global__ void zero_kernel(float* __restrict__ p, size_t n) {
    size_t i = (size_t)blockIdx.x*blockDim.x + threadIdx.x;
    if (i < n) p[i] = 0.f;
}
__global__ void c2b_kernel(const float* __restrict__ in, bf16* __restrict__ out, size_t n) {
    size_t i = (size_t)blockIdx.x*blockDim.x + threadIdx.x;
    if (i < n) out[i] = __float2bfloat16(in[i]);
}
__global__ void count_kernel(const int* __restrict__ at, int* __restrict__ cnt, int N) {
    int n = blockIdx.x*blockDim.x + threadIdx.x;
    if (n < N) atomicAdd(&cnt[at[n]], 1);
}
__global__ void prefix_kernel(const int* __restrict__ cnt, int* __restrict__ offs) {
    if (threadIdx.x == 0) { int s = 0; for (int i = 0; i < 64; i++) { offs[i] = s; s += cnt[i]; } offs[64] = s; }
}
__global__ void order_kernel(const int* __restrict__ at, const int* __restrict__ offs,
                             int* __restrict__ cur, int* __restrict__ order, int N) {
    int n = blockIdx.x*blockDim.x + threadIdx.x;
    if (n < N) { int t = at[n]; order[offs[t] + atomicAdd(&cur[t], 1)] = n; }
}

// ---------------------------------------------------------------------------
// ONE fused weight-prep kernel: all transposed bf16 weights + latents cast.
__device__ __forceinline__ void tr_elem(const float* in, bf16* out, int C, int R, int i) {
    int r = i / C, c = i - r*C;            // in [R,C] -> out[c*R + r]
    out[(size_t)c*R + r] = __float2bfloat16(in[i]);
}
__device__ __forceinline__ void trt_elem(const float* in, bf16* out, int U, int Nc, int i) {
    int u = i / (64*Nc); int rem = i - u*64*Nc; int t = rem / Nc; int n = rem - t*Nc;
    out[((size_t)t*Nc + n)*U + u] = __float2bfloat16(in[i]);
}
__global__ void prep_all_kernel(const float* __restrict__ w0,
                                const float* __restrict__ w1r, const float* __restrict__ w1i,
                                const float* __restrict__ envw, const float* __restrict__ lpws,
                                const float* __restrict__ lpwv, const float* __restrict__ ohwss,
                                const float* __restrict__ ohwsg, const float* __restrict__ ohwvv,
                                const float* __restrict__ ohlws, const float* __restrict__ ohlwv,
                                const float* __restrict__ latents, bf16* __restrict__ bb,
                                size_t latN) {
    size_t gi = (size_t)blockIdx.x*blockDim.x + threadIdx.x;
    if (gi < 65536) {                       // wcpT [512c][128k]
        int i = (int)gi, c = i / 128, k = i - c*128;
        float v = (c < 256) ? w0[(size_t)k*256 + c] : w0[(size_t)(256 + k)*256 + c - 256];
        bb[WCPT + i] = __float2bfloat16(v);
    } else if (gi < 147456) {               // w0mT [256c][320k]
        int i = (int)(gi - 65536), c = i / 320, k = i - c*320;
        int src = (k < 128) ? k + 128 : k + 256;
        bb[W0MT + i] = __float2bfloat16(w0[(size_t)src*256 + c]);
    } else if (gi < 196608) {               // w1cT [128c][384r]
        int i = (int)(gi - 147456), c = i / 384, r = i - c*384;
        float v;
        if (r < 192) v = (c < 64) ? w1r[r*64 + c] : w1i[r*64 + c - 64];
        else { int r2 = r - 192; v = (c < 64) ? -w1i[r2*64 + c] : w1r[r2*64 + c - 64]; }
        bb[W1CT + i] = __float2bfloat16(v);
    } else if (gi < 221184) {               // envT: tr 128x192
        tr_elem(envw, bb + ENVT, 192, 128, (int)(gi - 196608));
    } else if (gi < 237568) {               // lpwsT: tr 128x128
        tr_elem(lpws, bb + LPWST, 128, 128, (int)(gi - 221184));
    } else if (gi < 241664) {               // lpwvT: tr 64x64
        tr_elem(lpwv, bb + LPWVT, 64, 64, (int)(gi - 237568));
    } else if (gi < 1290240) {              // wssT: trt U=128 Nc=128
        trt_elem(ohwss, bb + WSST, 128, 128, (int)(gi - 241664));
    } else if (gi < 1814528) {              // wsgT: trt U=128 Nc=64
        trt_elem(ohwsg, bb + WSGT, 128, 64, (int)(gi - 1290240));
    } else if (gi < 2076672) {              // wvvT: trt U=64 Nc=64
        trt_elem(ohwvv, bb + WVVT, 64, 64, (int)(gi - 1814528));
    } else if (gi < 2093056) {              // ohlwT: tr 128x128
        tr_elem(ohlws, bb + OHLWT, 128, 128, (int)(gi - 2076672));
    } else if (gi < 2097152) {              // ohlvT: tr 64x64
        tr_elem(ohlwv, bb + OHLVT, 64, 64, (int)(gi - 2093056));
    } else {                                // latB
        size_t i = gi - 2097152;
        if (i < latN) bb[LATB + i] = __float2bfloat16(latents[i]);
    }
}

// ---------------------------------------------------------------------------
__global__ void node_ln_kernel(const float* __restrict__ nf, const float* __restrict__ ws,
                               const float* __restrict__ bs, const float* __restrict__ wv,
                               bf16* __restrict__ ns, float* __restrict__ nv, int N) {
    int node = (blockIdx.x*blockDim.x + threadIdx.x) >> 5;
    int lane = threadIdx.x & 31;
    if (node >= N) return;
    const float* row = nf + (size_t)node*320;
    float s[4]; float sum = 0.f;
#pragma unroll
    for (int i = 0; i < 4; i++) { s[i] = row[lane + 32*i]; sum += s[i]; }
#pragma unroll
    for (int o = 16; o; o >>= 1) sum += __shfl_xor_sync(~0u, sum, o);
    float mu = sum*(1.f/128.f), var = 0.f;
#pragma unroll
    for (int i = 0; i < 4; i++) { s[i] -= mu; var += s[i]*s[i]; }
#pragma unroll
    for (int o = 16; o; o >>= 1) var += __shfl_xor_sync(~0u, var, o);
    float rs = rsqrtf(var*(1.f/128.f) + 1e-8f);
#pragma unroll
    for (int i = 0; i < 4; i++) {
        int c = lane + 32*i;
        ns[(size_t)node*128 + c] = __float2bfloat16(s[i]*rs*ws[c] + bs[c]);
    }
    float v[6]; float vs = 0.f;
#pragma unroll
    for (int i = 0; i < 6; i++) { v[i] = row[128 + lane + 32*i]; vs += v[i]*v[i]; }
#pragma unroll
    for (int o = 16; o; o >>= 1) vs += __shfl_xor_sync(~0u, vs, o);
    float rv = rsqrtf(vs*(1.f/192.f) + 1e-8f);
#pragma unroll
    for (int i = 0; i < 6; i++) { int c = lane + 32*i; nv[(size_t)node*192 + c] = v[i]*rv*wv[c/3]; }
}

__global__ void edge_prep_kernel(const float* __restrict__ ef, const int* __restrict__ ei,
                                 const int* __restrict__ act, const float* __restrict__ evec,
                                 const float* __restrict__ ws, const float* __restrict__ bs,
                                 const float* __restrict__ wv, const float* __restrict__ nv,
                                 bf16* __restrict__ esv0, bf16* __restrict__ vf12,
                                 float* __restrict__ Rout, int* __restrict__ idx, int E, int Etot) {
    __shared__ float evs[8][192];
    int wi = threadIdx.x >> 5, lane = threadIdx.x & 31;
    int e = blockIdx.x*8 + wi;
    if (e >= E) return;
    int ae = act[e];
    int ctr = ei[ae], nbr = ei[Etot + ae];
    if (lane == 0) { idx[e] = ctr; idx[E + e] = nbr; }
    const float* row = ef + (size_t)e*320;

    float s[4]; float sum = 0.f;
#pragma unroll
    for (int i = 0; i < 4; i++) { s[i] = row[lane + 32*i]; sum += s[i]; }
#pragma unroll
    for (int o = 16; o; o >>= 1) sum += __shfl_xor_sync(~0u, sum, o);
    float mu = sum*(1.f/128.f), var = 0.f;
#pragma unroll
    for (int i = 0; i < 4; i++) { s[i] -= mu; var += s[i]*s[i]; }
#pragma unroll
    for (int o = 16; o; o >>= 1) var += __shfl_xor_sync(~0u, var, o);
    float rs = rsqrtf(var*(1.f/128.f) + 1e-8f);
    bf16* esv = esv0 + (size_t)e*320;
#pragma unroll
    for (int i = 0; i < 4; i++) { int c = lane + 32*i; esv[c] = __float2bfloat16(s[i]*rs*ws[c] + bs[c]); }

    float v[6]; float vs = 0.f;
#pragma unroll
    for (int i = 0; i < 6; i++) { v[i] = row[128 + lane + 32*i]; vs += v[i]*v[i]; }
#pragma unroll
    for (int o = 16; o; o >>= 1) vs += __shfl_xor_sync(~0u, vs, o);
    float rv = rsqrtf(vs*(1.f/192.f) + 1e-8f);
#pragma unroll
    for (int i = 0; i < 6; i++) { int c = lane + 32*i; evs[wi][c] = v[i]*rv*wv[c/3]; }
    __syncwarp();

    float e0 = evec[(size_t)ae*3], e1 = evec[(size_t)ae*3+1], e2 = evec[(size_t)ae*3+2];
    float rn = rsqrtf(e0*e0 + e1*e1 + e2*e2 + 1e-8f);
    float ax = e0*rn, ay = e1*rn, az = e2*rn;
    float refx = (fabsf(ax) < 0.9f) ? 1.f : 0.f, refy = 1.f - refx;
    float bx = -az*refy, by = az*refx, bz = ax*refy - ay*refx;
    float rb = rsqrtf(bx*bx + by*by + bz*bz + 1e-8f);
    bx *= rb; by *= rb; bz *= rb;
    float cx = ay*bz - az*by, cy = az*bx - ax*bz, cz = ax*by - ay*bx;
    if (lane == 0) {
        float* Rp = Rout + (size_t)e*9;
        Rp[0]=ax; Rp[1]=ay; Rp[2]=az; Rp[3]=bx; Rp[4]=by; Rp[5]=bz; Rp[6]=cx; Rp[7]=cy; Rp[8]=cz;
    }
    bf16* vf = vf12 + (size_t)e*384;
#pragma unroll
    for (int i = 0; i < 6; i++) {
        int u = lane + 32*i;
        float vx, vy, vz;
        if (u < 64)       { const float* p = nv + (size_t)ctr*192 + u*3;        vx=p[0]; vy=p[1]; vz=p[2]; }
        else if (u < 128) { const float* p = &evs[wi][(u-64)*3];                vx=p[0]; vy=p[1]; vz=p[2]; }
        else              { const float* p = nv + (size_t)nbr*192 + (u-128)*3;  vx=p[0]; vy=p[1]; vz=p[2]; }
        esv[128 + u] = __float2bfloat16(ax*vx + ay*vy + az*vz);
        vf[u]        = __float2bfloat16(bx*vx + by*vy + bz*vz);
        vf[192 + u]  = __float2bfloat16(cx*vx + cy*vy + cz*vz);
    }
}

// ---------------------------------------------------------------------------
// bf16 tensor-core GEMM (m16n8k16) + ldmatrix fragment loads, cp.async 3-stage.
static constexpr int STG_B = 12288;
static constexpr int GEMM_SMEM = 3*STG_B;     // 36864
static constexpr int GEMM_SMEM4 = 128*132*4;  // 67584

template<int MODE, bool GATHER>
__global__ __launch_bounds__(256, 2)
void mma_gemm_kernel(const bf16* __restrict__ A, const bf16* __restrict__ B,
                     float* __restrict__ C, int M, int Nc, int K, int lda, int ldb,
                     float scale, const float* __restrict__ bias, const int* __restrict__ rowidx,
                     const int* __restrict__ ctr, const int* __restrict__ nbr,
                     const float* __restrict__ proj, const float* __restrict__ Rrot,
                     const float* __restrict__ gvbuf, const float* __restrict__ wenv,
                     float* __restrict__ agg, float* __restrict__ aux,
                     const float* __restrict__ nf, const float* __restrict__ resp,
                     const int* __restrict__ offs, const int* __restrict__ order,
                     int tOffB, size_t aplane, int Nnodes, int E) {
    constexpr bool TYPED = (MODE == 5 || MODE == 6 || MODE == 7);
    extern __shared__ char smc[];
    const int tid = threadIdx.x, lane = tid & 31, wid = tid >> 5;
    const int g = lane >> 2, t = lane & 3;
    const int wm = (wid >> 2)*64, wn = (wid & 3)*32;

    int mplane = 0, bn;
    if (MODE == 7 || MODE == 9) { mplane = blockIdx.x; bn = 0; } else bn = blockIdx.x*128;
    const int bm = blockIdx.y*128;

    int Mloc = M, rowbase = 0, typ = 0;
    if (TYPED) {
        typ = blockIdx.z;
        rowbase = offs[typ];
        Mloc = offs[typ+1] - rowbase;
        if (Mloc == 0 || bm >= Mloc) return;
    }
    const bf16* Ause = A + (size_t)mplane*aplane;
    const bf16* Buse = B + (TYPED ? (size_t)typ*tOffB : 0);

    // cp.async setup: one 16B A chunk + one 16B B chunk per thread per stage
    int arow = tid >> 1, ahalf = tid & 1;
    int r = bm + arow, gr;
    if (TYPED) { if (r >= Mloc) r = Mloc - 1; gr = order[rowbase + r]; }
    else       { if (r >= M) r = M - 1;       gr = GATHER ? rowidx[r] : r; }
    const bf16* asrc = Ause + (size_t)gr*lda + ahalf*8;
    int bn_row = bn + arow;
    int bby = (bn_row < Nc) ? 16 : 0;
    const bf16* bsrc = Buse + (size_t)min(bn_row, Nc-1)*ldb + ahalf*8;
    uint32_t sbase = (uint32_t)__cvta_generic_to_shared(smc);
    uint32_t adst = sbase + arow*48 + ahalf*16;
    uint32_t bdst = sbase + 6144 + arow*48 + ahalf*16;

    // ldmatrix per-lane addresses (within stage 0)
    const int q = lane >> 3, rr8 = lane & 7;
    uint32_t aLd = sbase + ((wm + (q & 1)*8 + rr8)*24 + (q >> 1)*8)*2;
    uint32_t bLd = sbase + 6144 + ((wn + (q >> 1)*8 + rr8)*24 + (q & 1)*8)*2;

    const int kT = K >> 4;
    auto loadStage = [&](int slot, int k0) {
        uint32_t so = slot*STG_B;
        asm volatile("cp.async.cg.shared.global [%0], [%1], 16;" :: "r"(adst + so), "l"(asrc + k0) : "memory");
        asm volatile("cp.async.cg.shared.global [%0], [%1], 16, %2;" :: "r"(bdst + so), "l"(bsrc + k0), "r"(bby) : "memory");
        asm volatile("cp.async.commit_group;");
    };

    float acc[4][4][4];
#pragma unroll
    for (int mi = 0; mi < 4; mi++)
#pragma unroll
        for (int ni = 0; ni < 4; ni++)
#pragma unroll
            for (int j = 0; j < 4; j++) acc[mi][ni][j] = 0.f;

    loadStage(0, 0); loadStage(1, 16);

    for (int kt = 0; kt < kT; kt++) {
        asm volatile("cp.async.wait_group 1;");
        __syncthreads();
        int pf = kt + 2;
        if (pf < kT) loadStage(pf % 3, pf*16);
        else asm volatile("cp.async.commit_group;");

        uint32_t so = (kt % 3)*STG_B;
        uint32_t af[4][4], bf[4][2];
#pragma unroll
        for (int mi = 0; mi < 4; mi++)
            asm volatile("ldmatrix.sync.aligned.m8n8.x4.shared.b16 {%0,%1,%2,%3}, [%4];"
                : "=r"(af[mi][0]), "=r"(af[mi][1]), "=r"(af[mi][2]), "=r"(af[mi][3])
                : "r"(aLd + so + mi*16*48));
#pragma unroll
        for (int np = 0; np < 2; np++)
            asm volatile("ldmatrix.sync.aligned.m8n8.x4.shared.b16 {%0,%1,%2,%3}, [%4];"
                : "=r"(bf[2*np][0]), "=r"(bf[2*np][1]), "=r"(bf[2*np+1][0]), "=r"(bf[2*np+1][1])
                : "r"(bLd + so + np*16*48));
#pragma unroll
        for (int mi = 0; mi < 4; mi++)
#pragma unroll
            for (int ni = 0; ni < 4; ni++) {
                asm volatile(
                    "mma.sync.aligned.m16n8k16.row.col.f32.bf16.bf16.f32 "
                    "{%0,%1,%2,%3}, {%4,%5,%6,%7}, {%8,%9}, {%0,%1,%2,%3};"
                    : "+f"(acc[mi][ni][0]), "+f"(acc[mi][ni][1]),
                      "+f"(acc[mi][ni][2]), "+f"(acc[mi][ni][3])
                    : "r"(af[mi][0]), "r"(af[mi][1]), "r"(af[mi][2]), "r"(af[mi][3]),
                      "r"(bf[ni][0]), "r"(bf[ni][1]));
            }
    }

    // ---------------- epilogue ----------------
    const float INV = 0.28867513459481287f;
    if (MODE == 4) {
        __syncthreads();
        float* Vs = (float*)smc;
#pragma unroll
        for (int mi = 0; mi < 4; mi++)
#pragma unroll
            for (int h = 0; h < 2; h++) {
                int rw = wm + mi*16 + g + 8*h;
#pragma unroll
                for (int ni = 0; ni < 4; ni++) {
                    int c = wn + ni*8 + 2*t;
                    *(float2*)&Vs[rw*132 + c] = make_float2(acc[mi][ni][2*h]*scale, acc[mi][ni][2*h+1]*scale);
                }
            }
        __syncthreads();
        bf16* Cb = (bf16*)C;
        for (int rw = wid; rw < 128; rw += 8) {
            int e = bm + rw;
            const float* Rp = Rrot + (size_t)e*9;
            float R0=Rp[0],R1=Rp[1],R2=Rp[2],R3=Rp[3],R4=Rp[4],R5=Rp[5],R6=Rp[6],R7=Rp[7],R8=Rp[8];
            const float* gvp = gvbuf + (size_t)e*128;
#pragma unroll
            for (int i = 0; i < 2; i++) {
                int u = lane + 32*i;
                float sg = gvp[u], i0 = gvp[64 + u];
                float i1 = Vs[rw*132 + u], i2 = Vs[rw*132 + 64 + u];
                Cb[(size_t)0*E*64 + (size_t)e*64 + u] = __float2bfloat16(sg*(R0*i0 + R3*i1 + R6*i2));
                Cb[(size_t)1*E*64 + (size_t)e*64 + u] = __float2bfloat16(sg*(R1*i0 + R4*i1 + R7*i2));
                Cb[(size_t)2*E*64 + (size_t)e*64 + u] = __float2bfloat16(sg*(R2*i0 + R5*i1 + R8*i2));
            }
        }
        return;
    }

    float alpha = 0.f, beta = 0.f;
    if (MODE == 8 || MODE == 9) { alpha = 1.f/(1.f + expf(-resp[0])); beta = 1.f - alpha; }

#pragma unroll
    for (int mi = 0; mi < 4; mi++) {
        int r0 = bm + wm + mi*16 + g;
#pragma unroll
        for (int h = 0; h < 2; h++) {
            int row = r0 + 8*h;
            if (row >= (TYPED ? Mloc : M)) continue;
            if (MODE == 0) {
#pragma unroll
                for (int ni = 0; ni < 4; ni++) {
                    int c = bn + wn + ni*8 + 2*t;
                    if (c >= Nc) continue;
                    float a0 = acc[mi][ni][2*h]*scale + (bias ? bias[c] : 0.f);
                    float a1 = acc[mi][ni][2*h+1]*scale + (bias ? bias[c+1] : 0.f);
                    *(float2*)&C[(size_t)row*Nc + c] = make_float2(a0, a1);
                }
            } else if (MODE == 1) {
                const float* pc = proj + (size_t)ctr[row]*512;
                const float* pn = proj + (size_t)nbr[row]*512 + 256;
                bf16* Cb = (bf16*)C;
#pragma unroll
                for (int ni = 0; ni < 4; ni++) {
                    int c = bn + wn + ni*8 + 2*t;
                    float v0 = (acc[mi][ni][2*h]   + pc[c]   + pn[c]  )*scale;
                    float v1 = (acc[mi][ni][2*h+1] + pc[c+1] + pn[c+1])*scale;
                    if (c < 128) {
                        *(bf162*)&Cb[(size_t)row*128 + c] = f2b2(v0/(1.f+expf(-v0)), v1/(1.f+expf(-v1)));
                    } else if (c < 192) {
                        *(float2*)&aux[(size_t)row*128 + c-128] =
                            make_float2(1.f/(1.f+expf(-v0)), 1.f/(1.f+expf(-v1)));
                    } else {
                        *(float2*)&aux[(size_t)row*128 + c-128] = make_float2(v0, v1);
                    }
                }
            } else if (MODE == 2) {
                float* ap = agg + (size_t)ctr[row]*128;
                const float* we = wenv + (size_t)row*192;
#pragma unroll
                for (int ni = 0; ni < 4; ni++) {
                    int c = bn + wn + ni*8 + 2*t;
                    if (c >= Nc) continue;
                    atomicAdd(&ap[c],   (acc[mi][ni][2*h]  *scale + bias[c])  *we[c]  *INV);
                    atomicAdd(&ap[c+1], (acc[mi][ni][2*h+1]*scale + bias[c+1])*we[c+1]*INV);
                }
            } else if (MODE == 3) {
                int m = row / E, e = row - m*E;
                float* ap = agg + (size_t)m*Nnodes*64 + (size_t)ctr[e]*64;
                const float* we = wenv + (size_t)e*192 + 128;
#pragma unroll
                for (int ni = 0; ni < 4; ni++) {
                    int c = bn + wn + ni*8 + 2*t;
                    if (c >= Nc) continue;
                    atomicAdd(&ap[c],   acc[mi][ni][2*h]  *scale*we[c]  *INV);
                    atomicAdd(&ap[c+1], acc[mi][ni][2*h+1]*scale*we[c+1]*INV);
                }
            } else if (MODE == 5) {
                int node = order[rowbase + row];
                bf16* Cb = (bf16*)C;
#pragma unroll
                for (int ni = 0; ni < 4; ni++) {
                    int c = wn + ni*8 + 2*t;
                    float v0 = acc[mi][ni][2*h]*scale, v1 = acc[mi][ni][2*h+1]*scale;
                    *(bf162*)&Cb[(size_t)node*128 + c] = f2b2(v0/(1.f+expf(-v0)), v1/(1.f+expf(-v1)));
                }
            } else if (MODE == 6) {
                int node = order[rowbase + row];
#pragma unroll
                for (int ni = 0; ni < 4; ni++) {
                    int c = wn + ni*8 + 2*t;
                    if (c >= Nc) continue;
                    *(float2*)&C[(size_t)node*64 + c] =
                        make_float2(1.f/(1.f+expf(-acc[mi][ni][2*h]*scale)),
                                    1.f/(1.f+expf(-acc[mi][ni][2*h+1]*scale)));
                }
            } else if (MODE == 7) {
                int node = order[rowbase + row];
                const float* tgp = gvbuf + (size_t)node*64;
                bf16* Cb = (bf16*)C;
#pragma unroll
                for (int ni = 0; ni < 4; ni++) {
                    int c = wn + ni*8 + 2*t;
                    if (c >= Nc) continue;
                    *(bf162*)&Cb[(size_t)mplane*aplane + (size_t)node*64 + c] =
                        f2b2(acc[mi][ni][2*h]*scale*tgp[c], acc[mi][ni][2*h+1]*scale*tgp[c+1]);
                }
            } else if (MODE == 8) {
#pragma unroll
                for (int ni = 0; ni < 4; ni++) {
                    int c = wn + ni*8 + 2*t;
                    float a0 = acc[mi][ni][2*h]*scale + bias[c];
                    float a1 = acc[mi][ni][2*h+1]*scale + bias[c+1];
                    *(float2*)&C[(size_t)row*320 + c] =
                        make_float2(alpha*nf[(size_t)row*320 + c] + beta*a0,
                                    alpha*nf[(size_t)row*320 + c + 1] + beta*a1);
                }
            } else { // MODE 9
#pragma unroll
                for (int ni = 0; ni < 4; ni++) {
                    int c = wn + ni*8 + 2*t;
                    if (c >= Nc) continue;
                    size_t o0 = (size_t)row*320 + 128 + 3*c + mplane;
                    size_t o1 = (size_t)row*320 + 128 + 3*(c+1) + mplane;
                    C[o0] = alpha*nf[o0] + beta*acc[mi][ni][2*h]*scale;
                    C[o1] = alpha*nf[o1] + beta*acc[mi][ni][2*h+1]*scale;
                }
            }
        }
    }
}

// ---------------------------------------------------------------------------
extern "C" void kernel_launch(void* const* d_in, const int* in_sizes, int n_in,
                              void* d_out, int out_size) {
    const float* latents = (const float*)d_in[0];
    const float* nf    = (const float*)d_in[1];
    const float* ef    = (const float*)d_in[2];
    const int*   at    = (const int*)  d_in[3];
    const int*   ei    = (const int*)  d_in[5];
    const float* evec  = (const float*)d_in[6];
    const int*   act   = (const int*)  d_in[7];
    const float* snws  = (const float*)d_in[8];
    const float* snbs  = (const float*)d_in[9];
    const float* snwv  = (const float*)d_in[10];
    const float* sews  = (const float*)d_in[11];
    const float* sebs  = (const float*)d_in[12];
    const float* sewv  = (const float*)d_in[13];
    const float* so2w0 = (const float*)d_in[14];
    const float* w1r   = (const float*)d_in[15];
    const float* w1i   = (const float*)d_in[16];
    const float* envw  = (const float*)d_in[17];
    const float* lpws  = (const float*)d_in[18];
    const float* lpbs  = (const float*)d_in[19];
    const float* lpwv  = (const float*)d_in[20];
    const float* ohwss = (const float*)d_in[21];
    const float* ohwsg = (const float*)d_in[22];
    const float* ohwvv = (const float*)d_in[23];
    const float* ohlws = (const float*)d_in[24];
    const float* ohlbs = (const float*)d_in[25];
    const float* ohlwv = (const float*)d_in[26];
    const float* resp  = (const float*)d_in[27];

    int N = in_sizes[1]/320, E = in_sizes[7], Etot = in_sizes[5]/2;
    size_t latN = (size_t)in_sizes[0];

    float* fb = nullptr;  cudaGetSymbolAddress((void**)&fb, g_buf);
    bf16* bb = nullptr;   cudaGetSymbolAddress((void**)&bb, g_bbuf);
    int* idx = nullptr;   cudaGetSymbolAddress((void**)&idx, g_idx);
    int* cnt = nullptr;   cudaGetSymbolAddress((void**)&cnt, g_cnt);
    int* offs = nullptr;  cudaGetSymbolAddress((void**)&offs, g_offs);
    int* order = nullptr; cudaGetSymbolAddress((void**)&order, g_order);

    float *nv = fb+NV_OFF, *Rbuf = fb+R_OFF, *proj = fb+PROJ_OFF, *gvb = fb+GVF_OFF,
          *wenv = fb+WENV_OFF, *aggs = fb+AGGS_OFF, *aggv = fb+AGGV_OFF, *tgb = fb+TG_OFF;
    bf16 *nsB = bb+NSB, *esvB = bb+ESVB, *vfB = bb+VF12B, *msgsB = bb+MSGSB, *msgvB = bb+MSGVB,
         *latB = bb+LATB, *gsB = bb+GSB, *gvmB = bb+GVMB, *agsB = bb+AGSB, *agvB = bb+AGVB,
         *wcpT = bb+WCPT, *w0mT = bb+W0MT, *w1cT = bb+W1CT, *envT = bb+ENVT, *lpwsT = bb+LPWST,
         *lpwvT = bb+LPWVT, *wssT = bb+WSST, *wsgT = bb+WSGT, *wvvT = bb+WVVT,
         *ohlwT = bb+OHLWT, *ohlvT = bb+OHLVT;
    int *ctr = idx, *nbr = idx + E;

    const float isq576 = 0.041666666666666664f, isq192 = 0.07216878364870323f,
                isq128 = 0.08838834764831845f, n_ss = 0.011048543456039806f, n_vv = 0.015625f;

    cudaFuncSetAttribute(mma_gemm_kernel<0,false>, cudaFuncAttributeMaxDynamicSharedMemorySize, GEMM_SMEM);
    cudaFuncSetAttribute(mma_gemm_kernel<0,true>,  cudaFuncAttributeMaxDynamicSharedMemorySize, GEMM_SMEM);
    cudaFuncSetAttribute(mma_gemm_kernel<1,false>, cudaFuncAttributeMaxDynamicSharedMemorySize, GEMM_SMEM);
    cudaFuncSetAttribute(mma_gemm_kernel<2,false>, cudaFuncAttributeMaxDynamicSharedMemorySize, GEMM_SMEM);
    cudaFuncSetAttribute(mma_gemm_kernel<3,false>, cudaFuncAttributeMaxDynamicSharedMemorySize, GEMM_SMEM);
    cudaFuncSetAttribute(mma_gemm_kernel<4,false>, cudaFuncAttributeMaxDynamicSharedMemorySize, GEMM_SMEM4);
    cudaFuncSetAttribute(mma_gemm_kernel<5,false>, cudaFuncAttributeMaxDynamicSharedMemorySize, GEMM_SMEM);
    cudaFuncSetAttribute(mma_gemm_kernel<6,false>, cudaFuncAttributeMaxDynamicSharedMemorySize, GEMM_SMEM);
    cudaFuncSetAttribute(mma_gemm_kernel<7,false>, cudaFuncAttributeMaxDynamicSharedMemorySize, GEMM_SMEM);
    cudaFuncSetAttribute(mma_gemm_kernel<8,false>, cudaFuncAttributeMaxDynamicSharedMemorySize, GEMM_SMEM);
    cudaFuncSetAttribute(mma_gemm_kernel<9,false>, cudaFuncAttributeMaxDynamicSharedMemorySize, GEMM_SMEM);

    int etile = (E + 127)/128, ntile = (N + 127)/128;

    zero_kernel<<<(int)(((size_t)N*320 + 255)/256), 256>>>(aggs, (size_t)N*320);
    zero_kernel<<<1, 128>>>((float*)cnt, 128);
    node_ln_kernel<<<(N + 7)/8, 256>>>(nf, snws, snbs, snwv, nsB, nv, N);
    // fused weight prep (single launch)
    {
        size_t tot = 2097152 + latN;
        prep_all_kernel<<<(int)((tot + 255)/256), 256>>>(
            so2w0, w1r, w1i, envw, lpws, lpwv, ohwss, ohwsg, ohwvv, ohlws, ohlwv,
            latents, bb, latN);
    }
    count_kernel<<<(N + 255)/256, 256>>>(at, cnt, N);
    prefix_kernel<<<1, 32>>>(cnt, offs);
    order_kernel<<<(N + 255)/256, 256>>>(at, offs, cnt + 64, order, N);
    edge_prep_kernel<<<(E + 7)/8, 256>>>(ef, ei, act, evec, sews, sebs, sewv,
                                         nv, esvB, vfB, Rbuf, idx, E, Etot);

    // proj = ns @ wcpT  (N x 512, fp32 out)
    mma_gemm_kernel<0,false><<<dim3(4, ntile), 256, GEMM_SMEM>>>(
        nsB, wcpT, proj, N, 512, 128, 128, 128, 1.0f, nullptr, nullptr,
        nullptr, nullptr, nullptr, nullptr, nullptr, nullptr, nullptr, nullptr,
        nullptr, nullptr, nullptr, nullptr, 0, 0, N, E);
    // wenv = latB[act] @ envT / sqrt(128)
    mma_gemm_kernel<0,true><<<dim3(2, etile), 256, GEMM_SMEM>>>(
        latB, envT, wenv, E, 192, 128, 128, 128, isq128, nullptr, act,
        nullptr, nullptr, nullptr, nullptr, nullptr, nullptr, nullptr, nullptr,
        nullptr, nullptr, nullptr, nullptr, 0, 0, N, E);
    // main SO2 -> msgs(bf16) + gv(fp32)
    mma_gemm_kernel<1,false><<<dim3(2, etile), 256, GEMM_SMEM>>>(
        esvB, w0mT, (float*)msgsB, E, 256, 320, 320, 320, isq576, nullptr, nullptr,
        ctr, nbr, proj, nullptr, nullptr, nullptr, nullptr, gvb,
        nullptr, nullptr, nullptr, nullptr, 0, 0, N, E);
    // complex GEMM + fused rotation/gate -> msgv(bf16)
    mma_gemm_kernel<4,false><<<dim3(1, etile), 256, GEMM_SMEM4>>>(
        vfB, w1cT, (float*)msgvB, E, 128, 384, 384, 384, isq192, nullptr, nullptr,
        nullptr, nullptr, nullptr, Rbuf, gvb, nullptr, nullptr, nullptr,
        nullptr, nullptr, nullptr, nullptr, 0, 0, N, E);
    // lps + env-weight + scatter -> aggs
    mma_gemm_kernel<2,false><<<dim3(1, etile), 256, GEMM_SMEM>>>(
        msgsB, lpwsT, nullptr, E, 128, 128, 128, 128, isq128, lpbs, nullptr,
        ctr, nullptr, nullptr, nullptr, nullptr, wenv, aggs, nullptr,
        nullptr, nullptr, nullptr, nullptr, 0, 0, N, E);
    // lpv + env-weight + scatter -> aggv
    mma_gemm_kernel<3,false><<<dim3(1, (3*E + 127)/128), 256, GEMM_SMEM>>>(
        msgvB, lpwvT, nullptr, 3*E, 64, 64, 64, 64, 0.125f, nullptr, nullptr,
        ctr, nullptr, nullptr, nullptr, nullptr, wenv, aggv, nullptr,
        nullptr, nullptr, nullptr, nullptr, 0, 0, N, E);
    // aggs|aggv -> bf16
    c2b_kernel<<<(int)(((size_t)N*320 + 255)/256), 256>>>(aggs, agsB, (size_t)N*320);
    // typed: gs = bf16(silu(aggsB @ wssT[t] * n_ss))
    mma_gemm_kernel<5,false><<<dim3(1, 2, 64), 256, GEMM_SMEM>>>(
        agsB, wssT, (float*)gsB, N, 128, 128, 128, 128, n_ss, nullptr, nullptr,
        nullptr, nullptr, nullptr, nullptr, nullptr, nullptr, nullptr, nullptr,
        nullptr, nullptr, offs, order, 128*128, 0, N, E);
    // typed: tg = sigmoid(aggsB @ wsgT[t] * n_ss)
    mma_gemm_kernel<6,false><<<dim3(1, 2, 64), 256, GEMM_SMEM>>>(
        agsB, wsgT, tgb, N, 64, 128, 128, 128, n_ss, nullptr, nullptr,
        nullptr, nullptr, nullptr, nullptr, nullptr, nullptr, nullptr, nullptr,
        nullptr, nullptr, offs, order, 64*128, 0, N, E);
    // typed, 3 planes: gvm = bf16(tg * (aggvB @ wvvT[t] * n_vv))
    mma_gemm_kernel<7,false><<<dim3(3, 2, 64), 256, GEMM_SMEM>>>(
        agvB, wvvT, (float*)gvmB, N, 64, 64, 64, 64, n_vv, nullptr, nullptr,
        nullptr, nullptr, nullptr, nullptr, tgb, nullptr, nullptr, nullptr,
        nullptr, nullptr, offs, order, 64*64, (size_t)N*64, N, E);
    // final scalar: out[:,0:128]
    mma_gemm_kernel<8,false><<<dim3(1, ntile), 256, GEMM_SMEM>>>(
        gsB, ohlwT, (float*)d_out, N, 128, 128, 128, 128, isq128, ohlbs, nullptr,
        nullptr, nullptr, nullptr, nullptr, nullptr, nullptr, nullptr, nullptr,
        nf, resp, nullptr, nullptr, 0, 0, N, E);
    // final vector: out[:,128+3k+m]
    mma_gemm_kernel<9,false><<<dim3(3, ntile), 256, GEMM_SMEM>>>(
        gvmB, ohlvT, (float*)d_out, N, 64, 64, 64, 64, 0.125f, nullptr, nullptr,
        nullptr, nullptr, nullptr, nullptr, nullptr, nullptr, nullptr, nullptr,
        nf, resp, nullptr, nullptr, 0, (size_t)N*64, N, E);
}

// round 9
// speedup vs baseline: 3.3299x; 1.0408x over previous
#include <cuda_runtime.h>
#include <cuda_bf16.h>
#include <math.h>
#include <stdint.h>

static constexpr int NMAXN = 8000;
static constexpr int EMAX  = 96000;

// ---- fp32 scratch ----
static constexpr size_t NV_OFF   = 0;                                  // nv:   N x 192
static constexpr size_t R_OFF    = NV_OFF   + (size_t)NMAXN*192;       // R:    E x 9
static constexpr size_t PROJ_OFF = R_OFF    + (size_t)EMAX*9;          // proj: N x 512
static constexpr size_t GVF_OFF  = PROJ_OFF + (size_t)NMAXN*512;       // gv:   E x 128
static constexpr size_t WENV_OFF = GVF_OFF  + (size_t)EMAX*128;        // wenv: E x 192
static constexpr size_t AGGS_OFF = WENV_OFF + (size_t)EMAX*192;        // aggs: N x 128
static constexpr size_t AGGV_OFF = AGGS_OFF + (size_t)NMAXN*128;       // aggv: 3 x N x 64
static constexpr size_t TG_OFF   = AGGV_OFF + (size_t)3*NMAXN*64;      // tg:   N x 64
static constexpr size_t TOTAL_F  = TG_OFF   + (size_t)NMAXN*64;
__device__ __align__(256) float g_buf[TOTAL_F];

// ---- bf16 scratch ----  (weights all stored [K,N] row-major now)
static constexpr size_t NSB   = 0;                                     // ns:    N x 128
static constexpr size_t ESVB  = NSB   + (size_t)NMAXN*128;             // esvf0: E x 320
static constexpr size_t VF12B = ESVB  + (size_t)EMAX*320;              // vf12:  E x 384
static constexpr size_t MSGSB = VF12B + (size_t)EMAX*384;              // msgs:  E x 128
static constexpr size_t MSGVB = MSGSB + (size_t)EMAX*128;              // msgv:  3 x E x 64
static constexpr size_t LATB  = MSGVB + (size_t)3*EMAX*64;             // latB:  E x 128
static constexpr size_t GSB   = LATB  + (size_t)EMAX*128;              // gs:    N x 128
static constexpr size_t GVMB  = GSB   + (size_t)NMAXN*128;             // gvm:   3 x N x 64
static constexpr size_t AGSB  = GVMB  + (size_t)3*NMAXN*64;            // aggsB: N x 128
static constexpr size_t AGVB  = AGSB  + (size_t)NMAXN*128;             // aggvB: 3 x N x 64
static constexpr size_t WCPT  = AGVB  + (size_t)3*NMAXN*64;            // wcp:  128K x 512N
static constexpr size_t W0MT  = WCPT  + (size_t)128*512;               // w0m:  320K x 256N
static constexpr size_t W1CT  = W0MT  + (size_t)320*256;               // w1c:  384K x 128N
static constexpr size_t ENVT  = W1CT  + (size_t)384*128;               // env:  128K x 192N
static constexpr size_t LPWST = ENVT  + (size_t)128*192;               // lpws: 128 x 128
static constexpr size_t LPWVT = LPWST + (size_t)128*128;               // lpwv: 64 x 64
static constexpr size_t WSST  = LPWVT + (size_t)64*64;                 // wss:  128 x (64x128)
static constexpr size_t WSGT  = WSST  + (size_t)128*64*128;            // wsg:  128 x (64x64)
static constexpr size_t WVVT  = WSGT  + (size_t)128*64*64;             // wvv:  64 x (64x64)
static constexpr size_t OHLWT = WVVT  + (size_t)64*64*64;              // ohlw: 128 x 128
static constexpr size_t OHLVT = OHLWT + (size_t)128*128;               // ohlv: 64 x 64
static constexpr size_t TOTAL_B = OHLVT + (size_t)64*64;
__device__ __align__(256) __nv_bfloat16 g_bbuf[TOTAL_B];

__device__ int g_idx[2*EMAX];
__device__ int g_cnt[128];
__device__ int g_offs[65];
__device__ int g_order[NMAXN];

typedef __nv_bfloat16 bf16;
typedef __nv_bfloat162 bf162;
__device__ __forceinline__ bf162 f2b2(float a, float b) { return __floats2bfloat162_rn(a, b); }

// ---------------------------------------------------------------------------
__global__ void zero_kernel(float* __restrict__ p, size_t n) {
    size_t i = (size_t)blockIdx.x*blockDim.x + threadIdx.x;
    if (i < n) p[i] = 0.f;
}
__global__ void c2b_kernel(const float* __restrict__ in, bf16* __restrict__ out, size_t n) {
    size_t i = (size_t)blockIdx.x*blockDim.x + threadIdx.x;
    if (i < n) out[i] = __float2bfloat16(in[i]);
}
__global__ void count_kernel(const int* __restrict__ at, int* __restrict__ cnt, int N) {
    int n = blockIdx.x*blockDim.x + threadIdx.x;
    if (n < N) atomicAdd(&cnt[at[n]], 1);
}
__global__ void prefix_kernel(const int* __restrict__ cnt, int* __restrict__ offs) {
    if (threadIdx.x == 0) { int s = 0; for (int i = 0; i < 64; i++) { offs[i] = s; s += cnt[i]; } offs[64] = s; }
}
__global__ void order_kernel(const int* __restrict__ at, const int* __restrict__ offs,
                             int* __restrict__ cur, int* __restrict__ order, int N) {
    int n = blockIdx.x*blockDim.x + threadIdx.x;
    if (n < N) { int t = at[n]; order[offs[t] + atomicAdd(&cur[t], 1)] = n; }
}

// ---------------------------------------------------------------------------
// ONE fused weight-prep kernel — ALL writes coalesced (no transposes: B is K-major).
__global__ void prep_all_kernel(const float* __restrict__ w0,
                                const float* __restrict__ w1r, const float* __restrict__ w1i,
                                const float* __restrict__ envw, const float* __restrict__ lpws,
                                const float* __restrict__ lpwv, const float* __restrict__ ohwss,
                                const float* __restrict__ ohwsg, const float* __restrict__ ohwvv,
                                const float* __restrict__ ohlws, const float* __restrict__ ohlwv,
                                const float* __restrict__ latents, bf16* __restrict__ bb,
                                size_t latN) {
    size_t gi = (size_t)blockIdx.x*blockDim.x + threadIdx.x;
    if (gi < 65536) {                       // wcp [128K][512N]
        int i = (int)gi, k = i >> 9, c = i & 511;
        float v = (c < 256) ? w0[(size_t)k*256 + c] : w0[(size_t)(256 + k)*256 + c - 256];
        bb[WCPT + i] = __float2bfloat16(v);
    } else if (gi < 147456) {               // w0m [320K][256N] (row remap of w0)
        int i = (int)(gi - 65536), k = i >> 8, c = i & 255;
        int src = (k < 128) ? k + 128 : k + 256;
        bb[W0MT + i] = __float2bfloat16(w0[(size_t)src*256 + c]);
    } else if (gi < 196608) {               // w1c [384K][128N]
        int i = (int)(gi - 147456), r = i >> 7, c = i & 127;
        float v;
        if (r < 192) v = (c < 64) ? w1r[r*64 + c] : w1i[r*64 + c - 64];
        else { int r2 = r - 192; v = (c < 64) ? -w1i[r2*64 + c] : w1r[r2*64 + c - 64]; }
        bb[W1CT + i] = __float2bfloat16(v);
    } else if (gi < 221184) {               // env (natural [K,N])
        int i = (int)(gi - 196608); bb[ENVT + i] = __float2bfloat16(envw[i]);
    } else if (gi < 237568) {               // lpws
        int i = (int)(gi - 221184); bb[LPWST + i] = __float2bfloat16(lpws[i]);
    } else if (gi < 241664) {               // lpwv
        int i = (int)(gi - 237568); bb[LPWVT + i] = __float2bfloat16(lpwv[i]);
    } else if (gi < 1290240) {              // wss (natural [u][t][n])
        int i = (int)(gi - 241664); bb[WSST + i] = __float2bfloat16(ohwss[i]);
    } else if (gi < 1814528) {              // wsg
        int i = (int)(gi - 1290240); bb[WSGT + i] = __float2bfloat16(ohwsg[i]);
    } else if (gi < 2076672) {              // wvv
        int i = (int)(gi - 1814528); bb[WVVT + i] = __float2bfloat16(ohwvv[i]);
    } else if (gi < 2093056) {              // ohlw
        int i = (int)(gi - 2076672); bb[OHLWT + i] = __float2bfloat16(ohlws[i]);
    } else if (gi < 2097152) {              // ohlv
        int i = (int)(gi - 2093056); bb[OHLVT + i] = __float2bfloat16(ohlwv[i]);
    } else {                                // latB
        size_t i = gi - 2097152;
        if (i < latN) bb[LATB + i] = __float2bfloat16(latents[i]);
    }
}

// ---------------------------------------------------------------------------
__global__ void node_ln_kernel(const float* __restrict__ nf, const float* __restrict__ ws,
                               const float* __restrict__ bs, const float* __restrict__ wv,
                               bf16* __restrict__ ns, float* __restrict__ nv, int N) {
    int node = (blockIdx.x*blockDim.x + threadIdx.x) >> 5;
    int lane = threadIdx.x & 31;
    if (node >= N) return;
    const float* row = nf + (size_t)node*320;
    float s[4]; float sum = 0.f;
#pragma unroll
    for (int i = 0; i < 4; i++) { s[i] = row[lane + 32*i]; sum += s[i]; }
#pragma unroll
    for (int o = 16; o; o >>= 1) sum += __shfl_xor_sync(~0u, sum, o);
    float mu = sum*(1.f/128.f), var = 0.f;
#pragma unroll
    for (int i = 0; i < 4; i++) { s[i] -= mu; var += s[i]*s[i]; }
#pragma unroll
    for (int o = 16; o; o >>= 1) var += __shfl_xor_sync(~0u, var, o);
    float rs = rsqrtf(var*(1.f/128.f) + 1e-8f);
#pragma unroll
    for (int i = 0; i < 4; i++) {
        int c = lane + 32*i;
        ns[(size_t)node*128 + c] = __float2bfloat16(s[i]*rs*ws[c] + bs[c]);
    }
    float v[6]; float vs = 0.f;
#pragma unroll
    for (int i = 0; i < 6; i++) { v[i] = row[128 + lane + 32*i]; vs += v[i]*v[i]; }
#pragma unroll
    for (int o = 16; o; o >>= 1) vs += __shfl_xor_sync(~0u, vs, o);
    float rv = rsqrtf(vs*(1.f/192.f) + 1e-8f);
#pragma unroll
    for (int i = 0; i < 6; i++) { int c = lane + 32*i; nv[(size_t)node*192 + c] = v[i]*rv*wv[c/3]; }
}

__global__ void edge_prep_kernel(const float* __restrict__ ef, const int* __restrict__ ei,
                                 const int* __restrict__ act, const float* __restrict__ evec,
                                 const float* __restrict__ ws, const float* __restrict__ bs,
                                 const float* __restrict__ wv, const float* __restrict__ nv,
                                 bf16* __restrict__ esv0, bf16* __restrict__ vf12,
                                 float* __restrict__ Rout, int* __restrict__ idx, int E, int Etot) {
    __shared__ float evs[8][192];
    int wi = threadIdx.x >> 5, lane = threadIdx.x & 31;
    int e = blockIdx.x*8 + wi;
    if (e >= E) return;
    int ae = act[e];
    int ctr = ei[ae], nbr = ei[Etot + ae];
    if (lane == 0) { idx[e] = ctr; idx[E + e] = nbr; }
    const float* row = ef + (size_t)e*320;

    float s[4]; float sum = 0.f;
#pragma unroll
    for (int i = 0; i < 4; i++) { s[i] = row[lane + 32*i]; sum += s[i]; }
#pragma unroll
    for (int o = 16; o; o >>= 1) sum += __shfl_xor_sync(~0u, sum, o);
    float mu = sum*(1.f/128.f), var = 0.f;
#pragma unroll
    for (int i = 0; i < 4; i++) { s[i] -= mu; var += s[i]*s[i]; }
#pragma unroll
    for (int o = 16; o; o >>= 1) var += __shfl_xor_sync(~0u, var, o);
    float rs = rsqrtf(var*(1.f/128.f) + 1e-8f);
    bf16* esv = esv0 + (size_t)e*320;
#pragma unroll
    for (int i = 0; i < 4; i++) { int c = lane + 32*i; esv[c] = __float2bfloat16(s[i]*rs*ws[c] + bs[c]); }

    float v[6]; float vs = 0.f;
#pragma unroll
    for (int i = 0; i < 6; i++) { v[i] = row[128 + lane + 32*i]; vs += v[i]*v[i]; }
#pragma unroll
    for (int o = 16; o; o >>= 1) vs += __shfl_xor_sync(~0u, vs, o);
    float rv = rsqrtf(vs*(1.f/192.f) + 1e-8f);
#pragma unroll
    for (int i = 0; i < 6; i++) { int c = lane + 32*i; evs[wi][c] = v[i]*rv*wv[c/3]; }
    __syncwarp();

    float e0 = evec[(size_t)ae*3], e1 = evec[(size_t)ae*3+1], e2 = evec[(size_t)ae*3+2];
    float rn = rsqrtf(e0*e0 + e1*e1 + e2*e2 + 1e-8f);
    float ax = e0*rn, ay = e1*rn, az = e2*rn;
    float refx = (fabsf(ax) < 0.9f) ? 1.f : 0.f, refy = 1.f - refx;
    float bx = -az*refy, by = az*refx, bz = ax*refy - ay*refx;
    float rb = rsqrtf(bx*bx + by*by + bz*bz + 1e-8f);
    bx *= rb; by *= rb; bz *= rb;
    float cx = ay*bz - az*by, cy = az*bx - ax*bz, cz = ax*by - ay*bx;
    if (lane == 0) {
        float* Rp = Rout + (size_t)e*9;
        Rp[0]=ax; Rp[1]=ay; Rp[2]=az; Rp[3]=bx; Rp[4]=by; Rp[5]=bz; Rp[6]=cx; Rp[7]=cy; Rp[8]=cz;
    }
    bf16* vf = vf12 + (size_t)e*384;
#pragma unroll
    for (int i = 0; i < 6; i++) {
        int u = lane + 32*i;
        float vx, vy, vz;
        if (u < 64)       { const float* p = nv + (size_t)ctr*192 + u*3;        vx=p[0]; vy=p[1]; vz=p[2]; }
        else if (u < 128) { const float* p = &evs[wi][(u-64)*3];                vx=p[0]; vy=p[1]; vz=p[2]; }
        else              { const float* p = nv + (size_t)nbr*192 + (u-128)*3;  vx=p[0]; vy=p[1]; vz=p[2]; }
        esv[128 + u] = __float2bfloat16(ax*vx + ay*vy + az*vz);
        vf[u]        = __float2bfloat16(bx*vx + by*vy + bz*vz);
        vf[192 + u]  = __float2bfloat16(cx*vx + cy*vy + cz*vz);
    }
}

// ---------------------------------------------------------------------------
// bf16 GEMM (m16n8k16): A [M,K] + ldmatrix, B [K,N] + ldmatrix.trans, cp.async 3-stage.
static constexpr int ASTG = 6144;             // A stage: 128 rows x 48B
static constexpr int BSTG = 4352;             // B stage: 16 rows x 272B
static constexpr int STG  = ASTG + BSTG;      // 10496
static constexpr int GEMM_SMEM = 3*STG;       // 31488
static constexpr int GEMM_SMEM4 = 128*132*4;  // 67584

template<int MODE, bool GATHER>
__global__ __launch_bounds__(256, 2)
void mma_gemm_kernel(const bf16* __restrict__ A, const bf16* __restrict__ B,
                     float* __restrict__ C, int M, int Nc, int K, int lda, int ldb,
                     float scale, const float* __restrict__ bias, const int* __restrict__ rowidx,
                     const int* __restrict__ ctr, const int* __restrict__ nbr,
                     const float* __restrict__ proj, const float* __restrict__ Rrot,
                     const float* __restrict__ gvbuf, const float* __restrict__ wenv,
                     float* __restrict__ agg, float* __restrict__ aux,
                     const float* __restrict__ nf, const float* __restrict__ resp,
                     const int* __restrict__ offs, const int* __restrict__ order,
                     int tOffB, size_t aplane, int Nnodes, int E) {
    constexpr bool TYPED = (MODE == 5 || MODE == 6 || MODE == 7);
    extern __shared__ char smc[];
    const int tid = threadIdx.x, lane = tid & 31, wid = tid >> 5;
    const int g = lane >> 2, t = lane & 3;
    const int wm = (wid >> 2)*64, wn = (wid & 3)*32;

    int mplane = 0, bn;
    if (MODE == 7 || MODE == 9) { mplane = blockIdx.x; bn = 0; } else bn = blockIdx.x*128;
    const int bm = blockIdx.y*128;

    int Mloc = M, rowbase = 0, typ = 0;
    if (TYPED) {
        typ = blockIdx.z;
        rowbase = offs[typ];
        Mloc = offs[typ+1] - rowbase;
        if (Mloc == 0 || bm >= Mloc) return;
    }
    const bf16* Ause = A + (size_t)mplane*aplane;
    const bf16* Buse = B + (TYPED ? (size_t)typ*tOffB : 0);   // column offset per type

    // A cp.async: 256 chunks/stage, 1/thread
    int arow = tid >> 1, ahalf = tid & 1;
    int r = bm + arow, gr;
    if (TYPED) { if (r >= Mloc) r = Mloc - 1; gr = order[rowbase + r]; }
    else       { if (r >= M) r = M - 1;       gr = GATHER ? rowidx[r] : r; }
    const bf16* asrc = Ause + (size_t)gr*lda + ahalf*8;
    // B cp.async: 16 k-rows x 16 chunks = 256 chunks/stage, 1/thread
    int brow = tid >> 4, bc16 = tid & 15;
    int bcol = bn + bc16*8;
    int bby = (bcol < Nc) ? 16 : 0;
    if (bcol >= Nc) bcol = Nc - 8;
    const bf16* bsrc = Buse + (size_t)brow*ldb + bcol;

    uint32_t sbase = (uint32_t)__cvta_generic_to_shared(smc);
    uint32_t adst = sbase + arow*48 + ahalf*16;
    uint32_t bdst = sbase + ASTG + brow*272 + bc16*16;

    // ldmatrix lane addressing
    const int q = lane >> 3, rr8 = lane & 7;
    uint32_t aLd = sbase + ((wm + (q & 1)*8 + rr8)*24 + (q >> 1)*8)*2;
    uint32_t bLd = sbase + ASTG + ((q & 1)*8 + rr8)*272 + (wn + (q >> 1)*8)*2;

    const int kT = K >> 4;
    auto loadStage = [&](int slot, int k0) {
        uint32_t so = slot*STG;
        asm volatile("cp.async.cg.shared.global [%0], [%1], 16;" :: "r"(adst + so), "l"(asrc + k0) : "memory");
        asm volatile("cp.async.cg.shared.global [%0], [%1], 16, %2;" :: "r"(bdst + so), "l"(bsrc + (size_t)k0*ldb), "r"(bby) : "memory");
        asm volatile("cp.async.commit_group;");
    };

    float acc[4][4][4];
#pragma unroll
    for (int mi = 0; mi < 4; mi++)
#pragma unroll
        for (int ni = 0; ni < 4; ni++)
#pragma unroll
            for (int j = 0; j < 4; j++) acc[mi][ni][j] = 0.f;

    loadStage(0, 0); loadStage(1, 16);

    for (int kt = 0; kt < kT; kt++) {
        asm volatile("cp.async.wait_group 1;");
        __syncthreads();
        int pf = kt + 2;
        if (pf < kT) loadStage(pf % 3, pf*16);
        else asm volatile("cp.async.commit_group;");

        uint32_t so = (kt % 3)*STG;
        uint32_t af[4][4], bf[4][2];
#pragma unroll
        for (int mi = 0; mi < 4; mi++)
            asm volatile("ldmatrix.sync.aligned.m8n8.x4.shared.b16 {%0,%1,%2,%3}, [%4];"
                : "=r"(af[mi][0]), "=r"(af[mi][1]), "=r"(af[mi][2]), "=r"(af[mi][3])
                : "r"(aLd + so + mi*16*48));
#pragma unroll
        for (int np = 0; np < 2; np++)
            asm volatile("ldmatrix.sync.aligned.m8n8.x4.trans.shared.b16 {%0,%1,%2,%3}, [%4];"
                : "=r"(bf[2*np][0]), "=r"(bf[2*np][1]), "=r"(bf[2*np+1][0]), "=r"(bf[2*np+1][1])
                : "r"(bLd + so + np*32));
#pragma unroll
        for (int mi = 0; mi < 4; mi++)
#pragma unroll
            for (int ni = 0; ni < 4; ni++) {
                asm volatile(
                    "mma.sync.aligned.m16n8k16.row.col.f32.bf16.bf16.f32 "
                    "{%0,%1,%2,%3}, {%4,%5,%6,%7}, {%8,%9}, {%0,%1,%2,%3};"
                    : "+f"(acc[mi][ni][0]), "+f"(acc[mi][ni][1]),
                      "+f"(acc[mi][ni][2]), "+f"(acc[mi][ni][3])
                    : "r"(af[mi][0]), "r"(af[mi][1]), "r"(af[mi][2]), "r"(af[mi][3]),
                      "r"(bf[ni][0]), "r"(bf[ni][1]));
            }
    }

    // ---------------- epilogue ----------------
    const float INV = 0.28867513459481287f;
    if (MODE == 4) {
        __syncthreads();
        float* Vs = (float*)smc;
#pragma unroll
        for (int mi = 0; mi < 4; mi++)
#pragma unroll
            for (int h = 0; h < 2; h++) {
                int rw = wm + mi*16 + g + 8*h;
#pragma unroll
                for (int ni = 0; ni < 4; ni++) {
                    int c = wn + ni*8 + 2*t;
                    *(float2*)&Vs[rw*132 + c] = make_float2(acc[mi][ni][2*h]*scale, acc[mi][ni][2*h+1]*scale);
                }
            }
        __syncthreads();
        bf16* Cb = (bf16*)C;
        for (int rw = wid; rw < 128; rw += 8) {
            int e = bm + rw;
            const float* Rp = Rrot + (size_t)e*9;
            float R0=Rp[0],R1=Rp[1],R2=Rp[2],R3=Rp[3],R4=Rp[4],R5=Rp[5],R6=Rp[6],R7=Rp[7],R8=Rp[8];
            const float* gvp = gvbuf + (size_t)e*128;
#pragma unroll
            for (int i = 0; i < 2; i++) {
                int u = lane + 32*i;
                float sg = gvp[u], i0 = gvp[64 + u];
                float i1 = Vs[rw*132 + u], i2 = Vs[rw*132 + 64 + u];
                Cb[(size_t)0*E*64 + (size_t)e*64 + u] = __float2bfloat16(sg*(R0*i0 + R3*i1 + R6*i2));
                Cb[(size_t)1*E*64 + (size_t)e*64 + u] = __float2bfloat16(sg*(R1*i0 + R4*i1 + R7*i2));
                Cb[(size_t)2*E*64 + (size_t)e*64 + u] = __float2bfloat16(sg*(R2*i0 + R5*i1 + R8*i2));
            }
        }
        return;
    }

    float alpha = 0.f, beta = 0.f;
    if (MODE == 8 || MODE == 9) { alpha = 1.f/(1.f + expf(-resp[0])); beta = 1.f - alpha; }

#pragma unroll
    for (int mi = 0; mi < 4; mi++) {
        int r0 = bm + wm + mi*16 + g;
#pragma unroll
        for (int h = 0; h < 2; h++) {
            int row = r0 + 8*h;
            if (row >= (TYPED ? Mloc : M)) continue;
            if (MODE == 0) {
#pragma unroll
                for (int ni = 0; ni < 4; ni++) {
                    int c = bn + wn + ni*8 + 2*t;
                    if (c >= Nc) continue;
                    float a0 = acc[mi][ni][2*h]*scale + (bias ? bias[c] : 0.f);
                    float a1 = acc[mi][ni][2*h+1]*scale + (bias ? bias[c+1] : 0.f);
                    *(float2*)&C[(size_t)row*Nc + c] = make_float2(a0, a1);
                }
            } else if (MODE == 1) {
                const float* pc = proj + (size_t)ctr[row]*512;
                const float* pn = proj + (size_t)nbr[row]*512 + 256;
                bf16* Cb = (bf16*)C;
#pragma unroll
                for (int ni = 0; ni < 4; ni++) {
                    int c = bn + wn + ni*8 + 2*t;
                    float v0 = (acc[mi][ni][2*h]   + pc[c]   + pn[c]  )*scale;
                    float v1 = (acc[mi][ni][2*h+1] + pc[c+1] + pn[c+1])*scale;
                    if (c < 128) {
                        *(bf162*)&Cb[(size_t)row*128 + c] = f2b2(v0/(1.f+expf(-v0)), v1/(1.f+expf(-v1)));
                    } else if (c < 192) {
                        *(float2*)&aux[(size_t)row*128 + c-128] =
                            make_float2(1.f/(1.f+expf(-v0)), 1.f/(1.f+expf(-v1)));
                    } else {
                        *(float2*)&aux[(size_t)row*128 + c-128] = make_float2(v0, v1);
                    }
                }
            } else if (MODE == 2) {
                float* ap = agg + (size_t)ctr[row]*128;
                const float* we = wenv + (size_t)row*192;
#pragma unroll
                for (int ni = 0; ni < 4; ni++) {
                    int c = bn + wn + ni*8 + 2*t;
                    if (c >= Nc) continue;
                    atomicAdd(&ap[c],   (acc[mi][ni][2*h]  *scale + bias[c])  *we[c]  *INV);
                    atomicAdd(&ap[c+1], (acc[mi][ni][2*h+1]*scale + bias[c+1])*we[c+1]*INV);
                }
            } else if (MODE == 3) {
                int m = row / E, e = row - m*E;
                float* ap = agg + (size_t)m*Nnodes*64 + (size_t)ctr[e]*64;
                const float* we = wenv + (size_t)e*192 + 128;
#pragma unroll
                for (int ni = 0; ni < 4; ni++) {
                    int c = bn + wn + ni*8 + 2*t;
                    if (c >= Nc) continue;
                    atomicAdd(&ap[c],   acc[mi][ni][2*h]  *scale*we[c]  *INV);
                    atomicAdd(&ap[c+1], acc[mi][ni][2*h+1]*scale*we[c+1]*INV);
                }
            } else if (MODE == 5) {
                int node = order[rowbase + row];
                bf16* Cb = (bf16*)C;
#pragma unroll
                for (int ni = 0; ni < 4; ni++) {
                    int c = wn + ni*8 + 2*t;
                    float v0 = acc[mi][ni][2*h]*scale, v1 = acc[mi][ni][2*h+1]*scale;
                    *(bf162*)&Cb[(size_t)node*128 + c] = f2b2(v0/(1.f+expf(-v0)), v1/(1.f+expf(-v1)));
                }
            } else if (MODE == 6) {
                int node = order[rowbase + row];
#pragma unroll
                for (int ni = 0; ni < 4; ni++) {
                    int c = wn + ni*8 + 2*t;
                    if (c >= Nc) continue;
                    *(float2*)&C[(size_t)node*64 + c] =
                        make_float2(1.f/(1.f+expf(-acc[mi][ni][2*h]*scale)),
                                    1.f/(1.f+expf(-acc[mi][ni][2*h+1]*scale)));
                }
            } else if (MODE == 7) {
                int node = order[rowbase + row];
                const float* tgp = gvbuf + (size_t)node*64;
                bf16* Cb = (bf16*)C;
#pragma unroll
                for (int ni = 0; ni < 4; ni++) {
                    int c = wn + ni*8 + 2*t;
                    if (c >= Nc) continue;
                    *(bf162*)&Cb[(size_t)mplane*aplane + (size_t)node*64 + c] =
                        f2b2(acc[mi][ni][2*h]*scale*tgp[c], acc[mi][ni][2*h+1]*scale*tgp[c+1]);
                }
            } else if (MODE == 8) {
#pragma unroll
                for (int ni = 0; ni < 4; ni++) {
                    int c = wn + ni*8 + 2*t;
                    float a0 = acc[mi][ni][2*h]*scale + bias[c];
                    float a1 = acc[mi][ni][2*h+1]*scale + bias[c+1];
                    *(float2*)&C[(size_t)row*320 + c] =
                        make_float2(alpha*nf[(size_t)row*320 + c] + beta*a0,
                                    alpha*nf[(size_t)row*320 + c + 1] + beta*a1);
                }
            } else { // MODE 9
#pragma unroll
                for (int ni = 0; ni < 4; ni++) {
                    int c = wn + ni*8 + 2*t;
                    if (c >= Nc) continue;
                    size_t o0 = (size_t)row*320 + 128 + 3*c + mplane;
                    size_t o1 = (size_t)row*320 + 128 + 3*(c+1) + mplane;
                    C[o0] = alpha*nf[o0] + beta*acc[mi][ni][2*h]*scale;
                    C[o1] = alpha*nf[o1] + beta*acc[mi][ni][2*h+1]*scale;
                }
            }
        }
    }
}

// ---------------------------------------------------------------------------
extern "C" void kernel_launch(void* const* d_in, const int* in_sizes, int n_in,
                              void* d_out, int out_size) {
    const float* latents = (const float*)d_in[0];
    const float* nf    = (const float*)d_in[1];
    const float* ef    = (const float*)d_in[2];
    const int*   at    = (const int*)  d_in[3];
    const int*   ei    = (const int*)  d_in[5];
    const float* evec  = (const float*)d_in[6];
    const int*   act   = (const int*)  d_in[7];
    const float* snws  = (const float*)d_in[8];
    const float* snbs  = (const float*)d_in[9];
    const float* snwv  = (const float*)d_in[10];
    const float* sews  = (const float*)d_in[11];
    const float* sebs  = (const float*)d_in[12];
    const float* sewv  = (const float*)d_in[13];
    const float* so2w0 = (const float*)d_in[14];
    const float* w1r   = (const float*)d_in[15];
    const float* w1i   = (const float*)d_in[16];
    const float* envw  = (const float*)d_in[17];
    const float* lpws  = (const float*)d_in[18];
    const float* lpbs  = (const float*)d_in[19];
    const float* lpwv  = (const float*)d_in[20];
    const float* ohwss = (const float*)d_in[21];
    const float* ohwsg = (const float*)d_in[22];
    const float* ohwvv = (const float*)d_in[23];
    const float* ohlws = (const float*)d_in[24];
    const float* ohlbs = (const float*)d_in[25];
    const float* ohlwv = (const float*)d_in[26];
    const float* resp  = (const float*)d_in[27];

    int N = in_sizes[1]/320, E = in_sizes[7], Etot = in_sizes[5]/2;
    size_t latN = (size_t)in_sizes[0];

    float* fb = nullptr;  cudaGetSymbolAddress((void**)&fb, g_buf);
    bf16* bb = nullptr;   cudaGetSymbolAddress((void**)&bb, g_bbuf);
    int* idx = nullptr;   cudaGetSymbolAddress((void**)&idx, g_idx);
    int* cnt = nullptr;   cudaGetSymbolAddress((void**)&cnt, g_cnt);
    int* offs = nullptr;  cudaGetSymbolAddress((void**)&offs, g_offs);
    int* order = nullptr; cudaGetSymbolAddress((void**)&order, g_order);

    float *nv = fb+NV_OFF, *Rbuf = fb+R_OFF, *proj = fb+PROJ_OFF, *gvb = fb+GVF_OFF,
          *wenv = fb+WENV_OFF, *aggs = fb+AGGS_OFF, *aggv = fb+AGGV_OFF, *tgb = fb+TG_OFF;
    bf16 *nsB = bb+NSB, *esvB = bb+ESVB, *vfB = bb+VF12B, *msgsB = bb+MSGSB, *msgvB = bb+MSGVB,
         *latB = bb+LATB, *gsB = bb+GSB, *gvmB = bb+GVMB, *agsB = bb+AGSB, *agvB = bb+AGVB,
         *wcpK = bb+WCPT, *w0mK = bb+W0MT, *w1cK = bb+W1CT, *envK = bb+ENVT, *lpwsK = bb+LPWST,
         *lpwvK = bb+LPWVT, *wssK = bb+WSST, *wsgK = bb+WSGT, *wvvK = bb+WVVT,
         *ohlwK = bb+OHLWT, *ohlvK = bb+OHLVT;
    int *ctr = idx, *nbr = idx + E;

    const float isq576 = 0.041666666666666664f, isq192 = 0.07216878364870323f,
                isq128 = 0.08838834764831845f, n_ss = 0.011048543456039806f, n_vv = 0.015625f;

    cudaFuncSetAttribute(mma_gemm_kernel<0,false>, cudaFuncAttributeMaxDynamicSharedMemorySize, GEMM_SMEM);
    cudaFuncSetAttribute(mma_gemm_kernel<0,true>,  cudaFuncAttributeMaxDynamicSharedMemorySize, GEMM_SMEM);
    cudaFuncSetAttribute(mma_gemm_kernel<1,false>, cudaFuncAttributeMaxDynamicSharedMemorySize, GEMM_SMEM);
    cudaFuncSetAttribute(mma_gemm_kernel<2,false>, cudaFuncAttributeMaxDynamicSharedMemorySize, GEMM_SMEM);
    cudaFuncSetAttribute(mma_gemm_kernel<3,false>, cudaFuncAttributeMaxDynamicSharedMemorySize, GEMM_SMEM);
    cudaFuncSetAttribute(mma_gemm_kernel<4,false>, cudaFuncAttributeMaxDynamicSharedMemorySize, GEMM_SMEM4);
    cudaFuncSetAttribute(mma_gemm_kernel<5,false>, cudaFuncAttributeMaxDynamicSharedMemorySize, GEMM_SMEM);
    cudaFuncSetAttribute(mma_gemm_kernel<6,false>, cudaFuncAttributeMaxDynamicSharedMemorySize, GEMM_SMEM);
    cudaFuncSetAttribute(mma_gemm_kernel<7,false>, cudaFuncAttributeMaxDynamicSharedMemorySize, GEMM_SMEM);
    cudaFuncSetAttribute(mma_gemm_kernel<8,false>, cudaFuncAttributeMaxDynamicSharedMemorySize, GEMM_SMEM);
    cudaFuncSetAttribute(mma_gemm_kernel<9,false>, cudaFuncAttributeMaxDynamicSharedMemorySize, GEMM_SMEM);

    int etile = (E + 127)/128, ntile = (N + 127)/128;

    zero_kernel<<<(int)(((size_t)N*320 + 255)/256), 256>>>(aggs, (size_t)N*320);
    zero_kernel<<<1, 128>>>((float*)cnt, 128);
    node_ln_kernel<<<(N + 7)/8, 256>>>(nf, snws, snbs, snwv, nsB, nv, N);
    {
        size_t tot = 2097152 + latN;
        prep_all_kernel<<<(int)((tot + 255)/256), 256>>>(
            so2w0, w1r, w1i, envw, lpws, lpwv, ohwss, ohwsg, ohwvv, ohlws, ohlwv,
            latents, bb, latN);
    }
    count_kernel<<<(N + 255)/256, 256>>>(at, cnt, N);
    prefix_kernel<<<1, 32>>>(cnt, offs);
    order_kernel<<<(N + 255)/256, 256>>>(at, offs, cnt + 64, order, N);
    edge_prep_kernel<<<(E + 7)/8, 256>>>(ef, ei, act, evec, sews, sebs, sewv,
                                         nv, esvB, vfB, Rbuf, idx, E, Etot);

    // proj = ns @ wcp  (N x 512)
    mma_gemm_kernel<0,false><<<dim3(4, ntile), 256, GEMM_SMEM>>>(
        nsB, wcpK, proj, N, 512, 128, 128, 512, 1.0f, nullptr, nullptr,
        nullptr, nullptr, nullptr, nullptr, nullptr, nullptr, nullptr, nullptr,
        nullptr, nullptr, nullptr, nullptr, 0, 0, N, E);
    // wenv = latB[act] @ env / sqrt(128)
    mma_gemm_kernel<0,true><<<dim3(2, etile), 256, GEMM_SMEM>>>(
        latB, envK, wenv, E, 192, 128, 128, 192, isq128, nullptr, act,
        nullptr, nullptr, nullptr, nullptr, nullptr, nullptr, nullptr, nullptr,
        nullptr, nullptr, nullptr, nullptr, 0, 0, N, E);
    // main SO2 -> msgs(bf16) + gv(fp32)
    mma_gemm_kernel<1,false><<<dim3(2, etile), 256, GEMM_SMEM>>>(
        esvB, w0mK, (float*)msgsB, E, 256, 320, 320, 256, isq576, nullptr, nullptr,
        ctr, nbr, proj, nullptr, nullptr, nullptr, nullptr, gvb,
        nullptr, nullptr, nullptr, nullptr, 0, 0, N, E);
    // complex GEMM + fused rotation/gate -> msgv(bf16)
    mma_gemm_kernel<4,false><<<dim3(1, etile), 256, GEMM_SMEM4>>>(
        vfB, w1cK, (float*)msgvB, E, 128, 384, 384, 128, isq192, nullptr, nullptr,
        nullptr, nullptr, nullptr, Rbuf, gvb, nullptr, nullptr, nullptr,
        nullptr, nullptr, nullptr, nullptr, 0, 0, N, E);
    // lps + env-weight + scatter -> aggs
    mma_gemm_kernel<2,false><<<dim3(1, etile), 256, GEMM_SMEM>>>(
        msgsB, lpwsK, nullptr, E, 128, 128, 128, 128, isq128, lpbs, nullptr,
        ctr, nullptr, nullptr, nullptr, nullptr, wenv, aggs, nullptr,
        nullptr, nullptr, nullptr, nullptr, 0, 0, N, E);
    // lpv + env-weight + scatter -> aggv
    mma_gemm_kernel<3,false><<<dim3(1, (3*E + 127)/128), 256, GEMM_SMEM>>>(
        msgvB, lpwvK, nullptr, 3*E, 64, 64, 64, 64, 0.125f, nullptr, nullptr,
        ctr, nullptr, nullptr, nullptr, nullptr, wenv, aggv, nullptr,
        nullptr, nullptr, nullptr, nullptr, 0, 0, N, E);
    // aggs|aggv -> bf16
    c2b_kernel<<<(int)(((size_t)N*320 + 255)/256), 256>>>(aggs, agsB, (size_t)N*320);
    // typed: gs = bf16(silu(aggsB @ wss[:,t,:] * n_ss))
    mma_gemm_kernel<5,false><<<dim3(1, 2, 64), 256, GEMM_SMEM>>>(
        agsB, wssK, (float*)gsB, N, 128, 128, 128, 64*128, n_ss, nullptr, nullptr,
        nullptr, nullptr, nullptr, nullptr, nullptr, nullptr, nullptr, nullptr,
        nullptr, nullptr, offs, order, 128, 0, N, E);
    // typed: tg = sigmoid(aggsB @ wsg[:,t,:] * n_ss)
    mma_gemm_kernel<6,false><<<dim3(1, 2, 64), 256, GEMM_SMEM>>>(
        agsB, wsgK, tgb, N, 64, 128, 128, 64*64, n_ss, nullptr, nullptr,
        nullptr, nullptr, nullptr, nullptr, nullptr, nullptr, nullptr, nullptr,
        nullptr, nullptr, offs, order, 64, 0, N, E);
    // typed, 3 planes: gvm = bf16(tg * (aggvB @ wvv[:,t,:] * n_vv))
    mma_gemm_kernel<7,false><<<dim3(3, 2, 64), 256, GEMM_SMEM>>>(
        agvB, wvvK, (float*)gvmB, N, 64, 64, 64, 64*64, n_vv, nullptr, nullptr,
        nullptr, nullptr, nullptr, nullptr, tgb, nullptr, nullptr, nullptr,
        nullptr, nullptr, offs, order, 64, (size_t)N*64, N, E);
    // final scalar: out[:,0:128]
    mma_gemm_kernel<8,false><<<dim3(1, ntile), 256, GEMM_SMEM>>>(
        gsB, ohlwK, (float*)d_out, N, 128, 128, 128, 128, isq128, ohlbs, nullptr,
        nullptr, nullptr, nullptr, nullptr, nullptr, nullptr, nullptr, nullptr,
        nf, resp, nullptr, nullptr, 0, 0, N, E);
    // final vector: out[:,128+3k+m]
    mma_gemm_kernel<9,false><<<dim3(3, ntile), 256, GEMM_SMEM>>>(
        gvmB, ohlvK, (float*)d_out, N, 64, 64, 64, 64, 0.125f, nullptr, nullptr,
        nullptr, nullptr, nullptr, nullptr, nullptr, nullptr, nullptr, nullptr,
        nf, resp, nullptr, nullptr, 0, (size_t)N*64, N, E);
}

// round 10
// speedup vs baseline: 3.8807x; 1.1654x over previous
#include <cuda_runtime.h>
#include <cuda_bf16.h>
#include <math.h>
#include <stdint.h>

static constexpr int NMAXN = 8000;
static constexpr int EMAX  = 96000;

// ---- fp32 scratch ----
static constexpr size_t NV_OFF   = 0;                                  // nv:   N x 192
static constexpr size_t R_OFF    = NV_OFF   + (size_t)NMAXN*192;       // R:    E x 9
static constexpr size_t AGGS_OFF = R_OFF    + (size_t)EMAX*9;          // aggs: N x 128
static constexpr size_t AGGV_OFF = AGGS_OFF + (size_t)NMAXN*128;       // aggv: 3 x N x 64
static constexpr size_t TG_OFF   = AGGV_OFF + (size_t)3*NMAXN*64;      // tg:   N x 64
static constexpr size_t TOTAL_F  = TG_OFF   + (size_t)NMAXN*64;
__device__ __align__(256) float g_buf[TOTAL_F];

// ---- bf16 scratch ----
static constexpr size_t NSB   = 0;
static constexpr size_t ESVB  = NSB   + (size_t)NMAXN*128;
static constexpr size_t VF12B = ESVB  + (size_t)EMAX*320;
static constexpr size_t MSGSB = VF12B + (size_t)EMAX*384;
static constexpr size_t MSGVB = MSGSB + (size_t)EMAX*128;
static constexpr size_t LATB  = MSGVB + (size_t)3*EMAX*64;
static constexpr size_t GSB   = LATB  + (size_t)EMAX*128;
static constexpr size_t GVMB  = GSB   + (size_t)NMAXN*128;
static constexpr size_t AGSB  = GVMB  + (size_t)3*NMAXN*64;
static constexpr size_t AGVB  = AGSB  + (size_t)NMAXN*128;
static constexpr size_t PROJB = AGVB  + (size_t)3*NMAXN*64;            // proj: N x 512
static constexpr size_t GVB   = PROJB + (size_t)NMAXN*512;             // gv:   E x 128
static constexpr size_t WENVB = GVB   + (size_t)EMAX*128;              // wenv: E x 192
static constexpr size_t WCPT  = WENVB + (size_t)EMAX*192;              // 128K x 512N
static constexpr size_t W0MT  = WCPT  + (size_t)128*512;               // 320K x 256N
static constexpr size_t W1CT  = W0MT  + (size_t)320*256;               // 384K x 128N
static constexpr size_t ENVT  = W1CT  + (size_t)384*128;               // 128K x 192N
static constexpr size_t LPWST = ENVT  + (size_t)128*192;               // 128 x 128
static constexpr size_t LPWVT = LPWST + (size_t)128*128;               // 64 x 64
static constexpr size_t WSC   = LPWVT + (size_t)64*64;                 // 128u x 64t x 192
static constexpr size_t WVVT  = WSC   + (size_t)128*64*192;            // 64u x 64t x 64
static constexpr size_t OHLWT = WVVT  + (size_t)64*64*64;              // 128 x 128
static constexpr size_t OHLVT = OHLWT + (size_t)128*128;               // 64 x 64
static constexpr size_t TOTAL_B = OHLVT + (size_t)64*64;
__device__ __align__(256) __nv_bfloat16 g_bbuf[TOTAL_B];

__device__ int g_idx[2*EMAX];
__device__ int g_cnt[128];
__device__ int g_offs[65];
__device__ int g_order[NMAXN];

typedef __nv_bfloat16 bf16;
typedef __nv_bfloat162 bf162;
__device__ __forceinline__ bf162 f2b2(float a, float b) { return __floats2bfloat162_rn(a, b); }

// ---------------------------------------------------------------------------
__global__ void zero_kernel(float* __restrict__ p, size_t n) {
    size_t i = (size_t)blockIdx.x*blockDim.x + threadIdx.x;
    if (i < n) p[i] = 0.f;
}
__global__ void c2b_kernel(const float* __restrict__ in, bf16* __restrict__ out, size_t n) {
    size_t i = (size_t)blockIdx.x*blockDim.x + threadIdx.x;
    if (i < n) out[i] = __float2bfloat16(in[i]);
}
__global__ void count_kernel(const int* __restrict__ at, int* __restrict__ cnt, int N) {
    int n = blockIdx.x*blockDim.x + threadIdx.x;
    if (n < N) atomicAdd(&cnt[at[n]], 1);
}
__global__ void prefix_kernel(const int* __restrict__ cnt, int* __restrict__ offs) {
    if (threadIdx.x == 0) { int s = 0; for (int i = 0; i < 64; i++) { offs[i] = s; s += cnt[i]; } offs[64] = s; }
}
__global__ void order_kernel(const int* __restrict__ at, const int* __restrict__ offs,
                             int* __restrict__ cur, int* __restrict__ order, int N) {
    int n = blockIdx.x*blockDim.x + threadIdx.x;
    if (n < N) { int t = at[n]; order[offs[t] + atomicAdd(&cur[t], 1)] = n; }
}

// ---------------------------------------------------------------------------
// Fused weight-prep, 8 elements per thread, 16B stores.
__device__ __forceinline__ void copy8(const float* __restrict__ in, bf16* __restrict__ out, float sgn) {
    float4 a = *(const float4*)in, b = *(const float4*)(in + 4);
    bf162 h[4] = { f2b2(sgn*a.x, sgn*a.y), f2b2(sgn*a.z, sgn*a.w),
                   f2b2(sgn*b.x, sgn*b.y), f2b2(sgn*b.z, sgn*b.w) };
    *(uint4*)out = *(uint4*)h;
}
__global__ void prep_all_kernel(const float* __restrict__ w0,
                                const float* __restrict__ w1r, const float* __restrict__ w1i,
                                const float* __restrict__ envw, const float* __restrict__ lpws,
                                const float* __restrict__ lpwv, const float* __restrict__ ohwss,
                                const float* __restrict__ ohwsg, const float* __restrict__ ohwvv,
                                const float* __restrict__ ohlws, const float* __restrict__ ohlwv,
                                const float* __restrict__ latents, bf16* __restrict__ bb,
                                size_t latN) {
    size_t g8 = ((size_t)blockIdx.x*blockDim.x + threadIdx.x)*8;
    if (g8 >= 2097152 + latN) return;
    if (g8 < 65536) {                           // wcp [128k][512c]
        int i = (int)g8, k = i >> 9, c = i & 511;
        const float* s = (c < 256) ? w0 + (size_t)k*256 + c : w0 + (size_t)(256 + k)*256 + (c - 256);
        copy8(s, bb + WCPT + i, 1.f);
    } else if (g8 < 147456) {                   // w0m [320k][256c]
        int i = (int)(g8 - 65536), k = i >> 8, c = i & 255;
        int src = (k < 128) ? k + 128 : k + 256;
        copy8(w0 + (size_t)src*256 + c, bb + W0MT + i, 1.f);
    } else if (g8 < 196608) {                   // w1c [384r][128c]
        int i = (int)(g8 - 147456), r = i >> 7, c = i & 127;
        const float* s; float sgn = 1.f;
        if (r < 192) s = (c < 64) ? w1r + r*64 + c : w1i + r*64 + (c - 64);
        else { int r2 = r - 192; if (c < 64) { s = w1i + r2*64 + c; sgn = -1.f; } else s = w1r + r2*64 + (c - 64); }
        copy8(s, bb + W1CT + i, sgn);
    } else if (g8 < 221184) { int i = (int)(g8 - 196608); copy8(envw + i,  bb + ENVT  + i, 1.f);
    } else if (g8 < 237568) { int i = (int)(g8 - 221184); copy8(lpws + i,  bb + LPWST + i, 1.f);
    } else if (g8 < 241664) { int i = (int)(g8 - 237568); copy8(lpwv + i,  bb + LPWVT + i, 1.f);
    } else if (g8 < 1290240) {                  // wsc[:, :, 0:128] <- ohwss
        int i = (int)(g8 - 241664), ut = i >> 7, n = i & 127;
        copy8(ohwss + i, bb + WSC + (size_t)ut*192 + n, 1.f);
    } else if (g8 < 1814528) {                  // wsc[:, :, 128:192] <- ohwsg
        int i = (int)(g8 - 1290240), ut = i >> 6, gg = i & 63;
        copy8(ohwsg + i, bb + WSC + (size_t)ut*192 + 128 + gg, 1.f);
    } else if (g8 < 2076672) { int i = (int)(g8 - 1814528); copy8(ohwvv + i, bb + WVVT + i, 1.f);
    } else if (g8 < 2093056) { int i = (int)(g8 - 2076672); copy8(ohlws + i, bb + OHLWT + i, 1.f);
    } else if (g8 < 2097152) { int i = (int)(g8 - 2093056); copy8(ohlwv + i, bb + OHLVT + i, 1.f);
    } else {
        size_t i = g8 - 2097152;
        if (i + 8 <= latN) copy8(latents + i, bb + LATB + i, 1.f);
        else for (size_t j = i; j < latN; j++) bb[LATB + j] = __float2bfloat16(latents[j]);
    }
}

// ---------------------------------------------------------------------------
__global__ void node_ln_kernel(const float* __restrict__ nf, const float* __restrict__ ws,
                               const float* __restrict__ bs, const float* __restrict__ wv,
                               bf16* __restrict__ ns, float* __restrict__ nv, int N) {
    int node = (blockIdx.x*blockDim.x + threadIdx.x) >> 5;
    int lane = threadIdx.x & 31;
    if (node >= N) return;
    const float* row = nf + (size_t)node*320;
    float s[4]; float sum = 0.f;
#pragma unroll
    for (int i = 0; i < 4; i++) { s[i] = row[lane + 32*i]; sum += s[i]; }
#pragma unroll
    for (int o = 16; o; o >>= 1) sum += __shfl_xor_sync(~0u, sum, o);
    float mu = sum*(1.f/128.f), var = 0.f;
#pragma unroll
    for (int i = 0; i < 4; i++) { s[i] -= mu; var += s[i]*s[i]; }
#pragma unroll
    for (int o = 16; o; o >>= 1) var += __shfl_xor_sync(~0u, var, o);
    float rs = rsqrtf(var*(1.f/128.f) + 1e-8f);
#pragma unroll
    for (int i = 0; i < 4; i++) {
        int c = lane + 32*i;
        ns[(size_t)node*128 + c] = __float2bfloat16(s[i]*rs*ws[c] + bs[c]);
    }
    float v[6]; float vs = 0.f;
#pragma unroll
    for (int i = 0; i < 6; i++) { v[i] = row[128 + lane + 32*i]; vs += v[i]*v[i]; }
#pragma unroll
    for (int o = 16; o; o >>= 1) vs += __shfl_xor_sync(~0u, vs, o);
    float rv = rsqrtf(vs*(1.f/192.f) + 1e-8f);
#pragma unroll
    for (int i = 0; i < 6; i++) { int c = lane + 32*i; nv[(size_t)node*192 + c] = v[i]*rv*wv[c/3]; }
}

__global__ void edge_prep_kernel(const float* __restrict__ ef, const int* __restrict__ ei,
                                 const int* __restrict__ act, const float* __restrict__ evec,
                                 const float* __restrict__ ws, const float* __restrict__ bs,
                                 const float* __restrict__ wv, const float* __restrict__ nv,
                                 bf16* __restrict__ esv0, bf16* __restrict__ vf12,
                                 float* __restrict__ Rout, int* __restrict__ idx, int E, int Etot) {
    __shared__ float evs[8][192];
    int wi = threadIdx.x >> 5, lane = threadIdx.x & 31;
    int e = blockIdx.x*8 + wi;
    if (e >= E) return;
    int ae = act[e];
    int ctr = ei[ae], nbr = ei[Etot + ae];
    if (lane == 0) { idx[e] = ctr; idx[E + e] = nbr; }
    const float* row = ef + (size_t)e*320;

    float s[4]; float sum = 0.f;
#pragma unroll
    for (int i = 0; i < 4; i++) { s[i] = row[lane + 32*i]; sum += s[i]; }
#pragma unroll
    for (int o = 16; o; o >>= 1) sum += __shfl_xor_sync(~0u, sum, o);
    float mu = sum*(1.f/128.f), var = 0.f;
#pragma unroll
    for (int i = 0; i < 4; i++) { s[i] -= mu; var += s[i]*s[i]; }
#pragma unroll
    for (int o = 16; o; o >>= 1) var += __shfl_xor_sync(~0u, var, o);
    float rs = rsqrtf(var*(1.f/128.f) + 1e-8f);
    bf16* esv = esv0 + (size_t)e*320;
#pragma unroll
    for (int i = 0; i < 4; i++) { int c = lane + 32*i; esv[c] = __float2bfloat16(s[i]*rs*ws[c] + bs[c]); }

    float v[6]; float vs = 0.f;
#pragma unroll
    for (int i = 0; i < 6; i++) { v[i] = row[128 + lane + 32*i]; vs += v[i]*v[i]; }
#pragma unroll
    for (int o = 16; o; o >>= 1) vs += __shfl_xor_sync(~0u, vs, o);
    float rv = rsqrtf(vs*(1.f/192.f) + 1e-8f);
#pragma unroll
    for (int i = 0; i < 6; i++) { int c = lane + 32*i; evs[wi][c] = v[i]*rv*wv[c/3]; }
    __syncwarp();

    float e0 = evec[(size_t)ae*3], e1 = evec[(size_t)ae*3+1], e2 = evec[(size_t)ae*3+2];
    float rn = rsqrtf(e0*e0 + e1*e1 + e2*e2 + 1e-8f);
    float ax = e0*rn, ay = e1*rn, az = e2*rn;
    float refx = (fabsf(ax) < 0.9f) ? 1.f : 0.f, refy = 1.f - refx;
    float bx = -az*refy, by = az*refx, bz = ax*refy - ay*refx;
    float rb = rsqrtf(bx*bx + by*by + bz*bz + 1e-8f);
    bx *= rb; by *= rb; bz *= rb;
    float cx = ay*bz - az*by, cy = az*bx - ax*bz, cz = ax*by - ay*bx;
    if (lane == 0) {
        float* Rp = Rout + (size_t)e*9;
        Rp[0]=ax; Rp[1]=ay; Rp[2]=az; Rp[3]=bx; Rp[4]=by; Rp[5]=bz; Rp[6]=cx; Rp[7]=cy; Rp[8]=cz;
    }
    bf16* vf = vf12 + (size_t)e*384;
#pragma unroll
    for (int i = 0; i < 6; i++) {
        int u = lane + 32*i;
        float vx, vy, vz;
        if (u < 64)       { const float* p = nv + (size_t)ctr*192 + u*3;        vx=p[0]; vy=p[1]; vz=p[2]; }
        else if (u < 128) { const float* p = &evs[wi][(u-64)*3];                vx=p[0]; vy=p[1]; vz=p[2]; }
        else              { const float* p = nv + (size_t)nbr*192 + (u-128)*3;  vx=p[0]; vy=p[1]; vz=p[2]; }
        esv[128 + u] = __float2bfloat16(ax*vx + ay*vy + az*vz);
        vf[u]        = __float2bfloat16(bx*vx + by*vy + bz*vz);
        vf[192 + u]  = __float2bfloat16(cx*vx + cy*vy + cz*vz);
    }
}

// ---------------------------------------------------------------------------
// bf16 GEMM (m16n8k16): A [M,K] ldmatrix, B [K,N] ldmatrix.trans, cp.async 3-stage.
// MODE 0: fp32 C = A@B*scale (+bias)
// MODE 10: bf16 C = A@B*scale
// MODE 1: main SO2 (proj bf16, gv bf16 out)
// MODE 2/3: scatter (wenv bf16)
// MODE 4: complex + rotation (gv bf16 in)
// MODE 5: merged typed gs/tg (Nc=192): c<128 -> gs bf16 silu; 128<=c<192 -> tg fp32 sigmoid (aux)
// MODE 7: typed gvm (tg fp32 in via gvbuf)
// MODE 8/9: final output + residual
static constexpr int ASTG = 6144;
static constexpr int BSTG = 4352;
static constexpr int STG  = ASTG + BSTG;
static constexpr int GEMM_SMEM = 3*STG;
static constexpr int GEMM_SMEM4 = 128*132*4;

template<int MODE, bool GATHER>
__global__ __launch_bounds__(256, 2)
void mma_gemm_kernel(const bf16* __restrict__ A, const bf16* __restrict__ B,
                     float* __restrict__ C, int M, int Nc, int K, int lda, int ldb,
                     float scale, const float* __restrict__ bias, const int* __restrict__ rowidx,
                     const int* __restrict__ ctr, const int* __restrict__ nbr,
                     const float* __restrict__ proj, const float* __restrict__ Rrot,
                     const float* __restrict__ gvbuf, const float* __restrict__ wenv,
                     float* __restrict__ agg, float* __restrict__ aux,
                     const float* __restrict__ nf, const float* __restrict__ resp,
                     const int* __restrict__ offs, const int* __restrict__ order,
                     int tOffB, size_t aplane, int Nnodes, int E) {
    constexpr bool TYPED = (MODE == 5 || MODE == 7);
    extern __shared__ char smc[];
    const int tid = threadIdx.x, lane = tid & 31, wid = tid >> 5;
    const int g = lane >> 2, t = lane & 3;
    const int wm = (wid >> 2)*64, wn = (wid & 3)*32;

    int mplane = 0, bn;
    if (MODE == 7 || MODE == 9) { mplane = blockIdx.x; bn = 0; } else bn = blockIdx.x*128;
    const int bm = blockIdx.y*128;

    int Mloc = M, rowbase = 0, typ = 0;
    if (TYPED) {
        typ = blockIdx.z;
        rowbase = offs[typ];
        Mloc = offs[typ+1] - rowbase;
        if (Mloc == 0 || bm >= Mloc) return;
    }
    const bf16* Ause = A + (size_t)mplane*aplane;
    const bf16* Buse = B + (TYPED ? (size_t)typ*tOffB : 0);

    int arow = tid >> 1, ahalf = tid & 1;
    int r = bm + arow, gr;
    if (TYPED) { if (r >= Mloc) r = Mloc - 1; gr = order[rowbase + r]; }
    else       { if (r >= M) r = M - 1;       gr = GATHER ? rowidx[r] : r; }
    const bf16* asrc = Ause + (size_t)gr*lda + ahalf*8;
    int brow = tid >> 4, bc16 = tid & 15;
    int bcol = bn + bc16*8;
    int bby = (bcol < Nc) ? 16 : 0;
    if (bcol >= Nc) bcol = Nc - 8;
    const bf16* bsrc = Buse + (size_t)brow*ldb + bcol;

    uint32_t sbase = (uint32_t)__cvta_generic_to_shared(smc);
    uint32_t adst = sbase + arow*48 + ahalf*16;
    uint32_t bdst = sbase + ASTG + brow*272 + bc16*16;

    const int q = lane >> 3, rr8 = lane & 7;
    uint32_t aLd = sbase + ((wm + (q & 1)*8 + rr8)*24 + (q >> 1)*8)*2;
    uint32_t bLd = sbase + ASTG + ((q & 1)*8 + rr8)*272 + (wn + (q >> 1)*8)*2;

    const int kT = K >> 4;
    auto loadStage = [&](int slot, int k0) {
        uint32_t so = slot*STG;
        asm volatile("cp.async.cg.shared.global [%0], [%1], 16;" :: "r"(adst + so), "l"(asrc + k0) : "memory");
        asm volatile("cp.async.cg.shared.global [%0], [%1], 16, %2;" :: "r"(bdst + so), "l"(bsrc + (size_t)k0*ldb), "r"(bby) : "memory");
        asm volatile("cp.async.commit_group;");
    };

    float acc[4][4][4];
#pragma unroll
    for (int mi = 0; mi < 4; mi++)
#pragma unroll
        for (int ni = 0; ni < 4; ni++)
#pragma unroll
            for (int j = 0; j < 4; j++) acc[mi][ni][j] = 0.f;

    loadStage(0, 0); loadStage(1, 16);

    for (int kt = 0; kt < kT; kt++) {
        asm volatile("cp.async.wait_group 1;");
        __syncthreads();
        int pf = kt + 2;
        if (pf < kT) loadStage(pf % 3, pf*16);
        else asm volatile("cp.async.commit_group;");

        uint32_t so = (kt % 3)*STG;
        uint32_t af[4][4], bf[4][2];
#pragma unroll
        for (int mi = 0; mi < 4; mi++)
            asm volatile("ldmatrix.sync.aligned.m8n8.x4.shared.b16 {%0,%1,%2,%3}, [%4];"
                : "=r"(af[mi][0]), "=r"(af[mi][1]), "=r"(af[mi][2]), "=r"(af[mi][3])
                : "r"(aLd + so + mi*16*48));
#pragma unroll
        for (int np = 0; np < 2; np++)
            asm volatile("ldmatrix.sync.aligned.m8n8.x4.trans.shared.b16 {%0,%1,%2,%3}, [%4];"
                : "=r"(bf[2*np][0]), "=r"(bf[2*np][1]), "=r"(bf[2*np+1][0]), "=r"(bf[2*np+1][1])
                : "r"(bLd + so + np*32));
#pragma unroll
        for (int mi = 0; mi < 4; mi++)
#pragma unroll
            for (int ni = 0; ni < 4; ni++) {
                asm volatile(
                    "mma.sync.aligned.m16n8k16.row.col.f32.bf16.bf16.f32 "
                    "{%0,%1,%2,%3}, {%4,%5,%6,%7}, {%8,%9}, {%0,%1,%2,%3};"
                    : "+f"(acc[mi][ni][0]), "+f"(acc[mi][ni][1]),
                      "+f"(acc[mi][ni][2]), "+f"(acc[mi][ni][3])
                    : "r"(af[mi][0]), "r"(af[mi][1]), "r"(af[mi][2]), "r"(af[mi][3]),
                      "r"(bf[ni][0]), "r"(bf[ni][1]));
            }
    }

    // ---------------- epilogue ----------------
    const float INV = 0.28867513459481287f;
    if (MODE == 4) {
        __syncthreads();
        float* Vs = (float*)smc;
#pragma unroll
        for (int mi = 0; mi < 4; mi++)
#pragma unroll
            for (int h = 0; h < 2; h++) {
                int rw = wm + mi*16 + g + 8*h;
#pragma unroll
                for (int ni = 0; ni < 4; ni++) {
                    int c = wn + ni*8 + 2*t;
                    *(float2*)&Vs[rw*132 + c] = make_float2(acc[mi][ni][2*h]*scale, acc[mi][ni][2*h+1]*scale);
                }
            }
        __syncthreads();
        bf16* Cb = (bf16*)C;
        const bf16* gvB = (const bf16*)gvbuf;
        for (int rw = wid; rw < 128; rw += 8) {
            int e = bm + rw;
            const float* Rp = Rrot + (size_t)e*9;
            float R0=Rp[0],R1=Rp[1],R2=Rp[2],R3=Rp[3],R4=Rp[4],R5=Rp[5],R6=Rp[6],R7=Rp[7],R8=Rp[8];
            const bf16* gvp = gvB + (size_t)e*128;
#pragma unroll
            for (int i = 0; i < 2; i++) {
                int u = lane + 32*i;
                float sg = __bfloat162float(gvp[u]), i0 = __bfloat162float(gvp[64 + u]);
                float i1 = Vs[rw*132 + u], i2 = Vs[rw*132 + 64 + u];
                Cb[(size_t)0*E*64 + (size_t)e*64 + u] = __float2bfloat16(sg*(R0*i0 + R3*i1 + R6*i2));
                Cb[(size_t)1*E*64 + (size_t)e*64 + u] = __float2bfloat16(sg*(R1*i0 + R4*i1 + R7*i2));
                Cb[(size_t)2*E*64 + (size_t)e*64 + u] = __float2bfloat16(sg*(R2*i0 + R5*i1 + R8*i2));
            }
        }
        return;
    }

    float alpha = 0.f, beta = 0.f;
    if (MODE == 8 || MODE == 9) { alpha = 1.f/(1.f + expf(-resp[0])); beta = 1.f - alpha; }

#pragma unroll
    for (int mi = 0; mi < 4; mi++) {
        int r0 = bm + wm + mi*16 + g;
#pragma unroll
        for (int h = 0; h < 2; h++) {
            int row = r0 + 8*h;
            if (row >= (TYPED ? Mloc : M)) continue;
            if (MODE == 0) {
#pragma unroll
                for (int ni = 0; ni < 4; ni++) {
                    int c = bn + wn + ni*8 + 2*t;
                    if (c >= Nc) continue;
                    float a0 = acc[mi][ni][2*h]*scale + (bias ? bias[c] : 0.f);
                    float a1 = acc[mi][ni][2*h+1]*scale + (bias ? bias[c+1] : 0.f);
                    *(float2*)&C[(size_t)row*Nc + c] = make_float2(a0, a1);
                }
            } else if (MODE == 10) {
                bf16* Cb = (bf16*)C;
#pragma unroll
                for (int ni = 0; ni < 4; ni++) {
                    int c = bn + wn + ni*8 + 2*t;
                    if (c >= Nc) continue;
                    *(bf162*)&Cb[(size_t)row*Nc + c] =
                        f2b2(acc[mi][ni][2*h]*scale, acc[mi][ni][2*h+1]*scale);
                }
            } else if (MODE == 1) {
                const bf16* pc = (const bf16*)proj + (size_t)ctr[row]*512;
                const bf16* pn = (const bf16*)proj + (size_t)nbr[row]*512 + 256;
                bf16* Cb = (bf16*)C;
                bf16* auxB = (bf16*)aux;
#pragma unroll
                for (int ni = 0; ni < 4; ni++) {
                    int c = bn + wn + ni*8 + 2*t;
                    float2 pcv = __bfloat1622float2(*(const bf162*)&pc[c]);
                    float2 pnv = __bfloat1622float2(*(const bf162*)&pn[c]);
                    float v0 = (acc[mi][ni][2*h]   + pcv.x + pnv.x)*scale;
                    float v1 = (acc[mi][ni][2*h+1] + pcv.y + pnv.y)*scale;
                    if (c < 128) {
                        *(bf162*)&Cb[(size_t)row*128 + c] = f2b2(v0/(1.f+expf(-v0)), v1/(1.f+expf(-v1)));
                    } else if (c < 192) {
                        *(bf162*)&auxB[(size_t)row*128 + c-128] =
                            f2b2(1.f/(1.f+expf(-v0)), 1.f/(1.f+expf(-v1)));
                    } else {
                        *(bf162*)&auxB[(size_t)row*128 + c-128] = f2b2(v0, v1);
                    }
                }
            } else if (MODE == 2) {
                float* ap = agg + (size_t)ctr[row]*128;
                const bf16* we = (const bf16*)wenv + (size_t)row*192;
#pragma unroll
                for (int ni = 0; ni < 4; ni++) {
                    int c = bn + wn + ni*8 + 2*t;
                    if (c >= Nc) continue;
                    float2 w = __bfloat1622float2(*(const bf162*)&we[c]);
                    atomicAdd(&ap[c],   (acc[mi][ni][2*h]  *scale + bias[c])  *w.x*INV);
                    atomicAdd(&ap[c+1], (acc[mi][ni][2*h+1]*scale + bias[c+1])*w.y*INV);
                }
            } else if (MODE == 3) {
                int m = row / E, e = row - m*E;
                float* ap = agg + (size_t)m*Nnodes*64 + (size_t)ctr[e]*64;
                const bf16* we = (const bf16*)wenv + (size_t)e*192 + 128;
#pragma unroll
                for (int ni = 0; ni < 4; ni++) {
                    int c = bn + wn + ni*8 + 2*t;
                    if (c >= Nc) continue;
                    float2 w = __bfloat1622float2(*(const bf162*)&we[c]);
                    atomicAdd(&ap[c],   acc[mi][ni][2*h]  *scale*w.x*INV);
                    atomicAdd(&ap[c+1], acc[mi][ni][2*h+1]*scale*w.y*INV);
                }
            } else if (MODE == 5) {
                int node = order[rowbase + row];
                bf16* Cb = (bf16*)C;
#pragma unroll
                for (int ni = 0; ni < 4; ni++) {
                    int c = bn + wn + ni*8 + 2*t;
                    float v0 = acc[mi][ni][2*h]*scale, v1 = acc[mi][ni][2*h+1]*scale;
                    if (c < 128) {
                        *(bf162*)&Cb[(size_t)node*128 + c] = f2b2(v0/(1.f+expf(-v0)), v1/(1.f+expf(-v1)));
                    } else if (c < 192) {
                        *(float2*)&aux[(size_t)node*64 + c-128] =
                            make_float2(1.f/(1.f+expf(-v0)), 1.f/(1.f+expf(-v1)));
                    }
                }
            } else if (MODE == 7) {
                int node = order[rowbase + row];
                const float* tgp = gvbuf + (size_t)node*64;
                bf16* Cb = (bf16*)C;
#pragma unroll
                for (int ni = 0; ni < 4; ni++) {
                    int c = wn + ni*8 + 2*t;
                    if (c >= Nc) continue;
                    *(bf162*)&Cb[(size_t)mplane*aplane + (size_t)node*64 + c] =
                        f2b2(acc[mi][ni][2*h]*scale*tgp[c], acc[mi][ni][2*h+1]*scale*tgp[c+1]);
                }
            } else if (MODE == 8) {
#pragma unroll
                for (int ni = 0; ni < 4; ni++) {
                    int c = wn + ni*8 + 2*t;
                    float a0 = acc[mi][ni][2*h]*scale + bias[c];
                    float a1 = acc[mi][ni][2*h+1]*scale + bias[c+1];
                    *(float2*)&C[(size_t)row*320 + c] =
                        make_float2(alpha*nf[(size_t)row*320 + c] + beta*a0,
                                    alpha*nf[(size_t)row*320 + c + 1] + beta*a1);
                }
            } else { // MODE 9
#pragma unroll
                for (int ni = 0; ni < 4; ni++) {
                    int c = wn + ni*8 + 2*t;
                    if (c >= Nc) continue;
                    size_t o0 = (size_t)row*320 + 128 + 3*c + mplane;
                    size_t o1 = (size_t)row*320 + 128 + 3*(c+1) + mplane;
                    C[o0] = alpha*nf[o0] + beta*acc[mi][ni][2*h]*scale;
                    C[o1] = alpha*nf[o1] + beta*acc[mi][ni][2*h+1]*scale;
                }
            }
        }
    }
}

// ---------------------------------------------------------------------------
extern "C" void kernel_launch(void* const* d_in, const int* in_sizes, int n_in,
                              void* d_out, int out_size) {
    const float* latents = (const float*)d_in[0];
    const float* nf    = (const float*)d_in[1];
    const float* ef    = (const float*)d_in[2];
    const int*   at    = (const int*)  d_in[3];
    const int*   ei    = (const int*)  d_in[5];
    const float* evec  = (const float*)d_in[6];
    const int*   act   = (const int*)  d_in[7];
    const float* snws  = (const float*)d_in[8];
    const float* snbs  = (const float*)d_in[9];
    const float* snwv  = (const float*)d_in[10];
    const float* sews  = (const float*)d_in[11];
    const float* sebs  = (const float*)d_in[12];
    const float* sewv  = (const float*)d_in[13];
    const float* so2w0 = (const float*)d_in[14];
    const float* w1r   = (const float*)d_in[15];
    const float* w1i   = (const float*)d_in[16];
    const float* envw  = (const float*)d_in[17];
    const float* lpws  = (const float*)d_in[18];
    const float* lpbs  = (const float*)d_in[19];
    const float* lpwv  = (const float*)d_in[20];
    const float* ohwss = (const float*)d_in[21];
    const float* ohwsg = (const float*)d_in[22];
    const float* ohwvv = (const float*)d_in[23];
    const float* ohlws = (const float*)d_in[24];
    const float* ohlbs = (const float*)d_in[25];
    const float* ohlwv = (const float*)d_in[26];
    const float* resp  = (const float*)d_in[27];

    int N = in_sizes[1]/320, E = in_sizes[7], Etot = in_sizes[5]/2;
    size_t latN = (size_t)in_sizes[0];

    float* fb = nullptr;  cudaGetSymbolAddress((void**)&fb, g_buf);
    bf16* bb = nullptr;   cudaGetSymbolAddress((void**)&bb, g_bbuf);
    int* idx = nullptr;   cudaGetSymbolAddress((void**)&idx, g_idx);
    int* cnt = nullptr;   cudaGetSymbolAddress((void**)&cnt, g_cnt);
    int* offs = nullptr;  cudaGetSymbolAddress((void**)&offs, g_offs);
    int* order = nullptr; cudaGetSymbolAddress((void**)&order, g_order);

    float *nv = fb+NV_OFF, *Rbuf = fb+R_OFF, *aggs = fb+AGGS_OFF, *aggv = fb+AGGV_OFF, *tgb = fb+TG_OFF;
    bf16 *nsB = bb+NSB, *esvB = bb+ESVB, *vfB = bb+VF12B, *msgsB = bb+MSGSB, *msgvB = bb+MSGVB,
         *latB = bb+LATB, *gsB = bb+GSB, *gvmB = bb+GVMB, *agsB = bb+AGSB, *agvB = bb+AGVB,
         *projB = bb+PROJB, *gvB = bb+GVB, *wenvB = bb+WENVB,
         *wcpK = bb+WCPT, *w0mK = bb+W0MT, *w1cK = bb+W1CT, *envK = bb+ENVT, *lpwsK = bb+LPWST,
         *lpwvK = bb+LPWVT, *wscK = bb+WSC, *wvvK = bb+WVVT, *ohlwK = bb+OHLWT, *ohlvK = bb+OHLVT;
    int *ctr = idx, *nbr = idx + E;

    const float isq576 = 0.041666666666666664f, isq192 = 0.07216878364870323f,
                isq128 = 0.08838834764831845f, n_ss = 0.011048543456039806f, n_vv = 0.015625f;

    cudaFuncSetAttribute(mma_gemm_kernel<10,false>, cudaFuncAttributeMaxDynamicSharedMemorySize, GEMM_SMEM);
    cudaFuncSetAttribute(mma_gemm_kernel<10,true>,  cudaFuncAttributeMaxDynamicSharedMemorySize, GEMM_SMEM);
    cudaFuncSetAttribute(mma_gemm_kernel<1,false>, cudaFuncAttributeMaxDynamicSharedMemorySize, GEMM_SMEM);
    cudaFuncSetAttribute(mma_gemm_kernel<2,false>, cudaFuncAttributeMaxDynamicSharedMemorySize, GEMM_SMEM);
    cudaFuncSetAttribute(mma_gemm_kernel<3,false>, cudaFuncAttributeMaxDynamicSharedMemorySize, GEMM_SMEM);
    cudaFuncSetAttribute(mma_gemm_kernel<4,false>, cudaFuncAttributeMaxDynamicSharedMemorySize, GEMM_SMEM4);
    cudaFuncSetAttribute(mma_gemm_kernel<5,false>, cudaFuncAttributeMaxDynamicSharedMemorySize, GEMM_SMEM);
    cudaFuncSetAttribute(mma_gemm_kernel<7,false>, cudaFuncAttributeMaxDynamicSharedMemorySize, GEMM_SMEM);
    cudaFuncSetAttribute(mma_gemm_kernel<8,false>, cudaFuncAttributeMaxDynamicSharedMemorySize, GEMM_SMEM);
    cudaFuncSetAttribute(mma_gemm_kernel<9,false>, cudaFuncAttributeMaxDynamicSharedMemorySize, GEMM_SMEM);

    int etile = (E + 127)/128, ntile = (N + 127)/128;

    zero_kernel<<<(int)(((size_t)N*320 + 255)/256), 256>>>(aggs, (size_t)N*320);
    zero_kernel<<<1, 128>>>((float*)cnt, 128);
    node_ln_kernel<<<(N + 7)/8, 256>>>(nf, snws, snbs, snwv, nsB, nv, N);
    {
        size_t tot8 = (2097152 + latN + 7)/8;
        prep_all_kernel<<<(int)((tot8 + 255)/256), 256>>>(
            so2w0, w1r, w1i, envw, lpws, lpwv, ohwss, ohwsg, ohwvv, ohlws, ohlwv,
            latents, bb, latN);
    }
    count_kernel<<<(N + 255)/256, 256>>>(at, cnt, N);
    prefix_kernel<<<1, 32>>>(cnt, offs);
    order_kernel<<<(N + 255)/256, 256>>>(at, offs, cnt + 64, order, N);
    edge_prep_kernel<<<(E + 7)/8, 256>>>(ef, ei, act, evec, sews, sebs, sewv,
                                         nv, esvB, vfB, Rbuf, idx, E, Etot);

    // proj = ns @ wcp  (N x 512, bf16 out)
    mma_gemm_kernel<10,false><<<dim3(4, ntile), 256, GEMM_SMEM>>>(
        nsB, wcpK, (float*)projB, N, 512, 128, 128, 512, 1.0f, nullptr, nullptr,
        nullptr, nullptr, nullptr, nullptr, nullptr, nullptr, nullptr, nullptr,
        nullptr, nullptr, nullptr, nullptr, 0, 0, N, E);
    // wenv = latB[act] @ env / sqrt(128)  (bf16 out)
    mma_gemm_kernel<10,true><<<dim3(2, etile), 256, GEMM_SMEM>>>(
        latB, envK, (float*)wenvB, E, 192, 128, 128, 192, isq128, nullptr, act,
        nullptr, nullptr, nullptr, nullptr, nullptr, nullptr, nullptr, nullptr,
        nullptr, nullptr, nullptr, nullptr, 0, 0, N, E);
    // main SO2 -> msgs(bf16) + gv(bf16)
    mma_gemm_kernel<1,false><<<dim3(2, etile), 256, GEMM_SMEM>>>(
        esvB, w0mK, (float*)msgsB, E, 256, 320, 320, 256, isq576, nullptr, nullptr,
        ctr, nbr, (const float*)projB, nullptr, nullptr, nullptr, nullptr, (float*)gvB,
        nullptr, nullptr, nullptr, nullptr, 0, 0, N, E);
    // complex GEMM + rotation/gate -> msgv(bf16)
    mma_gemm_kernel<4,false><<<dim3(1, etile), 256, GEMM_SMEM4>>>(
        vfB, w1cK, (float*)msgvB, E, 128, 384, 384, 128, isq192, nullptr, nullptr,
        nullptr, nullptr, nullptr, Rbuf, (const float*)gvB, nullptr, nullptr, nullptr,
        nullptr, nullptr, nullptr, nullptr, 0, 0, N, E);
    // lps + env-weight + scatter -> aggs
    mma_gemm_kernel<2,false><<<dim3(1, etile), 256, GEMM_SMEM>>>(
        msgsB, lpwsK, nullptr, E, 128, 128, 128, 128, isq128, lpbs, nullptr,
        ctr, nullptr, nullptr, nullptr, nullptr, (const float*)wenvB, aggs, nullptr,
        nullptr, nullptr, nullptr, nullptr, 0, 0, N, E);
    // lpv + env-weight + scatter -> aggv
    mma_gemm_kernel<3,false><<<dim3(1, (3*E + 127)/128), 256, GEMM_SMEM>>>(
        msgvB, lpwvK, nullptr, 3*E, 64, 64, 64, 64, 0.125f, nullptr, nullptr,
        ctr, nullptr, nullptr, nullptr, nullptr, (const float*)wenvB, aggv, nullptr,
        nullptr, nullptr, nullptr, nullptr, 0, 0, N, E);
    // aggs|aggv -> bf16
    c2b_kernel<<<(int)(((size_t)N*320 + 255)/256), 256>>>(aggs, agsB, (size_t)N*320);
    // merged typed gs/tg: Nc=192 against wsc
    mma_gemm_kernel<5,false><<<dim3(2, 2, 64), 256, GEMM_SMEM>>>(
        agsB, wscK, (float*)gsB, N, 192, 128, 128, 64*192, n_ss, nullptr, nullptr,
        nullptr, nullptr, nullptr, nullptr, nullptr, nullptr, nullptr, tgb,
        nullptr, nullptr, offs, order, 192, 0, N, E);
    // typed, 3 planes: gvm = bf16(tg * (aggvB @ wvv[:,t,:] * n_vv))
    mma_gemm_kernel<7,false><<<dim3(3, 2, 64), 256, GEMM_SMEM>>>(
        agvB, wvvK, (float*)gvmB, N, 64, 64, 64, 64*64, n_vv, nullptr, nullptr,
        nullptr, nullptr, nullptr, nullptr, tgb, nullptr, nullptr, nullptr,
        nullptr, nullptr, offs, order, 64, (size_t)N*64, N, E);
    // final scalar: out[:,0:128]
    mma_gemm_kernel<8,false><<<dim3(1, ntile), 256, GEMM_SMEM>>>(
        gsB, ohlwK, (float*)d_out, N, 128, 128, 128, 128, isq128, ohlbs, nullptr,
        nullptr, nullptr, nullptr, nullptr, nullptr, nullptr, nullptr, nullptr,
        nf, resp, nullptr, nullptr, 0, 0, N, E);
    // final vector: out[:,128+3k+m]
    mma_gemm_kernel<9,false><<<dim3(3, ntile), 256, GEMM_SMEM>>>(
        gvmB, ohlvK, (float*)d_out, N, 64, 64, 64, 64, 0.125f, nullptr, nullptr,
        nullptr, nullptr, nullptr, nullptr, nullptr, nullptr, nullptr, nullptr,
        nf, resp, nullptr, nullptr, 0, (size_t)N*64, N, E);
}

// round 11
// speedup vs baseline: 3.9222x; 1.0107x over previous
#include <cuda_runtime.h>
#include <cuda_bf16.h>
#include <math.h>
#include <stdint.h>

static constexpr int NMAXN = 8000;
static constexpr int EMAX  = 96000;

// ---- fp32 scratch ----
static constexpr size_t NV_OFF   = 0;                                  // nv:   N x 192
static constexpr size_t R_OFF    = NV_OFF   + (size_t)NMAXN*192;       // R:    E x 9
static constexpr size_t AGGS_OFF = R_OFF    + (size_t)EMAX*9;          // aggs: N x 128
static constexpr size_t AGGV_OFF = AGGS_OFF + (size_t)NMAXN*128;       // aggv: 3 x N x 64
static constexpr size_t TG_OFF   = AGGV_OFF + (size_t)3*NMAXN*64;      // tg:   N x 64
static constexpr size_t TOTAL_F  = TG_OFF   + (size_t)NMAXN*64;
__device__ __align__(256) float g_buf[TOTAL_F];

// ---- bf16 scratch ----
static constexpr size_t NSB   = 0;
static constexpr size_t ESVB  = NSB   + (size_t)NMAXN*128;
static constexpr size_t VF12B = ESVB  + (size_t)EMAX*320;
static constexpr size_t MSGSB = VF12B + (size_t)EMAX*384;
static constexpr size_t MSGVB = MSGSB + (size_t)EMAX*128;
static constexpr size_t LATB  = MSGVB + (size_t)3*EMAX*64;
static constexpr size_t GSB   = LATB  + (size_t)EMAX*128;
static constexpr size_t GVMB  = GSB   + (size_t)NMAXN*128;
static constexpr size_t AGSB  = GVMB  + (size_t)3*NMAXN*64;
static constexpr size_t AGVB  = AGSB  + (size_t)NMAXN*128;
static constexpr size_t PROJB = AGVB  + (size_t)3*NMAXN*64;            // proj: N x 512
static constexpr size_t GVB   = PROJB + (size_t)NMAXN*512;             // gv:   E x 128
static constexpr size_t WENVB = GVB   + (size_t)EMAX*128;              // wenv: E x 192
static constexpr size_t WCPT  = WENVB + (size_t)EMAX*192;              // 128K x 512N
static constexpr size_t W0MT  = WCPT  + (size_t)128*512;               // 320K x 256N
static constexpr size_t W1CT  = W0MT  + (size_t)320*256;               // 384K x 128N
static constexpr size_t ENVT  = W1CT  + (size_t)384*128;               // 128K x 192N
static constexpr size_t LPWST = ENVT  + (size_t)128*192;               // 128 x 128
static constexpr size_t LPWVT = LPWST + (size_t)128*128;               // 64 x 64
static constexpr size_t WSC   = LPWVT + (size_t)64*64;                 // 128u x 64t x 192
static constexpr size_t WVVT  = WSC   + (size_t)128*64*192;            // 64u x 64t x 64
static constexpr size_t OHLWT = WVVT  + (size_t)64*64*64;              // 128 x 128
static constexpr size_t OHLVT = OHLWT + (size_t)128*128;               // 64 x 64
static constexpr size_t TOTAL_B = OHLVT + (size_t)64*64;
__device__ __align__(256) __nv_bfloat16 g_bbuf[TOTAL_B];

__device__ int g_idx[2*EMAX];
__device__ int g_cnt[128];
__device__ int g_offs[65];
__device__ int g_order[NMAXN];

typedef __nv_bfloat16 bf16;
typedef __nv_bfloat162 bf162;
__device__ __forceinline__ bf162 f2b2(float a, float b) { return __floats2bfloat162_rn(a, b); }

// ---------------------------------------------------------------------------
__global__ void zero_kernel(float* __restrict__ p, size_t n) {
    size_t i = (size_t)blockIdx.x*blockDim.x + threadIdx.x;
    if (i < n) p[i] = 0.f;
}
__global__ void c2b_kernel(const float* __restrict__ in, bf16* __restrict__ out, size_t n) {
    size_t i = (size_t)blockIdx.x*blockDim.x + threadIdx.x;
    if (i < n) out[i] = __float2bfloat16(in[i]);
}
__global__ void count_kernel(const int* __restrict__ at, int* __restrict__ cnt, int N) {
    int n = blockIdx.x*blockDim.x + threadIdx.x;
    if (n < N) atomicAdd(&cnt[at[n]], 1);
}
__global__ void prefix_kernel(const int* __restrict__ cnt, int* __restrict__ offs) {
    if (threadIdx.x == 0) { int s = 0; for (int i = 0; i < 64; i++) { offs[i] = s; s += cnt[i]; } offs[64] = s; }
}
__global__ void order_kernel(const int* __restrict__ at, const int* __restrict__ offs,
                             int* __restrict__ cur, int* __restrict__ order, int N) {
    int n = blockIdx.x*blockDim.x + threadIdx.x;
    if (n < N) { int t = at[n]; order[offs[t] + atomicAdd(&cur[t], 1)] = n; }
}

// ---------------------------------------------------------------------------
// Fused weight-prep, 8 elements per thread, 16B stores.
__device__ __forceinline__ void copy8(const float* __restrict__ in, bf16* __restrict__ out, float sgn) {
    float4 a = *(const float4*)in, b = *(const float4*)(in + 4);
    bf162 h[4] = { f2b2(sgn*a.x, sgn*a.y), f2b2(sgn*a.z, sgn*a.w),
                   f2b2(sgn*b.x, sgn*b.y), f2b2(sgn*b.z, sgn*b.w) };
    *(uint4*)out = *(uint4*)h;
}
__global__ void prep_all_kernel(const float* __restrict__ w0,
                                const float* __restrict__ w1r, const float* __restrict__ w1i,
                                const float* __restrict__ envw, const float* __restrict__ lpws,
                                const float* __restrict__ lpwv, const float* __restrict__ ohwss,
                                const float* __restrict__ ohwsg, const float* __restrict__ ohwvv,
                                const float* __restrict__ ohlws, const float* __restrict__ ohlwv,
                                const float* __restrict__ latents, bf16* __restrict__ bb,
                                size_t latN) {
    size_t g8 = ((size_t)blockIdx.x*blockDim.x + threadIdx.x)*8;
    if (g8 >= 2097152 + latN) return;
    if (g8 < 65536) {                           // wcp [128k][512c]
        int i = (int)g8, k = i >> 9, c = i & 511;
        const float* s = (c < 256) ? w0 + (size_t)k*256 + c : w0 + (size_t)(256 + k)*256 + (c - 256);
        copy8(s, bb + WCPT + i, 1.f);
    } else if (g8 < 147456) {                   // w0m [320k][256c]
        int i = (int)(g8 - 65536), k = i >> 8, c = i & 255;
        int src = (k < 128) ? k + 128 : k + 256;
        copy8(w0 + (size_t)src*256 + c, bb + W0MT + i, 1.f);
    } else if (g8 < 196608) {                   // w1c [384r][128c]
        int i = (int)(g8 - 147456), r = i >> 7, c = i & 127;
        const float* s; float sgn = 1.f;
        if (r < 192) s = (c < 64) ? w1r + r*64 + c : w1i + r*64 + (c - 64);
        else { int r2 = r - 192; if (c < 64) { s = w1i + r2*64 + c; sgn = -1.f; } else s = w1r + r2*64 + (c - 64); }
        copy8(s, bb + W1CT + i, sgn);
    } else if (g8 < 221184) { int i = (int)(g8 - 196608); copy8(envw + i,  bb + ENVT  + i, 1.f);
    } else if (g8 < 237568) { int i = (int)(g8 - 221184); copy8(lpws + i,  bb + LPWST + i, 1.f);
    } else if (g8 < 241664) { int i = (int)(g8 - 237568); copy8(lpwv + i,  bb + LPWVT + i, 1.f);
    } else if (g8 < 1290240) {                  // wsc[:, :, 0:128] <- ohwss
        int i = (int)(g8 - 241664), ut = i >> 7, n = i & 127;
        copy8(ohwss + i, bb + WSC + (size_t)ut*192 + n, 1.f);
    } else if (g8 < 1814528) {                  // wsc[:, :, 128:192] <- ohwsg
        int i = (int)(g8 - 1290240), ut = i >> 6, gg = i & 63;
        copy8(ohwsg + i, bb + WSC + (size_t)ut*192 + 128 + gg, 1.f);
    } else if (g8 < 2076672) { int i = (int)(g8 - 1814528); copy8(ohwvv + i, bb + WVVT + i, 1.f);
    } else if (g8 < 2093056) { int i = (int)(g8 - 2076672); copy8(ohlws + i, bb + OHLWT + i, 1.f);
    } else if (g8 < 2097152) { int i = (int)(g8 - 2093056); copy8(ohlwv + i, bb + OHLVT + i, 1.f);
    } else {
        size_t i = g8 - 2097152;
        if (i + 8 <= latN) copy8(latents + i, bb + LATB + i, 1.f);
        else for (size_t j = i; j < latN; j++) bb[LATB + j] = __float2bfloat16(latents[j]);
    }
}

// ---------------------------------------------------------------------------
__global__ void node_ln_kernel(const float* __restrict__ nf, const float* __restrict__ ws,
                               const float* __restrict__ bs, const float* __restrict__ wv,
                               bf16* __restrict__ ns, float* __restrict__ nv, int N) {
    int node = (blockIdx.x*blockDim.x + threadIdx.x) >> 5;
    int lane = threadIdx.x & 31;
    if (node >= N) return;
    const float* row = nf + (size_t)node*320;
    float s[4]; float sum = 0.f;
#pragma unroll
    for (int i = 0; i < 4; i++) { s[i] = row[lane + 32*i]; sum += s[i]; }
#pragma unroll
    for (int o = 16; o; o >>= 1) sum += __shfl_xor_sync(~0u, sum, o);
    float mu = sum*(1.f/128.f), var = 0.f;
#pragma unroll
    for (int i = 0; i < 4; i++) { s[i] -= mu; var += s[i]*s[i]; }
#pragma unroll
    for (int o = 16; o; o >>= 1) var += __shfl_xor_sync(~0u, var, o);
    float rs = rsqrtf(var*(1.f/128.f) + 1e-8f);
#pragma unroll
    for (int i = 0; i < 4; i++) {
        int c = lane + 32*i;
        ns[(size_t)node*128 + c] = __float2bfloat16(s[i]*rs*ws[c] + bs[c]);
    }
    float v[6]; float vs = 0.f;
#pragma unroll
    for (int i = 0; i < 6; i++) { v[i] = row[128 + lane + 32*i]; vs += v[i]*v[i]; }
#pragma unroll
    for (int o = 16; o; o >>= 1) vs += __shfl_xor_sync(~0u, vs, o);
    float rv = rsqrtf(vs*(1.f/192.f) + 1e-8f);
#pragma unroll
    for (int i = 0; i < 6; i++) { int c = lane + 32*i; nv[(size_t)node*192 + c] = v[i]*rv*wv[c/3]; }
}

__global__ void edge_prep_kernel(const float* __restrict__ ef, const int* __restrict__ ei,
                                 const int* __restrict__ act, const float* __restrict__ evec,
                                 const float* __restrict__ ws, const float* __restrict__ bs,
                                 const float* __restrict__ wv, const float* __restrict__ nv,
                                 bf16* __restrict__ esv0, bf16* __restrict__ vf12,
                                 float* __restrict__ Rout, int* __restrict__ idx, int E, int Etot) {
    __shared__ float evs[8][192];
    int wi = threadIdx.x >> 5, lane = threadIdx.x & 31;
    int e = blockIdx.x*8 + wi;
    if (e >= E) return;
    int ae = act[e];
    int ctr = ei[ae], nbr = ei[Etot + ae];
    if (lane == 0) { idx[e] = ctr; idx[E + e] = nbr; }
    const float* row = ef + (size_t)e*320;

    float s[4]; float sum = 0.f;
#pragma unroll
    for (int i = 0; i < 4; i++) { s[i] = row[lane + 32*i]; sum += s[i]; }
#pragma unroll
    for (int o = 16; o; o >>= 1) sum += __shfl_xor_sync(~0u, sum, o);
    float mu = sum*(1.f/128.f), var = 0.f;
#pragma unroll
    for (int i = 0; i < 4; i++) { s[i] -= mu; var += s[i]*s[i]; }
#pragma unroll
    for (int o = 16; o; o >>= 1) var += __shfl_xor_sync(~0u, var, o);
    float rs = rsqrtf(var*(1.f/128.f) + 1e-8f);
    bf16* esv = esv0 + (size_t)e*320;
#pragma unroll
    for (int i = 0; i < 4; i++) { int c = lane + 32*i; esv[c] = __float2bfloat16(s[i]*rs*ws[c] + bs[c]); }

    float v[6]; float vs = 0.f;
#pragma unroll
    for (int i = 0; i < 6; i++) { v[i] = row[128 + lane + 32*i]; vs += v[i]*v[i]; }
#pragma unroll
    for (int o = 16; o; o >>= 1) vs += __shfl_xor_sync(~0u, vs, o);
    float rv = rsqrtf(vs*(1.f/192.f) + 1e-8f);
#pragma unroll
    for (int i = 0; i < 6; i++) { int c = lane + 32*i; evs[wi][c] = v[i]*rv*wv[c/3]; }
    __syncwarp();

    float e0 = evec[(size_t)ae*3], e1 = evec[(size_t)ae*3+1], e2 = evec[(size_t)ae*3+2];
    float rn = rsqrtf(e0*e0 + e1*e1 + e2*e2 + 1e-8f);
    float ax = e0*rn, ay = e1*rn, az = e2*rn;
    float refx = (fabsf(ax) < 0.9f) ? 1.f : 0.f, refy = 1.f - refx;
    float bx = -az*refy, by = az*refx, bz = ax*refy - ay*refx;
    float rb = rsqrtf(bx*bx + by*by + bz*bz + 1e-8f);
    bx *= rb; by *= rb; bz *= rb;
    float cx = ay*bz - az*by, cy = az*bx - ax*bz, cz = ax*by - ay*bx;
    if (lane == 0) {
        float* Rp = Rout + (size_t)e*9;
        Rp[0]=ax; Rp[1]=ay; Rp[2]=az; Rp[3]=bx; Rp[4]=by; Rp[5]=bz; Rp[6]=cx; Rp[7]=cy; Rp[8]=cz;
    }
    bf16* vf = vf12 + (size_t)e*384;
#pragma unroll
    for (int i = 0; i < 6; i++) {
        int u = lane + 32*i;
        float vx, vy, vz;
        if (u < 64)       { const float* p = nv + (size_t)ctr*192 + u*3;        vx=p[0]; vy=p[1]; vz=p[2]; }
        else if (u < 128) { const float* p = &evs[wi][(u-64)*3];                vx=p[0]; vy=p[1]; vz=p[2]; }
        else              { const float* p = nv + (size_t)nbr*192 + (u-128)*3;  vx=p[0]; vy=p[1]; vz=p[2]; }
        esv[128 + u] = __float2bfloat16(ax*vx + ay*vy + az*vz);
        vf[u]        = __float2bfloat16(bx*vx + by*vy + bz*vz);
        vf[192 + u]  = __float2bfloat16(cx*vx + cy*vy + cz*vz);
    }
}

// ---------------------------------------------------------------------------
// bf16 GEMM (m16n8k16), BK=32 stages (2x 16-K sub-blocks per cp.async group),
// A [M,K] ldmatrix, B [K,N] ldmatrix.trans, 3-stage pipeline.
static constexpr int ASUB = 6144;             // 128 rows x 48B (one 16-K sub-block)
static constexpr int BSUB = 4352;             // 16 rows x 272B
static constexpr int ASTG = 2*ASUB;           // 12288
static constexpr int BSTG = 2*BSUB;           // 8704
static constexpr int STG  = ASTG + BSTG;      // 20992
static constexpr int GEMM_SMEM = 3*STG;       // 62976
static constexpr int GEMM_SMEM4 = 128*132*4;  // 67584 (MODE4 epilogue staging)

template<int MODE, bool GATHER>
__global__ __launch_bounds__(256, 2)
void mma_gemm_kernel(const bf16* __restrict__ A, const bf16* __restrict__ B,
                     float* __restrict__ C, int M, int Nc, int K, int lda, int ldb,
                     float scale, const float* __restrict__ bias, const int* __restrict__ rowidx,
                     const int* __restrict__ ctr, const int* __restrict__ nbr,
                     const float* __restrict__ proj, const float* __restrict__ Rrot,
                     const float* __restrict__ gvbuf, const float* __restrict__ wenv,
                     float* __restrict__ agg, float* __restrict__ aux,
                     const float* __restrict__ nf, const float* __restrict__ resp,
                     const int* __restrict__ offs, const int* __restrict__ order,
                     int tOffB, size_t aplane, int Nnodes, int E) {
    constexpr bool TYPED = (MODE == 5 || MODE == 7);
    extern __shared__ char smc[];
    const int tid = threadIdx.x, lane = tid & 31, wid = tid >> 5;
    const int g = lane >> 2, t = lane & 3;
    const int wm = (wid >> 2)*64, wn = (wid & 3)*32;

    int mplane = 0, bn;
    if (MODE == 7 || MODE == 9) { mplane = blockIdx.x; bn = 0; } else bn = blockIdx.x*128;
    const int bm = blockIdx.y*128;

    int Mloc = M, rowbase = 0, typ = 0;
    if (TYPED) {
        typ = blockIdx.z;
        rowbase = offs[typ];
        Mloc = offs[typ+1] - rowbase;
        if (Mloc == 0 || bm >= Mloc) return;
    }
    const bf16* Ause = A + (size_t)mplane*aplane;
    const bf16* Buse = B + (TYPED ? (size_t)typ*tOffB : 0);

    int arow = tid >> 1, ahalf = tid & 1;
    int r = bm + arow, gr;
    if (TYPED) { if (r >= Mloc) r = Mloc - 1; gr = order[rowbase + r]; }
    else       { if (r >= M) r = M - 1;       gr = GATHER ? rowidx[r] : r; }
    const bf16* asrc = Ause + (size_t)gr*lda + ahalf*8;
    int brow = tid >> 4, bc16 = tid & 15;
    int bcol = bn + bc16*8;
    int bby = (bcol < Nc) ? 16 : 0;
    if (bcol >= Nc) bcol = Nc - 8;
    const bf16* bsrc = Buse + (size_t)brow*ldb + bcol;

    uint32_t sbase = (uint32_t)__cvta_generic_to_shared(smc);
    uint32_t adst = sbase + arow*48 + ahalf*16;
    uint32_t bdst = sbase + ASTG + brow*272 + bc16*16;

    const int q = lane >> 3, rr8 = lane & 7;
    uint32_t aLd = sbase + ((wm + (q & 1)*8 + rr8)*24 + (q >> 1)*8)*2;
    uint32_t bLd = sbase + ASTG + ((q & 1)*8 + rr8)*272 + (wn + (q >> 1)*8)*2;

    const int kT = K >> 5;   // 32-K stages
    auto loadStage = [&](int slot, int k0) {
        uint32_t so = slot*STG;
        asm volatile("cp.async.cg.shared.global [%0], [%1], 16;"
                     :: "r"(adst + so), "l"(asrc + k0) : "memory");
        asm volatile("cp.async.cg.shared.global [%0], [%1], 16;"
                     :: "r"(adst + so + ASUB), "l"(asrc + k0 + 16) : "memory");
        asm volatile("cp.async.cg.shared.global [%0], [%1], 16, %2;"
                     :: "r"(bdst + so), "l"(bsrc + (size_t)k0*ldb), "r"(bby) : "memory");
        asm volatile("cp.async.cg.shared.global [%0], [%1], 16, %2;"
                     :: "r"(bdst + so + BSUB), "l"(bsrc + (size_t)(k0+16)*ldb), "r"(bby) : "memory");
        asm volatile("cp.async.commit_group;");
    };

    float acc[4][4][4];
#pragma unroll
    for (int mi = 0; mi < 4; mi++)
#pragma unroll
        for (int ni = 0; ni < 4; ni++)
#pragma unroll
            for (int j = 0; j < 4; j++) acc[mi][ni][j] = 0.f;

    loadStage(0, 0);
    if (kT > 1) loadStage(1, 32); else asm volatile("cp.async.commit_group;");

    for (int kt = 0; kt < kT; kt++) {
        asm volatile("cp.async.wait_group 1;");
        __syncthreads();
        int pf = kt + 2;
        if (pf < kT) loadStage(pf % 3, pf*32);
        else asm volatile("cp.async.commit_group;");

        uint32_t so = (kt % 3)*STG;
#pragma unroll
        for (int sub = 0; sub < 2; sub++) {
            uint32_t offA = so + sub*ASUB, offB = so + sub*BSUB;
            uint32_t af[4][4], bf[4][2];
#pragma unroll
            for (int mi = 0; mi < 4; mi++)
                asm volatile("ldmatrix.sync.aligned.m8n8.x4.shared.b16 {%0,%1,%2,%3}, [%4];"
                    : "=r"(af[mi][0]), "=r"(af[mi][1]), "=r"(af[mi][2]), "=r"(af[mi][3])
                    : "r"(aLd + offA + mi*16*48));
#pragma unroll
            for (int np = 0; np < 2; np++)
                asm volatile("ldmatrix.sync.aligned.m8n8.x4.trans.shared.b16 {%0,%1,%2,%3}, [%4];"
                    : "=r"(bf[2*np][0]), "=r"(bf[2*np][1]), "=r"(bf[2*np+1][0]), "=r"(bf[2*np+1][1])
                    : "r"(bLd + offB + np*32));
#pragma unroll
            for (int mi = 0; mi < 4; mi++)
#pragma unroll
                for (int ni = 0; ni < 4; ni++) {
                    asm volatile(
                        "mma.sync.aligned.m16n8k16.row.col.f32.bf16.bf16.f32 "
                        "{%0,%1,%2,%3}, {%4,%5,%6,%7}, {%8,%9}, {%0,%1,%2,%3};"
                        : "+f"(acc[mi][ni][0]), "+f"(acc[mi][ni][1]),
                          "+f"(acc[mi][ni][2]), "+f"(acc[mi][ni][3])
                        : "r"(af[mi][0]), "r"(af[mi][1]), "r"(af[mi][2]), "r"(af[mi][3]),
                          "r"(bf[ni][0]), "r"(bf[ni][1]));
                }
        }
    }

    // ---------------- epilogue ----------------
    const float INV = 0.28867513459481287f;
    if (MODE == 4) {
        __syncthreads();
        float* Vs = (float*)smc;
#pragma unroll
        for (int mi = 0; mi < 4; mi++)
#pragma unroll
            for (int h = 0; h < 2; h++) {
                int rw = wm + mi*16 + g + 8*h;
#pragma unroll
                for (int ni = 0; ni < 4; ni++) {
                    int c = wn + ni*8 + 2*t;
                    *(float2*)&Vs[rw*132 + c] = make_float2(acc[mi][ni][2*h]*scale, acc[mi][ni][2*h+1]*scale);
                }
            }
        __syncthreads();
        bf16* Cb = (bf16*)C;
        const bf16* gvB = (const bf16*)gvbuf;
        for (int rw = wid; rw < 128; rw += 8) {
            int e = bm + rw;
            const float* Rp = Rrot + (size_t)e*9;
            float R0=Rp[0],R1=Rp[1],R2=Rp[2],R3=Rp[3],R4=Rp[4],R5=Rp[5],R6=Rp[6],R7=Rp[7],R8=Rp[8];
            const bf16* gvp = gvB + (size_t)e*128;
#pragma unroll
            for (int i = 0; i < 2; i++) {
                int u = lane + 32*i;
                float sg = __bfloat162float(gvp[u]), i0 = __bfloat162float(gvp[64 + u]);
                float i1 = Vs[rw*132 + u], i2 = Vs[rw*132 + 64 + u];
                Cb[(size_t)0*E*64 + (size_t)e*64 + u] = __float2bfloat16(sg*(R0*i0 + R3*i1 + R6*i2));
                Cb[(size_t)1*E*64 + (size_t)e*64 + u] = __float2bfloat16(sg*(R1*i0 + R4*i1 + R7*i2));
                Cb[(size_t)2*E*64 + (size_t)e*64 + u] = __float2bfloat16(sg*(R2*i0 + R5*i1 + R8*i2));
            }
        }
        return;
    }

    float alpha = 0.f, beta = 0.f;
    if (MODE == 8 || MODE == 9) { alpha = 1.f/(1.f + expf(-resp[0])); beta = 1.f - alpha; }

#pragma unroll
    for (int mi = 0; mi < 4; mi++) {
        int r0 = bm + wm + mi*16 + g;
#pragma unroll
        for (int h = 0; h < 2; h++) {
            int row = r0 + 8*h;
            if (row >= (TYPED ? Mloc : M)) continue;
            if (MODE == 0) {
#pragma unroll
                for (int ni = 0; ni < 4; ni++) {
                    int c = bn + wn + ni*8 + 2*t;
                    if (c >= Nc) continue;
                    float a0 = acc[mi][ni][2*h]*scale + (bias ? bias[c] : 0.f);
                    float a1 = acc[mi][ni][2*h+1]*scale + (bias ? bias[c+1] : 0.f);
                    *(float2*)&C[(size_t)row*Nc + c] = make_float2(a0, a1);
                }
            } else if (MODE == 10) {
                bf16* Cb = (bf16*)C;
#pragma unroll
                for (int ni = 0; ni < 4; ni++) {
                    int c = bn + wn + ni*8 + 2*t;
                    if (c >= Nc) continue;
                    *(bf162*)&Cb[(size_t)row*Nc + c] =
                        f2b2(acc[mi][ni][2*h]*scale, acc[mi][ni][2*h+1]*scale);
                }
            } else if (MODE == 1) {
                const bf16* pc = (const bf16*)proj + (size_t)ctr[row]*512;
                const bf16* pn = (const bf16*)proj + (size_t)nbr[row]*512 + 256;
                bf16* Cb = (bf16*)C;
                bf16* auxB = (bf16*)aux;
#pragma unroll
                for (int ni = 0; ni < 4; ni++) {
                    int c = bn + wn + ni*8 + 2*t;
                    float2 pcv = __bfloat1622float2(*(const bf162*)&pc[c]);
                    float2 pnv = __bfloat1622float2(*(const bf162*)&pn[c]);
                    float v0 = (acc[mi][ni][2*h]   + pcv.x + pnv.x)*scale;
                    float v1 = (acc[mi][ni][2*h+1] + pcv.y + pnv.y)*scale;
                    if (c < 128) {
                        *(bf162*)&Cb[(size_t)row*128 + c] = f2b2(v0/(1.f+expf(-v0)), v1/(1.f+expf(-v1)));
                    } else if (c < 192) {
                        *(bf162*)&auxB[(size_t)row*128 + c-128] =
                            f2b2(1.f/(1.f+expf(-v0)), 1.f/(1.f+expf(-v1)));
                    } else {
                        *(bf162*)&auxB[(size_t)row*128 + c-128] = f2b2(v0, v1);
                    }
                }
            } else if (MODE == 2) {
                float* ap = agg + (size_t)ctr[row]*128;
                const bf16* we = (const bf16*)wenv + (size_t)row*192;
#pragma unroll
                for (int ni = 0; ni < 4; ni++) {
                    int c = bn + wn + ni*8 + 2*t;
                    if (c >= Nc) continue;
                    float2 w = __bfloat1622float2(*(const bf162*)&we[c]);
                    atomicAdd(&ap[c],   (acc[mi][ni][2*h]  *scale + bias[c])  *w.x*INV);
                    atomicAdd(&ap[c+1], (acc[mi][ni][2*h+1]*scale + bias[c+1])*w.y*INV);
                }
            } else if (MODE == 3) {
                int m = row / E, e = row - m*E;
                float* ap = agg + (size_t)m*Nnodes*64 + (size_t)ctr[e]*64;
                const bf16* we = (const bf16*)wenv + (size_t)e*192 + 128;
#pragma unroll
                for (int ni = 0; ni < 4; ni++) {
                    int c = bn + wn + ni*8 + 2*t;
                    if (c >= Nc) continue;
                    float2 w = __bfloat1622float2(*(const bf162*)&we[c]);
                    atomicAdd(&ap[c],   acc[mi][ni][2*h]  *scale*w.x*INV);
                    atomicAdd(&ap[c+1], acc[mi][ni][2*h+1]*scale*w.y*INV);
                }
            } else if (MODE == 5) {
                int node = order[rowbase + row];
                bf16* Cb = (bf16*)C;
#pragma unroll
                for (int ni = 0; ni < 4; ni++) {
                    int c = bn + wn + ni*8 + 2*t;
                    float v0 = acc[mi][ni][2*h]*scale, v1 = acc[mi][ni][2*h+1]*scale;
                    if (c < 128) {
                        *(bf162*)&Cb[(size_t)node*128 + c] = f2b2(v0/(1.f+expf(-v0)), v1/(1.f+expf(-v1)));
                    } else if (c < 192) {
                        *(float2*)&aux[(size_t)node*64 + c-128] =
                            make_float2(1.f/(1.f+expf(-v0)), 1.f/(1.f+expf(-v1)));
                    }
                }
            } else if (MODE == 7) {
                int node = order[rowbase + row];
                const float* tgp = gvbuf + (size_t)node*64;
                bf16* Cb = (bf16*)C;
#pragma unroll
                for (int ni = 0; ni < 4; ni++) {
                    int c = wn + ni*8 + 2*t;
                    if (c >= Nc) continue;
                    *(bf162*)&Cb[(size_t)mplane*aplane + (size_t)node*64 + c] =
                        f2b2(acc[mi][ni][2*h]*scale*tgp[c], acc[mi][ni][2*h+1]*scale*tgp[c+1]);
                }
            } else if (MODE == 8) {
#pragma unroll
                for (int ni = 0; ni < 4; ni++) {
                    int c = wn + ni*8 + 2*t;
                    float a0 = acc[mi][ni][2*h]*scale + bias[c];
                    float a1 = acc[mi][ni][2*h+1]*scale + bias[c+1];
                    *(float2*)&C[(size_t)row*320 + c] =
                        make_float2(alpha*nf[(size_t)row*320 + c] + beta*a0,
                                    alpha*nf[(size_t)row*320 + c + 1] + beta*a1);
                }
            } else { // MODE 9
#pragma unroll
                for (int ni = 0; ni < 4; ni++) {
                    int c = wn + ni*8 + 2*t;
                    if (c >= Nc) continue;
                    size_t o0 = (size_t)row*320 + 128 + 3*c + mplane;
                    size_t o1 = (size_t)row*320 + 128 + 3*(c+1) + mplane;
                    C[o0] = alpha*nf[o0] + beta*acc[mi][ni][2*h]*scale;
                    C[o1] = alpha*nf[o1] + beta*acc[mi][ni][2*h+1]*scale;
                }
            }
        }
    }
}

// ---------------------------------------------------------------------------
extern "C" void kernel_launch(void* const* d_in, const int* in_sizes, int n_in,
                              void* d_out, int out_size) {
    const float* latents = (const float*)d_in[0];
    const float* nf    = (const float*)d_in[1];
    const float* ef    = (const float*)d_in[2];
    const int*   at    = (const int*)  d_in[3];
    const int*   ei    = (const int*)  d_in[5];
    const float* evec  = (const float*)d_in[6];
    const int*   act   = (const int*)  d_in[7];
    const float* snws  = (const float*)d_in[8];
    const float* snbs  = (const float*)d_in[9];
    const float* snwv  = (const float*)d_in[10];
    const float* sews  = (const float*)d_in[11];
    const float* sebs  = (const float*)d_in[12];
    const float* sewv  = (const float*)d_in[13];
    const float* so2w0 = (const float*)d_in[14];
    const float* w1r   = (const float*)d_in[15];
    const float* w1i   = (const float*)d_in[16];
    const float* envw  = (const float*)d_in[17];
    const float* lpws  = (const float*)d_in[18];
    const float* lpbs  = (const float*)d_in[19];
    const float* lpwv  = (const float*)d_in[20];
    const float* ohwss = (const float*)d_in[21];
    const float* ohwsg = (const float*)d_in[22];
    const float* ohwvv = (const float*)d_in[23];
    const float* ohlws = (const float*)d_in[24];
    const float* ohlbs = (const float*)d_in[25];
    const float* ohlwv = (const float*)d_in[26];
    const float* resp  = (const float*)d_in[27];

    int N = in_sizes[1]/320, E = in_sizes[7], Etot = in_sizes[5]/2;
    size_t latN = (size_t)in_sizes[0];

    float* fb = nullptr;  cudaGetSymbolAddress((void**)&fb, g_buf);
    bf16* bb = nullptr;   cudaGetSymbolAddress((void**)&bb, g_bbuf);
    int* idx = nullptr;   cudaGetSymbolAddress((void**)&idx, g_idx);
    int* cnt = nullptr;   cudaGetSymbolAddress((void**)&cnt, g_cnt);
    int* offs = nullptr;  cudaGetSymbolAddress((void**)&offs, g_offs);
    int* order = nullptr; cudaGetSymbolAddress((void**)&order, g_order);

    float *nv = fb+NV_OFF, *Rbuf = fb+R_OFF, *aggs = fb+AGGS_OFF, *aggv = fb+AGGV_OFF, *tgb = fb+TG_OFF;
    bf16 *nsB = bb+NSB, *esvB = bb+ESVB, *vfB = bb+VF12B, *msgsB = bb+MSGSB, *msgvB = bb+MSGVB,
         *latB = bb+LATB, *gsB = bb+GSB, *gvmB = bb+GVMB, *agsB = bb+AGSB, *agvB = bb+AGVB,
         *projB = bb+PROJB, *gvB = bb+GVB, *wenvB = bb+WENVB,
         *wcpK = bb+WCPT, *w0mK = bb+W0MT, *w1cK = bb+W1CT, *envK = bb+ENVT, *lpwsK = bb+LPWST,
         *lpwvK = bb+LPWVT, *wscK = bb+WSC, *wvvK = bb+WVVT, *ohlwK = bb+OHLWT, *ohlvK = bb+OHLVT;
    int *ctr = idx, *nbr = idx + E;

    const float isq576 = 0.041666666666666664f, isq192 = 0.07216878364870323f,
                isq128 = 0.08838834764831845f, n_ss = 0.011048543456039806f, n_vv = 0.015625f;

    cudaFuncSetAttribute(mma_gemm_kernel<10,false>, cudaFuncAttributeMaxDynamicSharedMemorySize, GEMM_SMEM);
    cudaFuncSetAttribute(mma_gemm_kernel<10,true>,  cudaFuncAttributeMaxDynamicSharedMemorySize, GEMM_SMEM);
    cudaFuncSetAttribute(mma_gemm_kernel<1,false>, cudaFuncAttributeMaxDynamicSharedMemorySize, GEMM_SMEM);
    cudaFuncSetAttribute(mma_gemm_kernel<2,false>, cudaFuncAttributeMaxDynamicSharedMemorySize, GEMM_SMEM);
    cudaFuncSetAttribute(mma_gemm_kernel<3,false>, cudaFuncAttributeMaxDynamicSharedMemorySize, GEMM_SMEM);
    cudaFuncSetAttribute(mma_gemm_kernel<4,false>, cudaFuncAttributeMaxDynamicSharedMemorySize, GEMM_SMEM4);
    cudaFuncSetAttribute(mma_gemm_kernel<5,false>, cudaFuncAttributeMaxDynamicSharedMemorySize, GEMM_SMEM);
    cudaFuncSetAttribute(mma_gemm_kernel<7,false>, cudaFuncAttributeMaxDynamicSharedMemorySize, GEMM_SMEM);
    cudaFuncSetAttribute(mma_gemm_kernel<8,false>, cudaFuncAttributeMaxDynamicSharedMemorySize, GEMM_SMEM);
    cudaFuncSetAttribute(mma_gemm_kernel<9,false>, cudaFuncAttributeMaxDynamicSharedMemorySize, GEMM_SMEM);

    int etile = (E + 127)/128, ntile = (N + 127)/128;

    zero_kernel<<<(int)(((size_t)N*320 + 255)/256), 256>>>(aggs, (size_t)N*320);
    zero_kernel<<<1, 128>>>((float*)cnt, 128);
    node_ln_kernel<<<(N + 7)/8, 256>>>(nf, snws, snbs, snwv, nsB, nv, N);
    {
        size_t tot8 = (2097152 + latN + 7)/8;
        prep_all_kernel<<<(int)((tot8 + 255)/256), 256>>>(
            so2w0, w1r, w1i, envw, lpws, lpwv, ohwss, ohwsg, ohwvv, ohlws, ohlwv,
            latents, bb, latN);
    }
    count_kernel<<<(N + 255)/256, 256>>>(at, cnt, N);
    prefix_kernel<<<1, 32>>>(cnt, offs);
    order_kernel<<<(N + 255)/256, 256>>>(at, offs, cnt + 64, order, N);
    edge_prep_kernel<<<(E + 7)/8, 256>>>(ef, ei, act, evec, sews, sebs, sewv,
                                         nv, esvB, vfB, Rbuf, idx, E, Etot);

    // proj = ns @ wcp  (N x 512, bf16 out)
    mma_gemm_kernel<10,false><<<dim3(4, ntile), 256, GEMM_SMEM>>>(
        nsB, wcpK, (float*)projB, N, 512, 128, 128, 512, 1.0f, nullptr, nullptr,
        nullptr, nullptr, nullptr, nullptr, nullptr, nullptr, nullptr, nullptr,
        nullptr, nullptr, nullptr, nullptr, 0, 0, N, E);
    // wenv = latB[act] @ env / sqrt(128)  (bf16 out)
    mma_gemm_kernel<10,true><<<dim3(2, etile), 256, GEMM_SMEM>>>(
        latB, envK, (float*)wenvB, E, 192, 128, 128, 192, isq128, nullptr, act,
        nullptr, nullptr, nullptr, nullptr, nullptr, nullptr, nullptr, nullptr,
        nullptr, nullptr, nullptr, nullptr, 0, 0, N, E);
    // main SO2 -> msgs(bf16) + gv(bf16)
    mma_gemm_kernel<1,false><<<dim3(2, etile), 256, GEMM_SMEM>>>(
        esvB, w0mK, (float*)msgsB, E, 256, 320, 320, 256, isq576, nullptr, nullptr,
        ctr, nbr, (const float*)projB, nullptr, nullptr, nullptr, nullptr, (float*)gvB,
        nullptr, nullptr, nullptr, nullptr, 0, 0, N, E);
    // complex GEMM + rotation/gate -> msgv(bf16)
    mma_gemm_kernel<4,false><<<dim3(1, etile), 256, GEMM_SMEM4>>>(
        vfB, w1cK, (float*)msgvB, E, 128, 384, 384, 128, isq192, nullptr, nullptr,
        nullptr, nullptr, nullptr, Rbuf, (const float*)gvB, nullptr, nullptr, nullptr,
        nullptr, nullptr, nullptr, nullptr, 0, 0, N, E);
    // lps + env-weight + scatter -> aggs
    mma_gemm_kernel<2,false><<<dim3(1, etile), 256, GEMM_SMEM>>>(
        msgsB, lpwsK, nullptr, E, 128, 128, 128, 128, isq128, lpbs, nullptr,
        ctr, nullptr, nullptr, nullptr, nullptr, (const float*)wenvB, aggs, nullptr,
        nullptr, nullptr, nullptr, nullptr, 0, 0, N, E);
    // lpv + env-weight + scatter -> aggv
    mma_gemm_kernel<3,false><<<dim3(1, (3*E + 127)/128), 256, GEMM_SMEM>>>(
        msgvB, lpwvK, nullptr, 3*E, 64, 64, 64, 64, 0.125f, nullptr, nullptr,
        ctr, nullptr, nullptr, nullptr, nullptr, (const float*)wenvB, aggv, nullptr,
        nullptr, nullptr, nullptr, nullptr, 0, 0, N, E);
    // aggs|aggv -> bf16
    c2b_kernel<<<(int)(((size_t)N*320 + 255)/256), 256>>>(aggs, agsB, (size_t)N*320);
    // merged typed gs/tg: Nc=192 against wsc
    mma_gemm_kernel<5,false><<<dim3(2, 2, 64), 256, GEMM_SMEM>>>(
        agsB, wscK, (float*)gsB, N, 192, 128, 128, 64*192, n_ss, nullptr, nullptr,
        nullptr, nullptr, nullptr, nullptr, nullptr, nullptr, nullptr, tgb,
        nullptr, nullptr, offs, order, 192, 0, N, E);
    // typed, 3 planes: gvm = bf16(tg * (aggvB @ wvv[:,t,:] * n_vv))
    mma_gemm_kernel<7,false><<<dim3(3, 2, 64), 256, GEMM_SMEM>>>(
        agvB, wvvK, (float*)gvmB, N, 64, 64, 64, 64*64, n_vv, nullptr, nullptr,
        nullptr, nullptr, nullptr, nullptr, tgb, nullptr, nullptr, nullptr,
        nullptr, nullptr, offs, order, 64, (size_t)N*64, N, E);
    // final scalar: out[:,0:128]
    mma_gemm_kernel<8,false><<<dim3(1, ntile), 256, GEMM_SMEM>>>(
        gsB, ohlwK, (float*)d_out, N, 128, 128, 128, 128, isq128, ohlbs, nullptr,
        nullptr, nullptr, nullptr, nullptr, nullptr, nullptr, nullptr, nullptr,
        nf, resp, nullptr, nullptr, 0, 0, N, E);
    // final vector: out[:,128+3k+m]
    mma_gemm_kernel<9,false><<<dim3(3, ntile), 256, GEMM_SMEM>>>(
        gvmB, ohlvK, (float*)d_out, N, 64, 64, 64, 64, 0.125f, nullptr, nullptr,
        nullptr, nullptr, nullptr, nullptr, nullptr, nullptr, nullptr, nullptr,
        nf, resp, nullptr, nullptr, 0, (size_t)N*64, N, E);
}

// round 12
// speedup vs baseline: 4.1657x; 1.0621x over previous
#include <cuda_runtime.h>
#include <cuda_bf16.h>
#include <math.h>
#include <stdint.h>

static constexpr int NMAXN = 8000;
static constexpr int EMAX  = 96000;

// ---- fp32 scratch ----
static constexpr size_t NV_OFF   = 0;                                  // nv:   N x 192
static constexpr size_t R_OFF    = NV_OFF   + (size_t)NMAXN*192;       // R:    E x 9
static constexpr size_t AGGS_OFF = R_OFF    + (size_t)EMAX*9;          // aggs: N x 128
static constexpr size_t AGGV_OFF = AGGS_OFF + (size_t)NMAXN*128;       // aggv: 3 x N x 64
static constexpr size_t TG_OFF   = AGGV_OFF + (size_t)3*NMAXN*64;      // tg:   N x 64
static constexpr size_t TOTAL_F  = TG_OFF   + (size_t)NMAXN*64;
__device__ __align__(256) float g_buf[TOTAL_F];

// ---- bf16 scratch ----
static constexpr size_t NSB   = 0;
static constexpr size_t ESVB  = NSB   + (size_t)NMAXN*128;
static constexpr size_t VF12B = ESVB  + (size_t)EMAX*320;
static constexpr size_t MSGVB = VF12B + (size_t)EMAX*384;
static constexpr size_t LATB  = MSGVB + (size_t)3*EMAX*64;
static constexpr size_t GSB   = LATB  + (size_t)EMAX*128;
static constexpr size_t GVMB  = GSB   + (size_t)NMAXN*128;
static constexpr size_t AGSB  = GVMB  + (size_t)3*NMAXN*64;
static constexpr size_t AGVB  = AGSB  + (size_t)NMAXN*128;
static constexpr size_t PROJB = AGVB  + (size_t)3*NMAXN*64;            // proj: N x 512
static constexpr size_t GVB   = PROJB + (size_t)NMAXN*512;             // gv:   E x 128
static constexpr size_t WENVB = GVB   + (size_t)EMAX*128;              // wenv: E x 192
static constexpr size_t WCPT  = WENVB + (size_t)EMAX*192;              // 128K x 512N
static constexpr size_t W0MT  = WCPT  + (size_t)128*512;               // 320K x 256N
static constexpr size_t W1CT  = W0MT  + (size_t)320*256;               // 384K x 128N
static constexpr size_t ENVT  = W1CT  + (size_t)384*128;               // 128K x 192N
static constexpr size_t LPWST = ENVT  + (size_t)128*192;               // 128 x 128
static constexpr size_t LPWVT = LPWST + (size_t)128*128;               // 64 x 64
static constexpr size_t WSC   = LPWVT + (size_t)64*64;                 // 128u x 64t x 192
static constexpr size_t WVVT  = WSC   + (size_t)128*64*192;            // 64u x 64t x 64
static constexpr size_t OHLWT = WVVT  + (size_t)64*64*64;              // 128 x 128
static constexpr size_t OHLVT = OHLWT + (size_t)128*128;               // 64 x 64
static constexpr size_t TOTAL_B = OHLVT + (size_t)64*64;
__device__ __align__(256) __nv_bfloat16 g_bbuf[TOTAL_B];

__device__ int g_idx[2*EMAX];
__device__ int g_cnt[128];
__device__ int g_offs[65];
__device__ int g_order[NMAXN];

typedef __nv_bfloat16 bf16;
typedef __nv_bfloat162 bf162;
__device__ __forceinline__ bf162 f2b2(float a, float b) { return __floats2bfloat162_rn(a, b); }

// ---------------------------------------------------------------------------
__global__ void zero_kernel(float* __restrict__ p, size_t n) {
    size_t i = (size_t)blockIdx.x*blockDim.x + threadIdx.x;
    if (i < n) p[i] = 0.f;
}
__global__ void c2b_kernel(const float* __restrict__ in, bf16* __restrict__ out, size_t n) {
    size_t i = (size_t)blockIdx.x*blockDim.x + threadIdx.x;
    if (i < n) out[i] = __float2bfloat16(in[i]);
}
__global__ void count_kernel(const int* __restrict__ at, int* __restrict__ cnt, int N) {
    int n = blockIdx.x*blockDim.x + threadIdx.x;
    if (n < N) atomicAdd(&cnt[at[n]], 1);
}
__global__ void prefix_kernel(const int* __restrict__ cnt, int* __restrict__ offs) {
    if (threadIdx.x == 0) { int s = 0; for (int i = 0; i < 64; i++) { offs[i] = s; s += cnt[i]; } offs[64] = s; }
}
__global__ void order_kernel(const int* __restrict__ at, const int* __restrict__ offs,
                             int* __restrict__ cur, int* __restrict__ order, int N) {
    int n = blockIdx.x*blockDim.x + threadIdx.x;
    if (n < N) { int t = at[n]; order[offs[t] + atomicAdd(&cur[t], 1)] = n; }
}

// ---------------------------------------------------------------------------
// Fused weight-prep, 8 elements per thread, 16B stores.
__device__ __forceinline__ void copy8(const float* __restrict__ in, bf16* __restrict__ out, float sgn) {
    float4 a = *(const float4*)in, b = *(const float4*)(in + 4);
    bf162 h[4] = { f2b2(sgn*a.x, sgn*a.y), f2b2(sgn*a.z, sgn*a.w),
                   f2b2(sgn*b.x, sgn*b.y), f2b2(sgn*b.z, sgn*b.w) };
    *(uint4*)out = *(uint4*)h;
}
__global__ void prep_all_kernel(const float* __restrict__ w0,
                                const float* __restrict__ w1r, const float* __restrict__ w1i,
                                const float* __restrict__ envw, const float* __restrict__ lpws,
                                const float* __restrict__ lpwv, const float* __restrict__ ohwss,
                                const float* __restrict__ ohwsg, const float* __restrict__ ohwvv,
                                const float* __restrict__ ohlws, const float* __restrict__ ohlwv,
                                const float* __restrict__ latents, bf16* __restrict__ bb,
                                size_t latN) {
    size_t g8 = ((size_t)blockIdx.x*blockDim.x + threadIdx.x)*8;
    if (g8 >= 2097152 + latN) return;
    if (g8 < 65536) {                           // wcp [128k][512c]
        int i = (int)g8, k = i >> 9, c = i & 511;
        const float* s = (c < 256) ? w0 + (size_t)k*256 + c : w0 + (size_t)(256 + k)*256 + (c - 256);
        copy8(s, bb + WCPT + i, 1.f);
    } else if (g8 < 147456) {                   // w0m [320k][256c]
        int i = (int)(g8 - 65536), k = i >> 8, c = i & 255;
        int src = (k < 128) ? k + 128 : k + 256;
        copy8(w0 + (size_t)src*256 + c, bb + W0MT + i, 1.f);
    } else if (g8 < 196608) {                   // w1c [384r][128c]
        int i = (int)(g8 - 147456), r = i >> 7, c = i & 127;
        const float* s; float sgn = 1.f;
        if (r < 192) s = (c < 64) ? w1r + r*64 + c : w1i + r*64 + (c - 64);
        else { int r2 = r - 192; if (c < 64) { s = w1i + r2*64 + c; sgn = -1.f; } else s = w1r + r2*64 + (c - 64); }
        copy8(s, bb + W1CT + i, sgn);
    } else if (g8 < 221184) { int i = (int)(g8 - 196608); copy8(envw + i,  bb + ENVT  + i, 1.f);
    } else if (g8 < 237568) { int i = (int)(g8 - 221184); copy8(lpws + i,  bb + LPWST + i, 1.f);
    } else if (g8 < 241664) { int i = (int)(g8 - 237568); copy8(lpwv + i,  bb + LPWVT + i, 1.f);
    } else if (g8 < 1290240) {                  // wsc[:, :, 0:128] <- ohwss
        int i = (int)(g8 - 241664), ut = i >> 7, n = i & 127;
        copy8(ohwss + i, bb + WSC + (size_t)ut*192 + n, 1.f);
    } else if (g8 < 1814528) {                  // wsc[:, :, 128:192] <- ohwsg
        int i = (int)(g8 - 1290240), ut = i >> 6, gg = i & 63;
        copy8(ohwsg + i, bb + WSC + (size_t)ut*192 + 128 + gg, 1.f);
    } else if (g8 < 2076672) { int i = (int)(g8 - 1814528); copy8(ohwvv + i, bb + WVVT + i, 1.f);
    } else if (g8 < 2093056) { int i = (int)(g8 - 2076672); copy8(ohlws + i, bb + OHLWT + i, 1.f);
    } else if (g8 < 2097152) { int i = (int)(g8 - 2093056); copy8(ohlwv + i, bb + OHLVT + i, 1.f);
    } else {
        size_t i = g8 - 2097152;
        if (i + 8 <= latN) copy8(latents + i, bb + LATB + i, 1.f);
        else for (size_t j = i; j < latN; j++) bb[LATB + j] = __float2bfloat16(latents[j]);
    }
}

// ---------------------------------------------------------------------------
__global__ void node_ln_kernel(const float* __restrict__ nf, const float* __restrict__ ws,
                               const float* __restrict__ bs, const float* __restrict__ wv,
                               bf16* __restrict__ ns, float* __restrict__ nv, int N) {
    int node = (blockIdx.x*blockDim.x + threadIdx.x) >> 5;
    int lane = threadIdx.x & 31;
    if (node >= N) return;
    const float* row = nf + (size_t)node*320;
    float s[4]; float sum = 0.f;
#pragma unroll
    for (int i = 0; i < 4; i++) { s[i] = row[lane + 32*i]; sum += s[i]; }
#pragma unroll
    for (int o = 16; o; o >>= 1) sum += __shfl_xor_sync(~0u, sum, o);
    float mu = sum*(1.f/128.f), var = 0.f;
#pragma unroll
    for (int i = 0; i < 4; i++) { s[i] -= mu; var += s[i]*s[i]; }
#pragma unroll
    for (int o = 16; o; o >>= 1) var += __shfl_xor_sync(~0u, var, o);
    float rs = rsqrtf(var*(1.f/128.f) + 1e-8f);
#pragma unroll
    for (int i = 0; i < 4; i++) {
        int c = lane + 32*i;
        ns[(size_t)node*128 + c] = __float2bfloat16(s[i]*rs*ws[c] + bs[c]);
    }
    float v[6]; float vs = 0.f;
#pragma unroll
    for (int i = 0; i < 6; i++) { v[i] = row[128 + lane + 32*i]; vs += v[i]*v[i]; }
#pragma unroll
    for (int o = 16; o; o >>= 1) vs += __shfl_xor_sync(~0u, vs, o);
    float rv = rsqrtf(vs*(1.f/192.f) + 1e-8f);
#pragma unroll
    for (int i = 0; i < 6; i++) { int c = lane + 32*i; nv[(size_t)node*192 + c] = v[i]*rv*wv[c/3]; }
}

__global__ void edge_prep_kernel(const float* __restrict__ ef, const int* __restrict__ ei,
                                 const int* __restrict__ act, const float* __restrict__ evec,
                                 const float* __restrict__ ws, const float* __restrict__ bs,
                                 const float* __restrict__ wv, const float* __restrict__ nv,
                                 bf16* __restrict__ esv0, bf16* __restrict__ vf12,
                                 float* __restrict__ Rout, int* __restrict__ idx, int E, int Etot) {
    __shared__ float evs[8][192];
    int wi = threadIdx.x >> 5, lane = threadIdx.x & 31;
    int e = blockIdx.x*8 + wi;
    if (e >= E) return;
    int ae = act[e];
    int ctr = ei[ae], nbr = ei[Etot + ae];
    if (lane == 0) { idx[e] = ctr; idx[E + e] = nbr; }
    const float* row = ef + (size_t)e*320;

    float s[4]; float sum = 0.f;
#pragma unroll
    for (int i = 0; i < 4; i++) { s[i] = row[lane + 32*i]; sum += s[i]; }
#pragma unroll
    for (int o = 16; o; o >>= 1) sum += __shfl_xor_sync(~0u, sum, o);
    float mu = sum*(1.f/128.f), var = 0.f;
#pragma unroll
    for (int i = 0; i < 4; i++) { s[i] -= mu; var += s[i]*s[i]; }
#pragma unroll
    for (int o = 16; o; o >>= 1) var += __shfl_xor_sync(~0u, var, o);
    float rs = rsqrtf(var*(1.f/128.f) + 1e-8f);
    bf16* esv = esv0 + (size_t)e*320;
#pragma unroll
    for (int i = 0; i < 4; i++) { int c = lane + 32*i; esv[c] = __float2bfloat16(s[i]*rs*ws[c] + bs[c]); }

    float v[6]; float vs = 0.f;
#pragma unroll
    for (int i = 0; i < 6; i++) { v[i] = row[128 + lane + 32*i]; vs += v[i]*v[i]; }
#pragma unroll
    for (int o = 16; o; o >>= 1) vs += __shfl_xor_sync(~0u, vs, o);
    float rv = rsqrtf(vs*(1.f/192.f) + 1e-8f);
#pragma unroll
    for (int i = 0; i < 6; i++) { int c = lane + 32*i; evs[wi][c] = v[i]*rv*wv[c/3]; }
    __syncwarp();

    float e0 = evec[(size_t)ae*3], e1 = evec[(size_t)ae*3+1], e2 = evec[(size_t)ae*3+2];
    float rn = rsqrtf(e0*e0 + e1*e1 + e2*e2 + 1e-8f);
    float ax = e0*rn, ay = e1*rn, az = e2*rn;
    float refx = (fabsf(ax) < 0.9f) ? 1.f : 0.f, refy = 1.f - refx;
    float bx = -az*refy, by = az*refx, bz = ax*refy - ay*refx;
    float rb = rsqrtf(bx*bx + by*by + bz*bz + 1e-8f);
    bx *= rb; by *= rb; bz *= rb;
    float cx = ay*bz - az*by, cy = az*bx - ax*bz, cz = ax*by - ay*bx;
    if (lane == 0) {
        float* Rp = Rout + (size_t)e*9;
        Rp[0]=ax; Rp[1]=ay; Rp[2]=az; Rp[3]=bx; Rp[4]=by; Rp[5]=bz; Rp[6]=cx; Rp[7]=cy; Rp[8]=cz;
    }
    bf16* vf = vf12 + (size_t)e*384;
#pragma unroll
    for (int i = 0; i < 6; i++) {
        int u = lane + 32*i;
        float vx, vy, vz;
        if (u < 64)       { const float* p = nv + (size_t)ctr*192 + u*3;        vx=p[0]; vy=p[1]; vz=p[2]; }
        else if (u < 128) { const float* p = &evs[wi][(u-64)*3];                vx=p[0]; vy=p[1]; vz=p[2]; }
        else              { const float* p = nv + (size_t)nbr*192 + (u-128)*3;  vx=p[0]; vy=p[1]; vz=p[2]; }
        esv[128 + u] = __float2bfloat16(ax*vx + ay*vy + az*vz);
        vf[u]        = __float2bfloat16(bx*vx + by*vy + bz*vz);
        vf[192 + u]  = __float2bfloat16(cx*vx + cy*vy + cz*vz);
    }
}

// ---------------------------------------------------------------------------
// bf16 GEMM (m16n8k16), BK=32 stages, A [M,K] ldmatrix, B [K,N] ldmatrix.trans.
// MODE 10: bf16 C = A@B*scale
// MODE 1:  main SO2; bn=0: fused silu->staged tile->lps GEMM->env-weight scatter
//          bn=128: gate/vraw -> gv (bf16)
// MODE 3:  lpv scatter
// MODE 4:  complex GEMM + rotation/gate -> msgv
// MODE 5:  merged typed gs/tg; MODE 7: typed gvm; MODE 8/9: final + residual
static constexpr int ASUB = 6144;
static constexpr int BSUB = 4352;
static constexpr int ASTG = 2*ASUB;           // 12288
static constexpr int BSTG = 2*BSUB;           // 8704
static constexpr int STG  = ASTG + BSTG;      // 20992
static constexpr int GEMM_SMEM  = 3*STG;      // 62976
static constexpr int GEMM_SMEM1 = 8*ASUB + 8*BSUB;  // 83968 (MODE1 fused: staged A 49152 + lpws 34816)
static constexpr int GEMM_SMEM4 = 128*132*4;  // 67584

template<int MODE, bool GATHER>
__global__ __launch_bounds__(256, 2)
void mma_gemm_kernel(const bf16* __restrict__ A, const bf16* __restrict__ B,
                     float* __restrict__ C, int M, int Nc, int K, int lda, int ldb,
                     float scale, const float* __restrict__ bias, const int* __restrict__ rowidx,
                     const int* __restrict__ ctr, const int* __restrict__ nbr,
                     const float* __restrict__ proj, const float* __restrict__ Rrot,
                     const float* __restrict__ gvbuf, const float* __restrict__ wenv,
                     float* __restrict__ agg, float* __restrict__ aux,
                     const float* __restrict__ nf, const float* __restrict__ resp,
                     const int* __restrict__ offs, const int* __restrict__ order,
                     int tOffB, size_t aplane, int Nnodes, int E,
                     const bf16* __restrict__ B2) {
    constexpr bool TYPED = (MODE == 5 || MODE == 7);
    extern __shared__ char smc[];
    const int tid = threadIdx.x, lane = tid & 31, wid = tid >> 5;
    const int g = lane >> 2, t = lane & 3;
    const int wm = (wid >> 2)*64, wn = (wid & 3)*32;

    int mplane = 0, bn;
    if (MODE == 7 || MODE == 9) { mplane = blockIdx.x; bn = 0; } else bn = blockIdx.x*128;
    const int bm = blockIdx.y*128;

    int Mloc = M, rowbase = 0, typ = 0;
    if (TYPED) {
        typ = blockIdx.z;
        rowbase = offs[typ];
        Mloc = offs[typ+1] - rowbase;
        if (Mloc == 0 || bm >= Mloc) return;
    }
    const bf16* Ause = A + (size_t)mplane*aplane;
    const bf16* Buse = B + (TYPED ? (size_t)typ*tOffB : 0);

    int arow = tid >> 1, ahalf = tid & 1;
    int r = bm + arow, gr;
    if (TYPED) { if (r >= Mloc) r = Mloc - 1; gr = order[rowbase + r]; }
    else       { if (r >= M) r = M - 1;       gr = GATHER ? rowidx[r] : r; }
    const bf16* asrc = Ause + (size_t)gr*lda + ahalf*8;
    int brow = tid >> 4, bc16 = tid & 15;
    int bcol = bn + bc16*8;
    int bby = (bcol < Nc) ? 16 : 0;
    if (bcol >= Nc) bcol = Nc - 8;
    const bf16* bsrc = Buse + (size_t)brow*ldb + bcol;

    uint32_t sbase = (uint32_t)__cvta_generic_to_shared(smc);
    uint32_t adst = sbase + arow*48 + ahalf*16;
    uint32_t bdst = sbase + ASTG + brow*272 + bc16*16;

    const int q = lane >> 3, rr8 = lane & 7;
    uint32_t aLd = sbase + ((wm + (q & 1)*8 + rr8)*24 + (q >> 1)*8)*2;
    uint32_t bLd = sbase + ASTG + ((q & 1)*8 + rr8)*272 + (wn + (q >> 1)*8)*2;

    const int kT = K >> 5;
    auto loadStage = [&](int slot, int k0) {
        uint32_t so = slot*STG;
        asm volatile("cp.async.cg.shared.global [%0], [%1], 16;"
                     :: "r"(adst + so), "l"(asrc + k0) : "memory");
        asm volatile("cp.async.cg.shared.global [%0], [%1], 16;"
                     :: "r"(adst + so + ASUB), "l"(asrc + k0 + 16) : "memory");
        asm volatile("cp.async.cg.shared.global [%0], [%1], 16, %2;"
                     :: "r"(bdst + so), "l"(bsrc + (size_t)k0*ldb), "r"(bby) : "memory");
        asm volatile("cp.async.cg.shared.global [%0], [%1], 16, %2;"
                     :: "r"(bdst + so + BSUB), "l"(bsrc + (size_t)(k0+16)*ldb), "r"(bby) : "memory");
        asm volatile("cp.async.commit_group;");
    };

    float acc[4][4][4];
#pragma unroll
    for (int mi = 0; mi < 4; mi++)
#pragma unroll
        for (int ni = 0; ni < 4; ni++)
#pragma unroll
            for (int j = 0; j < 4; j++) acc[mi][ni][j] = 0.f;

    loadStage(0, 0);
    if (kT > 1) loadStage(1, 32); else asm volatile("cp.async.commit_group;");

    for (int kt = 0; kt < kT; kt++) {
        asm volatile("cp.async.wait_group 1;");
        __syncthreads();
        int pf = kt + 2;
        if (pf < kT) loadStage(pf % 3, pf*32);
        else asm volatile("cp.async.commit_group;");

        uint32_t so = (kt % 3)*STG;
#pragma unroll
        for (int sub = 0; sub < 2; sub++) {
            uint32_t offA = so + sub*ASUB, offB = so + sub*BSUB;
            uint32_t af[4][4], bf[4][2];
#pragma unroll
            for (int mi = 0; mi < 4; mi++)
                asm volatile("ldmatrix.sync.aligned.m8n8.x4.shared.b16 {%0,%1,%2,%3}, [%4];"
                    : "=r"(af[mi][0]), "=r"(af[mi][1]), "=r"(af[mi][2]), "=r"(af[mi][3])
                    : "r"(aLd + offA + mi*16*48));
#pragma unroll
            for (int np = 0; np < 2; np++)
                asm volatile("ldmatrix.sync.aligned.m8n8.x4.trans.shared.b16 {%0,%1,%2,%3}, [%4];"
                    : "=r"(bf[2*np][0]), "=r"(bf[2*np][1]), "=r"(bf[2*np+1][0]), "=r"(bf[2*np+1][1])
                    : "r"(bLd + offB + np*32));
#pragma unroll
            for (int mi = 0; mi < 4; mi++)
#pragma unroll
                for (int ni = 0; ni < 4; ni++) {
                    asm volatile(
                        "mma.sync.aligned.m16n8k16.row.col.f32.bf16.bf16.f32 "
                        "{%0,%1,%2,%3}, {%4,%5,%6,%7}, {%8,%9}, {%0,%1,%2,%3};"
                        : "+f"(acc[mi][ni][0]), "+f"(acc[mi][ni][1]),
                          "+f"(acc[mi][ni][2]), "+f"(acc[mi][ni][3])
                        : "r"(af[mi][0]), "r"(af[mi][1]), "r"(af[mi][2]), "r"(af[mi][3]),
                          "r"(bf[ni][0]), "r"(bf[ni][1]));
                }
        }
    }

    // ---------------- epilogue ----------------
    const float INV = 0.28867513459481287f;

    if (MODE == 1 && bn == 0) {
        // Fused: silu -> staged tile -> lps GEMM (K=128) -> env-weight scatter.
        __syncthreads();   // pipeline smem now reusable
        // issue lpws load early (region beyond staged A)
        uint32_t lpB = sbase + 8*ASUB;
#pragma unroll
        for (int it = 0; it < 8; it++) {
            int id = tid + 256*it;           // 2048 chunks: k=id>>4, c16=id&15
            int k = id >> 4, c16 = id & 15;
            asm volatile("cp.async.cg.shared.global [%0], [%1], 16;"
                :: "r"(lpB + (k >> 4)*BSUB + (k & 15)*272 + c16*16),
                   "l"(B2 + (size_t)k*128 + c16*8) : "memory");
        }
        asm volatile("cp.async.commit_group;");
        // stage silu(msgs) tile into [0, 8*ASUB)
        const bf16* pcB = (const bf16*)proj;
#pragma unroll
        for (int mi = 0; mi < 4; mi++)
#pragma unroll
            for (int h = 0; h < 2; h++) {
                int rw = wm + mi*16 + g + 8*h;
                int row = bm + rw;
                const bf16* pc = pcB + (size_t)ctr[row]*512;
                const bf16* pn = pcB + (size_t)nbr[row]*512 + 256;
#pragma unroll
                for (int ni = 0; ni < 4; ni++) {
                    int c = wn + ni*8 + 2*t;
                    float2 pcv = __bfloat1622float2(*(const bf162*)&pc[c]);
                    float2 pnv = __bfloat1622float2(*(const bf162*)&pn[c]);
                    float v0 = (acc[mi][ni][2*h]   + pcv.x + pnv.x)*scale;
                    float v1 = (acc[mi][ni][2*h+1] + pcv.y + pnv.y)*scale;
                    bf162 m = f2b2(v0/(1.f+expf(-v0)), v1/(1.f+expf(-v1)));
                    *(bf162*)(smc + (size_t)(c >> 4)*ASUB + rw*48 + (c & 15)*2) = m;
                }
            }
        asm volatile("cp.async.wait_group 0;");
        __syncthreads();
        // second GEMM: staged[128x128] @ lpws[128x128]
#pragma unroll
        for (int mi = 0; mi < 4; mi++)
#pragma unroll
            for (int ni = 0; ni < 4; ni++)
#pragma unroll
                for (int j = 0; j < 4; j++) acc[mi][ni][j] = 0.f;
        uint32_t aLd2 = sbase + ((wm + (q & 1)*8 + rr8)*24 + (q >> 1)*8)*2;
        uint32_t bLd2 = sbase + 8*ASUB + ((q & 1)*8 + rr8)*272 + (wn + (q >> 1)*8)*2;
#pragma unroll
        for (int ks = 0; ks < 8; ks++) {
            uint32_t af[4][4], bf[4][2];
#pragma unroll
            for (int mi = 0; mi < 4; mi++)
                asm volatile("ldmatrix.sync.aligned.m8n8.x4.shared.b16 {%0,%1,%2,%3}, [%4];"
                    : "=r"(af[mi][0]), "=r"(af[mi][1]), "=r"(af[mi][2]), "=r"(af[mi][3])
                    : "r"(aLd2 + ks*ASUB + mi*16*48));
#pragma unroll
            for (int np = 0; np < 2; np++)
                asm volatile("ldmatrix.sync.aligned.m8n8.x4.trans.shared.b16 {%0,%1,%2,%3}, [%4];"
                    : "=r"(bf[2*np][0]), "=r"(bf[2*np][1]), "=r"(bf[2*np+1][0]), "=r"(bf[2*np+1][1])
                    : "r"(bLd2 + ks*BSUB + np*32));
#pragma unroll
            for (int mi = 0; mi < 4; mi++)
#pragma unroll
                for (int ni = 0; ni < 4; ni++) {
                    asm volatile(
                        "mma.sync.aligned.m16n8k16.row.col.f32.bf16.bf16.f32 "
                        "{%0,%1,%2,%3}, {%4,%5,%6,%7}, {%8,%9}, {%0,%1,%2,%3};"
                        : "+f"(acc[mi][ni][0]), "+f"(acc[mi][ni][1]),
                          "+f"(acc[mi][ni][2]), "+f"(acc[mi][ni][3])
                        : "r"(af[mi][0]), "r"(af[mi][1]), "r"(af[mi][2]), "r"(af[mi][3]),
                          "r"(bf[ni][0]), "r"(bf[ni][1]));
                }
        }
        // scatter: lps = acc/sqrt(128) + lpbs; * wenv * INV -> aggs[ctr]
        const float isq128 = 0.08838834764831845f;
#pragma unroll
        for (int mi = 0; mi < 4; mi++)
#pragma unroll
            for (int h = 0; h < 2; h++) {
                int row = bm + wm + mi*16 + g + 8*h;
                float* ap = agg + (size_t)ctr[row]*128;
                const bf16* we = (const bf16*)wenv + (size_t)row*192;
#pragma unroll
                for (int ni = 0; ni < 4; ni++) {
                    int c = wn + ni*8 + 2*t;
                    float2 w = __bfloat1622float2(*(const bf162*)&we[c]);
                    atomicAdd(&ap[c],   (acc[mi][ni][2*h]  *isq128 + bias[c])  *w.x*INV);
                    atomicAdd(&ap[c+1], (acc[mi][ni][2*h+1]*isq128 + bias[c+1])*w.y*INV);
                }
            }
        return;
    }

    if (MODE == 4) {
        __syncthreads();
        float* Vs = (float*)smc;
#pragma unroll
        for (int mi = 0; mi < 4; mi++)
#pragma unroll
            for (int h = 0; h < 2; h++) {
                int rw = wm + mi*16 + g + 8*h;
#pragma unroll
                for (int ni = 0; ni < 4; ni++) {
                    int c = wn + ni*8 + 2*t;
                    *(float2*)&Vs[rw*132 + c] = make_float2(acc[mi][ni][2*h]*scale, acc[mi][ni][2*h+1]*scale);
                }
            }
        __syncthreads();
        bf16* Cb = (bf16*)C;
        const bf16* gvB = (const bf16*)gvbuf;
        for (int rw = wid; rw < 128; rw += 8) {
            int e = bm + rw;
            const float* Rp = Rrot + (size_t)e*9;
            float R0=Rp[0],R1=Rp[1],R2=Rp[2],R3=Rp[3],R4=Rp[4],R5=Rp[5],R6=Rp[6],R7=Rp[7],R8=Rp[8];
            const bf16* gvp = gvB + (size_t)e*128;
#pragma unroll
            for (int i = 0; i < 2; i++) {
                int u = lane + 32*i;
                float sg = __bfloat162float(gvp[u]), i0 = __bfloat162float(gvp[64 + u]);
                float i1 = Vs[rw*132 + u], i2 = Vs[rw*132 + 64 + u];
                Cb[(size_t)0*E*64 + (size_t)e*64 + u] = __float2bfloat16(sg*(R0*i0 + R3*i1 + R6*i2));
                Cb[(size_t)1*E*64 + (size_t)e*64 + u] = __float2bfloat16(sg*(R1*i0 + R4*i1 + R7*i2));
                Cb[(size_t)2*E*64 + (size_t)e*64 + u] = __float2bfloat16(sg*(R2*i0 + R5*i1 + R8*i2));
            }
        }
        return;
    }

    float alpha = 0.f, beta = 0.f;
    if (MODE == 8 || MODE == 9) { alpha = 1.f/(1.f + expf(-resp[0])); beta = 1.f - alpha; }

#pragma unroll
    for (int mi = 0; mi < 4; mi++) {
        int r0 = bm + wm + mi*16 + g;
#pragma unroll
        for (int h = 0; h < 2; h++) {
            int row = r0 + 8*h;
            if (row >= (TYPED ? Mloc : M)) continue;
            if (MODE == 10) {
                bf16* Cb = (bf16*)C;
#pragma unroll
                for (int ni = 0; ni < 4; ni++) {
                    int c = bn + wn + ni*8 + 2*t;
                    if (c >= Nc) continue;
                    *(bf162*)&Cb[(size_t)row*Nc + c] =
                        f2b2(acc[mi][ni][2*h]*scale, acc[mi][ni][2*h+1]*scale);
                }
            } else if (MODE == 1) {   // bn == 128: gate/vraw -> gv
                const bf16* pc = (const bf16*)proj + (size_t)ctr[row]*512;
                const bf16* pn = (const bf16*)proj + (size_t)nbr[row]*512 + 256;
                bf16* auxB = (bf16*)aux;
#pragma unroll
                for (int ni = 0; ni < 4; ni++) {
                    int c = bn + wn + ni*8 + 2*t;
                    float2 pcv = __bfloat1622float2(*(const bf162*)&pc[c]);
                    float2 pnv = __bfloat1622float2(*(const bf162*)&pn[c]);
                    float v0 = (acc[mi][ni][2*h]   + pcv.x + pnv.x)*scale;
                    float v1 = (acc[mi][ni][2*h+1] + pcv.y + pnv.y)*scale;
                    if (c < 192) {
                        *(bf162*)&auxB[(size_t)row*128 + c-128] =
                            f2b2(1.f/(1.f+expf(-v0)), 1.f/(1.f+expf(-v1)));
                    } else {
                        *(bf162*)&auxB[(size_t)row*128 + c-128] = f2b2(v0, v1);
                    }
                }
            } else if (MODE == 3) {
                int m = row / E, e = row - m*E;
                float* ap = agg + (size_t)m*Nnodes*64 + (size_t)ctr[e]*64;
                const bf16* we = (const bf16*)wenv + (size_t)e*192 + 128;
#pragma unroll
                for (int ni = 0; ni < 4; ni++) {
                    int c = bn + wn + ni*8 + 2*t;
                    if (c >= Nc) continue;
                    float2 w = __bfloat1622float2(*(const bf162*)&we[c]);
                    atomicAdd(&ap[c],   acc[mi][ni][2*h]  *scale*w.x*INV);
                    atomicAdd(&ap[c+1], acc[mi][ni][2*h+1]*scale*w.y*INV);
                }
            } else if (MODE == 5) {
                int node = order[rowbase + row];
                bf16* Cb = (bf16*)C;
#pragma unroll
                for (int ni = 0; ni < 4; ni++) {
                    int c = bn + wn + ni*8 + 2*t;
                    float v0 = acc[mi][ni][2*h]*scale, v1 = acc[mi][ni][2*h+1]*scale;
                    if (c < 128) {
                        *(bf162*)&Cb[(size_t)node*128 + c] = f2b2(v0/(1.f+expf(-v0)), v1/(1.f+expf(-v1)));
                    } else if (c < 192) {
                        *(float2*)&aux[(size_t)node*64 + c-128] =
                            make_float2(1.f/(1.f+expf(-v0)), 1.f/(1.f+expf(-v1)));
                    }
                }
            } else if (MODE == 7) {
                int node = order[rowbase + row];
                const float* tgp = gvbuf + (size_t)node*64;
                bf16* Cb = (bf16*)C;
#pragma unroll
                for (int ni = 0; ni < 4; ni++) {
                    int c = wn + ni*8 + 2*t;
                    if (c >= Nc) continue;
                    *(bf162*)&Cb[(size_t)mplane*aplane + (size_t)node*64 + c] =
                        f2b2(acc[mi][ni][2*h]*scale*tgp[c], acc[mi][ni][2*h+1]*scale*tgp[c+1]);
                }
            } else if (MODE == 8) {
#pragma unroll
                for (int ni = 0; ni < 4; ni++) {
                    int c = wn + ni*8 + 2*t;
                    float a0 = acc[mi][ni][2*h]*scale + bias[c];
                    float a1 = acc[mi][ni][2*h+1]*scale + bias[c+1];
                    *(float2*)&C[(size_t)row*320 + c] =
                        make_float2(alpha*nf[(size_t)row*320 + c] + beta*a0,
                                    alpha*nf[(size_t)row*320 + c + 1] + beta*a1);
                }
            } else if (MODE == 9) {
#pragma unroll
                for (int ni = 0; ni < 4; ni++) {
                    int c = wn + ni*8 + 2*t;
                    if (c >= Nc) continue;
                    size_t o0 = (size_t)row*320 + 128 + 3*c + mplane;
                    size_t o1 = (size_t)row*320 + 128 + 3*(c+1) + mplane;
                    C[o0] = alpha*nf[o0] + beta*acc[mi][ni][2*h]*scale;
                    C[o1] = alpha*nf[o1] + beta*acc[mi][ni][2*h+1]*scale;
                }
            }
        }
    }
}

// ---------------------------------------------------------------------------
extern "C" void kernel_launch(void* const* d_in, const int* in_sizes, int n_in,
                              void* d_out, int out_size) {
    const float* latents = (const float*)d_in[0];
    const float* nf    = (const float*)d_in[1];
    const float* ef    = (const float*)d_in[2];
    const int*   at    = (const int*)  d_in[3];
    const int*   ei    = (const int*)  d_in[5];
    const float* evec  = (const float*)d_in[6];
    const int*   act   = (const int*)  d_in[7];
    const float* snws  = (const float*)d_in[8];
    const float* snbs  = (const float*)d_in[9];
    const float* snwv  = (const float*)d_in[10];
    const float* sews  = (const float*)d_in[11];
    const float* sebs  = (const float*)d_in[12];
    const float* sewv  = (const float*)d_in[13];
    const float* so2w0 = (const float*)d_in[14];
    const float* w1r   = (const float*)d_in[15];
    const float* w1i   = (const float*)d_in[16];
    const float* envw  = (const float*)d_in[17];
    const float* lpws  = (const float*)d_in[18];
    const float* lpbs  = (const float*)d_in[19];
    const float* lpwv  = (const float*)d_in[20];
    const float* ohwss = (const float*)d_in[21];
    const float* ohwsg = (const float*)d_in[22];
    const float* ohwvv = (const float*)d_in[23];
    const float* ohlws = (const float*)d_in[24];
    const float* ohlbs = (const float*)d_in[25];
    const float* ohlwv = (const float*)d_in[26];
    const float* resp  = (const float*)d_in[27];

    int N = in_sizes[1]/320, E = in_sizes[7], Etot = in_sizes[5]/2;
    size_t latN = (size_t)in_sizes[0];

    float* fb = nullptr;  cudaGetSymbolAddress((void**)&fb, g_buf);
    bf16* bb = nullptr;   cudaGetSymbolAddress((void**)&bb, g_bbuf);
    int* idx = nullptr;   cudaGetSymbolAddress((void**)&idx, g_idx);
    int* cnt = nullptr;   cudaGetSymbolAddress((void**)&cnt, g_cnt);
    int* offs = nullptr;  cudaGetSymbolAddress((void**)&offs, g_offs);
    int* order = nullptr; cudaGetSymbolAddress((void**)&order, g_order);

    float *nv = fb+NV_OFF, *Rbuf = fb+R_OFF, *aggs = fb+AGGS_OFF, *aggv = fb+AGGV_OFF, *tgb = fb+TG_OFF;
    bf16 *nsB = bb+NSB, *esvB = bb+ESVB, *vfB = bb+VF12B, *msgvB = bb+MSGVB,
         *latB = bb+LATB, *gsB = bb+GSB, *gvmB = bb+GVMB, *agsB = bb+AGSB, *agvB = bb+AGVB,
         *projB = bb+PROJB, *gvB = bb+GVB, *wenvB = bb+WENVB,
         *wcpK = bb+WCPT, *w0mK = bb+W0MT, *w1cK = bb+W1CT, *envK = bb+ENVT, *lpwsK = bb+LPWST,
         *lpwvK = bb+LPWVT, *wscK = bb+WSC, *wvvK = bb+WVVT, *ohlwK = bb+OHLWT, *ohlvK = bb+OHLVT;
    int *ctr = idx, *nbr = idx + E;

    const float isq576 = 0.041666666666666664f, isq192 = 0.07216878364870323f,
                isq128 = 0.08838834764831845f, n_ss = 0.011048543456039806f, n_vv = 0.015625f;

    cudaFuncSetAttribute(mma_gemm_kernel<10,false>, cudaFuncAttributeMaxDynamicSharedMemorySize, GEMM_SMEM);
    cudaFuncSetAttribute(mma_gemm_kernel<10,true>,  cudaFuncAttributeMaxDynamicSharedMemorySize, GEMM_SMEM);
    cudaFuncSetAttribute(mma_gemm_kernel<1,false>, cudaFuncAttributeMaxDynamicSharedMemorySize, GEMM_SMEM1);
    cudaFuncSetAttribute(mma_gemm_kernel<3,false>, cudaFuncAttributeMaxDynamicSharedMemorySize, GEMM_SMEM);
    cudaFuncSetAttribute(mma_gemm_kernel<4,false>, cudaFuncAttributeMaxDynamicSharedMemorySize, GEMM_SMEM4);
    cudaFuncSetAttribute(mma_gemm_kernel<5,false>, cudaFuncAttributeMaxDynamicSharedMemorySize, GEMM_SMEM);
    cudaFuncSetAttribute(mma_gemm_kernel<7,false>, cudaFuncAttributeMaxDynamicSharedMemorySize, GEMM_SMEM);
    cudaFuncSetAttribute(mma_gemm_kernel<8,false>, cudaFuncAttributeMaxDynamicSharedMemorySize, GEMM_SMEM);
    cudaFuncSetAttribute(mma_gemm_kernel<9,false>, cudaFuncAttributeMaxDynamicSharedMemorySize, GEMM_SMEM);

    int etile = (E + 127)/128, ntile = (N + 127)/128;

    zero_kernel<<<(int)(((size_t)N*320 + 255)/256), 256>>>(aggs, (size_t)N*320);
    zero_kernel<<<1, 128>>>((float*)cnt, 128);
    node_ln_kernel<<<(N + 7)/8, 256>>>(nf, snws, snbs, snwv, nsB, nv, N);
    {
        size_t tot8 = (2097152 + latN + 7)/8;
        prep_all_kernel<<<(int)((tot8 + 255)/256), 256>>>(
            so2w0, w1r, w1i, envw, lpws, lpwv, ohwss, ohwsg, ohwvv, ohlws, ohlwv,
            latents, bb, latN);
    }
    count_kernel<<<(N + 255)/256, 256>>>(at, cnt, N);
    prefix_kernel<<<1, 32>>>(cnt, offs);
    order_kernel<<<(N + 255)/256, 256>>>(at, offs, cnt + 64, order, N);
    edge_prep_kernel<<<(E + 7)/8, 256>>>(ef, ei, act, evec, sews, sebs, sewv,
                                         nv, esvB, vfB, Rbuf, idx, E, Etot);

    // proj = ns @ wcp  (N x 512, bf16 out)
    mma_gemm_kernel<10,false><<<dim3(4, ntile), 256, GEMM_SMEM>>>(
        nsB, wcpK, (float*)projB, N, 512, 128, 128, 512, 1.0f, nullptr, nullptr,
        nullptr, nullptr, nullptr, nullptr, nullptr, nullptr, nullptr, nullptr,
        nullptr, nullptr, nullptr, nullptr, 0, 0, N, E, nullptr);
    // wenv = latB[act] @ env / sqrt(128)  (bf16 out)
    mma_gemm_kernel<10,true><<<dim3(2, etile), 256, GEMM_SMEM>>>(
        latB, envK, (float*)wenvB, E, 192, 128, 128, 192, isq128, nullptr, act,
        nullptr, nullptr, nullptr, nullptr, nullptr, nullptr, nullptr, nullptr,
        nullptr, nullptr, nullptr, nullptr, 0, 0, N, E, nullptr);
    // main SO2; bn=0: fused silu+lps GEMM+scatter; bn=128: gv
    mma_gemm_kernel<1,false><<<dim3(2, etile), 256, GEMM_SMEM1>>>(
        esvB, w0mK, nullptr, E, 256, 320, 320, 256, isq576, lpbs, nullptr,
        ctr, nbr, (const float*)projB, nullptr, nullptr, (const float*)wenvB, aggs, (float*)gvB,
        nullptr, nullptr, nullptr, nullptr, 0, 0, N, E, lpwsK);
    // complex GEMM + rotation/gate -> msgv(bf16)
    mma_gemm_kernel<4,false><<<dim3(1, etile), 256, GEMM_SMEM4>>>(
        vfB, w1cK, (float*)msgvB, E, 128, 384, 384, 128, isq192, nullptr, nullptr,
        nullptr, nullptr, nullptr, Rbuf, (const float*)gvB, nullptr, nullptr, nullptr,
        nullptr, nullptr, nullptr, nullptr, 0, 0, N, E, nullptr);
    // lpv + env-weight + scatter -> aggv
    mma_gemm_kernel<3,false><<<dim3(1, (3*E + 127)/128), 256, GEMM_SMEM>>>(
        msgvB, lpwvK, nullptr, 3*E, 64, 64, 64, 64, 0.125f, nullptr, nullptr,
        ctr, nullptr, nullptr, nullptr, nullptr, (const float*)wenvB, aggv, nullptr,
        nullptr, nullptr, nullptr, nullptr, 0, 0, N, E, nullptr);
    // aggs|aggv -> bf16
    c2b_kernel<<<(int)(((size_t)N*320 + 255)/256), 256>>>(aggs, agsB, (size_t)N*320);
    // merged typed gs/tg: Nc=192 against wsc
    mma_gemm_kernel<5,false><<<dim3(2, 2, 64), 256, GEMM_SMEM>>>(
        agsB, wscK, (float*)gsB, N, 192, 128, 128, 64*192, n_ss, nullptr, nullptr,
        nullptr, nullptr, nullptr, nullptr, nullptr, nullptr, nullptr, tgb,
        nullptr, nullptr, offs, order, 192, 0, N, E, nullptr);
    // typed, 3 planes: gvm = bf16(tg * (aggvB @ wvv[:,t,:] * n_vv))
    mma_gemm_kernel<7,false><<<dim3(3, 2, 64), 256, GEMM_SMEM>>>(
        agvB, wvvK, (float*)gvmB, N, 64, 64, 64, 64*64, n_vv, nullptr, nullptr,
        nullptr, nullptr, nullptr, nullptr, tgb, nullptr, nullptr, nullptr,
        nullptr, nullptr, offs, order, 64, (size_t)N*64, N, E, nullptr);
    // final scalar: out[:,0:128]
    mma_gemm_kernel<8,false><<<dim3(1, ntile), 256, GEMM_SMEM>>>(
        gsB, ohlwK, (float*)d_out, N, 128, 128, 128, 128, isq128, ohlbs, nullptr,
        nullptr, nullptr, nullptr, nullptr, nullptr, nullptr, nullptr, nullptr,
        nf, resp, nullptr, nullptr, 0, 0, N, E, nullptr);
    // final vector: out[:,128+3k+m]
    mma_gemm_kernel<9,false><<<dim3(3, ntile), 256, GEMM_SMEM>>>(
        gvmB, ohlvK, (float*)d_out, N, 64, 64, 64, 64, 0.125f, nullptr, nullptr,
        nullptr, nullptr, nullptr, nullptr, nullptr, nullptr, nullptr, nullptr,
        nf, resp, nullptr, nullptr, 0, (size_t)N*64, N, E, nullptr);
}